// round 1
// baseline (speedup 1.0000x reference)
#include <cuda_runtime.h>

#define NH   16
#define HD   64
#define CD   1024
#define BB   4
#define HH   56
#define WW   28
#define NN   1568          // HH*WW
#define BHN  64            // BB*NH
#define BN   6272          // BB*NN
#define QSCALE 0.125f      // 64^-0.5

// ---------------- scratch (device globals; no allocations allowed) ----------
__device__ float g_q[BHN * NN * HD];
__device__ float g_k[BHN * NN * HD];
__device__ float g_v[BHN * NN * HD];
__device__ float g_relh[BHN * NN * HH];
__device__ float g_relw[BHN * NN * WW];
__device__ float g_ao[BHN * NN * HD];
__device__ float g_wT[CD * 3 * CD];   // qkv_w transposed: [1024][3072]
__device__ float g_pwT[CD * CD];      // proj_w transposed: [1024][1024]

// ---------------- transpose: out[c][r] = in[r][c] ---------------------------
template <int DST>
__global__ void __launch_bounds__(256) transpose_k(const float* __restrict__ in,
                                                   int R, int C) {
    float* out = (DST == 0) ? g_wT : g_pwT;
    __shared__ float tile[32][33];
    int cbase = blockIdx.x * 32;
    int rbase = blockIdx.y * 32;
    int c = cbase + threadIdx.x;
    for (int j = threadIdx.y; j < 32; j += 8) {
        int r = rbase + j;
        tile[j][threadIdx.x] = (r < R && c < C) ? in[r * C + c] : 0.f;
    }
    __syncthreads();
    int cc = rbase + threadIdx.x;   // output col = original row
    for (int j = threadIdx.y; j < 32; j += 8) {
        int orow = cbase + j;       // output row = original col
        if (orow < C && cc < R) out[orow * R + cc] = tile[threadIdx.x][j];
    }
}

// ---------------- SGEMM 128x128x8, 256 thr, 8x8 microtile -------------------
// MODE 0: A = hidden[6272,1024], B = g_wT[1024,3072], +qkv_b, scatter -> q/k/v
// MODE 1: A = gather(g_ao) [6272,1024], B = g_pwT[1024,1024], +proj_b -> Cout
template <int MODE>
__global__ void __launch_bounds__(256) sgemm_kernel(const float* __restrict__ A,
                                                    const float* __restrict__ bias,
                                                    float* __restrict__ Cout) {
    const float* Bg = (MODE == 0) ? g_wT : g_pwT;
    const int ldb = (MODE == 0) ? 3 * CD : CD;

    __shared__ float As[8][128];
    __shared__ float Bs[8][128];

    const int tid  = threadIdx.x;
    const int m0   = blockIdx.y * 128;
    const int j0   = blockIdx.x * 128;
    const int row0 = (tid >> 4) << 3;   // 0..120
    const int col0 = (tid & 15) << 3;   // 0..120

    // A-tile loader coords: each thread loads one float4 along k
    const int m_l = tid >> 1;           // 0..127
    const int kc  = (tid & 1) << 2;     // 0 or 4
    // B-tile loader coords
    const int brow = tid >> 5;          // 0..7
    const int bcol = (tid & 31) << 2;   // 0..124

    // precompute gather coords for MODE 1
    int b_ = 0, n_ = 0;
    const float* arow_ptr = nullptr;
    if (MODE == 0) {
        arow_ptr = A + (size_t)(m0 + m_l) * CD;
    } else {
        int m = m0 + m_l;
        b_ = m / NN;
        n_ = m - b_ * NN;
    }

    float acc[8][8];
#pragma unroll
    for (int i = 0; i < 8; i++)
#pragma unroll
        for (int j = 0; j < 8; j++) acc[i][j] = 0.f;

    for (int k0 = 0; k0 < CD; k0 += 8) {
        float4 a4;
        if (MODE == 0) {
            a4 = *(const float4*)(arow_ptr + k0 + kc);
        } else {
            int k = k0 + kc;
            int head = k >> 6;
            int d = k & 63;
            a4 = *(const float4*)&g_ao[(((b_ * NH + head) * NN) + n_) * HD + d];
        }
        As[kc + 0][m_l] = a4.x;
        As[kc + 1][m_l] = a4.y;
        As[kc + 2][m_l] = a4.z;
        As[kc + 3][m_l] = a4.w;

        float4 b4 = *(const float4*)(Bg + (size_t)(k0 + brow) * ldb + j0 + bcol);
        *(float4*)&Bs[brow][bcol] = b4;

        __syncthreads();
#pragma unroll
        for (int kk = 0; kk < 8; kk++) {
            float ar[8], br[8];
            *(float4*)&ar[0] = *(const float4*)&As[kk][row0];
            *(float4*)&ar[4] = *(const float4*)&As[kk][row0 + 4];
            *(float4*)&br[0] = *(const float4*)&Bs[kk][col0];
            *(float4*)&br[4] = *(const float4*)&Bs[kk][col0 + 4];
#pragma unroll
            for (int i = 0; i < 8; i++)
#pragma unroll
                for (int j = 0; j < 8; j++) acc[i][j] += ar[i] * br[j];
        }
        __syncthreads();
    }

    // epilogue
    if (MODE == 0) {
#pragma unroll
        for (int i = 0; i < 8; i++) {
            int m = m0 + row0 + i;
            int b = m / NN;
            int n = m - b * NN;
            int bh_base = b * NH;
#pragma unroll
            for (int j = 0; j < 8; j++) {
                int jj = j0 + col0 + j;
                float val = acc[i][j] + bias[jj];
                int t = jj >> 10;
                int r = jj & 1023;
                int head = r >> 6;
                int d = r & 63;
                float* dst = (t == 0) ? g_q : (t == 1) ? g_k : g_v;
                dst[((bh_base + head) * NN + n) * HD + d] = val;
            }
        }
    } else {
#pragma unroll
        for (int i = 0; i < 8; i++) {
            int m = m0 + row0 + i;
            float* orow = Cout + (size_t)m * CD + j0 + col0;
#pragma unroll
            for (int j = 0; j < 8; j++) orow[j] = acc[i][j] + bias[j0 + col0 + j];
        }
    }
}

// ---------------- rel-pos bias precompute ------------------------------------
// rel_h[bh,h,w,kh] = dot(q[bh,h*W+w,:], rel_pos_h[h-kh+H-1,:])
// rel_w[bh,h,w,kw] = dot(q[bh,h*W+w,:], rel_pos_w[w-kw+W-1,:])
__global__ void __launch_bounds__(256) relpos_kernel(const float* __restrict__ rph,
                                                     const float* __restrict__ rpw) {
    __shared__ float qs[WW][68];            // 28 x 64 (pad to 68 for float4)
    __shared__ float rhs[HH][68];           // 56 rows
    __shared__ float rws[2 * WW - 1][68];   // 55 rows (all of rel_pos_w)

    int h = blockIdx.x;
    int bh = blockIdx.y;
    int tid = threadIdx.x;

    for (int idx = tid; idx < WW * HD; idx += 256) {
        int w = idx >> 6, d = idx & 63;
        qs[w][d] = g_q[((bh * NN) + h * WW + w) * HD + d];
    }
    for (int idx = tid; idx < HH * HD; idx += 256) {
        int kh = idx >> 6, d = idx & 63;
        rhs[kh][d] = rph[(h + HH - 1 - kh) * HD + d];
    }
    for (int idx = tid; idx < (2 * WW - 1) * HD; idx += 256) {
        int r = idx >> 6, d = idx & 63;
        rws[r][d] = rpw[idx];
    }
    __syncthreads();

    for (int idx = tid; idx < WW * HH; idx += 256) {
        int w = idx / HH;
        int kh = idx - w * HH;
        float s = 0.f;
#pragma unroll
        for (int d4 = 0; d4 < HD; d4 += 4) {
            float4 a = *(const float4*)&qs[w][d4];
            float4 b = *(const float4*)&rhs[kh][d4];
            s += a.x * b.x + a.y * b.y + a.z * b.z + a.w * b.w;
        }
        g_relh[((bh * NN) + h * WW + w) * HH + kh] = s;
    }
    for (int idx = tid; idx < WW * WW; idx += 256) {
        int w = idx / WW;
        int kw = idx - w * WW;
        const float* rr = rws[w - kw + WW - 1];
        float s = 0.f;
#pragma unroll
        for (int d4 = 0; d4 < HD; d4 += 4) {
            float4 a = *(const float4*)&qs[w][d4];
            float4 b = *(const float4*)&rr[d4];
            s += a.x * b.x + a.y * b.y + a.z * b.z + a.w * b.w;
        }
        g_relw[((bh * NN) + h * WW + w) * WW + kw] = s;
    }
}

// ---------------- flash attention (64 q-rows/CTA, fp32) ----------------------
struct FlashSmem {
    float qt[HD][68];     // q transposed [d][r], pre-scaled
    float kt[HD][68];     // k transposed [d][c]
    float vs[64][68];     // v [k][d]
    float S[64][65];      // scores / probabilities
    float rh[64][HH];
    float rw[64][WW];
    float rowm[64];
    float rowl[64];
    float rowfac[64];
    float red[4][64];
};

__global__ void __launch_bounds__(256) flash_kernel() {
    extern __shared__ char raw[];
    FlashSmem& s = *reinterpret_cast<FlashSmem*>(raw);

    const int bh = blockIdx.y;
    const int qt0 = blockIdx.x;          // q-tile index (25 tiles)
    const int tid = threadIdx.x;
    const int tr4 = (tid >> 4) << 2;     // row base of 4x4 microtile
    const int tc4 = (tid & 15) << 2;     // col base

    // load q (scaled, transposed) + bias slices
    for (int idx = tid; idx < 64 * HD; idx += 256) {
        int r = idx >> 6, d = idx & 63;
        int n = qt0 * 64 + r;
        s.qt[d][r] = (n < NN) ? g_q[(bh * NN + n) * HD + d] * QSCALE : 0.f;
    }
    for (int idx = tid; idx < 64 * HH; idx += 256) {
        int r = idx / HH, kh = idx - r * HH;
        int n = qt0 * 64 + r;
        s.rh[r][kh] = (n < NN) ? g_relh[(bh * NN + n) * HH + kh] : 0.f;
    }
    for (int idx = tid; idx < 64 * WW; idx += 256) {
        int r = idx / WW, kw = idx - r * WW;
        int n = qt0 * 64 + r;
        s.rw[r][kw] = (n < NN) ? g_relw[(bh * NN + n) * WW + kw] : 0.f;
    }
    if (tid < 64) { s.rowm[tid] = -1e30f; s.rowl[tid] = 0.f; }

    float acc[4][4];
#pragma unroll
    for (int i = 0; i < 4; i++)
#pragma unroll
        for (int j = 0; j < 4; j++) acc[i][j] = 0.f;

    const int r2 = tid & 63;
    const int part = tid >> 6;

    for (int kt2 = 0; kt2 < 25; kt2++) {
        const int kbase = kt2 * 64;
        __syncthreads();   // prior-iter consumers done before overwrite
        for (int idx = tid; idx < 64 * HD; idx += 256) {
            int r = idx >> 6, d = idx & 63;
            int kn = kbase + r;
            float kv = 0.f, vv = 0.f;
            if (kn < NN) {
                kv = g_k[(bh * NN + kn) * HD + d];
                vv = g_v[(bh * NN + kn) * HD + d];
            }
            s.kt[d][r] = kv;
            s.vs[r][d] = vv;
        }
        __syncthreads();

        // scores: 4x4 microtile of scale*q@k^T
        float sv[4][4];
#pragma unroll
        for (int i = 0; i < 4; i++)
#pragma unroll
            for (int j = 0; j < 4; j++) sv[i][j] = 0.f;
#pragma unroll 8
        for (int d = 0; d < HD; d++) {
            float4 aa = *(const float4*)&s.qt[d][tr4];
            float4 bb = *(const float4*)&s.kt[d][tc4];
            float ar[4] = {aa.x, aa.y, aa.z, aa.w};
            float br[4] = {bb.x, bb.y, bb.z, bb.w};
#pragma unroll
            for (int i = 0; i < 4; i++)
#pragma unroll
                for (int j = 0; j < 4; j++) sv[i][j] += ar[i] * br[j];
        }
        // add decomposed rel-pos bias, stash in smem
#pragma unroll
        for (int j = 0; j < 4; j++) {
            int c = tc4 + j;
            int kn = kbase + c;
            if (kn < NN) {
                int kh = kn / WW;
                int kw = kn - kh * WW;
#pragma unroll
                for (int i = 0; i < 4; i++) {
                    int r = tr4 + i;
                    s.S[r][c] = sv[i][j] + s.rh[r][kh] + s.rw[r][kw];
                }
            } else {
#pragma unroll
                for (int i = 0; i < 4; i++) s.S[tr4 + i][c] = -1e30f;
            }
        }
        __syncthreads();

        // online softmax: partial row max
        float pm = -1e30f;
        for (int c = part * 16; c < part * 16 + 16; c++) pm = fmaxf(pm, s.S[r2][c]);
        s.red[part][r2] = pm;
        __syncthreads();
        if (tid < 64) {
            float mo = s.rowm[tid];
            float mn = fmaxf(fmaxf(s.red[0][tid], s.red[1][tid]),
                             fmaxf(s.red[2][tid], s.red[3][tid]));
            mn = fmaxf(mn, mo);
            s.rowm[tid] = mn;
            s.rowfac[tid] = __expf(mo - mn);
        }
        __syncthreads();
        // exponentiate + partial sums
        {
            float mn = s.rowm[r2];
            float ps = 0.f;
            for (int c = part * 16; c < part * 16 + 16; c++) {
                float p = __expf(s.S[r2][c] - mn);
                s.S[r2][c] = p;
                ps += p;
            }
            s.red[part][r2] = ps;
        }
        __syncthreads();
        if (tid < 64) {
            s.rowl[tid] = s.rowl[tid] * s.rowfac[tid] +
                          s.red[0][tid] + s.red[1][tid] + s.red[2][tid] + s.red[3][tid];
        }
        // rescale accumulators (rowfac written 2 syncs ago, stable until next iter)
        float f0 = s.rowfac[tr4 + 0];
        float f1 = s.rowfac[tr4 + 1];
        float f2 = s.rowfac[tr4 + 2];
        float f3 = s.rowfac[tr4 + 3];
#pragma unroll
        for (int j = 0; j < 4; j++) {
            acc[0][j] *= f0; acc[1][j] *= f1; acc[2][j] *= f2; acc[3][j] *= f3;
        }
        // P @ V
#pragma unroll 4
        for (int k = 0; k < 64; k++) {
            float4 vv = *(const float4*)&s.vs[k][tc4];
            float p0 = s.S[tr4 + 0][k];
            float p1 = s.S[tr4 + 1][k];
            float p2 = s.S[tr4 + 2][k];
            float p3 = s.S[tr4 + 3][k];
            acc[0][0] += p0 * vv.x; acc[0][1] += p0 * vv.y; acc[0][2] += p0 * vv.z; acc[0][3] += p0 * vv.w;
            acc[1][0] += p1 * vv.x; acc[1][1] += p1 * vv.y; acc[1][2] += p1 * vv.z; acc[1][3] += p1 * vv.w;
            acc[2][0] += p2 * vv.x; acc[2][1] += p2 * vv.y; acc[2][2] += p2 * vv.z; acc[2][3] += p2 * vv.w;
            acc[3][0] += p3 * vv.x; acc[3][1] += p3 * vv.y; acc[3][2] += p3 * vv.z; acc[3][3] += p3 * vv.w;
        }
    }
    __syncthreads();

    // normalize + store
#pragma unroll
    for (int i = 0; i < 4; i++) {
        int n = qt0 * 64 + tr4 + i;
        if (n < NN) {
            float li = 1.f / s.rowl[tr4 + i];
            float4 o;
            o.x = acc[i][0] * li;
            o.y = acc[i][1] * li;
            o.z = acc[i][2] * li;
            o.w = acc[i][3] * li;
            *(float4*)&g_ao[(bh * NN + n) * HD + tc4] = o;
        }
    }
}

// ---------------- launch -----------------------------------------------------
extern "C" void kernel_launch(void* const* d_in, const int* in_sizes, int n_in,
                              void* d_out, int out_size) {
    const float* hidden = (const float*)d_in[0];
    const float* qkv_w  = (const float*)d_in[1];
    const float* qkv_b  = (const float*)d_in[2];
    const float* proj_w = (const float*)d_in[3];
    const float* proj_b = (const float*)d_in[4];
    const float* rph    = (const float*)d_in[5];
    const float* rpw    = (const float*)d_in[6];
    float* out = (float*)d_out;

    cudaFuncSetAttribute(flash_kernel, cudaFuncAttributeMaxDynamicSharedMemorySize,
                         (int)sizeof(FlashSmem));

    dim3 tb(32, 8);
    transpose_k<0><<<dim3(CD / 32, 3 * CD / 32), tb>>>(qkv_w, 3 * CD, CD);
    transpose_k<1><<<dim3(CD / 32, CD / 32), tb>>>(proj_w, CD, CD);

    sgemm_kernel<0><<<dim3(3 * CD / 128, BN / 128), 256>>>(hidden, qkv_b, nullptr);

    relpos_kernel<<<dim3(HH, BHN), 256>>>(rph, rpw);

    flash_kernel<<<dim3((NN + 63) / 64, BHN), 256, sizeof(FlashSmem)>>>();

    sgemm_kernel<1><<<dim3(CD / 128, BN / 128), 256>>>(nullptr, proj_b, out);
}

// round 3
// speedup vs baseline: 1.4453x; 1.4453x over previous
#include <cuda_runtime.h>
#include <cstdint>

#define NH   16
#define HD   64
#define CD   1024
#define BB   4
#define HH   56
#define WW   28
#define NN   1568          // HH*WW
#define BHN  64            // BB*NH
#define BN   6272          // BB*NN
#define QSCALE 0.125f      // 64^-0.5

// ---------------- scratch (device globals; no allocations allowed) ----------
__device__ float g_q[BHN * NN * HD];
__device__ float g_k[BHN * NN * HD];
__device__ float g_v[BHN * NN * HD];
__device__ float g_relh[BHN * NN * HH];
__device__ float g_relw[BHN * NN * WW];
__device__ float g_ao[BN * CD];       // attention out, [B,N,heads,d] = [m,k]

// ---------------- helpers ----------------------------------------------------
__device__ __forceinline__ float tf32r(float x) {
    uint32_t r;
    asm("cvt.rna.tf32.f32 %0, %1;" : "=r"(r) : "f"(x));
    return __uint_as_float(r);
}

__device__ __forceinline__ void mma_tf32(float* c, const uint32_t* a, const uint32_t* b) {
    asm volatile(
        "mma.sync.aligned.m16n8k8.row.col.f32.tf32.tf32.f32 "
        "{%0,%1,%2,%3}, {%4,%5,%6,%7}, {%8,%9}, {%0,%1,%2,%3};"
        : "+f"(c[0]), "+f"(c[1]), "+f"(c[2]), "+f"(c[3])
        : "r"(a[0]), "r"(a[1]), "r"(a[2]), "r"(a[3]), "r"(b[0]), "r"(b[1]));
}

// ================== mma.sync TF32 GEMM: C[M,N] = A[M,K] . B[N,K]^T ============
// MODE 0: A=hidden[6272,1024], B=qkv_w[3072,1024], +qkv_b, scatter -> g_q/k/v
// MODE 1: A=g_ao[6272,1024],   B=proj_w[1024,1024], +proj_b -> Cout
#define BM 128
#define BNT 128
#define BK 32
#define PITCH 36   // floats per smem row (32 data + 4 pad)

template <int MODE>
__global__ void __launch_bounds__(256, 2) mm_mma(const float* __restrict__ Ain,
                                                 const float* __restrict__ Bin,
                                                 const float* __restrict__ bias,
                                                 float* __restrict__ Cout) {
    __shared__ float As[BM * PITCH];
    __shared__ float Bs[BNT * PITCH];

    const float* A = (MODE == 0) ? Ain : g_ao;

    const int tid = threadIdx.x;
    const int wid = tid >> 5;
    const int lid = tid & 31;
    const int g = lid >> 2;            // group id 0..7
    const int t = lid & 3;             // thread-in-group 0..3
    const int m0 = blockIdx.y * BM;
    const int n0 = blockIdx.x * BNT;
    const int wm = (wid & 1) * 64;     // warp m base
    const int wn = (wid >> 1) * 32;    // warp n base

    // loader coords: 1024 float4 slots per matrix / 256 thr = 4 each
    const int f4 = tid & 7;            // float4 index within row (k = f4*4)
    const int r0 = tid >> 3;           // base row, +32 per slot
    const int kgrp = f4 >> 1;          // k8 group 0..3
    const int kpar = f4 & 1;           // even/odd permuted positions
    const int cbase = kgrp * 8 + kpar; // smem col base; elements at +0,+2,+4,+6

    float acc[4][4][4];
#pragma unroll
    for (int mi = 0; mi < 4; mi++)
#pragma unroll
        for (int ni = 0; ni < 4; ni++)
#pragma unroll
            for (int e = 0; e < 4; e++) acc[mi][ni][e] = 0.f;

    for (int kt = 0; kt < 32; kt++) {
        const int kg = kt * BK + f4 * 4;
        __syncthreads();
#pragma unroll
        for (int i = 0; i < 4; i++) {
            int row = r0 + 32 * i;
            float4 va = *(const float4*)(A + (size_t)(m0 + row) * CD + kg);
            float4 vb = *(const float4*)(Bin + (size_t)(n0 + row) * CD + kg);
            float* pa = As + row * PITCH + cbase;
            float* pb = Bs + row * PITCH + cbase;
            pa[0] = tf32r(va.x); pa[2] = tf32r(va.y);
            pa[4] = tf32r(va.z); pa[6] = tf32r(va.w);
            pb[0] = tf32r(vb.x); pb[2] = tf32r(vb.y);
            pb[4] = tf32r(vb.z); pb[6] = tf32r(vb.w);
        }
        __syncthreads();

#pragma unroll
        for (int ko = 0; ko < 4; ko++) {
            uint32_t a[4][4];
            uint32_t b[4][2];
#pragma unroll
            for (int mi = 0; mi < 4; mi++) {
                float2 v0 = *(const float2*)(As + (wm + mi * 16 + g) * PITCH + ko * 8 + 2 * t);
                float2 v1 = *(const float2*)(As + (wm + mi * 16 + g + 8) * PITCH + ko * 8 + 2 * t);
                a[mi][0] = __float_as_uint(v0.x);
                a[mi][1] = __float_as_uint(v1.x);
                a[mi][2] = __float_as_uint(v0.y);
                a[mi][3] = __float_as_uint(v1.y);
            }
#pragma unroll
            for (int ni = 0; ni < 4; ni++) {
                float2 u = *(const float2*)(Bs + (wn + ni * 8 + g) * PITCH + ko * 8 + 2 * t);
                b[ni][0] = __float_as_uint(u.x);
                b[ni][1] = __float_as_uint(u.y);
            }
#pragma unroll
            for (int mi = 0; mi < 4; mi++)
#pragma unroll
                for (int ni = 0; ni < 4; ni++) mma_tf32(acc[mi][ni], a[mi], b[ni]);
        }
    }

    // epilogue: c0=(g,2t), c1=(g,2t+1), c2=(g+8,2t), c3=(g+8,2t+1)
#pragma unroll
    for (int mi = 0; mi < 4; mi++) {
        int mr0 = m0 + wm + mi * 16 + g;
        int mr1 = mr0 + 8;
#pragma unroll
        for (int ni = 0; ni < 4; ni++) {
            int jj = n0 + wn + ni * 8 + 2 * t;
            float b0 = bias[jj], b1 = bias[jj + 1];
            float v00 = acc[mi][ni][0] + b0, v01 = acc[mi][ni][1] + b1;
            float v10 = acc[mi][ni][2] + b0, v11 = acc[mi][ni][3] + b1;
            if (MODE == 0) {
                int tsel = jj >> 10;
                int rr = jj & 1023;
                int head = rr >> 6;
                int d = rr & 63;
                float* dst = (tsel == 0) ? g_q : (tsel == 1) ? g_k : g_v;
                {
                    int b_ = mr0 / NN, n_ = mr0 - b_ * NN;
                    float2 o = {v00, v01};
                    *(float2*)&dst[(size_t)((b_ * NH + head) * NN + n_) * HD + d] = o;
                }
                {
                    int b_ = mr1 / NN, n_ = mr1 - b_ * NN;
                    float2 o = {v10, v11};
                    *(float2*)&dst[(size_t)((b_ * NH + head) * NN + n_) * HD + d] = o;
                }
            } else {
                float2 o0 = {v00, v01};
                float2 o1 = {v10, v11};
                *(float2*)&Cout[(size_t)mr0 * CD + jj] = o0;
                *(float2*)&Cout[(size_t)mr1 * CD + jj] = o1;
            }
        }
    }
}

// ---------------- rel-pos bias precompute ------------------------------------
__global__ void __launch_bounds__(256) relpos_kernel(const float* __restrict__ rph,
                                                     const float* __restrict__ rpw) {
    __shared__ float qs[WW][68];
    __shared__ float rhs[HH][68];
    __shared__ float rws[2 * WW - 1][68];

    int h = blockIdx.x;
    int bh = blockIdx.y;
    int tid = threadIdx.x;

    for (int idx = tid; idx < WW * HD; idx += 256) {
        int w = idx >> 6, d = idx & 63;
        qs[w][d] = g_q[((bh * NN) + h * WW + w) * HD + d];
    }
    for (int idx = tid; idx < HH * HD; idx += 256) {
        int kh = idx >> 6, d = idx & 63;
        rhs[kh][d] = rph[(h + HH - 1 - kh) * HD + d];
    }
    for (int idx = tid; idx < (2 * WW - 1) * HD; idx += 256) {
        int r = idx >> 6, d = idx & 63;
        rws[r][d] = rpw[idx];
    }
    __syncthreads();

    for (int idx = tid; idx < WW * HH; idx += 256) {
        int w = idx / HH;
        int kh = idx - w * HH;
        float s = 0.f;
#pragma unroll
        for (int d4 = 0; d4 < HD; d4 += 4) {
            float4 a = *(const float4*)&qs[w][d4];
            float4 b = *(const float4*)&rhs[kh][d4];
            s += a.x * b.x + a.y * b.y + a.z * b.z + a.w * b.w;
        }
        g_relh[((bh * NN) + h * WW + w) * HH + kh] = s;
    }
    for (int idx = tid; idx < WW * WW; idx += 256) {
        int w = idx / WW;
        int kw = idx - w * WW;
        const float* rr = rws[w - kw + WW - 1];
        float s = 0.f;
#pragma unroll
        for (int d4 = 0; d4 < HD; d4 += 4) {
            float4 a = *(const float4*)&qs[w][d4];
            float4 b = *(const float4*)&rr[d4];
            s += a.x * b.x + a.y * b.y + a.z * b.z + a.w * b.w;
        }
        g_relw[((bh * NN) + h * WW + w) * WW + kw] = s;
    }
}

// ---------------- flash attention (64 q-rows/CTA, fp32) ----------------------
struct FlashSmem {
    float qt[HD][68];
    float kt[HD][68];
    float vs[64][68];
    float S[64][65];
    float rh[64][HH];
    float rw[64][WW];
    float rowm[64];
    float rowl[64];
    float rowfac[64];
    float red[4][64];
};

__global__ void __launch_bounds__(256) flash_kernel() {
    extern __shared__ char raw[];
    FlashSmem& s = *reinterpret_cast<FlashSmem*>(raw);

    const int bh = blockIdx.y;
    const int qt0 = blockIdx.x;
    const int tid = threadIdx.x;
    const int tr4 = (tid >> 4) << 2;
    const int tc4 = (tid & 15) << 2;

    for (int idx = tid; idx < 64 * HD; idx += 256) {
        int r = idx >> 6, d = idx & 63;
        int n = qt0 * 64 + r;
        s.qt[d][r] = (n < NN) ? g_q[(bh * NN + n) * HD + d] * QSCALE : 0.f;
    }
    for (int idx = tid; idx < 64 * HH; idx += 256) {
        int r = idx / HH, kh = idx - r * HH;
        int n = qt0 * 64 + r;
        s.rh[r][kh] = (n < NN) ? g_relh[(bh * NN + n) * HH + kh] : 0.f;
    }
    for (int idx = tid; idx < 64 * WW; idx += 256) {
        int r = idx / WW, kw = idx - r * WW;
        int n = qt0 * 64 + r;
        s.rw[r][kw] = (n < NN) ? g_relw[(bh * NN + n) * WW + kw] : 0.f;
    }
    if (tid < 64) { s.rowm[tid] = -1e30f; s.rowl[tid] = 0.f; }

    float acc[4][4];
#pragma unroll
    for (int i = 0; i < 4; i++)
#pragma unroll
        for (int j = 0; j < 4; j++) acc[i][j] = 0.f;

    const int r2 = tid & 63;
    const int part = tid >> 6;

    for (int kt2 = 0; kt2 < 25; kt2++) {
        const int kbase = kt2 * 64;
        __syncthreads();
        for (int idx = tid; idx < 64 * HD; idx += 256) {
            int r = idx >> 6, d = idx & 63;
            int kn = kbase + r;
            float kv = 0.f, vv = 0.f;
            if (kn < NN) {
                kv = g_k[(bh * NN + kn) * HD + d];
                vv = g_v[(bh * NN + kn) * HD + d];
            }
            s.kt[d][r] = kv;
            s.vs[r][d] = vv;
        }
        __syncthreads();

        float sv[4][4];
#pragma unroll
        for (int i = 0; i < 4; i++)
#pragma unroll
            for (int j = 0; j < 4; j++) sv[i][j] = 0.f;
#pragma unroll 8
        for (int d = 0; d < HD; d++) {
            float4 aa = *(const float4*)&s.qt[d][tr4];
            float4 bb = *(const float4*)&s.kt[d][tc4];
            float ar[4] = {aa.x, aa.y, aa.z, aa.w};
            float br[4] = {bb.x, bb.y, bb.z, bb.w};
#pragma unroll
            for (int i = 0; i < 4; i++)
#pragma unroll
                for (int j = 0; j < 4; j++) sv[i][j] += ar[i] * br[j];
        }
#pragma unroll
        for (int j = 0; j < 4; j++) {
            int c = tc4 + j;
            int kn = kbase + c;
            if (kn < NN) {
                int kh = kn / WW;
                int kw = kn - kh * WW;
#pragma unroll
                for (int i = 0; i < 4; i++) {
                    int r = tr4 + i;
                    s.S[r][c] = sv[i][j] + s.rh[r][kh] + s.rw[r][kw];
                }
            } else {
#pragma unroll
                for (int i = 0; i < 4; i++) s.S[tr4 + i][c] = -1e30f;
            }
        }
        __syncthreads();

        float pm = -1e30f;
        for (int c = part * 16; c < part * 16 + 16; c++) pm = fmaxf(pm, s.S[r2][c]);
        s.red[part][r2] = pm;
        __syncthreads();
        if (tid < 64) {
            float mo = s.rowm[tid];
            float mn = fmaxf(fmaxf(s.red[0][tid], s.red[1][tid]),
                             fmaxf(s.red[2][tid], s.red[3][tid]));
            mn = fmaxf(mn, mo);
            s.rowm[tid] = mn;
            s.rowfac[tid] = __expf(mo - mn);
        }
        __syncthreads();
        {
            float mn = s.rowm[r2];
            float ps = 0.f;
            for (int c = part * 16; c < part * 16 + 16; c++) {
                float p = __expf(s.S[r2][c] - mn);
                s.S[r2][c] = p;
                ps += p;
            }
            s.red[part][r2] = ps;
        }
        __syncthreads();
        if (tid < 64) {
            s.rowl[tid] = s.rowl[tid] * s.rowfac[tid] +
                          s.red[0][tid] + s.red[1][tid] + s.red[2][tid] + s.red[3][tid];
        }
        float f0 = s.rowfac[tr4 + 0];
        float f1 = s.rowfac[tr4 + 1];
        float f2 = s.rowfac[tr4 + 2];
        float f3 = s.rowfac[tr4 + 3];
#pragma unroll
        for (int j = 0; j < 4; j++) {
            acc[0][j] *= f0; acc[1][j] *= f1; acc[2][j] *= f2; acc[3][j] *= f3;
        }
#pragma unroll 4
        for (int k = 0; k < 64; k++) {
            float4 vv = *(const float4*)&s.vs[k][tc4];
            float p0 = s.S[tr4 + 0][k];
            float p1 = s.S[tr4 + 1][k];
            float p2 = s.S[tr4 + 2][k];
            float p3 = s.S[tr4 + 3][k];
            acc[0][0] += p0 * vv.x; acc[0][1] += p0 * vv.y; acc[0][2] += p0 * vv.z; acc[0][3] += p0 * vv.w;
            acc[1][0] += p1 * vv.x; acc[1][1] += p1 * vv.y; acc[1][2] += p1 * vv.z; acc[1][3] += p1 * vv.w;
            acc[2][0] += p2 * vv.x; acc[2][1] += p2 * vv.y; acc[2][2] += p2 * vv.z; acc[2][3] += p2 * vv.w;
            acc[3][0] += p3 * vv.x; acc[3][1] += p3 * vv.y; acc[3][2] += p3 * vv.z; acc[3][3] += p3 * vv.w;
        }
    }
    __syncthreads();

    const int b = bh >> 4;
    const int head = bh & 15;
#pragma unroll
    for (int i = 0; i < 4; i++) {
        int n = qt0 * 64 + tr4 + i;
        if (n < NN) {
            float li = 1.f / s.rowl[tr4 + i];
            float4 o;
            o.x = acc[i][0] * li;
            o.y = acc[i][1] * li;
            o.z = acc[i][2] * li;
            o.w = acc[i][3] * li;
            // [B,N,heads,d] layout so the proj GEMM reads contiguous rows
            *(float4*)&g_ao[(size_t)(b * NN + n) * CD + head * HD + tc4] = o;
        }
    }
}

// ---------------- launch -----------------------------------------------------
extern "C" void kernel_launch(void* const* d_in, const int* in_sizes, int n_in,
                              void* d_out, int out_size) {
    const float* hidden = (const float*)d_in[0];
    const float* qkv_w  = (const float*)d_in[1];
    const float* qkv_b  = (const float*)d_in[2];
    const float* proj_w = (const float*)d_in[3];
    const float* proj_b = (const float*)d_in[4];
    const float* rph    = (const float*)d_in[5];
    const float* rpw    = (const float*)d_in[6];
    float* out = (float*)d_out;

    cudaFuncSetAttribute(flash_kernel, cudaFuncAttributeMaxDynamicSharedMemorySize,
                         (int)sizeof(FlashSmem));

    // QKV: [6272,3072] = hidden . qkv_w^T  (mma.sync TF32)
    mm_mma<0><<<dim3(3 * CD / BNT, BN / BM), 256>>>(hidden, qkv_w, qkv_b, nullptr);

    relpos_kernel<<<dim3(HH, BHN), 256>>>(rph, rpw);

    flash_kernel<<<dim3((NN + 63) / 64, BHN), 256, sizeof(FlashSmem)>>>();

    // proj: [6272,1024] = g_ao . proj_w^T
    mm_mma<1><<<dim3(CD / BNT, BN / BM), 256>>>(nullptr, proj_w, proj_b, out);
}

// round 4
// speedup vs baseline: 2.0937x; 1.4487x over previous
#include <cuda_runtime.h>
#include <cstdint>

#define NH   16
#define HD   64
#define CD   1024
#define BB   4
#define HH   56
#define WW   28
#define NN   1568          // HH*WW
#define BHN  64            // BB*NH
#define BN   6272          // BB*NN
#define QSCALE 0.125f      // 64^-0.5

// ---------------- scratch (device globals; no allocations allowed) ----------
__device__ float g_q[BHN * NN * HD];
__device__ float g_k[BHN * NN * HD];
__device__ float g_v[BHN * NN * HD];
__device__ float g_relh[BHN * NN * HH];
__device__ float g_relw[BHN * NN * WW];
__device__ float g_ao[BN * CD];       // attention out, [B,N,heads,d] = [m,k]

// ---------------- helpers ----------------------------------------------------
__device__ __forceinline__ float tf32r(float x) {
    uint32_t r;
    asm("cvt.rna.tf32.f32 %0, %1;" : "=r"(r) : "f"(x));
    return __uint_as_float(r);
}

__device__ __forceinline__ void mma_tf32(float* c, const uint32_t* a, const uint32_t* b) {
    asm volatile(
        "mma.sync.aligned.m16n8k8.row.col.f32.tf32.tf32.f32 "
        "{%0,%1,%2,%3}, {%4,%5,%6,%7}, {%8,%9}, {%0,%1,%2,%3};"
        : "+f"(c[0]), "+f"(c[1]), "+f"(c[2]), "+f"(c[3])
        : "r"(a[0]), "r"(a[1]), "r"(a[2]), "r"(a[3]), "r"(b[0]), "r"(b[1]));
}

// ================== mma.sync TF32 GEMM: C[M,N] = A[M,K] . B[N,K]^T ============
#define BM 128
#define BNT 128
#define BK 32
#define PITCH 36

template <int MODE>
__global__ void __launch_bounds__(256, 2) mm_mma(const float* __restrict__ Ain,
                                                 const float* __restrict__ Bin,
                                                 const float* __restrict__ bias,
                                                 float* __restrict__ Cout) {
    __shared__ float As[BM * PITCH];
    __shared__ float Bs[BNT * PITCH];

    const float* A = (MODE == 0) ? Ain : g_ao;

    const int tid = threadIdx.x;
    const int wid = tid >> 5;
    const int lid = tid & 31;
    const int g = lid >> 2;
    const int t = lid & 3;
    const int m0 = blockIdx.y * BM;
    const int n0 = blockIdx.x * BNT;
    const int wm = (wid & 1) * 64;
    const int wn = (wid >> 1) * 32;

    const int f4 = tid & 7;
    const int r0 = tid >> 3;
    const int kgrp = f4 >> 1;
    const int kpar = f4 & 1;
    const int cbase = kgrp * 8 + kpar;

    float acc[4][4][4];
#pragma unroll
    for (int mi = 0; mi < 4; mi++)
#pragma unroll
        for (int ni = 0; ni < 4; ni++)
#pragma unroll
            for (int e = 0; e < 4; e++) acc[mi][ni][e] = 0.f;

    for (int kt = 0; kt < 32; kt++) {
        const int kg = kt * BK + f4 * 4;
        __syncthreads();
#pragma unroll
        for (int i = 0; i < 4; i++) {
            int row = r0 + 32 * i;
            float4 va = *(const float4*)(A + (size_t)(m0 + row) * CD + kg);
            float4 vb = *(const float4*)(Bin + (size_t)(n0 + row) * CD + kg);
            float* pa = As + row * PITCH + cbase;
            float* pb = Bs + row * PITCH + cbase;
            pa[0] = tf32r(va.x); pa[2] = tf32r(va.y);
            pa[4] = tf32r(va.z); pa[6] = tf32r(va.w);
            pb[0] = tf32r(vb.x); pb[2] = tf32r(vb.y);
            pb[4] = tf32r(vb.z); pb[6] = tf32r(vb.w);
        }
        __syncthreads();

#pragma unroll
        for (int ko = 0; ko < 4; ko++) {
            uint32_t a[4][4];
            uint32_t b[4][2];
#pragma unroll
            for (int mi = 0; mi < 4; mi++) {
                float2 v0 = *(const float2*)(As + (wm + mi * 16 + g) * PITCH + ko * 8 + 2 * t);
                float2 v1 = *(const float2*)(As + (wm + mi * 16 + g + 8) * PITCH + ko * 8 + 2 * t);
                a[mi][0] = __float_as_uint(v0.x);
                a[mi][1] = __float_as_uint(v1.x);
                a[mi][2] = __float_as_uint(v0.y);
                a[mi][3] = __float_as_uint(v1.y);
            }
#pragma unroll
            for (int ni = 0; ni < 4; ni++) {
                float2 u = *(const float2*)(Bs + (wn + ni * 8 + g) * PITCH + ko * 8 + 2 * t);
                b[ni][0] = __float_as_uint(u.x);
                b[ni][1] = __float_as_uint(u.y);
            }
#pragma unroll
            for (int mi = 0; mi < 4; mi++)
#pragma unroll
                for (int ni = 0; ni < 4; ni++) mma_tf32(acc[mi][ni], a[mi], b[ni]);
        }
    }

#pragma unroll
    for (int mi = 0; mi < 4; mi++) {
        int mr0 = m0 + wm + mi * 16 + g;
        int mr1 = mr0 + 8;
#pragma unroll
        for (int ni = 0; ni < 4; ni++) {
            int jj = n0 + wn + ni * 8 + 2 * t;
            float b0 = bias[jj], b1 = bias[jj + 1];
            float v00 = acc[mi][ni][0] + b0, v01 = acc[mi][ni][1] + b1;
            float v10 = acc[mi][ni][2] + b0, v11 = acc[mi][ni][3] + b1;
            if (MODE == 0) {
                int tsel = jj >> 10;
                int rr = jj & 1023;
                int head = rr >> 6;
                int d = rr & 63;
                float* dst = (tsel == 0) ? g_q : (tsel == 1) ? g_k : g_v;
                {
                    int b_ = mr0 / NN, n_ = mr0 - b_ * NN;
                    float2 o = {v00, v01};
                    *(float2*)&dst[(size_t)((b_ * NH + head) * NN + n_) * HD + d] = o;
                }
                {
                    int b_ = mr1 / NN, n_ = mr1 - b_ * NN;
                    float2 o = {v10, v11};
                    *(float2*)&dst[(size_t)((b_ * NH + head) * NN + n_) * HD + d] = o;
                }
            } else {
                float2 o0 = {v00, v01};
                float2 o1 = {v10, v11};
                *(float2*)&Cout[(size_t)mr0 * CD + jj] = o0;
                *(float2*)&Cout[(size_t)mr1 * CD + jj] = o1;
            }
        }
    }
}

// ---------------- rel-pos bias precompute ------------------------------------
__global__ void __launch_bounds__(256) relpos_kernel(const float* __restrict__ rph,
                                                     const float* __restrict__ rpw) {
    __shared__ float qs[WW][68];
    __shared__ float rhs[HH][68];
    __shared__ float rws[2 * WW - 1][68];

    int h = blockIdx.x;
    int bh = blockIdx.y;
    int tid = threadIdx.x;

    for (int idx = tid; idx < WW * HD; idx += 256) {
        int w = idx >> 6, d = idx & 63;
        qs[w][d] = g_q[((bh * NN) + h * WW + w) * HD + d];
    }
    for (int idx = tid; idx < HH * HD; idx += 256) {
        int kh = idx >> 6, d = idx & 63;
        rhs[kh][d] = rph[(h + HH - 1 - kh) * HD + d];
    }
    for (int idx = tid; idx < (2 * WW - 1) * HD; idx += 256) {
        int r = idx >> 6, d = idx & 63;
        rws[r][d] = rpw[idx];
    }
    __syncthreads();

    for (int idx = tid; idx < WW * HH; idx += 256) {
        int w = idx / HH;
        int kh = idx - w * HH;
        float s = 0.f;
#pragma unroll
        for (int d4 = 0; d4 < HD; d4 += 4) {
            float4 a = *(const float4*)&qs[w][d4];
            float4 b = *(const float4*)&rhs[kh][d4];
            s += a.x * b.x + a.y * b.y + a.z * b.z + a.w * b.w;
        }
        g_relh[((bh * NN) + h * WW + w) * HH + kh] = s;
    }
    for (int idx = tid; idx < WW * WW; idx += 256) {
        int w = idx / WW;
        int kw = idx - w * WW;
        const float* rr = rws[w - kw + WW - 1];
        float s = 0.f;
#pragma unroll
        for (int d4 = 0; d4 < HD; d4 += 4) {
            float4 a = *(const float4*)&qs[w][d4];
            float4 b = *(const float4*)&rr[d4];
            s += a.x * b.x + a.y * b.y + a.z * b.z + a.w * b.w;
        }
        g_relw[((bh * NN) + h * WW + w) * WW + kw] = s;
    }
}

// ---------------- flash attention v2 (TF32 mma, 64 q-rows/CTA) ---------------
#define FP 68   // smem pitch (floats) for 64-wide tiles

struct Flash2Smem {
    float qs[64 * FP];   // Q, k-permuted, pre-scaled tf32
    float kt[64 * FP];   // K rows=k-col, cols=d k-permuted, tf32
    float vs[64 * FP];   // V natural [k][d], tf32
    float S[64 * FP];    // scores / P, k-permuted cols
    float rh[64][HH];
    float rw[64][WW];
    float rowm[64];
    float rowl[64];
    float rowfac[64];
    float red[4][64];
    int   kh_a[64];
    int   kw_a[64];
};

__global__ void __launch_bounds__(256) flash2_kernel() {
    extern __shared__ char raw[];
    Flash2Smem& s = *reinterpret_cast<Flash2Smem*>(raw);

    const int bh = blockIdx.y;
    const int qt0 = blockIdx.x;
    const int tid = threadIdx.x;
    const int wid = tid >> 5;
    const int lid = tid & 31;
    const int g = lid >> 2;
    const int t = lid & 3;
    const int wm = (wid & 3) * 16;    // q-rows subtile
    const int wn = (wid >> 2) * 32;   // k-cols (QK) / d-cols (PV) subtile

    // permuted store positions for C-frag cols (logical 2t, 2t+1)
    const int p0 = (t < 2) ? 4 * t : 4 * t - 7;
    const int p1 = (t < 2) ? 4 * t + 2 : 4 * t - 5;

    // ---- load Q (scaled, tf32, k-permuted) + bias rows, init state ----
#pragma unroll
    for (int it = 0; it < 4; it++) {
        int idx = it * 256 + tid;
        int r = idx >> 4, f4 = idx & 15;
        int n = qt0 * 64 + r;
        float4 v = make_float4(0.f, 0.f, 0.f, 0.f);
        if (n < NN) v = *(const float4*)&g_q[(size_t)(bh * NN + n) * HD + f4 * 4];
        float* p = s.qs + r * FP + (f4 >> 1) * 8 + (f4 & 1);
        p[0] = tf32r(v.x * QSCALE); p[2] = tf32r(v.y * QSCALE);
        p[4] = tf32r(v.z * QSCALE); p[6] = tf32r(v.w * QSCALE);
    }
    for (int idx = tid; idx < 64 * HH; idx += 256) {
        int r = idx / HH, kh = idx - r * HH;
        int n = qt0 * 64 + r;
        s.rh[r][kh] = (n < NN) ? g_relh[(size_t)(bh * NN + n) * HH + kh] : 0.f;
    }
    for (int idx = tid; idx < 64 * WW; idx += 256) {
        int r = idx / WW, kw = idx - r * WW;
        int n = qt0 * 64 + r;
        s.rw[r][kw] = (n < NN) ? g_relw[(size_t)(bh * NN + n) * WW + kw] : 0.f;
    }
    if (tid < 64) { s.rowm[tid] = -1e30f; s.rowl[tid] = 0.f; }

    float acc[4][4];
#pragma unroll
    for (int ni = 0; ni < 4; ni++)
#pragma unroll
        for (int e = 0; e < 4; e++) acc[ni][e] = 0.f;

    const int part = tid & 3;
    const int r2 = tid >> 2;

    for (int kt2 = 0; kt2 < 25; kt2++) {
        const int kbase = kt2 * 64;
        __syncthreads();   // prior consumers done before K/V/S overwrite

        // ---- load K (permuted) and V (natural), tf32 ----
#pragma unroll
        for (int it = 0; it < 4; it++) {
            int idx = it * 256 + tid;
            int r = idx >> 4, f4 = idx & 15;
            int kn = kbase + r;
            float4 kv = make_float4(0.f, 0.f, 0.f, 0.f);
            float4 vv = make_float4(0.f, 0.f, 0.f, 0.f);
            if (kn < NN) {
                kv = *(const float4*)&g_k[(size_t)(bh * NN + kn) * HD + f4 * 4];
                vv = *(const float4*)&g_v[(size_t)(bh * NN + kn) * HD + f4 * 4];
            }
            float* pk = s.kt + r * FP + (f4 >> 1) * 8 + (f4 & 1);
            pk[0] = tf32r(kv.x); pk[2] = tf32r(kv.y);
            pk[4] = tf32r(kv.z); pk[6] = tf32r(kv.w);
            float4 vr;
            vr.x = tf32r(vv.x); vr.y = tf32r(vv.y);
            vr.z = tf32r(vv.z); vr.w = tf32r(vv.w);
            *(float4*)&s.vs[r * FP + f4 * 4] = vr;
        }
        if (tid < 64) {
            int kn = kbase + tid;
            s.kh_a[tid] = (kn < NN) ? kn / WW : -1;
            s.kw_a[tid] = (kn < NN) ? kn % WW : 0;
        }
        __syncthreads();

        // ---- QK^T mma: warp does m16 x n32 over k=64 ----
        float c[4][4];
#pragma unroll
        for (int ni = 0; ni < 4; ni++)
#pragma unroll
            for (int e = 0; e < 4; e++) c[ni][e] = 0.f;
#pragma unroll
        for (int ko = 0; ko < 8; ko++) {
            uint32_t a[4];
            float2 v0 = *(const float2*)(s.qs + (wm + g) * FP + ko * 8 + 2 * t);
            float2 v1 = *(const float2*)(s.qs + (wm + g + 8) * FP + ko * 8 + 2 * t);
            a[0] = __float_as_uint(v0.x); a[1] = __float_as_uint(v1.x);
            a[2] = __float_as_uint(v0.y); a[3] = __float_as_uint(v1.y);
#pragma unroll
            for (int ni = 0; ni < 4; ni++) {
                float2 u = *(const float2*)(s.kt + (wn + ni * 8 + g) * FP + ko * 8 + 2 * t);
                uint32_t b[2] = {__float_as_uint(u.x), __float_as_uint(u.y)};
                mma_tf32(c[ni], a, b);
            }
        }
        // ---- write S + rel-pos bias (permuted cols) ----
        {
            const int rr0 = wm + g, rr1 = wm + g + 8;
#pragma unroll
            for (int ni = 0; ni < 4; ni++) {
                int cb = wn + ni * 8;
                int c0l = cb + 2 * t, c1l = c0l + 1;
                int kh0 = s.kh_a[c0l], kw0 = s.kw_a[c0l];
                int kh1 = s.kh_a[c1l], kw1 = s.kw_a[c1l];
                float s00, s01, s10, s11;
                if (kh0 >= 0) {
                    s00 = c[ni][0] + s.rh[rr0][kh0] + s.rw[rr0][kw0];
                    s10 = c[ni][2] + s.rh[rr1][kh0] + s.rw[rr1][kw0];
                } else { s00 = -1e30f; s10 = -1e30f; }
                if (kh1 >= 0) {
                    s01 = c[ni][1] + s.rh[rr0][kh1] + s.rw[rr0][kw1];
                    s11 = c[ni][3] + s.rh[rr1][kh1] + s.rw[rr1][kw1];
                } else { s01 = -1e30f; s11 = -1e30f; }
                s.S[rr0 * FP + cb + p0] = s00;
                s.S[rr0 * FP + cb + p1] = s01;
                s.S[rr1 * FP + cb + p0] = s10;
                s.S[rr1 * FP + cb + p1] = s11;
            }
        }
        __syncthreads();

        // ---- online softmax ----
        float pm = -1e30f;
#pragma unroll
        for (int j = 0; j < 16; j++) pm = fmaxf(pm, s.S[r2 * FP + part * 16 + j]);
        s.red[part][r2] = pm;
        __syncthreads();
        if (tid < 64) {
            float mo = s.rowm[tid];
            float mn = fmaxf(fmaxf(s.red[0][tid], s.red[1][tid]),
                             fmaxf(s.red[2][tid], s.red[3][tid]));
            mn = fmaxf(mn, mo);
            s.rowm[tid] = mn;
            s.rowfac[tid] = __expf(mo - mn);
        }
        __syncthreads();
        {
            float mn = s.rowm[r2];
            float ps = 0.f;
#pragma unroll
            for (int j = 0; j < 16; j++) {
                float p = __expf(s.S[r2 * FP + part * 16 + j] - mn);
                p = tf32r(p);
                s.S[r2 * FP + part * 16 + j] = p;
                ps += p;
            }
            s.red[part][r2] = ps;
        }
        // rescale PV accumulators (rowfac stable since last sync)
        {
            float f0 = s.rowfac[wm + g];
            float f1 = s.rowfac[wm + g + 8];
#pragma unroll
            for (int ni = 0; ni < 4; ni++) {
                acc[ni][0] *= f0; acc[ni][1] *= f0;
                acc[ni][2] *= f1; acc[ni][3] *= f1;
            }
        }
        __syncthreads();
        if (tid < 64) {
            s.rowl[tid] = s.rowl[tid] * s.rowfac[tid] +
                          s.red[0][tid] + s.red[1][tid] + s.red[2][tid] + s.red[3][tid];
        }

        // ---- P @ V mma: warp does m16(q) x n32(d) over k=64 ----
#pragma unroll
        for (int ko = 0; ko < 8; ko++) {
            uint32_t a[4];
            float2 v0 = *(const float2*)(s.S + (wm + g) * FP + ko * 8 + 2 * t);
            float2 v1 = *(const float2*)(s.S + (wm + g + 8) * FP + ko * 8 + 2 * t);
            a[0] = __float_as_uint(v0.x); a[1] = __float_as_uint(v1.x);
            a[2] = __float_as_uint(v0.y); a[3] = __float_as_uint(v1.y);
#pragma unroll
            for (int ni = 0; ni < 4; ni++) {
                uint32_t b[2];
                b[0] = __float_as_uint(s.vs[(ko * 8 + t) * FP + wn + ni * 8 + g]);
                b[1] = __float_as_uint(s.vs[(ko * 8 + t + 4) * FP + wn + ni * 8 + g]);
                mma_tf32(acc[ni], a, b);
            }
        }
    }
    __syncthreads();

    // ---- normalize + store [B,N,heads,d] ----
    const int b = bh >> 4;
    const int head = bh & 15;
    const int n0g = qt0 * 64 + wm + g;
    const int n1g = n0g + 8;
    float li0 = 1.f / s.rowl[wm + g];
    float li1 = 1.f / s.rowl[wm + g + 8];
#pragma unroll
    for (int ni = 0; ni < 4; ni++) {
        int d = wn + ni * 8 + 2 * t;
        if (n0g < NN) {
            float2 o = {acc[ni][0] * li0, acc[ni][1] * li0};
            *(float2*)&g_ao[(size_t)(b * NN + n0g) * CD + head * HD + d] = o;
        }
        if (n1g < NN) {
            float2 o = {acc[ni][2] * li1, acc[ni][3] * li1};
            *(float2*)&g_ao[(size_t)(b * NN + n1g) * CD + head * HD + d] = o;
        }
    }
}

// ---------------- launch -----------------------------------------------------
extern "C" void kernel_launch(void* const* d_in, const int* in_sizes, int n_in,
                              void* d_out, int out_size) {
    const float* hidden = (const float*)d_in[0];
    const float* qkv_w  = (const float*)d_in[1];
    const float* qkv_b  = (const float*)d_in[2];
    const float* proj_w = (const float*)d_in[3];
    const float* proj_b = (const float*)d_in[4];
    const float* rph    = (const float*)d_in[5];
    const float* rpw    = (const float*)d_in[6];
    float* out = (float*)d_out;

    cudaFuncSetAttribute(flash2_kernel, cudaFuncAttributeMaxDynamicSharedMemorySize,
                         (int)sizeof(Flash2Smem));

    // QKV: [6272,3072] = hidden . qkv_w^T  (mma.sync TF32)
    mm_mma<0><<<dim3(3 * CD / BNT, BN / BM), 256>>>(hidden, qkv_w, qkv_b, nullptr);

    relpos_kernel<<<dim3(HH, BHN), 256>>>(rph, rpw);

    flash2_kernel<<<dim3((NN + 63) / 64, BHN), 256, sizeof(Flash2Smem)>>>();

    // proj: [6272,1024] = g_ao . proj_w^T
    mm_mma<1><<<dim3(CD / BNT, BN / BM), 256>>>(nullptr, proj_w, proj_b, out);
}

// round 5
// speedup vs baseline: 2.3732x; 1.1335x over previous
#include <cuda_runtime.h>
#include <cstdint>

#define NH   16
#define HD   64
#define CD   1024
#define BB   4
#define HH   56
#define WW   28
#define NN   1568          // HH*WW
#define BHN  64            // BB*NH
#define BN   6272          // BB*NN
#define QSCALE 0.125f      // 64^-0.5

// ---------------- scratch (device globals; no allocations allowed) ----------
__device__ float g_q[BHN * NN * HD];    // tf32, d-permuted, pre-scaled by QSCALE
__device__ float g_k[BHN * NN * HD];    // tf32, d-permuted
__device__ float g_v[BHN * NN * HD];    // tf32, natural layout
__device__ float g_relh[BHN * NN * HH];
__device__ float g_relw[BHN * NN * WW];
__device__ float g_ao[BN * CD];         // tf32, k-permuted, [B,N,heads,d]
__device__ float g_hp[BN * CD];         // hidden prepped (tf32 + perm)
__device__ float g_wp[3 * CD * CD];     // qkv_w prepped
__device__ float g_pwp[CD * CD];        // proj_w prepped

// ---------------- helpers ----------------------------------------------------
__device__ __forceinline__ float tf32r(float x) {
    uint32_t r;
    asm("cvt.rna.tf32.f32 %0, %1;" : "=r"(r) : "f"(x));
    return __uint_as_float(r);
}

__device__ __forceinline__ void mma_tf32(float* c, const uint32_t* a, const uint32_t* b) {
    asm volatile(
        "mma.sync.aligned.m16n8k8.row.col.f32.tf32.tf32.f32 "
        "{%0,%1,%2,%3}, {%4,%5,%6,%7}, {%8,%9}, {%0,%1,%2,%3};"
        : "+f"(c[0]), "+f"(c[1]), "+f"(c[2]), "+f"(c[3])
        : "r"(a[0]), "r"(a[1]), "r"(a[2]), "r"(a[3]), "r"(b[0]), "r"(b[1]));
}

__device__ __forceinline__ uint32_t smem_u32(const void* p) {
    uint32_t a;
    asm("{ .reg .u64 t; cvta.to.shared.u64 t, %1; cvt.u32.u64 %0, t; }"
        : "=r"(a) : "l"(p));
    return a;
}

__device__ __forceinline__ void cpa16(uint32_t dst, const void* src, uint32_t srcsize) {
    asm volatile("cp.async.ca.shared.global [%0], [%1], 16, %2;"
                 :: "r"(dst), "l"(src), "r"(srcsize) : "memory");
}
#define CPA_COMMIT() asm volatile("cp.async.commit_group;" ::: "memory")
#define CPA_WAIT0()  asm volatile("cp.async.wait_group 0;" ::: "memory")
#define CPA_WAIT1()  asm volatile("cp.async.wait_group 1;" ::: "memory")

// ---------------- prep: cvt to tf32 + k-permute within 8-groups --------------
// perm: within each 8-float group, src j goes to pos: j<4 -> 2j ; j>=4 -> 2j-7
__global__ void __launch_bounds__(256) prep_kernel(const float* __restrict__ src,
                                                   float* __restrict__ dst, int ngroups) {
    int i = blockIdx.x * blockDim.x + threadIdx.x;
    if (i >= ngroups) return;
    const float4* s = (const float4*)(src + (size_t)i * 8);
    float4 a = s[0], b = s[1];
    float4 o0 = make_float4(tf32r(a.x), tf32r(b.x), tf32r(a.y), tf32r(b.y));
    float4 o1 = make_float4(tf32r(a.z), tf32r(b.z), tf32r(a.w), tf32r(b.w));
    float4* d = (float4*)(dst + (size_t)i * 8);
    d[0] = o0; d[1] = o1;
}

// ================== cp.async double-buffered TF32 GEMM =======================
// C[M,N] = A[M,K] . B[N,K]^T   (A,B pre-converted tf32 + k-permuted in global)
// MODE 0: A=g_hp, B=g_wp, +qkv_b, scatter -> g_q (perm,scaled) / g_k (perm) / g_v
// MODE 1: A=g_ao, B=g_pwp, +proj_b -> Cout (natural)
#define PITCH 36
#define TSZ (128 * PITCH)   // floats per matrix tile buffer
#define MM_SMEM (4 * TSZ * 4)

template <int MODE>
__global__ void __launch_bounds__(256, 2) mm_cp(const float* __restrict__ bias,
                                                float* __restrict__ Cout) {
    extern __shared__ float smem[];
    uint32_t sb = smem_u32(smem);
    const float* A  = (MODE == 0) ? g_hp : g_ao;
    const float* Bm = (MODE == 0) ? g_wp : g_pwp;

    const int tid = threadIdx.x;
    const int wid = tid >> 5;
    const int lid = tid & 31;
    const int g = lid >> 2;
    const int t = lid & 3;
    const int m0 = blockIdx.y * 128;
    const int n0 = blockIdx.x * 128;
    const int wm = (wid & 1) * 64;
    const int wn = (wid >> 1) * 32;

    float acc[4][4][4];
#pragma unroll
    for (int mi = 0; mi < 4; mi++)
#pragma unroll
        for (int ni = 0; ni < 4; ni++)
#pragma unroll
            for (int e = 0; e < 4; e++) acc[mi][ni][e] = 0.f;

    // issue one k-tile (32 cols) of A and B into stage st
    auto issue = [&](int kt, int st) {
        const int k0 = kt * 32;
        uint32_t ab = sb + (uint32_t)(st * 2) * TSZ * 4;
        uint32_t bb = sb + (uint32_t)(st * 2 + 1) * TSZ * 4;
#pragma unroll
        for (int it = 0; it < 4; it++) {
            int idx = it * 256 + tid;
            int r = idx >> 3, cc = idx & 7;
            cpa16(ab + (uint32_t)(r * PITCH + cc * 4) * 4,
                  A + (size_t)(m0 + r) * CD + k0 + cc * 4, 16);
            cpa16(bb + (uint32_t)(r * PITCH + cc * 4) * 4,
                  Bm + (size_t)(n0 + r) * CD + k0 + cc * 4, 16);
        }
        CPA_COMMIT();
    };

    issue(0, 0);
    for (int kt = 0; kt < 32; kt++) {
        if (kt < 31) { issue(kt + 1, (kt + 1) & 1); CPA_WAIT1(); }
        else         { CPA_WAIT0(); }
        __syncthreads();
        const float* As = smem + (size_t)((kt & 1) * 2) * TSZ;
        const float* Bs = smem + (size_t)((kt & 1) * 2 + 1) * TSZ;

#pragma unroll
        for (int ko = 0; ko < 4; ko++) {
            uint32_t a[4][4];
            uint32_t b[4][2];
#pragma unroll
            for (int mi = 0; mi < 4; mi++) {
                float2 v0 = *(const float2*)(As + (wm + mi * 16 + g) * PITCH + ko * 8 + 2 * t);
                float2 v1 = *(const float2*)(As + (wm + mi * 16 + g + 8) * PITCH + ko * 8 + 2 * t);
                a[mi][0] = __float_as_uint(v0.x);
                a[mi][1] = __float_as_uint(v1.x);
                a[mi][2] = __float_as_uint(v0.y);
                a[mi][3] = __float_as_uint(v1.y);
            }
#pragma unroll
            for (int ni = 0; ni < 4; ni++) {
                float2 u = *(const float2*)(Bs + (wn + ni * 8 + g) * PITCH + ko * 8 + 2 * t);
                b[ni][0] = __float_as_uint(u.x);
                b[ni][1] = __float_as_uint(u.y);
            }
#pragma unroll
            for (int mi = 0; mi < 4; mi++)
#pragma unroll
                for (int ni = 0; ni < 4; ni++) mma_tf32(acc[mi][ni], a[mi], b[ni]);
        }
        __syncthreads();
    }

    // permuted positions for cols 2t, 2t+1 within their 8-group
    const int p0 = (t < 2) ? 4 * t : 4 * t - 7;
    const int p1 = (t < 2) ? 4 * t + 2 : 4 * t - 5;

#pragma unroll
    for (int mi = 0; mi < 4; mi++) {
        int mr0 = m0 + wm + mi * 16 + g;
        int mr1 = mr0 + 8;
#pragma unroll
        for (int ni = 0; ni < 4; ni++) {
            int jj = n0 + wn + ni * 8 + 2 * t;
            float b0 = bias[jj], b1 = bias[jj + 1];
            float v00 = acc[mi][ni][0] + b0, v01 = acc[mi][ni][1] + b1;
            float v10 = acc[mi][ni][2] + b0, v11 = acc[mi][ni][3] + b1;
            if (MODE == 0) {
                int tsel = jj >> 10;
                int rr = jj & 1023;
                int head = rr >> 6;
                int d = rr & 63;
                int dg = d & ~7;
                int b_0 = mr0 / NN, n_0 = mr0 - b_0 * NN;
                int b_1 = mr1 / NN, n_1 = mr1 - b_1 * NN;
                size_t base0 = (size_t)((b_0 * NH + head) * NN + n_0) * HD;
                size_t base1 = (size_t)((b_1 * NH + head) * NN + n_1) * HD;
                if (tsel == 0) {        // q: tf32 + perm + QSCALE
                    g_q[base0 + dg + p0] = tf32r(v00) * QSCALE;
                    g_q[base0 + dg + p1] = tf32r(v01) * QSCALE;
                    g_q[base1 + dg + p0] = tf32r(v10) * QSCALE;
                    g_q[base1 + dg + p1] = tf32r(v11) * QSCALE;
                } else if (tsel == 1) { // k: tf32 + perm
                    g_k[base0 + dg + p0] = tf32r(v00);
                    g_k[base0 + dg + p1] = tf32r(v01);
                    g_k[base1 + dg + p0] = tf32r(v10);
                    g_k[base1 + dg + p1] = tf32r(v11);
                } else {                // v: tf32, natural
                    float2 o0 = {tf32r(v00), tf32r(v01)};
                    float2 o1 = {tf32r(v10), tf32r(v11)};
                    *(float2*)&g_v[base0 + d] = o0;
                    *(float2*)&g_v[base1 + d] = o1;
                }
            } else {
                float2 o0 = {v00, v01};
                float2 o1 = {v10, v11};
                *(float2*)&Cout[(size_t)mr0 * CD + jj] = o0;
                *(float2*)&Cout[(size_t)mr1 * CD + jj] = o1;
            }
        }
    }
}

// ---------------- rel-pos bias precompute ------------------------------------
// g_q is tf32+permuted+QSCALEd: permute rel_pos rows the same way (dot invariant),
// multiply result by 8 to undo QSCALE.
__global__ void __launch_bounds__(256) relpos_kernel(const float* __restrict__ rph,
                                                     const float* __restrict__ rpw) {
    __shared__ float qs[WW][68];
    __shared__ float rhs[HH][68];
    __shared__ float rws[2 * WW - 1][68];

    int h = blockIdx.x;
    int bh = blockIdx.y;
    int tid = threadIdx.x;

    for (int idx = tid; idx < WW * HD; idx += 256) {
        int w = idx >> 6, d = idx & 63;
        qs[w][d] = g_q[((bh * NN) + h * WW + w) * HD + d];   // already permuted
    }
    for (int idx = tid; idx < HH * HD; idx += 256) {
        int kh = idx >> 6, d = idx & 63;
        int pd = (d & ~7) | (((d & 3) << 1) | ((d >> 2) & 1));
        rhs[kh][pd] = rph[(h + HH - 1 - kh) * HD + d];
    }
    for (int idx = tid; idx < (2 * WW - 1) * HD; idx += 256) {
        int r = idx >> 6, d = idx & 63;
        int pd = (d & ~7) | (((d & 3) << 1) | ((d >> 2) & 1));
        rws[r][pd] = rpw[r * HD + d];
    }
    __syncthreads();

    for (int idx = tid; idx < WW * HH; idx += 256) {
        int w = idx / HH;
        int kh = idx - w * HH;
        float s = 0.f;
#pragma unroll
        for (int d4 = 0; d4 < HD; d4 += 4) {
            float4 a = *(const float4*)&qs[w][d4];
            float4 b = *(const float4*)&rhs[kh][d4];
            s += a.x * b.x + a.y * b.y + a.z * b.z + a.w * b.w;
        }
        g_relh[((bh * NN) + h * WW + w) * HH + kh] = s * 8.f;
    }
    for (int idx = tid; idx < WW * WW; idx += 256) {
        int w = idx / WW;
        int kw = idx - w * WW;
        const float* rr = rws[w - kw + WW - 1];
        float s = 0.f;
#pragma unroll
        for (int d4 = 0; d4 < HD; d4 += 4) {
            float4 a = *(const float4*)&qs[w][d4];
            float4 b = *(const float4*)&rr[d4];
            s += a.x * b.x + a.y * b.y + a.z * b.z + a.w * b.w;
        }
        g_relw[((bh * NN) + h * WW + w) * WW + kw] = s * 8.f;
    }
}

// ---------------- flash attention v3 (cp.async + register softmax) -----------
#define FP 68

struct F3Smem {
    float qs[64 * FP];   // Q (tf32, perm, scaled) rows=q, cols=d-perm
    float kt[64 * FP];   // K rows=key, cols=d-perm
    float vs[64 * FP];   // V rows=key, cols=d natural
    float S[64 * FP];    // P, k-permuted cols
    float rh[64][HH];
    float rw[64][WW];
    float rowm[64];
    float rowl[64];
    float pm[2][64];
    float ps[2][64];
    int   kh_a[64];
    int   kw_a[64];
};

__global__ void __launch_bounds__(256) flash3_kernel() {
    extern __shared__ char raw[];
    F3Smem& s = *reinterpret_cast<F3Smem*>(raw);

    const int bh = blockIdx.y;
    const int qt0 = blockIdx.x;
    const int tid = threadIdx.x;
    const int wid = tid >> 5;
    const int lid = tid & 31;
    const int g = lid >> 2;
    const int t = lid & 3;
    const int wm = (wid & 3) * 16;
    const int wv = wid >> 2;
    const int wn = wv * 32;

    const int p0 = (t < 2) ? 4 * t : 4 * t - 7;
    const int p1 = (t < 2) ? 4 * t + 2 : 4 * t - 5;
    const int r0 = wm + g, r1 = wm + g + 8;

    // ---- Q via cp.async (already tf32+perm+scaled) ----
    {
        uint32_t qaddr = smem_u32(s.qs);
#pragma unroll
        for (int it = 0; it < 4; it++) {
            int idx = it * 256 + tid;
            int r = idx >> 4, cc = idx & 15;
            int n = qt0 * 64 + r;
            const float* src = g_q + (n < NN ? (size_t)(bh * NN + n) * HD + cc * 4 : 0);
            cpa16(qaddr + (uint32_t)(r * FP + cc * 4) * 4, src, n < NN ? 16u : 0u);
        }
        CPA_COMMIT();
    }
    for (int idx = tid; idx < 64 * HH; idx += 256) {
        int r = idx / HH, kh = idx - r * HH;
        int n = qt0 * 64 + r;
        s.rh[r][kh] = (n < NN) ? g_relh[(size_t)(bh * NN + n) * HH + kh] : 0.f;
    }
    for (int idx = tid; idx < 64 * WW; idx += 256) {
        int r = idx / WW, kw = idx - r * WW;
        int n = qt0 * 64 + r;
        s.rw[r][kw] = (n < NN) ? g_relw[(size_t)(bh * NN + n) * WW + kw] : 0.f;
    }
    if (tid < 64) { s.rowm[tid] = -1e30f; s.rowl[tid] = 0.f; }

    float acc[4][4];
#pragma unroll
    for (int ni = 0; ni < 4; ni++)
#pragma unroll
        for (int e = 0; e < 4; e++) acc[ni][e] = 0.f;

    CPA_WAIT0();
    __syncthreads();

    const uint32_t kaddr = smem_u32(s.kt);
    const uint32_t vaddr = smem_u32(s.vs);

    for (int kt2 = 0; kt2 < 25; kt2++) {
        const int kbase = kt2 * 64;
        __syncthreads();   // (A) prior QK/PV readers of kt/vs done

        // ---- K/V via cp.async ----
#pragma unroll
        for (int it = 0; it < 8; it++) {
            int idx = it * 256 + tid;
            int mat = idx >> 10;
            int cidx = idx & 1023;
            int r = cidx >> 4, cc = cidx & 15;
            int kn = kbase + r;
            bool ok = kn < NN;
            size_t off = ok ? (size_t)(bh * NN + kn) * HD + cc * 4 : 0;
            if (mat == 0)
                cpa16(kaddr + (uint32_t)(r * FP + cc * 4) * 4, g_k + off, ok ? 16u : 0u);
            else
                cpa16(vaddr + (uint32_t)(r * FP + cc * 4) * 4, g_v + off, ok ? 16u : 0u);
        }
        CPA_COMMIT();
        if (tid < 64) {
            int kn = kbase + tid;
            s.kh_a[tid] = (kn < NN) ? kn / WW : -1;
            s.kw_a[tid] = (kn < NN) ? kn % WW : 0;
        }
        CPA_WAIT0();
        __syncthreads();   // (B)

        // ---- QK^T mma ----
        float c[4][4];
#pragma unroll
        for (int ni = 0; ni < 4; ni++)
#pragma unroll
            for (int e = 0; e < 4; e++) c[ni][e] = 0.f;
#pragma unroll
        for (int ko = 0; ko < 8; ko++) {
            uint32_t a[4];
            float2 v0 = *(const float2*)(s.qs + r0 * FP + ko * 8 + 2 * t);
            float2 v1 = *(const float2*)(s.qs + r1 * FP + ko * 8 + 2 * t);
            a[0] = __float_as_uint(v0.x); a[1] = __float_as_uint(v1.x);
            a[2] = __float_as_uint(v0.y); a[3] = __float_as_uint(v1.y);
#pragma unroll
            for (int ni = 0; ni < 4; ni++) {
                float2 u = *(const float2*)(s.kt + (wn + ni * 8 + g) * FP + ko * 8 + 2 * t);
                uint32_t b[2] = {__float_as_uint(u.x), __float_as_uint(u.y)};
                mma_tf32(c[ni], a, b);
            }
        }
        // ---- bias + mask in registers ----
#pragma unroll
        for (int ni = 0; ni < 4; ni++) {
            int c0l = wn + ni * 8 + 2 * t, c1l = c0l + 1;
            int kh0 = s.kh_a[c0l], kw0 = s.kw_a[c0l];
            int kh1 = s.kh_a[c1l], kw1 = s.kw_a[c1l];
            if (kh0 >= 0) {
                c[ni][0] += s.rh[r0][kh0] + s.rw[r0][kw0];
                c[ni][2] += s.rh[r1][kh0] + s.rw[r1][kw0];
            } else { c[ni][0] = -1e30f; c[ni][2] = -1e30f; }
            if (kh1 >= 0) {
                c[ni][1] += s.rh[r0][kh1] + s.rw[r0][kw1];
                c[ni][3] += s.rh[r1][kh1] + s.rw[r1][kw1];
            } else { c[ni][1] = -1e30f; c[ni][3] = -1e30f; }
        }

        // ---- register softmax: quad-reduced max ----
        float tm0 = -1e30f, tm1 = -1e30f;
#pragma unroll
        for (int ni = 0; ni < 4; ni++) {
            tm0 = fmaxf(tm0, fmaxf(c[ni][0], c[ni][1]));
            tm1 = fmaxf(tm1, fmaxf(c[ni][2], c[ni][3]));
        }
        tm0 = fmaxf(tm0, __shfl_xor_sync(0xffffffffu, tm0, 1));
        tm0 = fmaxf(tm0, __shfl_xor_sync(0xffffffffu, tm0, 2));
        tm1 = fmaxf(tm1, __shfl_xor_sync(0xffffffffu, tm1, 1));
        tm1 = fmaxf(tm1, __shfl_xor_sync(0xffffffffu, tm1, 2));
        if (t == 0) { s.pm[wv][r0] = tm0; s.pm[wv][r1] = tm1; }
        __syncthreads();   // (C)

        // ---- exp on fragments, row-sum, P store ----
        float mo0 = s.rowm[r0], mo1 = s.rowm[r1];
        float mn0 = fmaxf(mo0, fmaxf(s.pm[0][r0], s.pm[1][r0]));
        float mn1 = fmaxf(mo1, fmaxf(s.pm[0][r1], s.pm[1][r1]));
        float fac0 = __expf(mo0 - mn0), fac1 = __expf(mo1 - mn1);
        float ts0 = 0.f, ts1 = 0.f;
#pragma unroll
        for (int ni = 0; ni < 4; ni++) {
            int cb = wn + ni * 8;
            float p00 = tf32r(__expf(c[ni][0] - mn0));
            float p01 = tf32r(__expf(c[ni][1] - mn0));
            float p10 = tf32r(__expf(c[ni][2] - mn1));
            float p11 = tf32r(__expf(c[ni][3] - mn1));
            ts0 += p00 + p01;
            ts1 += p10 + p11;
            s.S[r0 * FP + cb + p0] = p00;
            s.S[r0 * FP + cb + p1] = p01;
            s.S[r1 * FP + cb + p0] = p10;
            s.S[r1 * FP + cb + p1] = p11;
        }
        ts0 += __shfl_xor_sync(0xffffffffu, ts0, 1);
        ts0 += __shfl_xor_sync(0xffffffffu, ts0, 2);
        ts1 += __shfl_xor_sync(0xffffffffu, ts1, 1);
        ts1 += __shfl_xor_sync(0xffffffffu, ts1, 2);
        if (t == 0) { s.ps[wv][r0] = ts0; s.ps[wv][r1] = ts1; }

        // rescale running accumulators
#pragma unroll
        for (int ni = 0; ni < 4; ni++) {
            acc[ni][0] *= fac0; acc[ni][1] *= fac0;
            acc[ni][2] *= fac1; acc[ni][3] *= fac1;
        }
        __syncthreads();   // (D)

        // ---- running max/len update ----
        if (tid < 64) {
            float mo = s.rowm[tid];
            float mn = fmaxf(mo, fmaxf(s.pm[0][tid], s.pm[1][tid]));
            s.rowm[tid] = mn;
            s.rowl[tid] = s.rowl[tid] * __expf(mo - mn) + s.ps[0][tid] + s.ps[1][tid];
        }

        // ---- P @ V mma ----
#pragma unroll
        for (int ko = 0; ko < 8; ko++) {
            uint32_t a[4];
            float2 v0 = *(const float2*)(s.S + r0 * FP + ko * 8 + 2 * t);
            float2 v1 = *(const float2*)(s.S + r1 * FP + ko * 8 + 2 * t);
            a[0] = __float_as_uint(v0.x); a[1] = __float_as_uint(v1.x);
            a[2] = __float_as_uint(v0.y); a[3] = __float_as_uint(v1.y);
#pragma unroll
            for (int ni = 0; ni < 4; ni++) {
                uint32_t b[2];
                b[0] = __float_as_uint(s.vs[(ko * 8 + t) * FP + wn + ni * 8 + g]);
                b[1] = __float_as_uint(s.vs[(ko * 8 + t + 4) * FP + wn + ni * 8 + g]);
                mma_tf32(acc[ni], a, b);
            }
        }
    }
    __syncthreads();

    // ---- normalize + store g_ao (tf32, k-permuted) ----
    const int b = bh >> 4;
    const int head = bh & 15;
    const int n0g = qt0 * 64 + r0;
    const int n1g = qt0 * 64 + r1;
    float li0 = 1.f / s.rowl[r0];
    float li1 = 1.f / s.rowl[r1];
#pragma unroll
    for (int ni = 0; ni < 4; ni++) {
        int dg = wn + ni * 8;
        if (n0g < NN) {
            size_t base = (size_t)(b * NN + n0g) * CD + head * HD + dg;
            g_ao[base + p0] = tf32r(acc[ni][0] * li0);
            g_ao[base + p1] = tf32r(acc[ni][1] * li0);
        }
        if (n1g < NN) {
            size_t base = (size_t)(b * NN + n1g) * CD + head * HD + dg;
            g_ao[base + p0] = tf32r(acc[ni][2] * li1);
            g_ao[base + p1] = tf32r(acc[ni][3] * li1);
        }
    }
}

// ---------------- launch -----------------------------------------------------
extern "C" void kernel_launch(void* const* d_in, const int* in_sizes, int n_in,
                              void* d_out, int out_size) {
    const float* hidden = (const float*)d_in[0];
    const float* qkv_w  = (const float*)d_in[1];
    const float* qkv_b  = (const float*)d_in[2];
    const float* proj_w = (const float*)d_in[3];
    const float* proj_b = (const float*)d_in[4];
    const float* rph    = (const float*)d_in[5];
    const float* rpw    = (const float*)d_in[6];
    float* out = (float*)d_out;

    cudaFuncSetAttribute(flash3_kernel, cudaFuncAttributeMaxDynamicSharedMemorySize,
                         (int)sizeof(F3Smem));
    cudaFuncSetAttribute(mm_cp<0>, cudaFuncAttributeMaxDynamicSharedMemorySize, MM_SMEM);
    cudaFuncSetAttribute(mm_cp<1>, cudaFuncAttributeMaxDynamicSharedMemorySize, MM_SMEM);

    float* d_hp;  cudaGetSymbolAddress((void**)&d_hp,  g_hp);
    float* d_wp;  cudaGetSymbolAddress((void**)&d_wp,  g_wp);
    float* d_pwp; cudaGetSymbolAddress((void**)&d_pwp, g_pwp);

    // prep: cvt tf32 + k-permute
    prep_kernel<<<(BN * CD / 8 + 255) / 256, 256>>>(hidden, d_hp, BN * CD / 8);
    prep_kernel<<<(3 * CD * CD / 8 + 255) / 256, 256>>>(qkv_w, d_wp, 3 * CD * CD / 8);
    prep_kernel<<<(CD * CD / 8 + 255) / 256, 256>>>(proj_w, d_pwp, CD * CD / 8);

    // QKV: [6272,3072] = hidden . qkv_w^T
    mm_cp<0><<<dim3(3 * CD / 128, BN / 128), 256, MM_SMEM>>>(qkv_b, nullptr);

    relpos_kernel<<<dim3(HH, BHN), 256>>>(rph, rpw);

    flash3_kernel<<<dim3((NN + 63) / 64, BHN), 256, sizeof(F3Smem)>>>();

    // proj: [6272,1024] = g_ao . proj_w^T
    mm_cp<1><<<dim3(CD / 128, BN / 128), 256, MM_SMEM>>>(proj_b, out);
}

// round 6
// speedup vs baseline: 2.4871x; 1.0480x over previous
#include <cuda_runtime.h>
#include <cstdint>

#define NH   16
#define HD   64
#define CD   1024
#define BB   4
#define HH   56
#define WW   28
#define NN   1568          // HH*WW
#define BHN  64            // BB*NH
#define BN   6272          // BB*NN
#define QSCALE 0.125f      // 64^-0.5

// ---------------- scratch (device globals; no allocations allowed) ----------
__device__ float g_q[BHN * NN * HD];    // tf32, d-permuted, pre-scaled by QSCALE
__device__ float g_k[BHN * NN * HD];    // tf32, d-permuted
__device__ float g_v[BHN * NN * HD];    // tf32, natural layout
__device__ float g_relh[BHN * NN * HH];
__device__ float g_relw[BHN * NN * WW];
__device__ float g_ao[BN * CD];         // tf32, k-permuted, [B,N,heads,d]
__device__ float g_hp[BN * CD];         // hidden prepped (tf32 + perm)
__device__ float g_wp[3 * CD * CD];     // qkv_w prepped
__device__ float g_pwp[CD * CD];        // proj_w prepped

// ---------------- helpers ----------------------------------------------------
__device__ __forceinline__ float tf32r(float x) {
    uint32_t r;
    asm("cvt.rna.tf32.f32 %0, %1;" : "=r"(r) : "f"(x));
    return __uint_as_float(r);
}

__device__ __forceinline__ void mma_tf32(float* c, const uint32_t* a, const uint32_t* b) {
    asm volatile(
        "mma.sync.aligned.m16n8k8.row.col.f32.tf32.tf32.f32 "
        "{%0,%1,%2,%3}, {%4,%5,%6,%7}, {%8,%9}, {%0,%1,%2,%3};"
        : "+f"(c[0]), "+f"(c[1]), "+f"(c[2]), "+f"(c[3])
        : "r"(a[0]), "r"(a[1]), "r"(a[2]), "r"(a[3]), "r"(b[0]), "r"(b[1]));
}

__device__ __forceinline__ uint32_t smem_u32(const void* p) {
    uint32_t a;
    asm("{ .reg .u64 t; cvta.to.shared.u64 t, %1; cvt.u32.u64 %0, t; }"
        : "=r"(a) : "l"(p));
    return a;
}

__device__ __forceinline__ void cpa16(uint32_t dst, const void* src, uint32_t srcsize) {
    asm volatile("cp.async.ca.shared.global [%0], [%1], 16, %2;"
                 :: "r"(dst), "l"(src), "r"(srcsize) : "memory");
}
#define CPA_COMMIT() asm volatile("cp.async.commit_group;" ::: "memory")
#define CPA_WAIT0()  asm volatile("cp.async.wait_group 0;" ::: "memory")
#define CPA_WAIT1()  asm volatile("cp.async.wait_group 1;" ::: "memory")

// ---------------- prep: cvt to tf32 + k-permute within 8-groups --------------
__global__ void __launch_bounds__(256) prep_kernel(const float* __restrict__ src,
                                                   float* __restrict__ dst, int ngroups) {
    int i = blockIdx.x * blockDim.x + threadIdx.x;
    if (i >= ngroups) return;
    const float4* s = (const float4*)(src + (size_t)i * 8);
    float4 a = s[0], b = s[1];
    float4 o0 = make_float4(tf32r(a.x), tf32r(b.x), tf32r(a.y), tf32r(b.y));
    float4 o1 = make_float4(tf32r(a.z), tf32r(b.z), tf32r(a.w), tf32r(b.w));
    float4* d = (float4*)(dst + (size_t)i * 8);
    d[0] = o0; d[1] = o1;
}

// ================== cp.async 3-stage TF32 GEMM ===============================
// C[M,N] = A[M,K] . B[N,K]^T  (operands tf32+permuted in global)
#define MMTSZ (128 * 32)      // floats per matrix tile (16KB)
#define MMSTG (2 * MMTSZ)     // A+B per stage
#define MM_SMEM (3 * MMSTG * 4)

template <int MODE>
__global__ void __launch_bounds__(256, 2) mm_cp(const float* __restrict__ bias,
                                                float* __restrict__ Cout) {
    extern __shared__ float smem[];
    uint32_t sb = smem_u32(smem);
    const float* A  = (MODE == 0) ? g_hp : g_ao;
    const float* Bm = (MODE == 0) ? g_wp : g_pwp;

    const int tid = threadIdx.x;
    const int wid = tid >> 5;
    const int lid = tid & 31;
    const int g = lid >> 2;
    const int t = lid & 3;
    const int m0 = blockIdx.y * 128;
    const int n0 = blockIdx.x * 128;
    const int wm = (wid & 1) * 64;
    const int wn = (wid >> 1) * 32;

    float acc[4][4][4];
#pragma unroll
    for (int mi = 0; mi < 4; mi++)
#pragma unroll
        for (int ni = 0; ni < 4; ni++)
#pragma unroll
            for (int e = 0; e < 4; e++) acc[mi][ni][e] = 0.f;

    const int lr = tid >> 3;     // loader row
    const int lq = tid & 7;      // loader 16B chunk
    const uint32_t ldst = (uint32_t)(lr * 32 + ((lq ^ (lr & 7)) << 2)) * 4;

    auto issue = [&](int kt) {
        const int st = kt % 3;
        const int k0 = kt * 32;
        uint32_t ab = sb + (uint32_t)st * MMSTG * 4;
        uint32_t bb = ab + MMTSZ * 4;
#pragma unroll
        for (int it = 0; it < 4; it++) {
            int r = lr + it * 32;
            uint32_t dof = ldst + (uint32_t)(it * 32 * 32) * 4;
            cpa16(ab + dof, A + (size_t)(m0 + r) * CD + k0 + lq * 4, 16);
            cpa16(bb + dof, Bm + (size_t)(n0 + r) * CD + k0 + lq * 4, 16);
        }
        CPA_COMMIT();
    };

    issue(0); issue(1);
    for (int kt = 0; kt < 32; kt++) {
        if (kt < 31) CPA_WAIT1(); else CPA_WAIT0();
        __syncthreads();
        if (kt + 2 < 32) issue(kt + 2);

        const float* As = smem + (size_t)(kt % 3) * MMSTG;
        const float* Bs = As + MMTSZ;

#pragma unroll
        for (int ko = 0; ko < 4; ko++) {
            const int coff = (((ko * 2 + (t >> 1)) ^ g) << 2) + ((t & 1) << 1);
            uint32_t a[4][4];
            uint32_t b[4][2];
#pragma unroll
            for (int mi = 0; mi < 4; mi++) {
                float2 v0 = *(const float2*)(As + (wm + mi * 16 + g) * 32 + coff);
                float2 v1 = *(const float2*)(As + (wm + mi * 16 + g + 8) * 32 + coff);
                a[mi][0] = __float_as_uint(v0.x);
                a[mi][1] = __float_as_uint(v1.x);
                a[mi][2] = __float_as_uint(v0.y);
                a[mi][3] = __float_as_uint(v1.y);
            }
#pragma unroll
            for (int ni = 0; ni < 4; ni++) {
                float2 u = *(const float2*)(Bs + (wn + ni * 8 + g) * 32 + coff);
                b[ni][0] = __float_as_uint(u.x);
                b[ni][1] = __float_as_uint(u.y);
            }
#pragma unroll
            for (int mi = 0; mi < 4; mi++)
#pragma unroll
                for (int ni = 0; ni < 4; ni++) mma_tf32(acc[mi][ni], a[mi], b[ni]);
        }
    }

    const int p0 = (t < 2) ? 4 * t : 4 * t - 7;
    const int p1 = (t < 2) ? 4 * t + 2 : 4 * t - 5;

#pragma unroll
    for (int mi = 0; mi < 4; mi++) {
        int mr0 = m0 + wm + mi * 16 + g;
        int mr1 = mr0 + 8;
#pragma unroll
        for (int ni = 0; ni < 4; ni++) {
            int jj = n0 + wn + ni * 8 + 2 * t;
            float b0 = bias[jj], b1 = bias[jj + 1];
            float v00 = acc[mi][ni][0] + b0, v01 = acc[mi][ni][1] + b1;
            float v10 = acc[mi][ni][2] + b0, v11 = acc[mi][ni][3] + b1;
            if (MODE == 0) {
                int tsel = jj >> 10;
                int rr = jj & 1023;
                int head = rr >> 6;
                int d = rr & 63;
                int dg = d & ~7;
                int b_0 = mr0 / NN, n_0 = mr0 - b_0 * NN;
                int b_1 = mr1 / NN, n_1 = mr1 - b_1 * NN;
                size_t base0 = (size_t)((b_0 * NH + head) * NN + n_0) * HD;
                size_t base1 = (size_t)((b_1 * NH + head) * NN + n_1) * HD;
                if (tsel == 0) {
                    g_q[base0 + dg + p0] = tf32r(v00) * QSCALE;
                    g_q[base0 + dg + p1] = tf32r(v01) * QSCALE;
                    g_q[base1 + dg + p0] = tf32r(v10) * QSCALE;
                    g_q[base1 + dg + p1] = tf32r(v11) * QSCALE;
                } else if (tsel == 1) {
                    g_k[base0 + dg + p0] = tf32r(v00);
                    g_k[base0 + dg + p1] = tf32r(v01);
                    g_k[base1 + dg + p0] = tf32r(v10);
                    g_k[base1 + dg + p1] = tf32r(v11);
                } else {
                    float2 o0 = {tf32r(v00), tf32r(v01)};
                    float2 o1 = {tf32r(v10), tf32r(v11)};
                    *(float2*)&g_v[base0 + d] = o0;
                    *(float2*)&g_v[base1 + d] = o1;
                }
            } else {
                float2 o0 = {v00, v01};
                float2 o1 = {v10, v11};
                *(float2*)&Cout[(size_t)mr0 * CD + jj] = o0;
                *(float2*)&Cout[(size_t)mr1 * CD + jj] = o1;
            }
        }
    }
}

// ---------------- rel-pos bias via TF32 mma -----------------------------------
// Per (bh, h): C[32 x 112] = q_perm[32 x 64] . B^T, B rows: 0..55 = rph[h+55-kh]
// (perm), 56..110 = rpw[0..54] (perm), 111 = 0. rel_h written from frags;
// rel_w gathered: rel_w[w][kw] = C[w][56 + w - kw + 27]. Outputs x8 (undo QSCALE).
__global__ void __launch_bounds__(256) relpos_kernel(const float* __restrict__ rph,
                                                     const float* __restrict__ rpw) {
    __shared__ float qp[32 * 68];
    __shared__ float Bp[112 * 68];
    __shared__ float outw[32 * 60];

    const int h = blockIdx.x;
    const int bh = blockIdx.y;
    const int tid = threadIdx.x;
    const int wid = tid >> 5;
    const int lid = tid & 31;
    const int g = lid >> 2;
    const int t = lid & 3;

    for (int idx = tid; idx < 32 * 16; idx += 256) {
        int r = idx >> 4, cc = idx & 15;
        float4 v = make_float4(0.f, 0.f, 0.f, 0.f);
        if (r < WW) v = *(const float4*)&g_q[((size_t)(bh * NN) + h * WW + r) * HD + cc * 4];
        *(float4*)&qp[r * 68 + cc * 4] = v;
    }
    for (int idx = tid; idx < 112 * 16; idx += 256) {
        int r = idx >> 4, cc = idx & 15;
        float4 v = make_float4(0.f, 0.f, 0.f, 0.f);
        if (r < 56)       v = *(const float4*)&rph[(size_t)(h + 55 - r) * HD + cc * 4];
        else if (r < 111) v = *(const float4*)&rpw[(size_t)(r - 56) * HD + cc * 4];
        float* p = Bp + r * 68 + (cc >> 1) * 8 + (cc & 1);
        p[0] = tf32r(v.x); p[2] = tf32r(v.y);
        p[4] = tf32r(v.z); p[6] = tf32r(v.w);
    }
    __syncthreads();

    for (int ti = wid; ti < 14; ti += 8) {
        float c[2][4];
#pragma unroll
        for (int mi = 0; mi < 2; mi++)
#pragma unroll
            for (int e = 0; e < 4; e++) c[mi][e] = 0.f;
#pragma unroll
        for (int ko = 0; ko < 8; ko++) {
            uint32_t a0[4], a1[4], b[2];
            float2 v0 = *(const float2*)(qp + g * 68 + ko * 8 + 2 * t);
            float2 v1 = *(const float2*)(qp + (g + 8) * 68 + ko * 8 + 2 * t);
            float2 v2 = *(const float2*)(qp + (16 + g) * 68 + ko * 8 + 2 * t);
            float2 v3 = *(const float2*)(qp + (24 + g) * 68 + ko * 8 + 2 * t);
            a0[0] = __float_as_uint(v0.x); a0[1] = __float_as_uint(v1.x);
            a0[2] = __float_as_uint(v0.y); a0[3] = __float_as_uint(v1.y);
            a1[0] = __float_as_uint(v2.x); a1[1] = __float_as_uint(v3.x);
            a1[2] = __float_as_uint(v2.y); a1[3] = __float_as_uint(v3.y);
            float2 u = *(const float2*)(Bp + (ti * 8 + g) * 68 + ko * 8 + 2 * t);
            b[0] = __float_as_uint(u.x); b[1] = __float_as_uint(u.y);
            mma_tf32(c[0], a0, b);
            mma_tf32(c[1], a1, b);
        }
        if (ti < 7) {
            int kh0 = ti * 8 + 2 * t, kh1 = kh0 + 1;
            size_t nb = (size_t)(bh * NN) + h * WW;
            // rows g, g+8, 16+g always < 28; row 24+g needs g < 4
            g_relh[(nb + g) * HH + kh0]        = c[0][0] * 8.f;
            g_relh[(nb + g) * HH + kh1]        = c[0][1] * 8.f;
            g_relh[(nb + g + 8) * HH + kh0]    = c[0][2] * 8.f;
            g_relh[(nb + g + 8) * HH + kh1]    = c[0][3] * 8.f;
            g_relh[(nb + 16 + g) * HH + kh0]   = c[1][0] * 8.f;
            g_relh[(nb + 16 + g) * HH + kh1]   = c[1][1] * 8.f;
            if (g < 4) {
                g_relh[(nb + 24 + g) * HH + kh0] = c[1][2] * 8.f;
                g_relh[(nb + 24 + g) * HH + kh1] = c[1][3] * 8.f;
            }
        } else {
            int cb = (ti - 7) * 8 + 2 * t;
            outw[g * 60 + cb] = c[0][0];        outw[g * 60 + cb + 1] = c[0][1];
            outw[(g + 8) * 60 + cb] = c[0][2];  outw[(g + 8) * 60 + cb + 1] = c[0][3];
            outw[(16 + g) * 60 + cb] = c[1][0]; outw[(16 + g) * 60 + cb + 1] = c[1][1];
            outw[(24 + g) * 60 + cb] = c[1][2]; outw[(24 + g) * 60 + cb + 1] = c[1][3];
        }
    }
    __syncthreads();

    for (int idx = tid; idx < WW * WW; idx += 256) {
        int w = idx / WW, kw = idx - w * WW;
        g_relw[((size_t)(bh * NN) + h * WW + w) * WW + kw] =
            outw[w * 60 + (w - kw + 27)] * 8.f;
    }
}

// ---------------- flash attention v4 (split K/V waits) -----------------------
#define FP 68

struct F4Smem {
    float qs[64 * FP];
    float kt[64 * FP];
    float vs[64 * FP];
    float S[64 * FP];
    float rh[64][HH];
    float rw[64][WW];
    float rowm[64];
    float rowl[64];
    float pm[2][64];
    float ps[2][64];
    int   kh_a[64];
    int   kw_a[64];
};

__global__ void __launch_bounds__(256) flash4_kernel() {
    extern __shared__ char raw[];
    F4Smem& s = *reinterpret_cast<F4Smem*>(raw);

    const int bh = blockIdx.y;
    const int qt0 = blockIdx.x;
    const int tid = threadIdx.x;
    const int wid = tid >> 5;
    const int lid = tid & 31;
    const int g = lid >> 2;
    const int t = lid & 3;
    const int wm = (wid & 3) * 16;
    const int wv = wid >> 2;
    const int wn = wv * 32;

    const int p0 = (t < 2) ? 4 * t : 4 * t - 7;
    const int p1 = (t < 2) ? 4 * t + 2 : 4 * t - 5;
    const int r0 = wm + g, r1 = wm + g + 8;

    // ---- Q via cp.async ----
    {
        uint32_t qaddr = smem_u32(s.qs);
#pragma unroll
        for (int it = 0; it < 4; it++) {
            int idx = it * 256 + tid;
            int r = idx >> 4, cc = idx & 15;
            int n = qt0 * 64 + r;
            const float* src = g_q + (n < NN ? (size_t)(bh * NN + n) * HD + cc * 4 : 0);
            cpa16(qaddr + (uint32_t)(r * FP + cc * 4) * 4, src, n < NN ? 16u : 0u);
        }
        CPA_COMMIT();
    }
    for (int idx = tid; idx < 64 * HH; idx += 256) {
        int r = idx / HH, kh = idx - r * HH;
        int n = qt0 * 64 + r;
        s.rh[r][kh] = (n < NN) ? g_relh[(size_t)(bh * NN + n) * HH + kh] : 0.f;
    }
    for (int idx = tid; idx < 64 * WW; idx += 256) {
        int r = idx / WW, kw = idx - r * WW;
        int n = qt0 * 64 + r;
        s.rw[r][kw] = (n < NN) ? g_relw[(size_t)(bh * NN + n) * WW + kw] : 0.f;
    }
    if (tid < 64) { s.rowm[tid] = -1e30f; s.rowl[tid] = 0.f; }

    float acc[4][4];
#pragma unroll
    for (int ni = 0; ni < 4; ni++)
#pragma unroll
        for (int e = 0; e < 4; e++) acc[ni][e] = 0.f;

    const uint32_t kaddr = smem_u32(s.kt);
    const uint32_t vaddr = smem_u32(s.vs);

    for (int kt2 = 0; kt2 < 25; kt2++) {
        const int kbase = kt2 * 64;
        __syncthreads();   // (A) prior readers of kt/vs/S done

        // ---- K group ----
#pragma unroll
        for (int it = 0; it < 4; it++) {
            int idx = it * 256 + tid;
            int r = idx >> 4, cc = idx & 15;
            int kn = kbase + r;
            bool ok = kn < NN;
            size_t off = ok ? (size_t)(bh * NN + kn) * HD + cc * 4 : 0;
            cpa16(kaddr + (uint32_t)(r * FP + cc * 4) * 4, g_k + off, ok ? 16u : 0u);
        }
        CPA_COMMIT();
        // ---- V group ----
#pragma unroll
        for (int it = 0; it < 4; it++) {
            int idx = it * 256 + tid;
            int r = idx >> 4, cc = idx & 15;
            int kn = kbase + r;
            bool ok = kn < NN;
            size_t off = ok ? (size_t)(bh * NN + kn) * HD + cc * 4 : 0;
            cpa16(vaddr + (uint32_t)(r * FP + cc * 4) * 4, g_v + off, ok ? 16u : 0u);
        }
        CPA_COMMIT();
        if (tid < 64) {
            int kn = kbase + tid;
            s.kh_a[tid] = (kn < NN) ? kn / WW : -1;
            s.kw_a[tid] = (kn < NN) ? kn % WW : 0;
        }
        CPA_WAIT1();       // K (and Q on iter 0) done; V may still be in flight
        __syncthreads();   // (B)

        // ---- QK^T mma ----
        float c[4][4];
#pragma unroll
        for (int ni = 0; ni < 4; ni++)
#pragma unroll
            for (int e = 0; e < 4; e++) c[ni][e] = 0.f;
#pragma unroll
        for (int ko = 0; ko < 8; ko++) {
            uint32_t a[4];
            float2 v0 = *(const float2*)(s.qs + r0 * FP + ko * 8 + 2 * t);
            float2 v1 = *(const float2*)(s.qs + r1 * FP + ko * 8 + 2 * t);
            a[0] = __float_as_uint(v0.x); a[1] = __float_as_uint(v1.x);
            a[2] = __float_as_uint(v0.y); a[3] = __float_as_uint(v1.y);
#pragma unroll
            for (int ni = 0; ni < 4; ni++) {
                float2 u = *(const float2*)(s.kt + (wn + ni * 8 + g) * FP + ko * 8 + 2 * t);
                uint32_t b[2] = {__float_as_uint(u.x), __float_as_uint(u.y)};
                mma_tf32(c[ni], a, b);
            }
        }
        // ---- bias + mask ----
#pragma unroll
        for (int ni = 0; ni < 4; ni++) {
            int c0l = wn + ni * 8 + 2 * t, c1l = c0l + 1;
            int kh0 = s.kh_a[c0l], kw0 = s.kw_a[c0l];
            int kh1 = s.kh_a[c1l], kw1 = s.kw_a[c1l];
            if (kh0 >= 0) {
                c[ni][0] += s.rh[r0][kh0] + s.rw[r0][kw0];
                c[ni][2] += s.rh[r1][kh0] + s.rw[r1][kw0];
            } else { c[ni][0] = -1e30f; c[ni][2] = -1e30f; }
            if (kh1 >= 0) {
                c[ni][1] += s.rh[r0][kh1] + s.rw[r0][kw1];
                c[ni][3] += s.rh[r1][kh1] + s.rw[r1][kw1];
            } else { c[ni][1] = -1e30f; c[ni][3] = -1e30f; }
        }

        // ---- register softmax max ----
        float tm0 = -1e30f, tm1 = -1e30f;
#pragma unroll
        for (int ni = 0; ni < 4; ni++) {
            tm0 = fmaxf(tm0, fmaxf(c[ni][0], c[ni][1]));
            tm1 = fmaxf(tm1, fmaxf(c[ni][2], c[ni][3]));
        }
        tm0 = fmaxf(tm0, __shfl_xor_sync(0xffffffffu, tm0, 1));
        tm0 = fmaxf(tm0, __shfl_xor_sync(0xffffffffu, tm0, 2));
        tm1 = fmaxf(tm1, __shfl_xor_sync(0xffffffffu, tm1, 1));
        tm1 = fmaxf(tm1, __shfl_xor_sync(0xffffffffu, tm1, 2));
        if (t == 0) { s.pm[wv][r0] = tm0; s.pm[wv][r1] = tm1; }
        __syncthreads();   // (C)

        // ---- exp + P store + sums ----
        float mo0 = s.rowm[r0], mo1 = s.rowm[r1];
        float mn0 = fmaxf(mo0, fmaxf(s.pm[0][r0], s.pm[1][r0]));
        float mn1 = fmaxf(mo1, fmaxf(s.pm[0][r1], s.pm[1][r1]));
        float fac0 = __expf(mo0 - mn0), fac1 = __expf(mo1 - mn1);
        float ts0 = 0.f, ts1 = 0.f;
#pragma unroll
        for (int ni = 0; ni < 4; ni++) {
            int cb = wn + ni * 8;
            float p00 = tf32r(__expf(c[ni][0] - mn0));
            float p01 = tf32r(__expf(c[ni][1] - mn0));
            float p10 = tf32r(__expf(c[ni][2] - mn1));
            float p11 = tf32r(__expf(c[ni][3] - mn1));
            ts0 += p00 + p01;
            ts1 += p10 + p11;
            s.S[r0 * FP + cb + p0] = p00;
            s.S[r0 * FP + cb + p1] = p01;
            s.S[r1 * FP + cb + p0] = p10;
            s.S[r1 * FP + cb + p1] = p11;
        }
        ts0 += __shfl_xor_sync(0xffffffffu, ts0, 1);
        ts0 += __shfl_xor_sync(0xffffffffu, ts0, 2);
        ts1 += __shfl_xor_sync(0xffffffffu, ts1, 1);
        ts1 += __shfl_xor_sync(0xffffffffu, ts1, 2);
        if (t == 0) { s.ps[wv][r0] = ts0; s.ps[wv][r1] = ts1; }

#pragma unroll
        for (int ni = 0; ni < 4; ni++) {
            acc[ni][0] *= fac0; acc[ni][1] *= fac0;
            acc[ni][2] *= fac1; acc[ni][3] *= fac1;
        }
        CPA_WAIT0();       // this thread's V copies complete
        __syncthreads();   // (D) all V + S visible

        if (tid < 64) {
            float mo = s.rowm[tid];
            float mn = fmaxf(mo, fmaxf(s.pm[0][tid], s.pm[1][tid]));
            s.rowm[tid] = mn;
            s.rowl[tid] = s.rowl[tid] * __expf(mo - mn) + s.ps[0][tid] + s.ps[1][tid];
        }

        // ---- P @ V mma ----
#pragma unroll
        for (int ko = 0; ko < 8; ko++) {
            uint32_t a[4];
            float2 v0 = *(const float2*)(s.S + r0 * FP + ko * 8 + 2 * t);
            float2 v1 = *(const float2*)(s.S + r1 * FP + ko * 8 + 2 * t);
            a[0] = __float_as_uint(v0.x); a[1] = __float_as_uint(v1.x);
            a[2] = __float_as_uint(v0.y); a[3] = __float_as_uint(v1.y);
#pragma unroll
            for (int ni = 0; ni < 4; ni++) {
                uint32_t b[2];
                b[0] = __float_as_uint(s.vs[(ko * 8 + t) * FP + wn + ni * 8 + g]);
                b[1] = __float_as_uint(s.vs[(ko * 8 + t + 4) * FP + wn + ni * 8 + g]);
                mma_tf32(acc[ni], a, b);
            }
        }
    }
    __syncthreads();

    // ---- normalize + store g_ao (tf32, k-permuted) ----
    const int b = bh >> 4;
    const int head = bh & 15;
    const int n0g = qt0 * 64 + r0;
    const int n1g = qt0 * 64 + r1;
    float li0 = 1.f / s.rowl[r0];
    float li1 = 1.f / s.rowl[r1];
#pragma unroll
    for (int ni = 0; ni < 4; ni++) {
        int dg = wn + ni * 8;
        if (n0g < NN) {
            size_t base = (size_t)(b * NN + n0g) * CD + head * HD + dg;
            g_ao[base + p0] = tf32r(acc[ni][0] * li0);
            g_ao[base + p1] = tf32r(acc[ni][1] * li0);
        }
        if (n1g < NN) {
            size_t base = (size_t)(b * NN + n1g) * CD + head * HD + dg;
            g_ao[base + p0] = tf32r(acc[ni][2] * li1);
            g_ao[base + p1] = tf32r(acc[ni][3] * li1);
        }
    }
}

// ---------------- launch -----------------------------------------------------
extern "C" void kernel_launch(void* const* d_in, const int* in_sizes, int n_in,
                              void* d_out, int out_size) {
    const float* hidden = (const float*)d_in[0];
    const float* qkv_w  = (const float*)d_in[1];
    const float* qkv_b  = (const float*)d_in[2];
    const float* proj_w = (const float*)d_in[3];
    const float* proj_b = (const float*)d_in[4];
    const float* rph    = (const float*)d_in[5];
    const float* rpw    = (const float*)d_in[6];
    float* out = (float*)d_out;

    cudaFuncSetAttribute(flash4_kernel, cudaFuncAttributeMaxDynamicSharedMemorySize,
                         (int)sizeof(F4Smem));
    cudaFuncSetAttribute(mm_cp<0>, cudaFuncAttributeMaxDynamicSharedMemorySize, MM_SMEM);
    cudaFuncSetAttribute(mm_cp<1>, cudaFuncAttributeMaxDynamicSharedMemorySize, MM_SMEM);

    float* d_hp;  cudaGetSymbolAddress((void**)&d_hp,  g_hp);
    float* d_wp;  cudaGetSymbolAddress((void**)&d_wp,  g_wp);
    float* d_pwp; cudaGetSymbolAddress((void**)&d_pwp, g_pwp);

    prep_kernel<<<(BN * CD / 8 + 255) / 256, 256>>>(hidden, d_hp, BN * CD / 8);
    prep_kernel<<<(3 * CD * CD / 8 + 255) / 256, 256>>>(qkv_w, d_wp, 3 * CD * CD / 8);
    prep_kernel<<<(CD * CD / 8 + 255) / 256, 256>>>(proj_w, d_pwp, CD * CD / 8);

    // QKV: [6272,3072] = hidden . qkv_w^T
    mm_cp<0><<<dim3(3 * CD / 128, BN / 128), 256, MM_SMEM>>>(qkv_b, nullptr);

    relpos_kernel<<<dim3(HH, BHN), 256>>>(rph, rpw);

    flash4_kernel<<<dim3((NN + 63) / 64, BHN), 256, sizeof(F4Smem)>>>();

    // proj: [6272,1024] = g_ao . proj_w^T
    mm_cp<1><<<dim3(CD / 128, BN / 128), 256, MM_SMEM>>>(proj_b, out);
}

// round 7
// speedup vs baseline: 2.7840x; 1.1193x over previous
#include <cuda_runtime.h>
#include <cstdint>

#define NH   16
#define HD   64
#define CD   1024
#define BB   4
#define HH   56
#define WW   28
#define NN   1568          // HH*WW
#define BHN  64            // BB*NH
#define BN   6272          // BB*NN
#define QSCALE 0.125f      // 64^-0.5

// ---------------- scratch (device globals; no allocations allowed) ----------
__device__ float g_q[BHN * NN * HD];    // tf32, d-permuted, pre-scaled by QSCALE
__device__ float g_k[BHN * NN * HD];    // tf32, d-permuted
__device__ float g_v[BHN * NN * HD];    // tf32, natural layout
__device__ float g_relh[BHN * NN * HH];
__device__ float g_relw[BHN * NN * WW];
__device__ float g_ao[BN * CD];         // tf32, k-permuted, [B,N,heads,d]
__device__ float g_hp[BN * CD];         // hidden prepped (tf32 + perm)
__device__ float g_wp[3 * CD * CD];     // qkv_w prepped
__device__ float g_pwp[CD * CD];        // proj_w prepped

// ---------------- helpers ----------------------------------------------------
__device__ __forceinline__ float tf32r(float x) {
    uint32_t r;
    asm("cvt.rna.tf32.f32 %0, %1;" : "=r"(r) : "f"(x));
    return __uint_as_float(r);
}

__device__ __forceinline__ void mma_tf32(float* c, const uint32_t* a, const uint32_t* b) {
    asm volatile(
        "mma.sync.aligned.m16n8k8.row.col.f32.tf32.tf32.f32 "
        "{%0,%1,%2,%3}, {%4,%5,%6,%7}, {%8,%9}, {%0,%1,%2,%3};"
        : "+f"(c[0]), "+f"(c[1]), "+f"(c[2]), "+f"(c[3])
        : "r"(a[0]), "r"(a[1]), "r"(a[2]), "r"(a[3]), "r"(b[0]), "r"(b[1]));
}

__device__ __forceinline__ uint32_t smem_u32(const void* p) {
    uint32_t a;
    asm("{ .reg .u64 t; cvta.to.shared.u64 t, %1; cvt.u32.u64 %0, t; }"
        : "=r"(a) : "l"(p));
    return a;
}

__device__ __forceinline__ void cpa16(uint32_t dst, const void* src, uint32_t srcsize) {
    asm volatile("cp.async.cg.shared.global [%0], [%1], 16, %2;"
                 :: "r"(dst), "l"(src), "r"(srcsize) : "memory");
}
#define CPA_COMMIT() asm volatile("cp.async.commit_group;" ::: "memory")
#define CPA_WAIT0()  asm volatile("cp.async.wait_group 0;" ::: "memory")
#define CPA_WAIT1()  asm volatile("cp.async.wait_group 1;" ::: "memory")

// ---------------- prep: cvt to tf32 + k-permute within 8-groups --------------
__global__ void __launch_bounds__(256) prep_kernel(const float* __restrict__ src,
                                                   float* __restrict__ dst, int ngroups) {
    int i = blockIdx.x * blockDim.x + threadIdx.x;
    if (i >= ngroups) return;
    const float4* s = (const float4*)(src + (size_t)i * 8);
    float4 a = s[0], b = s[1];
    float4 o0 = make_float4(tf32r(a.x), tf32r(b.x), tf32r(a.y), tf32r(b.y));
    float4 o1 = make_float4(tf32r(a.z), tf32r(b.z), tf32r(a.w), tf32r(b.w));
    float4* d = (float4*)(dst + (size_t)i * 8);
    d[0] = o0; d[1] = o1;
}

// ================== cp.async 3-stage TF32 GEMM, 256x128 tile =================
// C[M,N] = A[M,K] . B[N,K]^T  (operands tf32+permuted in global)
#define ATSZ (256 * 32)       // A tile floats (32KB)
#define BTSZ (128 * 32)       // B tile floats (16KB)
#define STG2 (ATSZ + BTSZ)    // floats per stage (48KB)
#define MM_SMEM (3 * STG2 * 4)

template <int MODE>
__global__ void __launch_bounds__(256, 1) mm_cp(const float* __restrict__ bias,
                                                float* __restrict__ Cout) {
    extern __shared__ float smem[];
    uint32_t sb = smem_u32(smem);
    const float* A  = (MODE == 0) ? g_hp : g_ao;
    const float* Bm = (MODE == 0) ? g_wp : g_pwp;

    const int tid = threadIdx.x;
    const int wid = tid >> 5;
    const int lid = tid & 31;
    const int g = lid >> 2;
    const int t = lid & 3;
    const int m0 = blockIdx.y * 256;
    const int n0 = blockIdx.x * 128;
    const int wm = (wid & 3) * 64;     // 4 warp rows
    const int wn = (wid >> 2) * 64;    // 2 warp cols

    float acc[4][8][4];
#pragma unroll
    for (int mi = 0; mi < 4; mi++)
#pragma unroll
        for (int ni = 0; ni < 8; ni++)
#pragma unroll
            for (int e = 0; e < 4; e++) acc[mi][ni][e] = 0.f;

    const int lr = tid >> 3;     // loader row 0..31
    const int lq = tid & 7;      // loader 16B chunk
    const uint32_t ldst = (uint32_t)(lr * 32 + ((lq ^ (lr & 7)) << 2)) * 4;

    auto issue = [&](int kt) {
        const int st = kt % 3;
        const int k0 = kt * 32;
        uint32_t ab = sb + (uint32_t)st * STG2 * 4;
        uint32_t bb = ab + ATSZ * 4;
#pragma unroll
        for (int it = 0; it < 8; it++) {
            int r = lr + it * 32;
            int gr = m0 + r;
            bool ok = gr < BN;
            cpa16(ab + ldst + (uint32_t)(it * 32 * 32) * 4,
                  A + (ok ? (size_t)gr * CD + k0 + lq * 4 : 0), ok ? 16u : 0u);
        }
#pragma unroll
        for (int it = 0; it < 4; it++) {
            int r = lr + it * 32;
            cpa16(bb + ldst + (uint32_t)(it * 32 * 32) * 4,
                  Bm + (size_t)(n0 + r) * CD + k0 + lq * 4, 16);
        }
        CPA_COMMIT();
    };

    issue(0); issue(1);
    for (int kt = 0; kt < 32; kt++) {
        if (kt < 31) CPA_WAIT1(); else CPA_WAIT0();
        __syncthreads();
        if (kt + 2 < 32) issue(kt + 2);

        const float* As = smem + (size_t)(kt % 3) * STG2;
        const float* Bs = As + ATSZ;

#pragma unroll
        for (int ko = 0; ko < 4; ko++) {
            const int coff = (((ko * 2 + (t >> 1)) ^ g) << 2) + ((t & 1) << 1);
            uint32_t a[4][4];
            uint32_t b[8][2];
#pragma unroll
            for (int mi = 0; mi < 4; mi++) {
                float2 v0 = *(const float2*)(As + (wm + mi * 16 + g) * 32 + coff);
                float2 v1 = *(const float2*)(As + (wm + mi * 16 + g + 8) * 32 + coff);
                a[mi][0] = __float_as_uint(v0.x);
                a[mi][1] = __float_as_uint(v1.x);
                a[mi][2] = __float_as_uint(v0.y);
                a[mi][3] = __float_as_uint(v1.y);
            }
#pragma unroll
            for (int ni = 0; ni < 8; ni++) {
                float2 u = *(const float2*)(Bs + (wn + ni * 8 + g) * 32 + coff);
                b[ni][0] = __float_as_uint(u.x);
                b[ni][1] = __float_as_uint(u.y);
            }
#pragma unroll
            for (int mi = 0; mi < 4; mi++)
#pragma unroll
                for (int ni = 0; ni < 8; ni++) mma_tf32(acc[mi][ni], a[mi], b[ni]);
        }
    }

    const int p0 = (t < 2) ? 4 * t : 4 * t - 7;
    const int p1 = (t < 2) ? 4 * t + 2 : 4 * t - 5;

#pragma unroll
    for (int mi = 0; mi < 4; mi++) {
        int mr0 = m0 + wm + mi * 16 + g;
        int mr1 = mr0 + 8;
        bool ok0 = mr0 < BN, ok1 = mr1 < BN;
#pragma unroll
        for (int ni = 0; ni < 8; ni++) {
            int jj = n0 + wn + ni * 8 + 2 * t;
            float b0 = bias[jj], b1 = bias[jj + 1];
            float v00 = acc[mi][ni][0] + b0, v01 = acc[mi][ni][1] + b1;
            float v10 = acc[mi][ni][2] + b0, v11 = acc[mi][ni][3] + b1;
            if (MODE == 0) {
                int tsel = jj >> 10;
                int rr = jj & 1023;
                int head = rr >> 6;
                int d = rr & 63;
                int dg = d & ~7;
                if (ok0) {
                    int b_ = mr0 / NN, n_ = mr0 - b_ * NN;
                    size_t base = (size_t)((b_ * NH + head) * NN + n_) * HD;
                    if (tsel == 0) {
                        g_q[base + dg + p0] = tf32r(v00) * QSCALE;
                        g_q[base + dg + p1] = tf32r(v01) * QSCALE;
                    } else if (tsel == 1) {
                        g_k[base + dg + p0] = tf32r(v00);
                        g_k[base + dg + p1] = tf32r(v01);
                    } else {
                        float2 o = {tf32r(v00), tf32r(v01)};
                        *(float2*)&g_v[base + d] = o;
                    }
                }
                if (ok1) {
                    int b_ = mr1 / NN, n_ = mr1 - b_ * NN;
                    size_t base = (size_t)((b_ * NH + head) * NN + n_) * HD;
                    if (tsel == 0) {
                        g_q[base + dg + p0] = tf32r(v10) * QSCALE;
                        g_q[base + dg + p1] = tf32r(v11) * QSCALE;
                    } else if (tsel == 1) {
                        g_k[base + dg + p0] = tf32r(v10);
                        g_k[base + dg + p1] = tf32r(v11);
                    } else {
                        float2 o = {tf32r(v10), tf32r(v11)};
                        *(float2*)&g_v[base + d] = o;
                    }
                }
            } else {
                if (ok0) { float2 o = {v00, v01}; *(float2*)&Cout[(size_t)mr0 * CD + jj] = o; }
                if (ok1) { float2 o = {v10, v11}; *(float2*)&Cout[(size_t)mr1 * CD + jj] = o; }
            }
        }
    }
}

// ---------------- rel-pos bias via TF32 mma -----------------------------------
__global__ void __launch_bounds__(256) relpos_kernel(const float* __restrict__ rph,
                                                     const float* __restrict__ rpw) {
    __shared__ float qp[32 * 68];
    __shared__ float Bp[112 * 68];
    __shared__ float outw[32 * 60];

    const int h = blockIdx.x;
    const int bh = blockIdx.y;
    const int tid = threadIdx.x;
    const int wid = tid >> 5;
    const int lid = tid & 31;
    const int g = lid >> 2;
    const int t = lid & 3;

    for (int idx = tid; idx < 32 * 16; idx += 256) {
        int r = idx >> 4, cc = idx & 15;
        float4 v = make_float4(0.f, 0.f, 0.f, 0.f);
        if (r < WW) v = *(const float4*)&g_q[((size_t)(bh * NN) + h * WW + r) * HD + cc * 4];
        *(float4*)&qp[r * 68 + cc * 4] = v;
    }
    for (int idx = tid; idx < 112 * 16; idx += 256) {
        int r = idx >> 4, cc = idx & 15;
        float4 v = make_float4(0.f, 0.f, 0.f, 0.f);
        if (r < 56)       v = *(const float4*)&rph[(size_t)(h + 55 - r) * HD + cc * 4];
        else if (r < 111) v = *(const float4*)&rpw[(size_t)(r - 56) * HD + cc * 4];
        float* p = Bp + r * 68 + (cc >> 1) * 8 + (cc & 1);
        p[0] = tf32r(v.x); p[2] = tf32r(v.y);
        p[4] = tf32r(v.z); p[6] = tf32r(v.w);
    }
    __syncthreads();

    for (int ti = wid; ti < 14; ti += 8) {
        float c[2][4];
#pragma unroll
        for (int mi = 0; mi < 2; mi++)
#pragma unroll
            for (int e = 0; e < 4; e++) c[mi][e] = 0.f;
#pragma unroll
        for (int ko = 0; ko < 8; ko++) {
            uint32_t a0[4], a1[4], b[2];
            float2 v0 = *(const float2*)(qp + g * 68 + ko * 8 + 2 * t);
            float2 v1 = *(const float2*)(qp + (g + 8) * 68 + ko * 8 + 2 * t);
            float2 v2 = *(const float2*)(qp + (16 + g) * 68 + ko * 8 + 2 * t);
            float2 v3 = *(const float2*)(qp + (24 + g) * 68 + ko * 8 + 2 * t);
            a0[0] = __float_as_uint(v0.x); a0[1] = __float_as_uint(v1.x);
            a0[2] = __float_as_uint(v0.y); a0[3] = __float_as_uint(v1.y);
            a1[0] = __float_as_uint(v2.x); a1[1] = __float_as_uint(v3.x);
            a1[2] = __float_as_uint(v2.y); a1[3] = __float_as_uint(v3.y);
            float2 u = *(const float2*)(Bp + (ti * 8 + g) * 68 + ko * 8 + 2 * t);
            b[0] = __float_as_uint(u.x); b[1] = __float_as_uint(u.y);
            mma_tf32(c[0], a0, b);
            mma_tf32(c[1], a1, b);
        }
        if (ti < 7) {
            int kh0 = ti * 8 + 2 * t, kh1 = kh0 + 1;
            size_t nb = (size_t)(bh * NN) + h * WW;
            g_relh[(nb + g) * HH + kh0]        = c[0][0] * 8.f;
            g_relh[(nb + g) * HH + kh1]        = c[0][1] * 8.f;
            g_relh[(nb + g + 8) * HH + kh0]    = c[0][2] * 8.f;
            g_relh[(nb + g + 8) * HH + kh1]    = c[0][3] * 8.f;
            g_relh[(nb + 16 + g) * HH + kh0]   = c[1][0] * 8.f;
            g_relh[(nb + 16 + g) * HH + kh1]   = c[1][1] * 8.f;
            if (g < 4) {
                g_relh[(nb + 24 + g) * HH + kh0] = c[1][2] * 8.f;
                g_relh[(nb + 24 + g) * HH + kh1] = c[1][3] * 8.f;
            }
        } else {
            int cb = (ti - 7) * 8 + 2 * t;
            outw[g * 60 + cb] = c[0][0];        outw[g * 60 + cb + 1] = c[0][1];
            outw[(g + 8) * 60 + cb] = c[0][2];  outw[(g + 8) * 60 + cb + 1] = c[0][3];
            outw[(16 + g) * 60 + cb] = c[1][0]; outw[(16 + g) * 60 + cb + 1] = c[1][1];
            outw[(24 + g) * 60 + cb] = c[1][2]; outw[(24 + g) * 60 + cb + 1] = c[1][3];
        }
    }
    __syncthreads();

    for (int idx = tid; idx < WW * WW; idx += 256) {
        int w = idx / WW, kw = idx - w * WW;
        g_relw[((size_t)(bh * NN) + h * WW + w) * WW + kw] =
            outw[w * 60 + (w - kw + 27)] * 8.f;
    }
}

// ---------------- flash attention v4 (conflict-free V pitch) -----------------
#define FP  68
#define FPV 72   // V pitch: (8t+g) distinct banks for PV B-frag loads

struct F4Smem {
    float qs[64 * FP];
    float kt[64 * FP];
    float vs[64 * FPV];
    float S[64 * FP];
    float rh[64][HH];
    float rw[64][WW];
    float rowm[64];
    float rowl[64];
    float pm[2][64];
    float ps[2][64];
    int   kh_a[64];
    int   kw_a[64];
};

__global__ void __launch_bounds__(256, 2) flash4_kernel() {
    extern __shared__ char raw[];
    F4Smem& s = *reinterpret_cast<F4Smem*>(raw);

    const int bh = blockIdx.y;
    const int qt0 = blockIdx.x;
    const int tid = threadIdx.x;
    const int wid = tid >> 5;
    const int lid = tid & 31;
    const int g = lid >> 2;
    const int t = lid & 3;
    const int wm = (wid & 3) * 16;
    const int wv = wid >> 2;
    const int wn = wv * 32;

    const int p0 = (t < 2) ? 4 * t : 4 * t - 7;
    const int p1 = (t < 2) ? 4 * t + 2 : 4 * t - 5;
    const int r0 = wm + g, r1 = wm + g + 8;

    // ---- Q via cp.async ----
    {
        uint32_t qaddr = smem_u32(s.qs);
#pragma unroll
        for (int it = 0; it < 4; it++) {
            int idx = it * 256 + tid;
            int r = idx >> 4, cc = idx & 15;
            int n = qt0 * 64 + r;
            const float* src = g_q + (n < NN ? (size_t)(bh * NN + n) * HD + cc * 4 : 0);
            cpa16(qaddr + (uint32_t)(r * FP + cc * 4) * 4, src, n < NN ? 16u : 0u);
        }
        CPA_COMMIT();
    }
    for (int idx = tid; idx < 64 * HH; idx += 256) {
        int r = idx / HH, kh = idx - r * HH;
        int n = qt0 * 64 + r;
        s.rh[r][kh] = (n < NN) ? g_relh[(size_t)(bh * NN + n) * HH + kh] : 0.f;
    }
    for (int idx = tid; idx < 64 * WW; idx += 256) {
        int r = idx / WW, kw = idx - r * WW;
        int n = qt0 * 64 + r;
        s.rw[r][kw] = (n < NN) ? g_relw[(size_t)(bh * NN + n) * WW + kw] : 0.f;
    }
    if (tid < 64) { s.rowm[tid] = -1e30f; s.rowl[tid] = 0.f; }

    float acc[4][4];
#pragma unroll
    for (int ni = 0; ni < 4; ni++)
#pragma unroll
        for (int e = 0; e < 4; e++) acc[ni][e] = 0.f;

    const uint32_t kaddr = smem_u32(s.kt);
    const uint32_t vaddr = smem_u32(s.vs);

    for (int kt2 = 0; kt2 < 25; kt2++) {
        const int kbase = kt2 * 64;
        __syncthreads();   // (A)

#pragma unroll
        for (int it = 0; it < 4; it++) {
            int idx = it * 256 + tid;
            int r = idx >> 4, cc = idx & 15;
            int kn = kbase + r;
            bool ok = kn < NN;
            size_t off = ok ? (size_t)(bh * NN + kn) * HD + cc * 4 : 0;
            cpa16(kaddr + (uint32_t)(r * FP + cc * 4) * 4, g_k + off, ok ? 16u : 0u);
        }
        CPA_COMMIT();
#pragma unroll
        for (int it = 0; it < 4; it++) {
            int idx = it * 256 + tid;
            int r = idx >> 4, cc = idx & 15;
            int kn = kbase + r;
            bool ok = kn < NN;
            size_t off = ok ? (size_t)(bh * NN + kn) * HD + cc * 4 : 0;
            cpa16(vaddr + (uint32_t)(r * FPV + cc * 4) * 4, g_v + off, ok ? 16u : 0u);
        }
        CPA_COMMIT();
        if (tid < 64) {
            int kn = kbase + tid;
            s.kh_a[tid] = (kn < NN) ? kn / WW : -1;
            s.kw_a[tid] = (kn < NN) ? kn % WW : 0;
        }
        CPA_WAIT1();
        __syncthreads();   // (B)

        // ---- QK^T mma ----
        float c[4][4];
#pragma unroll
        for (int ni = 0; ni < 4; ni++)
#pragma unroll
            for (int e = 0; e < 4; e++) c[ni][e] = 0.f;
#pragma unroll
        for (int ko = 0; ko < 8; ko++) {
            uint32_t a[4];
            float2 v0 = *(const float2*)(s.qs + r0 * FP + ko * 8 + 2 * t);
            float2 v1 = *(const float2*)(s.qs + r1 * FP + ko * 8 + 2 * t);
            a[0] = __float_as_uint(v0.x); a[1] = __float_as_uint(v1.x);
            a[2] = __float_as_uint(v0.y); a[3] = __float_as_uint(v1.y);
#pragma unroll
            for (int ni = 0; ni < 4; ni++) {
                float2 u = *(const float2*)(s.kt + (wn + ni * 8 + g) * FP + ko * 8 + 2 * t);
                uint32_t b[2] = {__float_as_uint(u.x), __float_as_uint(u.y)};
                mma_tf32(c[ni], a, b);
            }
        }
#pragma unroll
        for (int ni = 0; ni < 4; ni++) {
            int c0l = wn + ni * 8 + 2 * t, c1l = c0l + 1;
            int kh0 = s.kh_a[c0l], kw0 = s.kw_a[c0l];
            int kh1 = s.kh_a[c1l], kw1 = s.kw_a[c1l];
            if (kh0 >= 0) {
                c[ni][0] += s.rh[r0][kh0] + s.rw[r0][kw0];
                c[ni][2] += s.rh[r1][kh0] + s.rw[r1][kw0];
            } else { c[ni][0] = -1e30f; c[ni][2] = -1e30f; }
            if (kh1 >= 0) {
                c[ni][1] += s.rh[r0][kh1] + s.rw[r0][kw1];
                c[ni][3] += s.rh[r1][kh1] + s.rw[r1][kw1];
            } else { c[ni][1] = -1e30f; c[ni][3] = -1e30f; }
        }

        float tm0 = -1e30f, tm1 = -1e30f;
#pragma unroll
        for (int ni = 0; ni < 4; ni++) {
            tm0 = fmaxf(tm0, fmaxf(c[ni][0], c[ni][1]));
            tm1 = fmaxf(tm1, fmaxf(c[ni][2], c[ni][3]));
        }
        tm0 = fmaxf(tm0, __shfl_xor_sync(0xffffffffu, tm0, 1));
        tm0 = fmaxf(tm0, __shfl_xor_sync(0xffffffffu, tm0, 2));
        tm1 = fmaxf(tm1, __shfl_xor_sync(0xffffffffu, tm1, 1));
        tm1 = fmaxf(tm1, __shfl_xor_sync(0xffffffffu, tm1, 2));
        if (t == 0) { s.pm[wv][r0] = tm0; s.pm[wv][r1] = tm1; }
        __syncthreads();   // (C)

        float mo0 = s.rowm[r0], mo1 = s.rowm[r1];
        float mn0 = fmaxf(mo0, fmaxf(s.pm[0][r0], s.pm[1][r0]));
        float mn1 = fmaxf(mo1, fmaxf(s.pm[0][r1], s.pm[1][r1]));
        float fac0 = __expf(mo0 - mn0), fac1 = __expf(mo1 - mn1);
        float ts0 = 0.f, ts1 = 0.f;
#pragma unroll
        for (int ni = 0; ni < 4; ni++) {
            int cb = wn + ni * 8;
            float p00 = tf32r(__expf(c[ni][0] - mn0));
            float p01 = tf32r(__expf(c[ni][1] - mn0));
            float p10 = tf32r(__expf(c[ni][2] - mn1));
            float p11 = tf32r(__expf(c[ni][3] - mn1));
            ts0 += p00 + p01;
            ts1 += p10 + p11;
            s.S[r0 * FP + cb + p0] = p00;
            s.S[r0 * FP + cb + p1] = p01;
            s.S[r1 * FP + cb + p0] = p10;
            s.S[r1 * FP + cb + p1] = p11;
        }
        ts0 += __shfl_xor_sync(0xffffffffu, ts0, 1);
        ts0 += __shfl_xor_sync(0xffffffffu, ts0, 2);
        ts1 += __shfl_xor_sync(0xffffffffu, ts1, 1);
        ts1 += __shfl_xor_sync(0xffffffffu, ts1, 2);
        if (t == 0) { s.ps[wv][r0] = ts0; s.ps[wv][r1] = ts1; }

#pragma unroll
        for (int ni = 0; ni < 4; ni++) {
            acc[ni][0] *= fac0; acc[ni][1] *= fac0;
            acc[ni][2] *= fac1; acc[ni][3] *= fac1;
        }
        CPA_WAIT0();
        __syncthreads();   // (D)

        if (tid < 64) {
            float mo = s.rowm[tid];
            float mn = fmaxf(mo, fmaxf(s.pm[0][tid], s.pm[1][tid]));
            s.rowm[tid] = mn;
            s.rowl[tid] = s.rowl[tid] * __expf(mo - mn) + s.ps[0][tid] + s.ps[1][tid];
        }

        // ---- P @ V mma ----
#pragma unroll
        for (int ko = 0; ko < 8; ko++) {
            uint32_t a[4];
            float2 v0 = *(const float2*)(s.S + r0 * FP + ko * 8 + 2 * t);
            float2 v1 = *(const float2*)(s.S + r1 * FP + ko * 8 + 2 * t);
            a[0] = __float_as_uint(v0.x); a[1] = __float_as_uint(v1.x);
            a[2] = __float_as_uint(v0.y); a[3] = __float_as_uint(v1.y);
#pragma unroll
            for (int ni = 0; ni < 4; ni++) {
                uint32_t b[2];
                b[0] = __float_as_uint(s.vs[(ko * 8 + t) * FPV + wn + ni * 8 + g]);
                b[1] = __float_as_uint(s.vs[(ko * 8 + t + 4) * FPV + wn + ni * 8 + g]);
                mma_tf32(acc[ni], a, b);
            }
        }
    }
    __syncthreads();

    // ---- normalize + store g_ao (tf32, k-permuted) ----
    const int b = bh >> 4;
    const int head = bh & 15;
    const int n0g = qt0 * 64 + r0;
    const int n1g = qt0 * 64 + r1;
    float li0 = 1.f / s.rowl[r0];
    float li1 = 1.f / s.rowl[r1];
#pragma unroll
    for (int ni = 0; ni < 4; ni++) {
        int dg = wn + ni * 8;
        if (n0g < NN) {
            size_t base = (size_t)(b * NN + n0g) * CD + head * HD + dg;
            g_ao[base + p0] = tf32r(acc[ni][0] * li0);
            g_ao[base + p1] = tf32r(acc[ni][1] * li0);
        }
        if (n1g < NN) {
            size_t base = (size_t)(b * NN + n1g) * CD + head * HD + dg;
            g_ao[base + p0] = tf32r(acc[ni][2] * li1);
            g_ao[base + p1] = tf32r(acc[ni][3] * li1);
        }
    }
}

// ---------------- launch -----------------------------------------------------
extern "C" void kernel_launch(void* const* d_in, const int* in_sizes, int n_in,
                              void* d_out, int out_size) {
    const float* hidden = (const float*)d_in[0];
    const float* qkv_w  = (const float*)d_in[1];
    const float* qkv_b  = (const float*)d_in[2];
    const float* proj_w = (const float*)d_in[3];
    const float* proj_b = (const float*)d_in[4];
    const float* rph    = (const float*)d_in[5];
    const float* rpw    = (const float*)d_in[6];
    float* out = (float*)d_out;

    cudaFuncSetAttribute(flash4_kernel, cudaFuncAttributeMaxDynamicSharedMemorySize,
                         (int)sizeof(F4Smem));
    cudaFuncSetAttribute(mm_cp<0>, cudaFuncAttributeMaxDynamicSharedMemorySize, MM_SMEM);
    cudaFuncSetAttribute(mm_cp<1>, cudaFuncAttributeMaxDynamicSharedMemorySize, MM_SMEM);

    float* d_hp;  cudaGetSymbolAddress((void**)&d_hp,  g_hp);
    float* d_wp;  cudaGetSymbolAddress((void**)&d_wp,  g_wp);
    float* d_pwp; cudaGetSymbolAddress((void**)&d_pwp, g_pwp);

    prep_kernel<<<(BN * CD / 8 + 255) / 256, 256>>>(hidden, d_hp, BN * CD / 8);
    prep_kernel<<<(3 * CD * CD / 8 + 255) / 256, 256>>>(qkv_w, d_wp, 3 * CD * CD / 8);
    prep_kernel<<<(CD * CD / 8 + 255) / 256, 256>>>(proj_w, d_pwp, CD * CD / 8);

    // QKV: [6272,3072] = hidden . qkv_w^T   (256-row tiles, 25 with guard)
    mm_cp<0><<<dim3(3 * CD / 128, (BN + 255) / 256), 256, MM_SMEM>>>(qkv_b, nullptr);

    relpos_kernel<<<dim3(HH, BHN), 256>>>(rph, rpw);

    flash4_kernel<<<dim3((NN + 63) / 64, BHN), 256, sizeof(F4Smem)>>>();

    // proj: [6272,1024] = g_ao . proj_w^T
    mm_cp<1><<<dim3(CD / 128, (BN + 255) / 256), 256, MM_SMEM>>>(proj_b, out);
}

// round 8
// speedup vs baseline: 3.4442x; 1.2372x over previous
#include <cuda_runtime.h>
#include <cstdint>

#define NH   16
#define HD   64
#define CD   1024
#define BB   4
#define HH   56
#define WW   28
#define NN   1568          // HH*WW
#define BHN  64            // BB*NH
#define BN   6272          // BB*NN
#define QSCALE 0.125f      // 64^-0.5

// ---------------- scratch (device globals; no allocations allowed) ----------
__device__ float g_q[BHN * NN * HD];    // tf32, d-permuted, pre-scaled by QSCALE
__device__ float g_k[BHN * NN * HD];    // tf32, d-permuted
__device__ float g_v[BHN * NN * HD];    // tf32, natural layout
__device__ float g_relh[BHN * NN * HH];
__device__ float g_relw[BHN * NN * WW];
__device__ float g_ao[BN * CD];         // tf32, k-permuted, [B,N,heads,d]
__device__ float g_hp[BN * CD];         // hidden prepped (tf32 + perm)
__device__ float g_wp[3 * CD * CD];     // qkv_w prepped
__device__ float g_pwp[CD * CD];        // proj_w prepped

// ---------------- helpers ----------------------------------------------------
__device__ __forceinline__ float tf32r(float x) {
    uint32_t r;
    asm("cvt.rna.tf32.f32 %0, %1;" : "=r"(r) : "f"(x));
    return __uint_as_float(r);
}

__device__ __forceinline__ void mma_tf32(float* c, const uint32_t* a, const uint32_t* b) {
    asm volatile(
        "mma.sync.aligned.m16n8k8.row.col.f32.tf32.tf32.f32 "
        "{%0,%1,%2,%3}, {%4,%5,%6,%7}, {%8,%9}, {%0,%1,%2,%3};"
        : "+f"(c[0]), "+f"(c[1]), "+f"(c[2]), "+f"(c[3])
        : "r"(a[0]), "r"(a[1]), "r"(a[2]), "r"(a[3]), "r"(b[0]), "r"(b[1]));
}

__device__ __forceinline__ uint32_t smem_u32(const void* p) {
    uint32_t a;
    asm("{ .reg .u64 t; cvta.to.shared.u64 t, %1; cvt.u32.u64 %0, t; }"
        : "=r"(a) : "l"(p));
    return a;
}

__device__ __forceinline__ void cpa16(uint32_t dst, const void* src, uint32_t srcsize) {
    asm volatile("cp.async.cg.shared.global [%0], [%1], 16, %2;"
                 :: "r"(dst), "l"(src), "r"(srcsize) : "memory");
}
#define CPA_COMMIT() asm volatile("cp.async.commit_group;" ::: "memory")
#define CPA_WAIT0()  asm volatile("cp.async.wait_group 0;" ::: "memory")
#define CPA_WAIT1()  asm volatile("cp.async.wait_group 1;" ::: "memory")

// ---------------- prep: cvt to tf32 + k-permute within 8-groups --------------
__global__ void __launch_bounds__(256) prep_kernel(const float* __restrict__ src,
                                                   float* __restrict__ dst, int ngroups) {
    int i = blockIdx.x * blockDim.x + threadIdx.x;
    if (i >= ngroups) return;
    const float4* s = (const float4*)(src + (size_t)i * 8);
    float4 a = s[0], b = s[1];
    float4 o0 = make_float4(tf32r(a.x), tf32r(b.x), tf32r(a.y), tf32r(b.y));
    float4 o1 = make_float4(tf32r(a.z), tf32r(b.z), tf32r(a.w), tf32r(b.w));
    float4* d = (float4*)(dst + (size_t)i * 8);
    d[0] = o0; d[1] = o1;
}

// ================== cp.async 3-stage TF32 GEMM, 256x128 tile =================
#define ATSZ (256 * 32)
#define BTSZ (128 * 32)
#define STG2 (ATSZ + BTSZ)
#define MM_SMEM (3 * STG2 * 4)

template <int MODE>
__global__ void __launch_bounds__(256, 1) mm_cp(const float* __restrict__ bias,
                                                float* __restrict__ Cout) {
    extern __shared__ float smem[];
    uint32_t sb = smem_u32(smem);
    const float* A  = (MODE == 0) ? g_hp : g_ao;
    const float* Bm = (MODE == 0) ? g_wp : g_pwp;

    const int tid = threadIdx.x;
    const int wid = tid >> 5;
    const int lid = tid & 31;
    const int g = lid >> 2;
    const int t = lid & 3;
    const int m0 = blockIdx.y * 256;
    const int n0 = blockIdx.x * 128;
    const int wm = (wid & 3) * 64;
    const int wn = (wid >> 2) * 64;

    float acc[4][8][4];
#pragma unroll
    for (int mi = 0; mi < 4; mi++)
#pragma unroll
        for (int ni = 0; ni < 8; ni++)
#pragma unroll
            for (int e = 0; e < 4; e++) acc[mi][ni][e] = 0.f;

    const int lr = tid >> 3;
    const int lq = tid & 7;
    const uint32_t ldst = (uint32_t)(lr * 32 + ((lq ^ (lr & 7)) << 2)) * 4;

    auto issue = [&](int kt) {
        const int st = kt % 3;
        const int k0 = kt * 32;
        uint32_t ab = sb + (uint32_t)st * STG2 * 4;
        uint32_t bb = ab + ATSZ * 4;
#pragma unroll
        for (int it = 0; it < 8; it++) {
            int r = lr + it * 32;
            int gr = m0 + r;
            bool ok = gr < BN;
            cpa16(ab + ldst + (uint32_t)(it * 32 * 32) * 4,
                  A + (ok ? (size_t)gr * CD + k0 + lq * 4 : 0), ok ? 16u : 0u);
        }
#pragma unroll
        for (int it = 0; it < 4; it++) {
            int r = lr + it * 32;
            cpa16(bb + ldst + (uint32_t)(it * 32 * 32) * 4,
                  Bm + (size_t)(n0 + r) * CD + k0 + lq * 4, 16);
        }
        CPA_COMMIT();
    };

    issue(0); issue(1);
    for (int kt = 0; kt < 32; kt++) {
        if (kt < 31) CPA_WAIT1(); else CPA_WAIT0();
        __syncthreads();
        if (kt + 2 < 32) issue(kt + 2);

        const float* As = smem + (size_t)(kt % 3) * STG2;
        const float* Bs = As + ATSZ;

#pragma unroll
        for (int ko = 0; ko < 4; ko++) {
            const int coff = (((ko * 2 + (t >> 1)) ^ g) << 2) + ((t & 1) << 1);
            uint32_t a[4][4];
            uint32_t b[8][2];
#pragma unroll
            for (int mi = 0; mi < 4; mi++) {
                float2 v0 = *(const float2*)(As + (wm + mi * 16 + g) * 32 + coff);
                float2 v1 = *(const float2*)(As + (wm + mi * 16 + g + 8) * 32 + coff);
                a[mi][0] = __float_as_uint(v0.x);
                a[mi][1] = __float_as_uint(v1.x);
                a[mi][2] = __float_as_uint(v0.y);
                a[mi][3] = __float_as_uint(v1.y);
            }
#pragma unroll
            for (int ni = 0; ni < 8; ni++) {
                float2 u = *(const float2*)(Bs + (wn + ni * 8 + g) * 32 + coff);
                b[ni][0] = __float_as_uint(u.x);
                b[ni][1] = __float_as_uint(u.y);
            }
#pragma unroll
            for (int mi = 0; mi < 4; mi++)
#pragma unroll
                for (int ni = 0; ni < 8; ni++) mma_tf32(acc[mi][ni], a[mi], b[ni]);
        }
    }

    const int p0 = (t < 2) ? 4 * t : 4 * t - 7;
    const int p1 = (t < 2) ? 4 * t + 2 : 4 * t - 5;

#pragma unroll
    for (int mi = 0; mi < 4; mi++) {
        int mr0 = m0 + wm + mi * 16 + g;
        int mr1 = mr0 + 8;
        bool ok0 = mr0 < BN, ok1 = mr1 < BN;
#pragma unroll
        for (int ni = 0; ni < 8; ni++) {
            int jj = n0 + wn + ni * 8 + 2 * t;
            float b0 = bias[jj], b1 = bias[jj + 1];
            float v00 = acc[mi][ni][0] + b0, v01 = acc[mi][ni][1] + b1;
            float v10 = acc[mi][ni][2] + b0, v11 = acc[mi][ni][3] + b1;
            if (MODE == 0) {
                int tsel = jj >> 10;
                int rr = jj & 1023;
                int head = rr >> 6;
                int d = rr & 63;
                int dg = d & ~7;
                if (ok0) {
                    int b_ = mr0 / NN, n_ = mr0 - b_ * NN;
                    size_t base = (size_t)((b_ * NH + head) * NN + n_) * HD;
                    if (tsel == 0) {
                        g_q[base + dg + p0] = tf32r(v00) * QSCALE;
                        g_q[base + dg + p1] = tf32r(v01) * QSCALE;
                    } else if (tsel == 1) {
                        g_k[base + dg + p0] = tf32r(v00);
                        g_k[base + dg + p1] = tf32r(v01);
                    } else {
                        float2 o = {tf32r(v00), tf32r(v01)};
                        *(float2*)&g_v[base + d] = o;
                    }
                }
                if (ok1) {
                    int b_ = mr1 / NN, n_ = mr1 - b_ * NN;
                    size_t base = (size_t)((b_ * NH + head) * NN + n_) * HD;
                    if (tsel == 0) {
                        g_q[base + dg + p0] = tf32r(v10) * QSCALE;
                        g_q[base + dg + p1] = tf32r(v11) * QSCALE;
                    } else if (tsel == 1) {
                        g_k[base + dg + p0] = tf32r(v10);
                        g_k[base + dg + p1] = tf32r(v11);
                    } else {
                        float2 o = {tf32r(v10), tf32r(v11)};
                        *(float2*)&g_v[base + d] = o;
                    }
                }
            } else {
                if (ok0) { float2 o = {v00, v01}; *(float2*)&Cout[(size_t)mr0 * CD + jj] = o; }
                if (ok1) { float2 o = {v10, v11}; *(float2*)&Cout[(size_t)mr1 * CD + jj] = o; }
            }
        }
    }
}

// ---------------- rel-pos bias via TF32 mma -----------------------------------
__global__ void __launch_bounds__(256) relpos_kernel(const float* __restrict__ rph,
                                                     const float* __restrict__ rpw) {
    __shared__ float qp[32 * 68];
    __shared__ float Bp[112 * 68];
    __shared__ float outw[32 * 60];

    const int h = blockIdx.x;
    const int bh = blockIdx.y;
    const int tid = threadIdx.x;
    const int wid = tid >> 5;
    const int lid = tid & 31;
    const int g = lid >> 2;
    const int t = lid & 3;

    for (int idx = tid; idx < 32 * 16; idx += 256) {
        int r = idx >> 4, cc = idx & 15;
        float4 v = make_float4(0.f, 0.f, 0.f, 0.f);
        if (r < WW) v = *(const float4*)&g_q[((size_t)(bh * NN) + h * WW + r) * HD + cc * 4];
        *(float4*)&qp[r * 68 + cc * 4] = v;
    }
    for (int idx = tid; idx < 112 * 16; idx += 256) {
        int r = idx >> 4, cc = idx & 15;
        float4 v = make_float4(0.f, 0.f, 0.f, 0.f);
        if (r < 56)       v = *(const float4*)&rph[(size_t)(h + 55 - r) * HD + cc * 4];
        else if (r < 111) v = *(const float4*)&rpw[(size_t)(r - 56) * HD + cc * 4];
        float* p = Bp + r * 68 + (cc >> 1) * 8 + (cc & 1);
        p[0] = tf32r(v.x); p[2] = tf32r(v.y);
        p[4] = tf32r(v.z); p[6] = tf32r(v.w);
    }
    __syncthreads();

    for (int ti = wid; ti < 14; ti += 8) {
        float c[2][4];
#pragma unroll
        for (int mi = 0; mi < 2; mi++)
#pragma unroll
            for (int e = 0; e < 4; e++) c[mi][e] = 0.f;
#pragma unroll
        for (int ko = 0; ko < 8; ko++) {
            uint32_t a0[4], a1[4], b[2];
            float2 v0 = *(const float2*)(qp + g * 68 + ko * 8 + 2 * t);
            float2 v1 = *(const float2*)(qp + (g + 8) * 68 + ko * 8 + 2 * t);
            float2 v2 = *(const float2*)(qp + (16 + g) * 68 + ko * 8 + 2 * t);
            float2 v3 = *(const float2*)(qp + (24 + g) * 68 + ko * 8 + 2 * t);
            a0[0] = __float_as_uint(v0.x); a0[1] = __float_as_uint(v1.x);
            a0[2] = __float_as_uint(v0.y); a0[3] = __float_as_uint(v1.y);
            a1[0] = __float_as_uint(v2.x); a1[1] = __float_as_uint(v3.x);
            a1[2] = __float_as_uint(v2.y); a1[3] = __float_as_uint(v3.y);
            float2 u = *(const float2*)(Bp + (ti * 8 + g) * 68 + ko * 8 + 2 * t);
            b[0] = __float_as_uint(u.x); b[1] = __float_as_uint(u.y);
            mma_tf32(c[0], a0, b);
            mma_tf32(c[1], a1, b);
        }
        if (ti < 7) {
            int kh0 = ti * 8 + 2 * t, kh1 = kh0 + 1;
            size_t nb = (size_t)(bh * NN) + h * WW;
            g_relh[(nb + g) * HH + kh0]        = c[0][0] * 8.f;
            g_relh[(nb + g) * HH + kh1]        = c[0][1] * 8.f;
            g_relh[(nb + g + 8) * HH + kh0]    = c[0][2] * 8.f;
            g_relh[(nb + g + 8) * HH + kh1]    = c[0][3] * 8.f;
            g_relh[(nb + 16 + g) * HH + kh0]   = c[1][0] * 8.f;
            g_relh[(nb + 16 + g) * HH + kh1]   = c[1][1] * 8.f;
            if (g < 4) {
                g_relh[(nb + 24 + g) * HH + kh0] = c[1][2] * 8.f;
                g_relh[(nb + 24 + g) * HH + kh1] = c[1][3] * 8.f;
            }
        } else {
            int cb = (ti - 7) * 8 + 2 * t;
            outw[g * 60 + cb] = c[0][0];        outw[g * 60 + cb + 1] = c[0][1];
            outw[(g + 8) * 60 + cb] = c[0][2];  outw[(g + 8) * 60 + cb + 1] = c[0][3];
            outw[(16 + g) * 60 + cb] = c[1][0]; outw[(16 + g) * 60 + cb + 1] = c[1][1];
            outw[(24 + g) * 60 + cb] = c[1][2]; outw[(24 + g) * 60 + cb + 1] = c[1][3];
        }
    }
    __syncthreads();

    for (int idx = tid; idx < WW * WW; idx += 256) {
        int w = idx / WW, kw = idx - w * WW;
        g_relw[((size_t)(bh * NN) + h * WW + w) * WW + kw] =
            outw[w * 60 + (w - kw + 27)] * 8.f;
    }
}

// ---------------- flash attention v5 (FA2: P in registers) -------------------
// 128 threads / 4 warps; each warp owns 16 full q-rows (all 64 key cols).
#define FP 68

struct F5Smem {
    float qs[64 * FP];   // Q (tf32, perm, scaled)
    float kt[64 * FP];   // K (tf32, perm)
    float vs[64 * FP];   // V (tf32, natural)
    float rh[64][HH];
    float rw[64][WW];
    int   kh_a[64];
    int   kw_a[64];
};

__global__ void __launch_bounds__(128, 3) flash5_kernel() {
    extern __shared__ char raw[];
    F5Smem& s = *reinterpret_cast<F5Smem*>(raw);

    const int bh = blockIdx.y;
    const int qt0 = blockIdx.x;
    const int tid = threadIdx.x;
    const int wid = tid >> 5;
    const int lid = tid & 31;
    const int g = lid >> 2;
    const int t = lid & 3;
    const int wm = wid * 16;
    const int r0 = wm + g, r1 = wm + g + 8;

    const int p0 = (t < 2) ? 4 * t : 4 * t - 7;
    const int p1 = (t < 2) ? 4 * t + 2 : 4 * t - 5;

    const uint32_t qaddr = smem_u32(s.qs);
    const uint32_t kaddr = smem_u32(s.kt);
    const uint32_t vaddr = smem_u32(s.vs);
    const uint32_t rhaddr = smem_u32(s.rh);
    const uint32_t rwaddr = smem_u32(s.rw);

    // ---- prologue group: Q + rh + rw via cp.async ----
#pragma unroll
    for (int it = 0; it < 8; it++) {
        int idx = it * 128 + tid;
        int r = idx >> 4, cc = idx & 15;
        int n = qt0 * 64 + r;
        const float* src = g_q + (n < NN ? (size_t)(bh * NN + n) * HD + cc * 4 : 0);
        cpa16(qaddr + (uint32_t)(r * FP + cc * 4) * 4, src, n < NN ? 16u : 0u);
    }
#pragma unroll
    for (int it = 0; it < 7; it++) {
        int idx = it * 128 + tid;
        int r = idx / 14, cc = idx % 14;          // 64 rows x 14 float4
        int n = qt0 * 64 + r;
        const float* src = g_relh + (n < NN ? (size_t)(bh * NN + n) * HH + cc * 4 : 0);
        cpa16(rhaddr + (uint32_t)(r * HH + cc * 4) * 4, src, n < NN ? 16u : 0u);
    }
#pragma unroll
    for (int it = 0; it < 4; it++) {
        int idx = it * 128 + tid;
        if (idx < 64 * 7) {
            int r = idx / 7, cc = idx % 7;        // 64 rows x 7 float4
            int n = qt0 * 64 + r;
            const float* src = g_relw + (n < NN ? (size_t)(bh * NN + n) * WW + cc * 4 : 0);
            cpa16(rwaddr + (uint32_t)(r * WW + cc * 4) * 4, src, n < NN ? 16u : 0u);
        }
    }
    CPA_COMMIT();

    float acc[8][4];
#pragma unroll
    for (int ni = 0; ni < 8; ni++)
#pragma unroll
        for (int e = 0; e < 4; e++) acc[ni][e] = 0.f;
    float rowm0 = -1e30f, rowm1 = -1e30f;
    float rowl0 = 0.f, rowl1 = 0.f;

    for (int kt2 = 0; kt2 < 25; kt2++) {
        const int kbase = kt2 * 64;
        __syncthreads();   // (A) prior readers of kt/vs done

        // ---- K group ----
#pragma unroll
        for (int it = 0; it < 8; it++) {
            int idx = it * 128 + tid;
            int r = idx >> 4, cc = idx & 15;
            int kn = kbase + r;
            bool ok = kn < NN;
            size_t off = ok ? (size_t)(bh * NN + kn) * HD + cc * 4 : 0;
            cpa16(kaddr + (uint32_t)(r * FP + cc * 4) * 4, g_k + off, ok ? 16u : 0u);
        }
        CPA_COMMIT();
        // ---- V group ----
#pragma unroll
        for (int it = 0; it < 8; it++) {
            int idx = it * 128 + tid;
            int r = idx >> 4, cc = idx & 15;
            int kn = kbase + r;
            bool ok = kn < NN;
            size_t off = ok ? (size_t)(bh * NN + kn) * HD + cc * 4 : 0;
            cpa16(vaddr + (uint32_t)(r * FP + cc * 4) * 4, g_v + off, ok ? 16u : 0u);
        }
        CPA_COMMIT();
        if (tid < 64) {
            int kn = kbase + tid;
            s.kh_a[tid] = (kn < NN) ? kn / WW : -1;
            s.kw_a[tid] = (kn < NN) ? kn % WW : 0;
        }
        CPA_WAIT1();       // K (and prologue on iter 0) done
        __syncthreads();   // (B)

        // ---- QK^T mma: 16 rows x 64 cols per warp ----
        float c[8][4];
#pragma unroll
        for (int ni = 0; ni < 8; ni++)
#pragma unroll
            for (int e = 0; e < 4; e++) c[ni][e] = 0.f;
#pragma unroll
        for (int ko = 0; ko < 8; ko++) {
            uint32_t a[4];
            float2 v0 = *(const float2*)(s.qs + r0 * FP + ko * 8 + 2 * t);
            float2 v1 = *(const float2*)(s.qs + r1 * FP + ko * 8 + 2 * t);
            a[0] = __float_as_uint(v0.x); a[1] = __float_as_uint(v1.x);
            a[2] = __float_as_uint(v0.y); a[3] = __float_as_uint(v1.y);
#pragma unroll
            for (int ni = 0; ni < 8; ni++) {
                float2 u = *(const float2*)(s.kt + (ni * 8 + g) * FP + ko * 8 + 2 * t);
                uint32_t b[2] = {__float_as_uint(u.x), __float_as_uint(u.y)};
                mma_tf32(c[ni], a, b);
            }
        }
        // ---- bias + mask ----
#pragma unroll
        for (int ni = 0; ni < 8; ni++) {
            int c0l = ni * 8 + 2 * t, c1l = c0l + 1;
            int kh0 = s.kh_a[c0l], kw0 = s.kw_a[c0l];
            int kh1 = s.kh_a[c1l], kw1 = s.kw_a[c1l];
            if (kh0 >= 0) {
                c[ni][0] += s.rh[r0][kh0] + s.rw[r0][kw0];
                c[ni][2] += s.rh[r1][kh0] + s.rw[r1][kw0];
            } else { c[ni][0] = -1e30f; c[ni][2] = -1e30f; }
            if (kh1 >= 0) {
                c[ni][1] += s.rh[r0][kh1] + s.rw[r0][kw1];
                c[ni][3] += s.rh[r1][kh1] + s.rw[r1][kw1];
            } else { c[ni][1] = -1e30f; c[ni][3] = -1e30f; }
        }

        // ---- in-warp softmax (rows fully owned by this warp) ----
        float tm0 = -1e30f, tm1 = -1e30f;
#pragma unroll
        for (int ni = 0; ni < 8; ni++) {
            tm0 = fmaxf(tm0, fmaxf(c[ni][0], c[ni][1]));
            tm1 = fmaxf(tm1, fmaxf(c[ni][2], c[ni][3]));
        }
        tm0 = fmaxf(tm0, __shfl_xor_sync(0xffffffffu, tm0, 1));
        tm0 = fmaxf(tm0, __shfl_xor_sync(0xffffffffu, tm0, 2));
        tm1 = fmaxf(tm1, __shfl_xor_sync(0xffffffffu, tm1, 1));
        tm1 = fmaxf(tm1, __shfl_xor_sync(0xffffffffu, tm1, 2));

        float mn0 = fmaxf(rowm0, tm0), mn1 = fmaxf(rowm1, tm1);
        float fac0 = __expf(rowm0 - mn0), fac1 = __expf(rowm1 - mn1);
        float ts0 = 0.f, ts1 = 0.f;
#pragma unroll
        for (int ni = 0; ni < 8; ni++) {
            c[ni][0] = tf32r(__expf(c[ni][0] - mn0));
            c[ni][1] = tf32r(__expf(c[ni][1] - mn0));
            c[ni][2] = tf32r(__expf(c[ni][2] - mn1));
            c[ni][3] = tf32r(__expf(c[ni][3] - mn1));
            ts0 += c[ni][0] + c[ni][1];
            ts1 += c[ni][2] + c[ni][3];
        }
        ts0 += __shfl_xor_sync(0xffffffffu, ts0, 1);
        ts0 += __shfl_xor_sync(0xffffffffu, ts0, 2);
        ts1 += __shfl_xor_sync(0xffffffffu, ts1, 1);
        ts1 += __shfl_xor_sync(0xffffffffu, ts1, 2);
        rowl0 = rowl0 * fac0 + ts0;
        rowl1 = rowl1 * fac1 + ts1;
        rowm0 = mn0; rowm1 = mn1;

#pragma unroll
        for (int ni = 0; ni < 8; ni++) {
            acc[ni][0] *= fac0; acc[ni][1] *= fac0;
            acc[ni][2] *= fac1; acc[ni][3] *= fac1;
        }

        CPA_WAIT0();       // V done
        __syncthreads();   // (C) all V writes visible

        // ---- P @ V mma: P fragments reused directly as A fragments ----
        // k-permuted convention: a-slots hold keys {8ko+2t, 8ko+2t+1};
        // feed matching V rows as b0/b1.
#pragma unroll
        for (int ko = 0; ko < 8; ko++) {
            uint32_t a[4];
            a[0] = __float_as_uint(c[ko][0]);   // P[r0][8ko+2t]
            a[1] = __float_as_uint(c[ko][2]);   // P[r1][8ko+2t]
            a[2] = __float_as_uint(c[ko][1]);   // P[r0][8ko+2t+1]
            a[3] = __float_as_uint(c[ko][3]);   // P[r1][8ko+2t+1]
#pragma unroll
            for (int ni = 0; ni < 8; ni++) {
                uint32_t b[2];
                b[0] = __float_as_uint(s.vs[(ko * 8 + 2 * t) * FP + ni * 8 + g]);
                b[1] = __float_as_uint(s.vs[(ko * 8 + 2 * t + 1) * FP + ni * 8 + g]);
                mma_tf32(acc[ni], a, b);
            }
        }
    }

    // ---- normalize + store g_ao (tf32, k-permuted) ----
    const int b = bh >> 4;
    const int head = bh & 15;
    const int n0g = qt0 * 64 + r0;
    const int n1g = qt0 * 64 + r1;
    float li0 = 1.f / rowl0;
    float li1 = 1.f / rowl1;
#pragma unroll
    for (int ni = 0; ni < 8; ni++) {
        int dg = ni * 8;
        if (n0g < NN) {
            size_t base = (size_t)(b * NN + n0g) * CD + head * HD + dg;
            g_ao[base + p0] = tf32r(acc[ni][0] * li0);
            g_ao[base + p1] = tf32r(acc[ni][1] * li0);
        }
        if (n1g < NN) {
            size_t base = (size_t)(b * NN + n1g) * CD + head * HD + dg;
            g_ao[base + p0] = tf32r(acc[ni][2] * li1);
            g_ao[base + p1] = tf32r(acc[ni][3] * li1);
        }
    }
}

// ---------------- launch -----------------------------------------------------
extern "C" void kernel_launch(void* const* d_in, const int* in_sizes, int n_in,
                              void* d_out, int out_size) {
    const float* hidden = (const float*)d_in[0];
    const float* qkv_w  = (const float*)d_in[1];
    const float* qkv_b  = (const float*)d_in[2];
    const float* proj_w = (const float*)d_in[3];
    const float* proj_b = (const float*)d_in[4];
    const float* rph    = (const float*)d_in[5];
    const float* rpw    = (const float*)d_in[6];
    float* out = (float*)d_out;

    cudaFuncSetAttribute(flash5_kernel, cudaFuncAttributeMaxDynamicSharedMemorySize,
                         (int)sizeof(F5Smem));
    cudaFuncSetAttribute(mm_cp<0>, cudaFuncAttributeMaxDynamicSharedMemorySize, MM_SMEM);
    cudaFuncSetAttribute(mm_cp<1>, cudaFuncAttributeMaxDynamicSharedMemorySize, MM_SMEM);

    float* d_hp;  cudaGetSymbolAddress((void**)&d_hp,  g_hp);
    float* d_wp;  cudaGetSymbolAddress((void**)&d_wp,  g_wp);
    float* d_pwp; cudaGetSymbolAddress((void**)&d_pwp, g_pwp);

    prep_kernel<<<(BN * CD / 8 + 255) / 256, 256>>>(hidden, d_hp, BN * CD / 8);
    prep_kernel<<<(3 * CD * CD / 8 + 255) / 256, 256>>>(qkv_w, d_wp, 3 * CD * CD / 8);
    prep_kernel<<<(CD * CD / 8 + 255) / 256, 256>>>(proj_w, d_pwp, CD * CD / 8);

    // QKV: [6272,3072] = hidden . qkv_w^T
    mm_cp<0><<<dim3(3 * CD / 128, (BN + 255) / 256), 256, MM_SMEM>>>(qkv_b, nullptr);

    relpos_kernel<<<dim3(HH, BHN), 256>>>(rph, rpw);

    flash5_kernel<<<dim3((NN + 63) / 64, BHN), 128, sizeof(F5Smem)>>>();

    // proj: [6272,1024] = g_ao . proj_w^T
    mm_cp<1><<<dim3(CD / 128, (BN + 255) / 256), 256, MM_SMEM>>>(proj_b, out);
}

// round 9
// speedup vs baseline: 5.2537x; 1.5254x over previous
#include <cuda_runtime.h>
#include <cuda_fp16.h>
#include <cstdint>

#define NH   16
#define HD   64
#define CD   1024
#define BB   4
#define HH   56
#define WW   28
#define NN   1568          // HH*WW
#define BHN  64            // BB*NH
#define BN   6272          // BB*NN
#define QSCALE 0.125f      // 64^-0.5

// ---------------- scratch (device globals; no allocations allowed) ----------
__device__ __half g_q[BHN * NN * HD];    // fp16, d-permuted, pre-scaled
__device__ __half g_k[BHN * NN * HD];    // fp16, d-permuted
__device__ __half g_vt[BHN * HD * NN];   // fp16, transposed [bh][d][n], n-permuted
__device__ float  g_relh[BHN * NN * HH];
__device__ float  g_relw[BHN * NN * WW];
__device__ __half g_ao[BN * CD];         // fp16, k-permuted, [B,N,heads,d]
__device__ __half g_hp[BN * CD];         // hidden prepped
__device__ __half g_wp[3 * CD * CD];     // qkv_w prepped
__device__ __half g_pwp[CD * CD];        // proj_w prepped

// ---------------- helpers ----------------------------------------------------
__device__ __forceinline__ uint32_t packh2(float a, float b) {
    __half2 h = __floats2half2_rn(a, b);
    return *reinterpret_cast<uint32_t*>(&h);
}

__device__ __forceinline__ void mma_f16(float* c, const uint32_t* a, const uint32_t* b) {
    asm volatile(
        "mma.sync.aligned.m16n8k16.row.col.f32.f16.f16.f32 "
        "{%0,%1,%2,%3}, {%4,%5,%6,%7}, {%8,%9}, {%0,%1,%2,%3};"
        : "+f"(c[0]), "+f"(c[1]), "+f"(c[2]), "+f"(c[3])
        : "r"(a[0]), "r"(a[1]), "r"(a[2]), "r"(a[3]), "r"(b[0]), "r"(b[1]));
}

__device__ __forceinline__ uint32_t smem_u32(const void* p) {
    uint32_t a;
    asm("{ .reg .u64 t; cvta.to.shared.u64 t, %1; cvt.u32.u64 %0, t; }"
        : "=r"(a) : "l"(p));
    return a;
}

__device__ __forceinline__ void cpa16(uint32_t dst, const void* src, uint32_t srcsize) {
    asm volatile("cp.async.cg.shared.global [%0], [%1], 16, %2;"
                 :: "r"(dst), "l"(src), "r"(srcsize) : "memory");
}
#define CPA_COMMIT() asm volatile("cp.async.commit_group;" ::: "memory")
#define CPA_WAIT0()  asm volatile("cp.async.wait_group 0;" ::: "memory")
#define CPA_WAIT1()  asm volatile("cp.async.wait_group 1;" ::: "memory")

// permuted position of half2-unit j within a 16-half group
__device__ __forceinline__ int posj(int j) { return (j < 4) ? 2 * j : 2 * j - 7; }
// permuted half-index of key n within its 16-group
__device__ __forceinline__ int permn(int n) {
    int u = (n >> 1) & 7;
    return (n & ~15) | (posj(u) << 1) | (n & 1);
}

// ---------------- prep: f32 -> fp16, half2-unit interleave per 16 ------------
__global__ void __launch_bounds__(256) prep_kernel(const float* __restrict__ src,
                                                   __half* __restrict__ dst, int ngroups) {
    int i = blockIdx.x * 256 + threadIdx.x;
    if (i >= ngroups) return;
    const float4* s = (const float4*)(src + (size_t)i * 16);
    float4 A = s[0], B = s[1], C = s[2], D = s[3];
    uint4* d = (uint4*)(dst + (size_t)i * 16);
    d[0] = make_uint4(packh2(A.x, A.y), packh2(C.x, C.y),
                      packh2(A.z, A.w), packh2(C.z, C.w));
    d[1] = make_uint4(packh2(B.x, B.y), packh2(D.x, D.y),
                      packh2(B.z, B.w), packh2(D.z, D.w));
}

// ================== cp.async 3-stage FP16 GEMM, 256x128 tile, BK=64 ==========
#define ATSZB (256 * 128)      // A tile bytes
#define BTSZB (128 * 128)
#define STGB  (ATSZB + BTSZB)  // 49152
#define MM_SMEM (3 * STGB)

template <int MODE>
__global__ void __launch_bounds__(256, 1) mm_cp(const float* __restrict__ bias,
                                                float* __restrict__ Cout) {
    extern __shared__ char smemc[];
    uint32_t sb = smem_u32(smemc);
    const __half* A  = (MODE == 0) ? g_hp : g_ao;
    const __half* Bm = (MODE == 0) ? g_wp : g_pwp;

    const int tid = threadIdx.x;
    const int wid = tid >> 5;
    const int lid = tid & 31;
    const int g = lid >> 2;
    const int t = lid & 3;
    const int m0 = blockIdx.y * 256;
    const int n0 = blockIdx.x * 128;
    const int wm = (wid & 3) * 64;
    const int wn = (wid >> 2) * 64;

    float acc[4][8][4];
#pragma unroll
    for (int mi = 0; mi < 4; mi++)
#pragma unroll
        for (int ni = 0; ni < 8; ni++)
#pragma unroll
            for (int e = 0; e < 4; e++) acc[mi][ni][e] = 0.f;

    const int lr = tid >> 3;
    const int lq = tid & 7;
    const uint32_t ldst = (uint32_t)(lr * 128 + ((lq ^ (lr & 7)) << 4));

    auto issue = [&](int kt) {
        const int st = kt % 3;
        const int k0 = kt * 64;
        uint32_t ab = sb + (uint32_t)st * STGB;
        uint32_t bb = ab + ATSZB;
#pragma unroll
        for (int it = 0; it < 8; it++) {
            int r = lr + it * 32;
            int gr = m0 + r;
            bool ok = gr < BN;
            cpa16(ab + ldst + (uint32_t)(it * 32 * 128),
                  A + (ok ? (size_t)gr * CD + k0 + lq * 8 : 0), ok ? 16u : 0u);
        }
#pragma unroll
        for (int it = 0; it < 4; it++) {
            int r = lr + it * 32;
            cpa16(bb + ldst + (uint32_t)(it * 32 * 128),
                  Bm + (size_t)(n0 + r) * CD + k0 + lq * 8, 16);
        }
        CPA_COMMIT();
    };

    issue(0); issue(1);
    for (int kt = 0; kt < 16; kt++) {
        if (kt < 15) CPA_WAIT1(); else CPA_WAIT0();
        __syncthreads();
        if (kt + 2 < 16) issue(kt + 2);

        const char* As = smemc + (size_t)(kt % 3) * STGB;
        const char* Bs = As + ATSZB;

#pragma unroll
        for (int kc = 0; kc < 4; kc++) {
            const int coff = (((kc * 2 + (t >> 1)) ^ g) << 4) + ((t & 1) << 3);
            uint32_t a[4][4];
            uint32_t b[8][2];
#pragma unroll
            for (int mi = 0; mi < 4; mi++) {
                uint2 v0 = *(const uint2*)(As + (wm + mi * 16 + g) * 128 + coff);
                uint2 v1 = *(const uint2*)(As + (wm + mi * 16 + g + 8) * 128 + coff);
                a[mi][0] = v0.x; a[mi][1] = v1.x; a[mi][2] = v0.y; a[mi][3] = v1.y;
            }
#pragma unroll
            for (int ni = 0; ni < 8; ni++) {
                uint2 u = *(const uint2*)(Bs + (wn + ni * 8 + g) * 128 + coff);
                b[ni][0] = u.x; b[ni][1] = u.y;
            }
#pragma unroll
            for (int mi = 0; mi < 4; mi++)
#pragma unroll
                for (int ni = 0; ni < 8; ni++) mma_f16(acc[mi][ni], a[mi], b[ni]);
        }
    }

#pragma unroll
    for (int mi = 0; mi < 4; mi++) {
        int mr0 = m0 + wm + mi * 16 + g;
        int mr1 = mr0 + 8;
        bool ok0 = mr0 < BN, ok1 = mr1 < BN;
#pragma unroll
        for (int ni = 0; ni < 8; ni++) {
            int jj = n0 + wn + ni * 8 + 2 * t;
            float b0 = bias[jj], b1 = bias[jj + 1];
            float v00 = acc[mi][ni][0] + b0, v01 = acc[mi][ni][1] + b1;
            float v10 = acc[mi][ni][2] + b0, v11 = acc[mi][ni][3] + b1;
            if (MODE == 0) {
                int tsel = jj >> 10;
                int rr = jj & 1023;
                int head = rr >> 6;
                int d = rr & 63;
                int dperm = (d & ~15) + posj((d & 15) >> 1) * 2;
                if (ok0) {
                    int b_ = mr0 / NN, n_ = mr0 - b_ * NN;
                    int bh = b_ * NH + head;
                    if (tsel == 0) {
                        *(__half2*)&g_q[((size_t)bh * NN + n_) * HD + dperm] =
                            __floats2half2_rn(v00 * QSCALE, v01 * QSCALE);
                    } else if (tsel == 1) {
                        *(__half2*)&g_k[((size_t)bh * NN + n_) * HD + dperm] =
                            __floats2half2_rn(v00, v01);
                    } else {
                        int np = permn(n_);
                        g_vt[((size_t)bh * HD + d) * NN + np]     = __float2half_rn(v00);
                        g_vt[((size_t)bh * HD + d + 1) * NN + np] = __float2half_rn(v01);
                    }
                }
                if (ok1) {
                    int b_ = mr1 / NN, n_ = mr1 - b_ * NN;
                    int bh = b_ * NH + head;
                    if (tsel == 0) {
                        *(__half2*)&g_q[((size_t)bh * NN + n_) * HD + dperm] =
                            __floats2half2_rn(v10 * QSCALE, v11 * QSCALE);
                    } else if (tsel == 1) {
                        *(__half2*)&g_k[((size_t)bh * NN + n_) * HD + dperm] =
                            __floats2half2_rn(v10, v11);
                    } else {
                        int np = permn(n_);
                        g_vt[((size_t)bh * HD + d) * NN + np]     = __float2half_rn(v10);
                        g_vt[((size_t)bh * HD + d + 1) * NN + np] = __float2half_rn(v11);
                    }
                }
            } else {
                if (ok0) { float2 o = {v00, v01}; *(float2*)&Cout[(size_t)mr0 * CD + jj] = o; }
                if (ok1) { float2 o = {v10, v11}; *(float2*)&Cout[(size_t)mr1 * CD + jj] = o; }
            }
        }
    }
}

// ---------------- rel-pos bias via FP16 mma -----------------------------------
__global__ void __launch_bounds__(256) relpos_kernel(const float* __restrict__ rph,
                                                     const float* __restrict__ rpw) {
    __shared__ __align__(16) __half qp[32 * 72];
    __shared__ __align__(16) __half Bp[112 * 72];
    __shared__ float outw[32 * 60];

    const int h = blockIdx.x;
    const int bh = blockIdx.y;
    const int tid = threadIdx.x;
    const int wid = tid >> 5;
    const int lid = tid & 31;
    const int g = lid >> 2;
    const int t = lid & 3;

    // qp: already permuted+scaled fp16 in g_q; 32 rows x 8 chunks
    {
        int r = tid >> 3, cc = tid & 7;
        uint4 v = make_uint4(0, 0, 0, 0);
        if (r < WW)
            v = *(const uint4*)&g_q[((size_t)bh * NN + h * WW + r) * HD + cc * 8];
        *(uint4*)&qp[r * 72 + cc * 8] = v;
    }
    // Bp: 112 rows x 4 groups of 16 floats -> fp16 permuted
#pragma unroll
    for (int it = 0; it < 2; it++) {
        int idx = it * 256 + tid;
        if (idx < 448) {
            int r = idx >> 2, grp = idx & 3;
            float4 A = {0,0,0,0}, B = {0,0,0,0}, C = {0,0,0,0}, D = {0,0,0,0};
            const float* sp = nullptr;
            if (r < 56)       sp = rph + (size_t)(h + 55 - r) * HD + grp * 16;
            else if (r < 111) sp = rpw + (size_t)(r - 56) * HD + grp * 16;
            if (sp) { A = ((const float4*)sp)[0]; B = ((const float4*)sp)[1];
                      C = ((const float4*)sp)[2]; D = ((const float4*)sp)[3]; }
            *(uint4*)&Bp[r * 72 + grp * 16] =
                make_uint4(packh2(A.x, A.y), packh2(C.x, C.y),
                           packh2(A.z, A.w), packh2(C.z, C.w));
            *(uint4*)&Bp[r * 72 + grp * 16 + 8] =
                make_uint4(packh2(B.x, B.y), packh2(D.x, D.y),
                           packh2(B.z, B.w), packh2(D.z, D.w));
        }
    }
    __syncthreads();

    for (int ti = wid; ti < 14; ti += 8) {
        float c[2][4];
#pragma unroll
        for (int mi = 0; mi < 2; mi++)
#pragma unroll
            for (int e = 0; e < 4; e++) c[mi][e] = 0.f;
#pragma unroll
        for (int kc = 0; kc < 4; kc++) {
            int qo = kc * 16 + t * 4;   // halves
            uint2 v0 = *(const uint2*)&qp[g * 72 + qo];
            uint2 v1 = *(const uint2*)&qp[(g + 8) * 72 + qo];
            uint2 v2 = *(const uint2*)&qp[(16 + g) * 72 + qo];
            uint2 v3 = *(const uint2*)&qp[(24 + g) * 72 + qo];
            uint32_t a0[4] = {v0.x, v1.x, v0.y, v1.y};
            uint32_t a1[4] = {v2.x, v3.x, v2.y, v3.y};
            uint2 u = *(const uint2*)&Bp[(ti * 8 + g) * 72 + qo];
            uint32_t b[2] = {u.x, u.y};
            mma_f16(c[0], a0, b);
            mma_f16(c[1], a1, b);
        }
        if (ti < 7) {
            int kh0 = ti * 8 + 2 * t, kh1 = kh0 + 1;
            size_t nb = (size_t)(bh * NN) + h * WW;
            g_relh[(nb + g) * HH + kh0]      = c[0][0] * 8.f;
            g_relh[(nb + g) * HH + kh1]      = c[0][1] * 8.f;
            g_relh[(nb + g + 8) * HH + kh0]  = c[0][2] * 8.f;
            g_relh[(nb + g + 8) * HH + kh1]  = c[0][3] * 8.f;
            g_relh[(nb + 16 + g) * HH + kh0] = c[1][0] * 8.f;
            g_relh[(nb + 16 + g) * HH + kh1] = c[1][1] * 8.f;
            if (g < 4) {
                g_relh[(nb + 24 + g) * HH + kh0] = c[1][2] * 8.f;
                g_relh[(nb + 24 + g) * HH + kh1] = c[1][3] * 8.f;
            }
        } else {
            int cb = (ti - 7) * 8 + 2 * t;
            outw[g * 60 + cb] = c[0][0];        outw[g * 60 + cb + 1] = c[0][1];
            outw[(g + 8) * 60 + cb] = c[0][2];  outw[(g + 8) * 60 + cb + 1] = c[0][3];
            outw[(16 + g) * 60 + cb] = c[1][0]; outw[(16 + g) * 60 + cb + 1] = c[1][1];
            outw[(24 + g) * 60 + cb] = c[1][2]; outw[(24 + g) * 60 + cb + 1] = c[1][3];
        }
    }
    __syncthreads();

    for (int idx = tid; idx < WW * WW; idx += 256) {
        int w = idx / WW, kw = idx - w * WW;
        g_relw[((size_t)(bh * NN) + h * WW + w) * WW + kw] =
            outw[w * 60 + (w - kw + 27)] * 8.f;
    }
}

// ---------------- flash attention v6 (fp16 mma, P in registers) --------------
#define FPH 72   // halves pitch (144B rows)

struct F6Smem {
    __align__(16) __half qs[64 * FPH];
    __align__(16) __half kt[64 * FPH];
    __align__(16) __half vs[64 * FPH];   // transposed: row=d, col=keys (permuted)
    float rh[64][HH];
    float rw[64][WW];
    int   kh_a[64];
    int   kw_a[64];
};

__global__ void __launch_bounds__(128, 3) flash6_kernel() {
    extern __shared__ char raw[];
    F6Smem& s = *reinterpret_cast<F6Smem*>(raw);

    const int bh = blockIdx.y;
    const int qt0 = blockIdx.x;
    const int tid = threadIdx.x;
    const int wid = tid >> 5;
    const int lid = tid & 31;
    const int g = lid >> 2;
    const int t = lid & 3;
    const int wm = wid * 16;
    const int r0 = wm + g, r1 = wm + g + 8;

    const uint32_t qaddr = smem_u32(s.qs);
    const uint32_t kaddr = smem_u32(s.kt);
    const uint32_t vaddr = smem_u32(s.vs);
    const uint32_t rhaddr = smem_u32(s.rh);
    const uint32_t rwaddr = smem_u32(s.rw);

    // ---- prologue group: Q + rh + rw ----
#pragma unroll
    for (int it = 0; it < 4; it++) {
        int idx = it * 128 + tid;
        int r = idx >> 3, cc = idx & 7;
        int n = qt0 * 64 + r;
        const __half* src = g_q + (n < NN ? (size_t)(bh * NN + n) * HD + cc * 8 : 0);
        cpa16(qaddr + (uint32_t)(r * 144 + cc * 16), src, n < NN ? 16u : 0u);
    }
#pragma unroll
    for (int it = 0; it < 7; it++) {
        int idx = it * 128 + tid;
        int r = idx / 14, cc = idx % 14;
        int n = qt0 * 64 + r;
        const float* src = g_relh + (n < NN ? (size_t)(bh * NN + n) * HH + cc * 4 : 0);
        cpa16(rhaddr + (uint32_t)(r * HH + cc * 4) * 4, src, n < NN ? 16u : 0u);
    }
#pragma unroll
    for (int it = 0; it < 4; it++) {
        int idx = it * 128 + tid;
        if (idx < 64 * 7) {
            int r = idx / 7, cc = idx % 7;
            int n = qt0 * 64 + r;
            const float* src = g_relw + (n < NN ? (size_t)(bh * NN + n) * WW + cc * 4 : 0);
            cpa16(rwaddr + (uint32_t)(r * WW + cc * 4) * 4, src, n < NN ? 16u : 0u);
        }
    }
    CPA_COMMIT();

    float acc[8][4];
#pragma unroll
    for (int ni = 0; ni < 8; ni++)
#pragma unroll
        for (int e = 0; e < 4; e++) acc[ni][e] = 0.f;
    float rowm0 = -1e30f, rowm1 = -1e30f;
    float rowl0 = 0.f, rowl1 = 0.f;

    for (int kt2 = 0; kt2 < 25; kt2++) {
        const int kbase = kt2 * 64;
        __syncthreads();   // (A) prior readers of kt/vs done

        // ---- K group (rows = keys) ----
#pragma unroll
        for (int it = 0; it < 4; it++) {
            int idx = it * 128 + tid;
            int r = idx >> 3, cc = idx & 7;
            int kn = kbase + r;
            bool ok = kn < NN;
            const __half* src = g_k + (ok ? (size_t)(bh * NN + kn) * HD + cc * 8 : 0);
            cpa16(kaddr + (uint32_t)(r * 144 + cc * 16), src, ok ? 16u : 0u);
        }
        CPA_COMMIT();
        // ---- V group (rows = d, cols = keys, chunk-guarded) ----
#pragma unroll
        for (int it = 0; it < 4; it++) {
            int idx = it * 128 + tid;
            int r = idx >> 3, cc = idx & 7;
            bool ok = (kbase + cc * 8 + 8) <= NN;
            const __half* src = g_vt + (ok ? (size_t)(bh * HD + r) * NN + kbase + cc * 8 : 0);
            cpa16(vaddr + (uint32_t)(r * 144 + cc * 16), src, ok ? 16u : 0u);
        }
        CPA_COMMIT();
        if (tid < 64) {
            int kn = kbase + tid;
            s.kh_a[tid] = (kn < NN) ? kn / WW : -1;
            s.kw_a[tid] = (kn < NN) ? kn % WW : 0;
        }
        CPA_WAIT1();       // K (and prologue on iter 0) done
        __syncthreads();   // (B)

        // ---- QK^T mma ----
        float c[8][4];
#pragma unroll
        for (int ni = 0; ni < 8; ni++)
#pragma unroll
            for (int e = 0; e < 4; e++) c[ni][e] = 0.f;
#pragma unroll
        for (int kc = 0; kc < 4; kc++) {
            const int qo = kc * 32 + t * 8;   // bytes within row
            uint2 v0 = *(const uint2*)((const char*)s.qs + r0 * 144 + qo);
            uint2 v1 = *(const uint2*)((const char*)s.qs + r1 * 144 + qo);
            uint32_t a[4] = {v0.x, v1.x, v0.y, v1.y};
#pragma unroll
            for (int ni = 0; ni < 8; ni++) {
                uint2 u = *(const uint2*)((const char*)s.kt + (ni * 8 + g) * 144 + qo);
                uint32_t b[2] = {u.x, u.y};
                mma_f16(c[ni], a, b);
            }
        }
        // ---- bias + mask ----
#pragma unroll
        for (int ni = 0; ni < 8; ni++) {
            int c0l = ni * 8 + 2 * t, c1l = c0l + 1;
            int kh0 = s.kh_a[c0l], kw0 = s.kw_a[c0l];
            int kh1 = s.kh_a[c1l], kw1 = s.kw_a[c1l];
            if (kh0 >= 0) {
                c[ni][0] += s.rh[r0][kh0] + s.rw[r0][kw0];
                c[ni][2] += s.rh[r1][kh0] + s.rw[r1][kw0];
            } else { c[ni][0] = -1e30f; c[ni][2] = -1e30f; }
            if (kh1 >= 0) {
                c[ni][1] += s.rh[r0][kh1] + s.rw[r0][kw1];
                c[ni][3] += s.rh[r1][kh1] + s.rw[r1][kw1];
            } else { c[ni][1] = -1e30f; c[ni][3] = -1e30f; }
        }

        // ---- in-warp softmax ----
        float tm0 = -1e30f, tm1 = -1e30f;
#pragma unroll
        for (int ni = 0; ni < 8; ni++) {
            tm0 = fmaxf(tm0, fmaxf(c[ni][0], c[ni][1]));
            tm1 = fmaxf(tm1, fmaxf(c[ni][2], c[ni][3]));
        }
        tm0 = fmaxf(tm0, __shfl_xor_sync(0xffffffffu, tm0, 1));
        tm0 = fmaxf(tm0, __shfl_xor_sync(0xffffffffu, tm0, 2));
        tm1 = fmaxf(tm1, __shfl_xor_sync(0xffffffffu, tm1, 1));
        tm1 = fmaxf(tm1, __shfl_xor_sync(0xffffffffu, tm1, 2));

        float mn0 = fmaxf(rowm0, tm0), mn1 = fmaxf(rowm1, tm1);
        float fac0 = __expf(rowm0 - mn0), fac1 = __expf(rowm1 - mn1);
        float ts0 = 0.f, ts1 = 0.f;
#pragma unroll
        for (int ni = 0; ni < 8; ni++) {
            c[ni][0] = __expf(c[ni][0] - mn0);
            c[ni][1] = __expf(c[ni][1] - mn0);
            c[ni][2] = __expf(c[ni][2] - mn1);
            c[ni][3] = __expf(c[ni][3] - mn1);
            ts0 += c[ni][0] + c[ni][1];
            ts1 += c[ni][2] + c[ni][3];
        }
        ts0 += __shfl_xor_sync(0xffffffffu, ts0, 1);
        ts0 += __shfl_xor_sync(0xffffffffu, ts0, 2);
        ts1 += __shfl_xor_sync(0xffffffffu, ts1, 1);
        ts1 += __shfl_xor_sync(0xffffffffu, ts1, 2);
        rowl0 = rowl0 * fac0 + ts0;
        rowl1 = rowl1 * fac1 + ts1;
        rowm0 = mn0; rowm1 = mn1;

#pragma unroll
        for (int ni = 0; ni < 8; ni++) {
            acc[ni][0] *= fac0; acc[ni][1] *= fac0;
            acc[ni][2] *= fac1; acc[ni][3] *= fac1;
        }

        CPA_WAIT0();       // V done
        __syncthreads();   // (C)

        // ---- P @ V: pack P frags to fp16, V from transposed tile ----
#pragma unroll
        for (int kc = 0; kc < 4; kc++) {
            uint32_t a[4];
            a[0] = packh2(c[2 * kc][0],     c[2 * kc][1]);
            a[1] = packh2(c[2 * kc][2],     c[2 * kc][3]);
            a[2] = packh2(c[2 * kc + 1][0], c[2 * kc + 1][1]);
            a[3] = packh2(c[2 * kc + 1][2], c[2 * kc + 1][3]);
            const int vo = kc * 32 + t * 8;
#pragma unroll
            for (int ni = 0; ni < 8; ni++) {
                uint2 u = *(const uint2*)((const char*)s.vs + (ni * 8 + g) * 144 + vo);
                uint32_t b[2] = {u.x, u.y};
                mma_f16(acc[ni], a, b);
            }
        }
    }

    // ---- normalize + store g_ao (fp16, k-permuted) ----
    const int b = bh >> 4;
    const int head = bh & 15;
    const int n0g = qt0 * 64 + r0;
    const int n1g = qt0 * 64 + r1;
    float li0 = 1.f / rowl0;
    float li1 = 1.f / rowl1;
#pragma unroll
    for (int ni = 0; ni < 8; ni++) {
        int col = head * HD + ni * 8 + 2 * t;
        int colp = (col & ~15) + posj((col & 15) >> 1) * 2;
        if (n0g < NN)
            *(__half2*)&g_ao[(size_t)(b * NN + n0g) * CD + colp] =
                __floats2half2_rn(acc[ni][0] * li0, acc[ni][1] * li0);
        if (n1g < NN)
            *(__half2*)&g_ao[(size_t)(b * NN + n1g) * CD + colp] =
                __floats2half2_rn(acc[ni][2] * li1, acc[ni][3] * li1);
    }
}

// ---------------- launch -----------------------------------------------------
extern "C" void kernel_launch(void* const* d_in, const int* in_sizes, int n_in,
                              void* d_out, int out_size) {
    const float* hidden = (const float*)d_in[0];
    const float* qkv_w  = (const float*)d_in[1];
    const float* qkv_b  = (const float*)d_in[2];
    const float* proj_w = (const float*)d_in[3];
    const float* proj_b = (const float*)d_in[4];
    const float* rph    = (const float*)d_in[5];
    const float* rpw    = (const float*)d_in[6];
    float* out = (float*)d_out;

    cudaFuncSetAttribute(flash6_kernel, cudaFuncAttributeMaxDynamicSharedMemorySize,
                         (int)sizeof(F6Smem));
    cudaFuncSetAttribute(mm_cp<0>, cudaFuncAttributeMaxDynamicSharedMemorySize, MM_SMEM);
    cudaFuncSetAttribute(mm_cp<1>, cudaFuncAttributeMaxDynamicSharedMemorySize, MM_SMEM);

    __half* d_hp;  cudaGetSymbolAddress((void**)&d_hp,  g_hp);
    __half* d_wp;  cudaGetSymbolAddress((void**)&d_wp,  g_wp);
    __half* d_pwp; cudaGetSymbolAddress((void**)&d_pwp, g_pwp);

    prep_kernel<<<(BN * CD / 16 + 255) / 256, 256>>>(hidden, d_hp, BN * CD / 16);
    prep_kernel<<<(3 * CD * CD / 16 + 255) / 256, 256>>>(qkv_w, d_wp, 3 * CD * CD / 16);
    prep_kernel<<<(CD * CD / 16 + 255) / 256, 256>>>(proj_w, d_pwp, CD * CD / 16);

    // QKV: [6272,3072] = hidden . qkv_w^T
    mm_cp<0><<<dim3(3 * CD / 128, (BN + 255) / 256), 256, MM_SMEM>>>(qkv_b, nullptr);

    relpos_kernel<<<dim3(HH, BHN), 256>>>(rph, rpw);

    flash6_kernel<<<dim3((NN + 63) / 64, BHN), 128, sizeof(F6Smem)>>>();

    // proj: [6272,1024] = g_ao . proj_w^T
    mm_cp<1><<<dim3(CD / 128, (BN + 255) / 256), 256, MM_SMEM>>>(proj_b, out);
}

// round 10
// speedup vs baseline: 5.3293x; 1.0144x over previous
#include <cuda_runtime.h>
#include <cuda_fp16.h>
#include <cstdint>

#define NH   16
#define HD   64
#define CD   1024
#define BB   4
#define HH   56
#define WW   28
#define NN   1568          // HH*WW
#define BHN  64            // BB*NH
#define BN   6272          // BB*NN
#define QSCALE 0.125f      // 64^-0.5

// ---------------- scratch (device globals; no allocations allowed) ----------
__device__ __half g_q[BHN * NN * HD];    // fp16, d-permuted, pre-scaled
__device__ __half g_k[BHN * NN * HD];    // fp16, d-permuted
__device__ __half g_vt[BHN * HD * NN];   // fp16, transposed [bh][d][n], n-permuted
__device__ float  g_relh[BHN * NN * HH];
__device__ float  g_relw[BHN * NN * WW];
__device__ __half g_ao[BN * CD];         // fp16, k-permuted, [B,N,heads,d]
__device__ __half g_hp[BN * CD];         // hidden prepped
__device__ __half g_wp[3 * CD * CD];     // qkv_w prepped
__device__ __half g_pwp[CD * CD];        // proj_w prepped

// ---------------- helpers ----------------------------------------------------
__device__ __forceinline__ uint32_t packh2(float a, float b) {
    __half2 h = __floats2half2_rn(a, b);
    return *reinterpret_cast<uint32_t*>(&h);
}

__device__ __forceinline__ void mma_f16(float* c, const uint32_t* a, const uint32_t* b) {
    asm volatile(
        "mma.sync.aligned.m16n8k16.row.col.f32.f16.f16.f32 "
        "{%0,%1,%2,%3}, {%4,%5,%6,%7}, {%8,%9}, {%0,%1,%2,%3};"
        : "+f"(c[0]), "+f"(c[1]), "+f"(c[2]), "+f"(c[3])
        : "r"(a[0]), "r"(a[1]), "r"(a[2]), "r"(a[3]), "r"(b[0]), "r"(b[1]));
}

__device__ __forceinline__ uint32_t smem_u32(const void* p) {
    uint32_t a;
    asm("{ .reg .u64 t; cvta.to.shared.u64 t, %1; cvt.u32.u64 %0, t; }"
        : "=r"(a) : "l"(p));
    return a;
}

__device__ __forceinline__ void cpa16(uint32_t dst, const void* src, uint32_t srcsize) {
    asm volatile("cp.async.cg.shared.global [%0], [%1], 16, %2;"
                 :: "r"(dst), "l"(src), "r"(srcsize) : "memory");
}
#define CPA_COMMIT() asm volatile("cp.async.commit_group;" ::: "memory")
#define CPA_WAIT0()  asm volatile("cp.async.wait_group 0;" ::: "memory")
#define CPA_WAIT1()  asm volatile("cp.async.wait_group 1;" ::: "memory")

// permuted position of half2-unit j within a 16-half group
__device__ __forceinline__ int posj(int j) { return (j < 4) ? 2 * j : 2 * j - 7; }
// permuted half-index of key n within its 16-group
__device__ __forceinline__ int permn(int n) {
    int u = (n >> 1) & 7;
    return (n & ~15) | (posj(u) << 1) | (n & 1);
}

// ---------------- prep: f32 -> fp16, half2-unit interleave per 16 ------------
__global__ void __launch_bounds__(256) prep_kernel(const float* __restrict__ src,
                                                   __half* __restrict__ dst, int ngroups) {
    int i = blockIdx.x * 256 + threadIdx.x;
    if (i >= ngroups) return;
    const float4* s = (const float4*)(src + (size_t)i * 16);
    float4 A = s[0], B = s[1], C = s[2], D = s[3];
    uint4* d = (uint4*)(dst + (size_t)i * 16);
    d[0] = make_uint4(packh2(A.x, A.y), packh2(C.x, C.y),
                      packh2(A.z, A.w), packh2(C.z, C.w));
    d[1] = make_uint4(packh2(B.x, B.y), packh2(D.x, D.y),
                      packh2(B.z, B.w), packh2(D.z, D.w));
}

// ================== cp.async 3-stage FP16 GEMM, 256x128 tile, BK=64 ==========
#define ATSZB (256 * 128)      // A tile bytes
#define BTSZB (128 * 128)
#define STGB  (ATSZB + BTSZB)  // 49152
#define MM_SMEM (3 * STGB)

template <int MODE>
__global__ void __launch_bounds__(256, 1) mm_cp(const float* __restrict__ bias,
                                                float* __restrict__ Cout) {
    extern __shared__ char smemc[];
    uint32_t sb = smem_u32(smemc);
    const __half* A  = (MODE == 0) ? g_hp : g_ao;
    const __half* Bm = (MODE == 0) ? g_wp : g_pwp;

    const int tid = threadIdx.x;
    const int wid = tid >> 5;
    const int lid = tid & 31;
    const int g = lid >> 2;
    const int t = lid & 3;
    const int m0 = blockIdx.y * 256;
    const int n0 = blockIdx.x * 128;
    const int wm = (wid & 3) * 64;
    const int wn = (wid >> 2) * 64;

    float acc[4][8][4];
#pragma unroll
    for (int mi = 0; mi < 4; mi++)
#pragma unroll
        for (int ni = 0; ni < 8; ni++)
#pragma unroll
            for (int e = 0; e < 4; e++) acc[mi][ni][e] = 0.f;

    const int lr = tid >> 3;
    const int lq = tid & 7;
    const uint32_t ldst = (uint32_t)(lr * 128 + ((lq ^ (lr & 7)) << 4));

    auto issue = [&](int kt) {
        const int st = kt % 3;
        const int k0 = kt * 64;
        uint32_t ab = sb + (uint32_t)st * STGB;
        uint32_t bb = ab + ATSZB;
#pragma unroll
        for (int it = 0; it < 8; it++) {
            int r = lr + it * 32;
            int gr = m0 + r;
            bool ok = gr < BN;
            cpa16(ab + ldst + (uint32_t)(it * 32 * 128),
                  A + (ok ? (size_t)gr * CD + k0 + lq * 8 : 0), ok ? 16u : 0u);
        }
#pragma unroll
        for (int it = 0; it < 4; it++) {
            int r = lr + it * 32;
            cpa16(bb + ldst + (uint32_t)(it * 32 * 128),
                  Bm + (size_t)(n0 + r) * CD + k0 + lq * 8, 16);
        }
        CPA_COMMIT();
    };

    issue(0); issue(1);
    for (int kt = 0; kt < 16; kt++) {
        if (kt < 15) CPA_WAIT1(); else CPA_WAIT0();
        __syncthreads();
        if (kt + 2 < 16) issue(kt + 2);

        const char* As = smemc + (size_t)(kt % 3) * STGB;
        const char* Bs = As + ATSZB;

#pragma unroll
        for (int kc = 0; kc < 4; kc++) {
            const int coff = (((kc * 2 + (t >> 1)) ^ g) << 4) + ((t & 1) << 3);
            uint32_t a[4][4];
            uint32_t b[8][2];
#pragma unroll
            for (int mi = 0; mi < 4; mi++) {
                uint2 v0 = *(const uint2*)(As + (wm + mi * 16 + g) * 128 + coff);
                uint2 v1 = *(const uint2*)(As + (wm + mi * 16 + g + 8) * 128 + coff);
                a[mi][0] = v0.x; a[mi][1] = v1.x; a[mi][2] = v0.y; a[mi][3] = v1.y;
            }
#pragma unroll
            for (int ni = 0; ni < 8; ni++) {
                uint2 u = *(const uint2*)(Bs + (wn + ni * 8 + g) * 128 + coff);
                b[ni][0] = u.x; b[ni][1] = u.y;
            }
#pragma unroll
            for (int mi = 0; mi < 4; mi++)
#pragma unroll
                for (int ni = 0; ni < 8; ni++) mma_f16(acc[mi][ni], a[mi], b[ni]);
        }
    }

#pragma unroll
    for (int mi = 0; mi < 4; mi++) {
        int mr0 = m0 + wm + mi * 16 + g;
        int mr1 = mr0 + 8;
        bool ok0 = mr0 < BN, ok1 = mr1 < BN;
#pragma unroll
        for (int ni = 0; ni < 8; ni++) {
            int jj = n0 + wn + ni * 8 + 2 * t;
            float b0 = bias[jj], b1 = bias[jj + 1];
            float v00 = acc[mi][ni][0] + b0, v01 = acc[mi][ni][1] + b1;
            float v10 = acc[mi][ni][2] + b0, v11 = acc[mi][ni][3] + b1;
            if (MODE == 0) {
                int tsel = jj >> 10;
                int rr = jj & 1023;
                int head = rr >> 6;
                int d = rr & 63;
                int dperm = (d & ~15) + posj((d & 15) >> 1) * 2;
                if (ok0) {
                    int b_ = mr0 / NN, n_ = mr0 - b_ * NN;
                    int bh = b_ * NH + head;
                    if (tsel == 0) {
                        *(__half2*)&g_q[((size_t)bh * NN + n_) * HD + dperm] =
                            __floats2half2_rn(v00 * QSCALE, v01 * QSCALE);
                    } else if (tsel == 1) {
                        *(__half2*)&g_k[((size_t)bh * NN + n_) * HD + dperm] =
                            __floats2half2_rn(v00, v01);
                    } else {
                        int np = permn(n_);
                        g_vt[((size_t)bh * HD + d) * NN + np]     = __float2half_rn(v00);
                        g_vt[((size_t)bh * HD + d + 1) * NN + np] = __float2half_rn(v01);
                    }
                }
                if (ok1) {
                    int b_ = mr1 / NN, n_ = mr1 - b_ * NN;
                    int bh = b_ * NH + head;
                    if (tsel == 0) {
                        *(__half2*)&g_q[((size_t)bh * NN + n_) * HD + dperm] =
                            __floats2half2_rn(v10 * QSCALE, v11 * QSCALE);
                    } else if (tsel == 1) {
                        *(__half2*)&g_k[((size_t)bh * NN + n_) * HD + dperm] =
                            __floats2half2_rn(v10, v11);
                    } else {
                        int np = permn(n_);
                        g_vt[((size_t)bh * HD + d) * NN + np]     = __float2half_rn(v10);
                        g_vt[((size_t)bh * HD + d + 1) * NN + np] = __float2half_rn(v11);
                    }
                }
            } else {
                if (ok0) { float2 o = {v00, v01}; *(float2*)&Cout[(size_t)mr0 * CD + jj] = o; }
                if (ok1) { float2 o = {v10, v11}; *(float2*)&Cout[(size_t)mr1 * CD + jj] = o; }
            }
        }
    }
}

// ---------------- rel-pos bias via FP16 mma -----------------------------------
__global__ void __launch_bounds__(256) relpos_kernel(const float* __restrict__ rph,
                                                     const float* __restrict__ rpw) {
    __shared__ __align__(16) __half qp[32 * 72];
    __shared__ __align__(16) __half Bp[112 * 72];
    __shared__ float outw[32 * 60];

    const int h = blockIdx.x;
    const int bh = blockIdx.y;
    const int tid = threadIdx.x;
    const int wid = tid >> 5;
    const int lid = tid & 31;
    const int g = lid >> 2;
    const int t = lid & 3;

    {
        int r = tid >> 3, cc = tid & 7;
        uint4 v = make_uint4(0, 0, 0, 0);
        if (r < WW)
            v = *(const uint4*)&g_q[((size_t)bh * NN + h * WW + r) * HD + cc * 8];
        *(uint4*)&qp[r * 72 + cc * 8] = v;
    }
#pragma unroll
    for (int it = 0; it < 2; it++) {
        int idx = it * 256 + tid;
        if (idx < 448) {
            int r = idx >> 2, grp = idx & 3;
            float4 A = {0,0,0,0}, B = {0,0,0,0}, C = {0,0,0,0}, D = {0,0,0,0};
            const float* sp = nullptr;
            if (r < 56)       sp = rph + (size_t)(h + 55 - r) * HD + grp * 16;
            else if (r < 111) sp = rpw + (size_t)(r - 56) * HD + grp * 16;
            if (sp) { A = ((const float4*)sp)[0]; B = ((const float4*)sp)[1];
                      C = ((const float4*)sp)[2]; D = ((const float4*)sp)[3]; }
            *(uint4*)&Bp[r * 72 + grp * 16] =
                make_uint4(packh2(A.x, A.y), packh2(C.x, C.y),
                           packh2(A.z, A.w), packh2(C.z, C.w));
            *(uint4*)&Bp[r * 72 + grp * 16 + 8] =
                make_uint4(packh2(B.x, B.y), packh2(D.x, D.y),
                           packh2(B.z, B.w), packh2(D.z, D.w));
        }
    }
    __syncthreads();

    for (int ti = wid; ti < 14; ti += 8) {
        float c[2][4];
#pragma unroll
        for (int mi = 0; mi < 2; mi++)
#pragma unroll
            for (int e = 0; e < 4; e++) c[mi][e] = 0.f;
#pragma unroll
        for (int kc = 0; kc < 4; kc++) {
            int qo = kc * 16 + t * 4;
            uint2 v0 = *(const uint2*)&qp[g * 72 + qo];
            uint2 v1 = *(const uint2*)&qp[(g + 8) * 72 + qo];
            uint2 v2 = *(const uint2*)&qp[(16 + g) * 72 + qo];
            uint2 v3 = *(const uint2*)&qp[(24 + g) * 72 + qo];
            uint32_t a0[4] = {v0.x, v1.x, v0.y, v1.y};
            uint32_t a1[4] = {v2.x, v3.x, v2.y, v3.y};
            uint2 u = *(const uint2*)&Bp[(ti * 8 + g) * 72 + qo];
            uint32_t b[2] = {u.x, u.y};
            mma_f16(c[0], a0, b);
            mma_f16(c[1], a1, b);
        }
        if (ti < 7) {
            int kh0 = ti * 8 + 2 * t, kh1 = kh0 + 1;
            size_t nb = (size_t)(bh * NN) + h * WW;
            g_relh[(nb + g) * HH + kh0]      = c[0][0] * 8.f;
            g_relh[(nb + g) * HH + kh1]      = c[0][1] * 8.f;
            g_relh[(nb + g + 8) * HH + kh0]  = c[0][2] * 8.f;
            g_relh[(nb + g + 8) * HH + kh1]  = c[0][3] * 8.f;
            g_relh[(nb + 16 + g) * HH + kh0] = c[1][0] * 8.f;
            g_relh[(nb + 16 + g) * HH + kh1] = c[1][1] * 8.f;
            if (g < 4) {
                g_relh[(nb + 24 + g) * HH + kh0] = c[1][2] * 8.f;
                g_relh[(nb + 24 + g) * HH + kh1] = c[1][3] * 8.f;
            }
        } else {
            int cb = (ti - 7) * 8 + 2 * t;
            outw[g * 60 + cb] = c[0][0];        outw[g * 60 + cb + 1] = c[0][1];
            outw[(g + 8) * 60 + cb] = c[0][2];  outw[(g + 8) * 60 + cb + 1] = c[0][3];
            outw[(16 + g) * 60 + cb] = c[1][0]; outw[(16 + g) * 60 + cb + 1] = c[1][1];
            outw[(24 + g) * 60 + cb] = c[1][2]; outw[(24 + g) * 60 + cb + 1] = c[1][3];
        }
    }
    __syncthreads();

    for (int idx = tid; idx < WW * WW; idx += 256) {
        int w = idx / WW, kw = idx - w * WW;
        g_relw[((size_t)(bh * NN) + h * WW + w) * WW + kw] =
            outw[w * 60 + (w - kw + 27)] * 8.f;
    }
}

// ---------------- flash attention v7: 128 q-rows, double-buffered K/V --------
#define FPH 72   // halves pitch (144B rows)

struct F7Smem {
    __align__(16) __half qs[128 * FPH];
    __align__(16) __half kt[2][64 * FPH];
    __align__(16) __half vs[2][64 * FPH];   // transposed: row=d, col=keys (perm)
    float rh[128][HH];
    float rw[128][WW];
    int   kh_a[64];
    int   kw_a[64];
};

__global__ void __launch_bounds__(256, 2) flash7_kernel() {
    extern __shared__ char raw[];
    F7Smem& s = *reinterpret_cast<F7Smem*>(raw);

    const int bh = blockIdx.y;
    const int qt0 = blockIdx.x;
    const int tid = threadIdx.x;
    const int wid = tid >> 5;
    const int lid = tid & 31;
    const int g = lid >> 2;
    const int t = lid & 3;
    const int wm = wid * 16;
    const int r0 = wm + g, r1 = wm + g + 8;

    const uint32_t qaddr = smem_u32(s.qs);
    const uint32_t kaddr = smem_u32(s.kt);
    const uint32_t vaddr = smem_u32(s.vs);
    const uint32_t rhaddr = smem_u32(s.rh);
    const uint32_t rwaddr = smem_u32(s.rw);

    // ---- prologue group: Q + rh + rw ----
#pragma unroll
    for (int it = 0; it < 4; it++) {
        int idx = it * 256 + tid;
        int r = idx >> 3, cc = idx & 7;
        int n = qt0 * 128 + r;
        const __half* src = g_q + (n < NN ? (size_t)(bh * NN + n) * HD + cc * 8 : 0);
        cpa16(qaddr + (uint32_t)(r * 144 + cc * 16), src, n < NN ? 16u : 0u);
    }
#pragma unroll
    for (int it = 0; it < 7; it++) {
        int idx = it * 256 + tid;
        int r = idx / 14, cc = idx % 14;
        int n = qt0 * 128 + r;
        const float* src = g_relh + (n < NN ? (size_t)(bh * NN + n) * HH + cc * 4 : 0);
        cpa16(rhaddr + (uint32_t)(r * HH + cc * 4) * 4, src, n < NN ? 16u : 0u);
    }
#pragma unroll
    for (int it = 0; it < 4; it++) {
        int idx = it * 256 + tid;
        if (idx < 128 * 7) {
            int r = idx / 7, cc = idx % 7;
            int n = qt0 * 128 + r;
            const float* src = g_relw + (n < NN ? (size_t)(bh * NN + n) * WW + cc * 4 : 0);
            cpa16(rwaddr + (uint32_t)(r * WW + cc * 4) * 4, src, n < NN ? 16u : 0u);
        }
    }
    CPA_COMMIT();

    // combined K+V issue for one tile into buffer j&1
    auto issueKV = [&](int j) {
        const int kb = j * 64;
        const uint32_t ka = kaddr + (uint32_t)((j & 1) * 64 * 144);
        const uint32_t va = vaddr + (uint32_t)((j & 1) * 64 * 144);
#pragma unroll
        for (int it = 0; it < 2; it++) {
            int idx = it * 256 + tid;
            int r = idx >> 3, cc = idx & 7;
            int kn = kb + r;
            bool ok = kn < NN;
            const __half* src = g_k + (ok ? (size_t)(bh * NN + kn) * HD + cc * 8 : 0);
            cpa16(ka + (uint32_t)(r * 144 + cc * 16), src, ok ? 16u : 0u);
        }
#pragma unroll
        for (int it = 0; it < 2; it++) {
            int idx = it * 256 + tid;
            int r = idx >> 3, cc = idx & 7;
            bool ok = (kb + cc * 8 + 8) <= NN;
            const __half* src = g_vt + (ok ? (size_t)(bh * HD + r) * NN + kb + cc * 8 : 0);
            cpa16(va + (uint32_t)(r * 144 + cc * 16), src, ok ? 16u : 0u);
        }
        CPA_COMMIT();
    };

    issueKV(0);
    issueKV(1);

    float acc[8][4];
#pragma unroll
    for (int ni = 0; ni < 8; ni++)
#pragma unroll
        for (int e = 0; e < 4; e++) acc[ni][e] = 0.f;
    float rowm0 = -1e30f, rowm1 = -1e30f;
    float rowl0 = 0.f, rowl1 = 0.f;

    for (int kt2 = 0; kt2 < 25; kt2++) {
        const int kbase = kt2 * 64;
        const int p = kt2 & 1;

        if (kt2 < 24) CPA_WAIT1(); else CPA_WAIT0();
        // tile kt2's K/V resident; prior iter's readers of kh_a done
        if (tid < 64) {
            int kn = kbase + tid;
            s.kh_a[tid] = (kn < NN) ? kn / WW : -1;
            s.kw_a[tid] = (kn < NN) ? kn % WW : 0;
        }
        __syncthreads();   // (1) K/V + kh_a visible

        const char* ktp = (const char*)s.kt[p];
        const char* vsp = (const char*)s.vs[p];

        // ---- QK^T mma ----
        float c[8][4];
#pragma unroll
        for (int ni = 0; ni < 8; ni++)
#pragma unroll
            for (int e = 0; e < 4; e++) c[ni][e] = 0.f;
#pragma unroll
        for (int kc = 0; kc < 4; kc++) {
            const int qo = kc * 32 + t * 8;
            uint2 v0 = *(const uint2*)((const char*)s.qs + r0 * 144 + qo);
            uint2 v1 = *(const uint2*)((const char*)s.qs + r1 * 144 + qo);
            uint32_t a[4] = {v0.x, v1.x, v0.y, v1.y};
#pragma unroll
            for (int ni = 0; ni < 8; ni++) {
                uint2 u = *(const uint2*)(ktp + (ni * 8 + g) * 144 + qo);
                uint32_t b[2] = {u.x, u.y};
                mma_f16(c[ni], a, b);
            }
        }
        // ---- bias + mask ----
#pragma unroll
        for (int ni = 0; ni < 8; ni++) {
            int c0l = ni * 8 + 2 * t, c1l = c0l + 1;
            int kh0 = s.kh_a[c0l], kw0 = s.kw_a[c0l];
            int kh1 = s.kh_a[c1l], kw1 = s.kw_a[c1l];
            if (kh0 >= 0) {
                c[ni][0] += s.rh[r0][kh0] + s.rw[r0][kw0];
                c[ni][2] += s.rh[r1][kh0] + s.rw[r1][kw0];
            } else { c[ni][0] = -1e30f; c[ni][2] = -1e30f; }
            if (kh1 >= 0) {
                c[ni][1] += s.rh[r0][kh1] + s.rw[r0][kw1];
                c[ni][3] += s.rh[r1][kh1] + s.rw[r1][kw1];
            } else { c[ni][1] = -1e30f; c[ni][3] = -1e30f; }
        }

        // ---- in-warp softmax ----
        float tm0 = -1e30f, tm1 = -1e30f;
#pragma unroll
        for (int ni = 0; ni < 8; ni++) {
            tm0 = fmaxf(tm0, fmaxf(c[ni][0], c[ni][1]));
            tm1 = fmaxf(tm1, fmaxf(c[ni][2], c[ni][3]));
        }
        tm0 = fmaxf(tm0, __shfl_xor_sync(0xffffffffu, tm0, 1));
        tm0 = fmaxf(tm0, __shfl_xor_sync(0xffffffffu, tm0, 2));
        tm1 = fmaxf(tm1, __shfl_xor_sync(0xffffffffu, tm1, 1));
        tm1 = fmaxf(tm1, __shfl_xor_sync(0xffffffffu, tm1, 2));

        float mn0 = fmaxf(rowm0, tm0), mn1 = fmaxf(rowm1, tm1);
        float fac0 = __expf(rowm0 - mn0), fac1 = __expf(rowm1 - mn1);
        float ts0 = 0.f, ts1 = 0.f;
#pragma unroll
        for (int ni = 0; ni < 8; ni++) {
            c[ni][0] = __expf(c[ni][0] - mn0);
            c[ni][1] = __expf(c[ni][1] - mn0);
            c[ni][2] = __expf(c[ni][2] - mn1);
            c[ni][3] = __expf(c[ni][3] - mn1);
            ts0 += c[ni][0] + c[ni][1];
            ts1 += c[ni][2] + c[ni][3];
        }
        ts0 += __shfl_xor_sync(0xffffffffu, ts0, 1);
        ts0 += __shfl_xor_sync(0xffffffffu, ts0, 2);
        ts1 += __shfl_xor_sync(0xffffffffu, ts1, 1);
        ts1 += __shfl_xor_sync(0xffffffffu, ts1, 2);
        rowl0 = rowl0 * fac0 + ts0;
        rowl1 = rowl1 * fac1 + ts1;
        rowm0 = mn0; rowm1 = mn1;

#pragma unroll
        for (int ni = 0; ni < 8; ni++) {
            acc[ni][0] *= fac0; acc[ni][1] *= fac0;
            acc[ni][2] *= fac1; acc[ni][3] *= fac1;
        }

        // ---- P @ V: pack P frags to fp16, V from transposed tile ----
#pragma unroll
        for (int kc = 0; kc < 4; kc++) {
            uint32_t a[4];
            a[0] = packh2(c[2 * kc][0],     c[2 * kc][1]);
            a[1] = packh2(c[2 * kc][2],     c[2 * kc][3]);
            a[2] = packh2(c[2 * kc + 1][0], c[2 * kc + 1][1]);
            a[3] = packh2(c[2 * kc + 1][2], c[2 * kc + 1][3]);
            const int vo = kc * 32 + t * 8;
#pragma unroll
            for (int ni = 0; ni < 8; ni++) {
                uint2 u = *(const uint2*)(vsp + (ni * 8 + g) * 144 + vo);
                uint32_t b[2] = {u.x, u.y};
                mma_f16(acc[ni], a, b);
            }
        }

        __syncthreads();   // (2) all readers of buffer p done
        if (kt2 + 2 < 25) issueKV(kt2 + 2);
    }

    // ---- normalize + store g_ao (fp16, k-permuted) ----
    const int b = bh >> 4;
    const int head = bh & 15;
    const int n0g = qt0 * 128 + r0;
    const int n1g = qt0 * 128 + r1;
    float li0 = 1.f / rowl0;
    float li1 = 1.f / rowl1;
#pragma unroll
    for (int ni = 0; ni < 8; ni++) {
        int col = head * HD + ni * 8 + 2 * t;
        int colp = (col & ~15) + posj((col & 15) >> 1) * 2;
        if (n0g < NN)
            *(__half2*)&g_ao[(size_t)(b * NN + n0g) * CD + colp] =
                __floats2half2_rn(acc[ni][0] * li0, acc[ni][1] * li0);
        if (n1g < NN)
            *(__half2*)&g_ao[(size_t)(b * NN + n1g) * CD + colp] =
                __floats2half2_rn(acc[ni][2] * li1, acc[ni][3] * li1);
    }
}

// ---------------- launch -----------------------------------------------------
extern "C" void kernel_launch(void* const* d_in, const int* in_sizes, int n_in,
                              void* d_out, int out_size) {
    const float* hidden = (const float*)d_in[0];
    const float* qkv_w  = (const float*)d_in[1];
    const float* qkv_b  = (const float*)d_in[2];
    const float* proj_w = (const float*)d_in[3];
    const float* proj_b = (const float*)d_in[4];
    const float* rph    = (const float*)d_in[5];
    const float* rpw    = (const float*)d_in[6];
    float* out = (float*)d_out;

    cudaFuncSetAttribute(flash7_kernel, cudaFuncAttributeMaxDynamicSharedMemorySize,
                         (int)sizeof(F7Smem));
    cudaFuncSetAttribute(mm_cp<0>, cudaFuncAttributeMaxDynamicSharedMemorySize, MM_SMEM);
    cudaFuncSetAttribute(mm_cp<1>, cudaFuncAttributeMaxDynamicSharedMemorySize, MM_SMEM);

    __half* d_hp;  cudaGetSymbolAddress((void**)&d_hp,  g_hp);
    __half* d_wp;  cudaGetSymbolAddress((void**)&d_wp,  g_wp);
    __half* d_pwp; cudaGetSymbolAddress((void**)&d_pwp, g_pwp);

    prep_kernel<<<(BN * CD / 16 + 255) / 256, 256>>>(hidden, d_hp, BN * CD / 16);
    prep_kernel<<<(3 * CD * CD / 16 + 255) / 256, 256>>>(qkv_w, d_wp, 3 * CD * CD / 16);
    prep_kernel<<<(CD * CD / 16 + 255) / 256, 256>>>(proj_w, d_pwp, CD * CD / 16);

    // QKV: [6272,3072] = hidden . qkv_w^T
    mm_cp<0><<<dim3(3 * CD / 128, (BN + 255) / 256), 256, MM_SMEM>>>(qkv_b, nullptr);

    relpos_kernel<<<dim3(HH, BHN), 256>>>(rph, rpw);

    flash7_kernel<<<dim3((NN + 127) / 128, BHN), 256, sizeof(F7Smem)>>>();

    // proj: [6272,1024] = g_ao . proj_w^T
    mm_cp<1><<<dim3(CD / 128, (BN + 255) / 256), 256, MM_SMEM>>>(proj_b, out);
}

// round 11
// speedup vs baseline: 5.5060x; 1.0332x over previous
#include <cuda_runtime.h>
#include <cuda_fp16.h>
#include <cstdint>

#define NH   16
#define HD   64
#define CD   1024
#define BB   4
#define HH   56
#define WW   28
#define NN   1568          // HH*WW
#define BHN  64            // BB*NH
#define BN   6272          // BB*NN
#define QSCALE 0.125f      // 64^-0.5
#define QS2   0.1803368801f // QSCALE * log2(e)

// ---------------- scratch (device globals; no allocations allowed) ----------
__device__ __half g_q[BHN * NN * HD];    // fp16, d-permuted, pre-scaled by QS2
__device__ __half g_k[BHN * NN * HD];    // fp16, d-permuted
__device__ __half g_vt[BHN * HD * NN];   // fp16, transposed [bh][d][n], n-permuted
__device__ float  g_relh[BHN * NN * HH]; // log2e units
__device__ float  g_relw[BHN * NN * WW]; // log2e units
__device__ __half g_ao[BN * CD];         // fp16, k-permuted, [B,N,heads,d]
__device__ __half g_hp[BN * CD];         // hidden prepped
__device__ __half g_wp[3 * CD * CD];     // qkv_w prepped
__device__ __half g_pwp[CD * CD];        // proj_w prepped

// ---------------- helpers ----------------------------------------------------
__device__ __forceinline__ uint32_t packh2(float a, float b) {
    __half2 h = __floats2half2_rn(a, b);
    return *reinterpret_cast<uint32_t*>(&h);
}

__device__ __forceinline__ void mma_f16(float* c, const uint32_t* a, const uint32_t* b) {
    asm volatile(
        "mma.sync.aligned.m16n8k16.row.col.f32.f16.f16.f32 "
        "{%0,%1,%2,%3}, {%4,%5,%6,%7}, {%8,%9}, {%0,%1,%2,%3};"
        : "+f"(c[0]), "+f"(c[1]), "+f"(c[2]), "+f"(c[3])
        : "r"(a[0]), "r"(a[1]), "r"(a[2]), "r"(a[3]), "r"(b[0]), "r"(b[1]));
}

__device__ __forceinline__ uint32_t smem_u32(const void* p) {
    uint32_t a;
    asm("{ .reg .u64 t; cvta.to.shared.u64 t, %1; cvt.u32.u64 %0, t; }"
        : "=r"(a) : "l"(p));
    return a;
}

__device__ __forceinline__ void cpa16(uint32_t dst, const void* src, uint32_t srcsize) {
    asm volatile("cp.async.cg.shared.global [%0], [%1], 16, %2;"
                 :: "r"(dst), "l"(src), "r"(srcsize) : "memory");
}
#define CPA_COMMIT() asm volatile("cp.async.commit_group;" ::: "memory")
#define CPA_WAIT0()  asm volatile("cp.async.wait_group 0;" ::: "memory")
#define CPA_WAIT1()  asm volatile("cp.async.wait_group 1;" ::: "memory")

// permuted position of half2-unit j within a 16-half group
__device__ __forceinline__ int posj(int j) { return (j < 4) ? 2 * j : 2 * j - 7; }
// permuted half-index of key n within its 16-group
__device__ __forceinline__ int permn(int n) {
    int u = (n >> 1) & 7;
    return (n & ~15) | (posj(u) << 1) | (n & 1);
}

// ---------------- prep: f32 -> fp16, half2-unit interleave per 16 ------------
#define PREP_N1 (BN * CD / 16)
#define PREP_N2 (3 * CD * CD / 16)
#define PREP_N3 (CD * CD / 16)

__global__ void __launch_bounds__(256) prep_all(const float* __restrict__ hidden,
                                                const float* __restrict__ w1,
                                                const float* __restrict__ w2) {
    int i = blockIdx.x * 256 + threadIdx.x;
    const float* src;
    __half* dst;
    if (i < PREP_N1) { src = hidden + (size_t)i * 16; dst = g_hp + (size_t)i * 16; }
    else if (i < PREP_N1 + PREP_N2) {
        int j = i - PREP_N1; src = w1 + (size_t)j * 16; dst = g_wp + (size_t)j * 16;
    } else if (i < PREP_N1 + PREP_N2 + PREP_N3) {
        int j = i - PREP_N1 - PREP_N2; src = w2 + (size_t)j * 16; dst = g_pwp + (size_t)j * 16;
    } else return;
    const float4* s = (const float4*)src;
    float4 A = s[0], B = s[1], C = s[2], D = s[3];
    uint4* d = (uint4*)dst;
    d[0] = make_uint4(packh2(A.x, A.y), packh2(C.x, C.y),
                      packh2(A.z, A.w), packh2(C.z, C.w));
    d[1] = make_uint4(packh2(B.x, B.y), packh2(D.x, D.y),
                      packh2(B.z, B.w), packh2(D.z, D.w));
}

// ================== cp.async 3-stage FP16 GEMM, 256x128 tile, BK=64 ==========
#define ATSZB (256 * 128)      // A tile bytes
#define BTSZB (128 * 128)
#define STGB  (ATSZB + BTSZB)  // 49152
#define MM_SMEM (3 * STGB)

template <int MODE>
__global__ void __launch_bounds__(256, 1) mm_cp(const float* __restrict__ bias,
                                                float* __restrict__ Cout) {
    extern __shared__ char smemc[];
    uint32_t sb = smem_u32(smemc);
    const __half* A  = (MODE == 0) ? g_hp : g_ao;
    const __half* Bm = (MODE == 0) ? g_wp : g_pwp;

    const int tid = threadIdx.x;
    const int wid = tid >> 5;
    const int lid = tid & 31;
    const int g = lid >> 2;
    const int t = lid & 3;
    const int m0 = blockIdx.y * 256;
    const int n0 = blockIdx.x * 128;
    const int wm = (wid & 3) * 64;
    const int wn = (wid >> 2) * 64;

    float acc[4][8][4];
#pragma unroll
    for (int mi = 0; mi < 4; mi++)
#pragma unroll
        for (int ni = 0; ni < 8; ni++)
#pragma unroll
            for (int e = 0; e < 4; e++) acc[mi][ni][e] = 0.f;

    const int lr = tid >> 3;
    const int lq = tid & 7;
    const uint32_t ldst = (uint32_t)(lr * 128 + ((lq ^ (lr & 7)) << 4));

    auto issue = [&](int kt) {
        const int st = kt % 3;
        const int k0 = kt * 64;
        uint32_t ab = sb + (uint32_t)st * STGB;
        uint32_t bb = ab + ATSZB;
#pragma unroll
        for (int it = 0; it < 8; it++) {
            int r = lr + it * 32;
            int gr = m0 + r;
            bool ok = gr < BN;
            cpa16(ab + ldst + (uint32_t)(it * 32 * 128),
                  A + (ok ? (size_t)gr * CD + k0 + lq * 8 : 0), ok ? 16u : 0u);
        }
#pragma unroll
        for (int it = 0; it < 4; it++) {
            int r = lr + it * 32;
            cpa16(bb + ldst + (uint32_t)(it * 32 * 128),
                  Bm + (size_t)(n0 + r) * CD + k0 + lq * 8, 16);
        }
        CPA_COMMIT();
    };

    issue(0); issue(1);
    for (int kt = 0; kt < 16; kt++) {
        if (kt < 15) CPA_WAIT1(); else CPA_WAIT0();
        __syncthreads();
        if (kt + 2 < 16) issue(kt + 2);

        const char* As = smemc + (size_t)(kt % 3) * STGB;
        const char* Bs = As + ATSZB;

#pragma unroll
        for (int kc = 0; kc < 4; kc++) {
            const int coff = (((kc * 2 + (t >> 1)) ^ g) << 4) + ((t & 1) << 3);
            uint32_t a[4][4];
            uint32_t b[8][2];
#pragma unroll
            for (int mi = 0; mi < 4; mi++) {
                uint2 v0 = *(const uint2*)(As + (wm + mi * 16 + g) * 128 + coff);
                uint2 v1 = *(const uint2*)(As + (wm + mi * 16 + g + 8) * 128 + coff);
                a[mi][0] = v0.x; a[mi][1] = v1.x; a[mi][2] = v0.y; a[mi][3] = v1.y;
            }
#pragma unroll
            for (int ni = 0; ni < 8; ni++) {
                uint2 u = *(const uint2*)(Bs + (wn + ni * 8 + g) * 128 + coff);
                b[ni][0] = u.x; b[ni][1] = u.y;
            }
#pragma unroll
            for (int mi = 0; mi < 4; mi++)
#pragma unroll
                for (int ni = 0; ni < 8; ni++) mma_f16(acc[mi][ni], a[mi], b[ni]);
        }
    }

#pragma unroll
    for (int mi = 0; mi < 4; mi++) {
        int mr0 = m0 + wm + mi * 16 + g;
        int mr1 = mr0 + 8;
        bool ok0 = mr0 < BN, ok1 = mr1 < BN;
#pragma unroll
        for (int ni = 0; ni < 8; ni++) {
            int jj = n0 + wn + ni * 8 + 2 * t;
            float b0 = bias[jj], b1 = bias[jj + 1];
            float v00 = acc[mi][ni][0] + b0, v01 = acc[mi][ni][1] + b1;
            float v10 = acc[mi][ni][2] + b0, v11 = acc[mi][ni][3] + b1;
            if (MODE == 0) {
                int tsel = jj >> 10;
                int rr = jj & 1023;
                int head = rr >> 6;
                int d = rr & 63;
                int dperm = (d & ~15) + posj((d & 15) >> 1) * 2;
                if (ok0) {
                    int b_ = mr0 / NN, n_ = mr0 - b_ * NN;
                    int bh = b_ * NH + head;
                    if (tsel == 0) {
                        *(__half2*)&g_q[((size_t)bh * NN + n_) * HD + dperm] =
                            __floats2half2_rn(v00 * QS2, v01 * QS2);
                    } else if (tsel == 1) {
                        *(__half2*)&g_k[((size_t)bh * NN + n_) * HD + dperm] =
                            __floats2half2_rn(v00, v01);
                    } else {
                        int np = permn(n_);
                        g_vt[((size_t)bh * HD + d) * NN + np]     = __float2half_rn(v00);
                        g_vt[((size_t)bh * HD + d + 1) * NN + np] = __float2half_rn(v01);
                    }
                }
                if (ok1) {
                    int b_ = mr1 / NN, n_ = mr1 - b_ * NN;
                    int bh = b_ * NH + head;
                    if (tsel == 0) {
                        *(__half2*)&g_q[((size_t)bh * NN + n_) * HD + dperm] =
                            __floats2half2_rn(v10 * QS2, v11 * QS2);
                    } else if (tsel == 1) {
                        *(__half2*)&g_k[((size_t)bh * NN + n_) * HD + dperm] =
                            __floats2half2_rn(v10, v11);
                    } else {
                        int np = permn(n_);
                        g_vt[((size_t)bh * HD + d) * NN + np]     = __float2half_rn(v10);
                        g_vt[((size_t)bh * HD + d + 1) * NN + np] = __float2half_rn(v11);
                    }
                }
            } else {
                if (ok0) { float2 o = {v00, v01}; *(float2*)&Cout[(size_t)mr0 * CD + jj] = o; }
                if (ok1) { float2 o = {v10, v11}; *(float2*)&Cout[(size_t)mr1 * CD + jj] = o; }
            }
        }
    }
}

// ---------------- rel-pos bias via FP16 mma -----------------------------------
// g_q carries QS2 = QSCALE*log2e; multiplying by 8 leaves rel_* in log2e units.
__global__ void __launch_bounds__(256) relpos_kernel(const float* __restrict__ rph,
                                                     const float* __restrict__ rpw) {
    __shared__ __align__(16) __half qp[32 * 72];
    __shared__ __align__(16) __half Bp[112 * 72];
    __shared__ float outw[32 * 60];

    const int h = blockIdx.x;
    const int bh = blockIdx.y;
    const int tid = threadIdx.x;
    const int wid = tid >> 5;
    const int lid = tid & 31;
    const int g = lid >> 2;
    const int t = lid & 3;

    {
        int r = tid >> 3, cc = tid & 7;
        uint4 v = make_uint4(0, 0, 0, 0);
        if (r < WW)
            v = *(const uint4*)&g_q[((size_t)bh * NN + h * WW + r) * HD + cc * 8];
        *(uint4*)&qp[r * 72 + cc * 8] = v;
    }
#pragma unroll
    for (int it = 0; it < 2; it++) {
        int idx = it * 256 + tid;
        if (idx < 448) {
            int r = idx >> 2, grp = idx & 3;
            float4 A = {0,0,0,0}, B = {0,0,0,0}, C = {0,0,0,0}, D = {0,0,0,0};
            const float* sp = nullptr;
            if (r < 56)       sp = rph + (size_t)(h + 55 - r) * HD + grp * 16;
            else if (r < 111) sp = rpw + (size_t)(r - 56) * HD + grp * 16;
            if (sp) { A = ((const float4*)sp)[0]; B = ((const float4*)sp)[1];
                      C = ((const float4*)sp)[2]; D = ((const float4*)sp)[3]; }
            *(uint4*)&Bp[r * 72 + grp * 16] =
                make_uint4(packh2(A.x, A.y), packh2(C.x, C.y),
                           packh2(A.z, A.w), packh2(C.z, C.w));
            *(uint4*)&Bp[r * 72 + grp * 16 + 8] =
                make_uint4(packh2(B.x, B.y), packh2(D.x, D.y),
                           packh2(B.z, B.w), packh2(D.z, D.w));
        }
    }
    __syncthreads();

    for (int ti = wid; ti < 14; ti += 8) {
        float c[2][4];
#pragma unroll
        for (int mi = 0; mi < 2; mi++)
#pragma unroll
            for (int e = 0; e < 4; e++) c[mi][e] = 0.f;
#pragma unroll
        for (int kc = 0; kc < 4; kc++) {
            int qo = kc * 16 + t * 4;
            uint2 v0 = *(const uint2*)&qp[g * 72 + qo];
            uint2 v1 = *(const uint2*)&qp[(g + 8) * 72 + qo];
            uint2 v2 = *(const uint2*)&qp[(16 + g) * 72 + qo];
            uint2 v3 = *(const uint2*)&qp[(24 + g) * 72 + qo];
            uint32_t a0[4] = {v0.x, v1.x, v0.y, v1.y};
            uint32_t a1[4] = {v2.x, v3.x, v2.y, v3.y};
            uint2 u = *(const uint2*)&Bp[(ti * 8 + g) * 72 + qo];
            uint32_t b[2] = {u.x, u.y};
            mma_f16(c[0], a0, b);
            mma_f16(c[1], a1, b);
        }
        if (ti < 7) {
            int kh0 = ti * 8 + 2 * t, kh1 = kh0 + 1;
            size_t nb = (size_t)(bh * NN) + h * WW;
            g_relh[(nb + g) * HH + kh0]      = c[0][0] * 8.f;
            g_relh[(nb + g) * HH + kh1]      = c[0][1] * 8.f;
            g_relh[(nb + g + 8) * HH + kh0]  = c[0][2] * 8.f;
            g_relh[(nb + g + 8) * HH + kh1]  = c[0][3] * 8.f;
            g_relh[(nb + 16 + g) * HH + kh0] = c[1][0] * 8.f;
            g_relh[(nb + 16 + g) * HH + kh1] = c[1][1] * 8.f;
            if (g < 4) {
                g_relh[(nb + 24 + g) * HH + kh0] = c[1][2] * 8.f;
                g_relh[(nb + 24 + g) * HH + kh1] = c[1][3] * 8.f;
            }
        } else {
            int cb = (ti - 7) * 8 + 2 * t;
            outw[g * 60 + cb] = c[0][0];        outw[g * 60 + cb + 1] = c[0][1];
            outw[(g + 8) * 60 + cb] = c[0][2];  outw[(g + 8) * 60 + cb + 1] = c[0][3];
            outw[(16 + g) * 60 + cb] = c[1][0]; outw[(16 + g) * 60 + cb + 1] = c[1][1];
            outw[(24 + g) * 60 + cb] = c[1][2]; outw[(24 + g) * 60 + cb + 1] = c[1][3];
        }
    }
    __syncthreads();

    for (int idx = tid; idx < WW * WW; idx += 256) {
        int w = idx / WW, kw = idx - w * WW;
        g_relw[((size_t)(bh * NN) + h * WW + w) * WW + kw] =
            outw[w * 60 + (w - kw + 27)] * 8.f;
    }
}

// ---------------- flash v8: exp2 softmax + packed kh/kw table ----------------
#define FPH 72   // halves pitch (144B rows)
#define NKEY 1600

struct F8Smem {
    __align__(16) __half qs[128 * FPH];
    __align__(16) __half kt[2][64 * FPH];
    __align__(16) __half vs[2][64 * FPH];   // transposed: row=d, col=keys (perm)
    float rh[128][HH];
    float rw[128][WW];
    __align__(4) uint16_t khkw[NKEY];       // (kh<<8)|kw ; kh=0xFF invalid
};

__global__ void __launch_bounds__(256, 2) flash8_kernel() {
    extern __shared__ char raw[];
    F8Smem& s = *reinterpret_cast<F8Smem*>(raw);

    const int bh = blockIdx.y;
    const int qt0 = blockIdx.x;
    const int tid = threadIdx.x;
    const int wid = tid >> 5;
    const int lid = tid & 31;
    const int g = lid >> 2;
    const int t = lid & 3;
    const int wm = wid * 16;
    const int r0 = wm + g, r1 = wm + g + 8;

    const uint32_t qaddr = smem_u32(s.qs);
    const uint32_t kaddr = smem_u32(s.kt);
    const uint32_t vaddr = smem_u32(s.vs);
    const uint32_t rhaddr = smem_u32(s.rh);
    const uint32_t rwaddr = smem_u32(s.rw);

    // ---- prologue group: Q + rh + rw; khkw table ----
#pragma unroll
    for (int it = 0; it < 4; it++) {
        int idx = it * 256 + tid;
        int r = idx >> 3, cc = idx & 7;
        int n = qt0 * 128 + r;
        const __half* src = g_q + (n < NN ? (size_t)(bh * NN + n) * HD + cc * 8 : 0);
        cpa16(qaddr + (uint32_t)(r * 144 + cc * 16), src, n < NN ? 16u : 0u);
    }
#pragma unroll
    for (int it = 0; it < 7; it++) {
        int idx = it * 256 + tid;
        int r = idx / 14, cc = idx % 14;
        int n = qt0 * 128 + r;
        const float* src = g_relh + (n < NN ? (size_t)(bh * NN + n) * HH + cc * 4 : 0);
        cpa16(rhaddr + (uint32_t)(r * HH + cc * 4) * 4, src, n < NN ? 16u : 0u);
    }
#pragma unroll
    for (int it = 0; it < 4; it++) {
        int idx = it * 256 + tid;
        if (idx < 128 * 7) {
            int r = idx / 7, cc = idx % 7;
            int n = qt0 * 128 + r;
            const float* src = g_relw + (n < NN ? (size_t)(bh * NN + n) * WW + cc * 4 : 0);
            cpa16(rwaddr + (uint32_t)(r * WW + cc * 4) * 4, src, n < NN ? 16u : 0u);
        }
    }
    CPA_COMMIT();
#pragma unroll
    for (int it = 0; it < 7; it++) {
        int kn = it * 256 + tid;
        if (kn < NKEY) {
            int kh = (kn < NN) ? kn / WW : 0xFF;
            int kw = (kn < NN) ? kn - (kn / WW) * WW : 0;
            s.khkw[kn] = (uint16_t)((kh << 8) | kw);
        }
    }

    // combined K+V issue for one tile into buffer j&1
    auto issueKV = [&](int j) {
        const int kb = j * 64;
        const uint32_t ka = kaddr + (uint32_t)((j & 1) * 64 * 144);
        const uint32_t va = vaddr + (uint32_t)((j & 1) * 64 * 144);
#pragma unroll
        for (int it = 0; it < 2; it++) {
            int idx = it * 256 + tid;
            int r = idx >> 3, cc = idx & 7;
            int kn = kb + r;
            bool ok = kn < NN;
            const __half* src = g_k + (ok ? (size_t)(bh * NN + kn) * HD + cc * 8 : 0);
            cpa16(ka + (uint32_t)(r * 144 + cc * 16), src, ok ? 16u : 0u);
        }
#pragma unroll
        for (int it = 0; it < 2; it++) {
            int idx = it * 256 + tid;
            int r = idx >> 3, cc = idx & 7;
            bool ok = (kb + cc * 8 + 8) <= NN;
            const __half* src = g_vt + (ok ? (size_t)(bh * HD + r) * NN + kb + cc * 8 : 0);
            cpa16(va + (uint32_t)(r * 144 + cc * 16), src, ok ? 16u : 0u);
        }
        CPA_COMMIT();
    };

    issueKV(0);
    issueKV(1);

    float acc[8][4];
#pragma unroll
    for (int ni = 0; ni < 8; ni++)
#pragma unroll
        for (int e = 0; e < 4; e++) acc[ni][e] = 0.f;
    float rowm0 = -1e30f, rowm1 = -1e30f;
    float rowl0 = 0.f, rowl1 = 0.f;

    const uint32_t* kk32 = (const uint32_t*)s.khkw;

    for (int kt2 = 0; kt2 < 25; kt2++) {
        const int kbase = kt2 * 64;
        const int p = kt2 & 1;

        if (kt2 < 24) CPA_WAIT1(); else CPA_WAIT0();
        __syncthreads();   // (1) K/V (+ prologue tables on iter 0) visible

        const char* ktp = (const char*)s.kt[p];
        const char* vsp = (const char*)s.vs[p];

        // ---- QK^T mma ----
        float c[8][4];
#pragma unroll
        for (int ni = 0; ni < 8; ni++)
#pragma unroll
            for (int e = 0; e < 4; e++) c[ni][e] = 0.f;
#pragma unroll
        for (int kc = 0; kc < 4; kc++) {
            const int qo = kc * 32 + t * 8;
            uint2 v0 = *(const uint2*)((const char*)s.qs + r0 * 144 + qo);
            uint2 v1 = *(const uint2*)((const char*)s.qs + r1 * 144 + qo);
            uint32_t a[4] = {v0.x, v1.x, v0.y, v1.y};
#pragma unroll
            for (int ni = 0; ni < 8; ni++) {
                uint2 u = *(const uint2*)(ktp + (ni * 8 + g) * 144 + qo);
                uint32_t b[2] = {u.x, u.y};
                mma_f16(c[ni], a, b);
            }
        }
        // ---- bias + mask (packed table: 1 LDS.32 per ni) ----
#pragma unroll
        for (int ni = 0; ni < 8; ni++) {
            int key0 = kbase + ni * 8 + 2 * t;      // even
            uint32_t w = kk32[key0 >> 1];
            int kh0 = (w >> 8) & 0xFF, kw0 = w & 0xFF;
            int kh1 = w >> 24,         kw1 = (w >> 16) & 0xFF;
            if (kh0 != 0xFF) {
                c[ni][0] += s.rh[r0][kh0] + s.rw[r0][kw0];
                c[ni][2] += s.rh[r1][kh0] + s.rw[r1][kw0];
            } else { c[ni][0] = -1e30f; c[ni][2] = -1e30f; }
            if (kh1 != 0xFF) {
                c[ni][1] += s.rh[r0][kh1] + s.rw[r0][kw1];
                c[ni][3] += s.rh[r1][kh1] + s.rw[r1][kw1];
            } else { c[ni][1] = -1e30f; c[ni][3] = -1e30f; }
        }

        // ---- in-warp softmax (log2 units -> exp2) ----
        float tm0 = -1e30f, tm1 = -1e30f;
#pragma unroll
        for (int ni = 0; ni < 8; ni++) {
            tm0 = fmaxf(tm0, fmaxf(c[ni][0], c[ni][1]));
            tm1 = fmaxf(tm1, fmaxf(c[ni][2], c[ni][3]));
        }
        tm0 = fmaxf(tm0, __shfl_xor_sync(0xffffffffu, tm0, 1));
        tm0 = fmaxf(tm0, __shfl_xor_sync(0xffffffffu, tm0, 2));
        tm1 = fmaxf(tm1, __shfl_xor_sync(0xffffffffu, tm1, 1));
        tm1 = fmaxf(tm1, __shfl_xor_sync(0xffffffffu, tm1, 2));

        float mn0 = fmaxf(rowm0, tm0), mn1 = fmaxf(rowm1, tm1);
        float fac0 = exp2f(rowm0 - mn0), fac1 = exp2f(rowm1 - mn1);
        float ts0 = 0.f, ts1 = 0.f;
#pragma unroll
        for (int ni = 0; ni < 8; ni++) {
            c[ni][0] = exp2f(c[ni][0] - mn0);
            c[ni][1] = exp2f(c[ni][1] - mn0);
            c[ni][2] = exp2f(c[ni][2] - mn1);
            c[ni][3] = exp2f(c[ni][3] - mn1);
            ts0 += c[ni][0] + c[ni][1];
            ts1 += c[ni][2] + c[ni][3];
        }
        ts0 += __shfl_xor_sync(0xffffffffu, ts0, 1);
        ts0 += __shfl_xor_sync(0xffffffffu, ts0, 2);
        ts1 += __shfl_xor_sync(0xffffffffu, ts1, 1);
        ts1 += __shfl_xor_sync(0xffffffffu, ts1, 2);
        rowl0 = rowl0 * fac0 + ts0;
        rowl1 = rowl1 * fac1 + ts1;
        rowm0 = mn0; rowm1 = mn1;

#pragma unroll
        for (int ni = 0; ni < 8; ni++) {
            acc[ni][0] *= fac0; acc[ni][1] *= fac0;
            acc[ni][2] *= fac1; acc[ni][3] *= fac1;
        }

        // ---- P @ V ----
#pragma unroll
        for (int kc = 0; kc < 4; kc++) {
            uint32_t a[4];
            a[0] = packh2(c[2 * kc][0],     c[2 * kc][1]);
            a[1] = packh2(c[2 * kc][2],     c[2 * kc][3]);
            a[2] = packh2(c[2 * kc + 1][0], c[2 * kc + 1][1]);
            a[3] = packh2(c[2 * kc + 1][2], c[2 * kc + 1][3]);
            const int vo = kc * 32 + t * 8;
#pragma unroll
            for (int ni = 0; ni < 8; ni++) {
                uint2 u = *(const uint2*)(vsp + (ni * 8 + g) * 144 + vo);
                uint32_t b[2] = {u.x, u.y};
                mma_f16(acc[ni], a, b);
            }
        }

        __syncthreads();   // (2) all readers of buffer p done
        if (kt2 + 2 < 25) issueKV(kt2 + 2);
    }

    // ---- normalize + store g_ao (fp16, k-permuted) ----
    const int b = bh >> 4;
    const int head = bh & 15;
    const int n0g = qt0 * 128 + r0;
    const int n1g = qt0 * 128 + r1;
    float li0 = 1.f / rowl0;
    float li1 = 1.f / rowl1;
#pragma unroll
    for (int ni = 0; ni < 8; ni++) {
        int col = head * HD + ni * 8 + 2 * t;
        int colp = (col & ~15) + posj((col & 15) >> 1) * 2;
        if (n0g < NN)
            *(__half2*)&g_ao[(size_t)(b * NN + n0g) * CD + colp] =
                __floats2half2_rn(acc[ni][0] * li0, acc[ni][1] * li0);
        if (n1g < NN)
            *(__half2*)&g_ao[(size_t)(b * NN + n1g) * CD + colp] =
                __floats2half2_rn(acc[ni][2] * li1, acc[ni][3] * li1);
    }
}

// ---------------- launch -----------------------------------------------------
extern "C" void kernel_launch(void* const* d_in, const int* in_sizes, int n_in,
                              void* d_out, int out_size) {
    const float* hidden = (const float*)d_in[0];
    const float* qkv_w  = (const float*)d_in[1];
    const float* qkv_b  = (const float*)d_in[2];
    const float* proj_w = (const float*)d_in[3];
    const float* proj_b = (const float*)d_in[4];
    const float* rph    = (const float*)d_in[5];
    const float* rpw    = (const float*)d_in[6];
    float* out = (float*)d_out;

    cudaFuncSetAttribute(flash8_kernel, cudaFuncAttributeMaxDynamicSharedMemorySize,
                         (int)sizeof(F8Smem));
    cudaFuncSetAttribute(mm_cp<0>, cudaFuncAttributeMaxDynamicSharedMemorySize, MM_SMEM);
    cudaFuncSetAttribute(mm_cp<1>, cudaFuncAttributeMaxDynamicSharedMemorySize, MM_SMEM);

    const int ptot = PREP_N1 + PREP_N2 + PREP_N3;
    prep_all<<<(ptot + 255) / 256, 256>>>(hidden, qkv_w, proj_w);

    // QKV: [6272,3072] = hidden . qkv_w^T
    mm_cp<0><<<dim3(3 * CD / 128, (BN + 255) / 256), 256, MM_SMEM>>>(qkv_b, nullptr);

    relpos_kernel<<<dim3(HH, BHN), 256>>>(rph, rpw);

    flash8_kernel<<<dim3((NN + 127) / 128, BHN), 256, sizeof(F8Smem)>>>();

    // proj: [6272,1024] = g_ao . proj_w^T
    mm_cp<1><<<dim3(CD / 128, (BN + 255) / 256), 256, MM_SMEM>>>(proj_b, out);
}

// round 12
// speedup vs baseline: 5.5500x; 1.0080x over previous
#include <cuda_runtime.h>
#include <cuda_fp16.h>
#include <cstdint>

#define NH   16
#define HD   64
#define CD   1024
#define BB   4
#define HH   56
#define WW   28
#define NN   1568          // HH*WW
#define BHN  64            // BB*NH
#define BN   6272          // BB*NN
#define QSCALE 0.125f      // 64^-0.5
#define QS2   0.1803368801f // QSCALE * log2(e)

// ---------------- scratch (device globals; no allocations allowed) ----------
__device__ __half g_q[BHN * NN * HD];    // fp16, d-permuted, pre-scaled by QS2
__device__ __half g_k[BHN * NN * HD];    // fp16, d-permuted
__device__ __half g_vt[BHN * HD * NN];   // fp16, transposed [bh][d][n], n-permuted
__device__ float  g_relh[BHN * NN * HH]; // log2e units
__device__ float  g_relw[BHN * NN * WW]; // log2e units
__device__ __half g_ao[BN * CD];         // fp16, k-permuted, [B,N,heads,d]
__device__ __half g_hp[BN * CD];         // hidden prepped
__device__ __half g_wp[3 * CD * CD];     // qkv_w prepped
__device__ __half g_pwp[CD * CD];        // proj_w prepped

// ---------------- helpers ----------------------------------------------------
__device__ __forceinline__ uint32_t packh2(float a, float b) {
    __half2 h = __floats2half2_rn(a, b);
    return *reinterpret_cast<uint32_t*>(&h);
}

__device__ __forceinline__ uint32_t h2exp2(uint32_t x) {
    uint32_t r;
    asm("ex2.approx.f16x2 %0, %1;" : "=r"(r) : "r"(x));
    return r;
}
__device__ __forceinline__ float fexp2(float x) {
    float r;
    asm("ex2.approx.ftz.f32 %0, %1;" : "=f"(r) : "f"(x));
    return r;
}

__device__ __forceinline__ void mma_f16(float* c, const uint32_t* a, const uint32_t* b) {
    asm volatile(
        "mma.sync.aligned.m16n8k16.row.col.f32.f16.f16.f32 "
        "{%0,%1,%2,%3}, {%4,%5,%6,%7}, {%8,%9}, {%0,%1,%2,%3};"
        : "+f"(c[0]), "+f"(c[1]), "+f"(c[2]), "+f"(c[3])
        : "r"(a[0]), "r"(a[1]), "r"(a[2]), "r"(a[3]), "r"(b[0]), "r"(b[1]));
}

__device__ __forceinline__ uint32_t smem_u32(const void* p) {
    uint32_t a;
    asm("{ .reg .u64 t; cvta.to.shared.u64 t, %1; cvt.u32.u64 %0, t; }"
        : "=r"(a) : "l"(p));
    return a;
}

__device__ __forceinline__ void cpa16(uint32_t dst, const void* src, uint32_t srcsize) {
    asm volatile("cp.async.cg.shared.global [%0], [%1], 16, %2;"
                 :: "r"(dst), "l"(src), "r"(srcsize) : "memory");
}
#define CPA_COMMIT() asm volatile("cp.async.commit_group;" ::: "memory")
#define CPA_WAIT0()  asm volatile("cp.async.wait_group 0;" ::: "memory")
#define CPA_WAIT1()  asm volatile("cp.async.wait_group 1;" ::: "memory")

// permuted position of half2-unit j within a 16-half group
__device__ __forceinline__ int posj(int j) { return (j < 4) ? 2 * j : 2 * j - 7; }
// permuted half-index of key n within its 16-group
__device__ __forceinline__ int permn(int n) {
    int u = (n >> 1) & 7;
    return (n & ~15) | (posj(u) << 1) | (n & 1);
}

// ---------------- prep: f32 -> fp16, half2-unit interleave per 16 ------------
#define PREP_N1 (BN * CD / 16)
#define PREP_N2 (3 * CD * CD / 16)
#define PREP_N3 (CD * CD / 16)

__global__ void __launch_bounds__(256) prep_all(const float* __restrict__ hidden,
                                                const float* __restrict__ w1,
                                                const float* __restrict__ w2) {
    int i = blockIdx.x * 256 + threadIdx.x;
    const float* src;
    __half* dst;
    if (i < PREP_N1) { src = hidden + (size_t)i * 16; dst = g_hp + (size_t)i * 16; }
    else if (i < PREP_N1 + PREP_N2) {
        int j = i - PREP_N1; src = w1 + (size_t)j * 16; dst = g_wp + (size_t)j * 16;
    } else if (i < PREP_N1 + PREP_N2 + PREP_N3) {
        int j = i - PREP_N1 - PREP_N2; src = w2 + (size_t)j * 16; dst = g_pwp + (size_t)j * 16;
    } else return;
    const float4* s = (const float4*)src;
    float4 A = s[0], B = s[1], C = s[2], D = s[3];
    uint4* d = (uint4*)dst;
    d[0] = make_uint4(packh2(A.x, A.y), packh2(C.x, C.y),
                      packh2(A.z, A.w), packh2(C.z, C.w));
    d[1] = make_uint4(packh2(B.x, B.y), packh2(D.x, D.y),
                      packh2(B.z, B.w), packh2(D.z, D.w));
}

// ================== cp.async 3-stage FP16 GEMM, 256x128 tile, BK=64 ==========
#define ATSZB (256 * 128)      // A tile bytes
#define BTSZB (128 * 128)
#define STGB  (ATSZB + BTSZB)  // 49152
#define MM_SMEM (3 * STGB)

template <int MODE>
__global__ void __launch_bounds__(256, 1) mm_cp(const float* __restrict__ bias,
                                                float* __restrict__ Cout) {
    extern __shared__ char smemc[];
    uint32_t sb = smem_u32(smemc);
    const __half* A  = (MODE == 0) ? g_hp : g_ao;
    const __half* Bm = (MODE == 0) ? g_wp : g_pwp;

    const int tid = threadIdx.x;
    const int wid = tid >> 5;
    const int lid = tid & 31;
    const int g = lid >> 2;
    const int t = lid & 3;
    const int m0 = blockIdx.y * 256;
    const int n0 = blockIdx.x * 128;
    const int wm = (wid & 3) * 64;
    const int wn = (wid >> 2) * 64;

    float acc[4][8][4];
#pragma unroll
    for (int mi = 0; mi < 4; mi++)
#pragma unroll
        for (int ni = 0; ni < 8; ni++)
#pragma unroll
            for (int e = 0; e < 4; e++) acc[mi][ni][e] = 0.f;

    const int lr = tid >> 3;
    const int lq = tid & 7;
    const uint32_t ldst = (uint32_t)(lr * 128 + ((lq ^ (lr & 7)) << 4));

    auto issue = [&](int kt) {
        const int st = kt % 3;
        const int k0 = kt * 64;
        uint32_t ab = sb + (uint32_t)st * STGB;
        uint32_t bb = ab + ATSZB;
#pragma unroll
        for (int it = 0; it < 8; it++) {
            int r = lr + it * 32;
            int gr = m0 + r;
            bool ok = gr < BN;
            cpa16(ab + ldst + (uint32_t)(it * 32 * 128),
                  A + (ok ? (size_t)gr * CD + k0 + lq * 8 : 0), ok ? 16u : 0u);
        }
#pragma unroll
        for (int it = 0; it < 4; it++) {
            int r = lr + it * 32;
            cpa16(bb + ldst + (uint32_t)(it * 32 * 128),
                  Bm + (size_t)(n0 + r) * CD + k0 + lq * 8, 16);
        }
        CPA_COMMIT();
    };

    issue(0); issue(1);
    for (int kt = 0; kt < 16; kt++) {
        if (kt < 15) CPA_WAIT1(); else CPA_WAIT0();
        __syncthreads();
        if (kt + 2 < 16) issue(kt + 2);

        const char* As = smemc + (size_t)(kt % 3) * STGB;
        const char* Bs = As + ATSZB;

#pragma unroll
        for (int kc = 0; kc < 4; kc++) {
            const int coff = (((kc * 2 + (t >> 1)) ^ g) << 4) + ((t & 1) << 3);
            uint32_t a[4][4];
            uint32_t b[8][2];
#pragma unroll
            for (int mi = 0; mi < 4; mi++) {
                uint2 v0 = *(const uint2*)(As + (wm + mi * 16 + g) * 128 + coff);
                uint2 v1 = *(const uint2*)(As + (wm + mi * 16 + g + 8) * 128 + coff);
                a[mi][0] = v0.x; a[mi][1] = v1.x; a[mi][2] = v0.y; a[mi][3] = v1.y;
            }
#pragma unroll
            for (int ni = 0; ni < 8; ni++) {
                uint2 u = *(const uint2*)(Bs + (wn + ni * 8 + g) * 128 + coff);
                b[ni][0] = u.x; b[ni][1] = u.y;
            }
#pragma unroll
            for (int mi = 0; mi < 4; mi++)
#pragma unroll
                for (int ni = 0; ni < 8; ni++) mma_f16(acc[mi][ni], a[mi], b[ni]);
        }
    }

#pragma unroll
    for (int mi = 0; mi < 4; mi++) {
        int mr0 = m0 + wm + mi * 16 + g;
        int mr1 = mr0 + 8;
        bool ok0 = mr0 < BN, ok1 = mr1 < BN;
#pragma unroll
        for (int ni = 0; ni < 8; ni++) {
            int jj = n0 + wn + ni * 8 + 2 * t;
            float b0 = bias[jj], b1 = bias[jj + 1];
            float v00 = acc[mi][ni][0] + b0, v01 = acc[mi][ni][1] + b1;
            float v10 = acc[mi][ni][2] + b0, v11 = acc[mi][ni][3] + b1;
            if (MODE == 0) {
                int tsel = jj >> 10;
                int rr = jj & 1023;
                int head = rr >> 6;
                int d = rr & 63;
                int dperm = (d & ~15) + posj((d & 15) >> 1) * 2;
                if (ok0) {
                    int b_ = mr0 / NN, n_ = mr0 - b_ * NN;
                    int bh = b_ * NH + head;
                    if (tsel == 0) {
                        *(__half2*)&g_q[((size_t)bh * NN + n_) * HD + dperm] =
                            __floats2half2_rn(v00 * QS2, v01 * QS2);
                    } else if (tsel == 1) {
                        *(__half2*)&g_k[((size_t)bh * NN + n_) * HD + dperm] =
                            __floats2half2_rn(v00, v01);
                    } else {
                        int np = permn(n_);
                        g_vt[((size_t)bh * HD + d) * NN + np]     = __float2half_rn(v00);
                        g_vt[((size_t)bh * HD + d + 1) * NN + np] = __float2half_rn(v01);
                    }
                }
                if (ok1) {
                    int b_ = mr1 / NN, n_ = mr1 - b_ * NN;
                    int bh = b_ * NH + head;
                    if (tsel == 0) {
                        *(__half2*)&g_q[((size_t)bh * NN + n_) * HD + dperm] =
                            __floats2half2_rn(v10 * QS2, v11 * QS2);
                    } else if (tsel == 1) {
                        *(__half2*)&g_k[((size_t)bh * NN + n_) * HD + dperm] =
                            __floats2half2_rn(v10, v11);
                    } else {
                        int np = permn(n_);
                        g_vt[((size_t)bh * HD + d) * NN + np]     = __float2half_rn(v10);
                        g_vt[((size_t)bh * HD + d + 1) * NN + np] = __float2half_rn(v11);
                    }
                }
            } else {
                if (ok0) { float2 o = {v00, v01}; *(float2*)&Cout[(size_t)mr0 * CD + jj] = o; }
                if (ok1) { float2 o = {v10, v11}; *(float2*)&Cout[(size_t)mr1 * CD + jj] = o; }
            }
        }
    }
}

// ---------------- rel-pos bias via FP16 mma -----------------------------------
// g_q carries QS2 = QSCALE*log2e; multiplying by 8 leaves rel_* in log2e units.
__global__ void __launch_bounds__(256) relpos_kernel(const float* __restrict__ rph,
                                                     const float* __restrict__ rpw) {
    __shared__ __align__(16) __half qp[32 * 72];
    __shared__ __align__(16) __half Bp[112 * 72];
    __shared__ float outw[32 * 60];

    const int h = blockIdx.x;
    const int bh = blockIdx.y;
    const int tid = threadIdx.x;
    const int wid = tid >> 5;
    const int lid = tid & 31;
    const int g = lid >> 2;
    const int t = lid & 3;

    {
        int r = tid >> 3, cc = tid & 7;
        uint4 v = make_uint4(0, 0, 0, 0);
        if (r < WW)
            v = *(const uint4*)&g_q[((size_t)bh * NN + h * WW + r) * HD + cc * 8];
        *(uint4*)&qp[r * 72 + cc * 8] = v;
    }
#pragma unroll
    for (int it = 0; it < 2; it++) {
        int idx = it * 256 + tid;
        if (idx < 448) {
            int r = idx >> 2, grp = idx & 3;
            float4 A = {0,0,0,0}, B = {0,0,0,0}, C = {0,0,0,0}, D = {0,0,0,0};
            const float* sp = nullptr;
            if (r < 56)       sp = rph + (size_t)(h + 55 - r) * HD + grp * 16;
            else if (r < 111) sp = rpw + (size_t)(r - 56) * HD + grp * 16;
            if (sp) { A = ((const float4*)sp)[0]; B = ((const float4*)sp)[1];
                      C = ((const float4*)sp)[2]; D = ((const float4*)sp)[3]; }
            *(uint4*)&Bp[r * 72 + grp * 16] =
                make_uint4(packh2(A.x, A.y), packh2(C.x, C.y),
                           packh2(A.z, A.w), packh2(C.z, C.w));
            *(uint4*)&Bp[r * 72 + grp * 16 + 8] =
                make_uint4(packh2(B.x, B.y), packh2(D.x, D.y),
                           packh2(B.z, B.w), packh2(D.z, D.w));
        }
    }
    __syncthreads();

    for (int ti = wid; ti < 14; ti += 8) {
        float c[2][4];
#pragma unroll
        for (int mi = 0; mi < 2; mi++)
#pragma unroll
            for (int e = 0; e < 4; e++) c[mi][e] = 0.f;
#pragma unroll
        for (int kc = 0; kc < 4; kc++) {
            int qo = kc * 16 + t * 4;
            uint2 v0 = *(const uint2*)&qp[g * 72 + qo];
            uint2 v1 = *(const uint2*)&qp[(g + 8) * 72 + qo];
            uint2 v2 = *(const uint2*)&qp[(16 + g) * 72 + qo];
            uint2 v3 = *(const uint2*)&qp[(24 + g) * 72 + qo];
            uint32_t a0[4] = {v0.x, v1.x, v0.y, v1.y};
            uint32_t a1[4] = {v2.x, v3.x, v2.y, v3.y};
            uint2 u = *(const uint2*)&Bp[(ti * 8 + g) * 72 + qo];
            uint32_t b[2] = {u.x, u.y};
            mma_f16(c[0], a0, b);
            mma_f16(c[1], a1, b);
        }
        if (ti < 7) {
            int kh0 = ti * 8 + 2 * t, kh1 = kh0 + 1;
            size_t nb = (size_t)(bh * NN) + h * WW;
            g_relh[(nb + g) * HH + kh0]      = c[0][0] * 8.f;
            g_relh[(nb + g) * HH + kh1]      = c[0][1] * 8.f;
            g_relh[(nb + g + 8) * HH + kh0]  = c[0][2] * 8.f;
            g_relh[(nb + g + 8) * HH + kh1]  = c[0][3] * 8.f;
            g_relh[(nb + 16 + g) * HH + kh0] = c[1][0] * 8.f;
            g_relh[(nb + 16 + g) * HH + kh1] = c[1][1] * 8.f;
            if (g < 4) {
                g_relh[(nb + 24 + g) * HH + kh0] = c[1][2] * 8.f;
                g_relh[(nb + 24 + g) * HH + kh1] = c[1][3] * 8.f;
            }
        } else {
            int cb = (ti - 7) * 8 + 2 * t;
            outw[g * 60 + cb] = c[0][0];        outw[g * 60 + cb + 1] = c[0][1];
            outw[(g + 8) * 60 + cb] = c[0][2];  outw[(g + 8) * 60 + cb + 1] = c[0][3];
            outw[(16 + g) * 60 + cb] = c[1][0]; outw[(16 + g) * 60 + cb + 1] = c[1][1];
            outw[(24 + g) * 60 + cb] = c[1][2]; outw[(24 + g) * 60 + cb + 1] = c[1][3];
        }
    }
    __syncthreads();

    for (int idx = tid; idx < WW * WW; idx += 256) {
        int w = idx / WW, kw = idx - w * WW;
        g_relw[((size_t)(bh * NN) + h * WW + w) * WW + kw] =
            outw[w * 60 + (w - kw + 27)] * 8.f;
    }
}

// ------- flash v9: f16x2 exp2 + ones-row rowsum via mma ----------------------
#define FPH 72   // halves pitch (144B rows)
#define NKEY 1600

struct F9Smem {
    __align__(16) __half qs[128 * FPH];
    __align__(16) __half kt[2][64 * FPH];
    __align__(16) __half vs[2][64 * FPH];   // transposed: row=d, col=keys (perm)
    float rh[128][HH];
    float rw[128][WW];
    __align__(4) uint16_t khkw[NKEY];       // (kh<<8)|kw ; kh=0xFF invalid
};

__global__ void __launch_bounds__(256, 2) flash9_kernel() {
    extern __shared__ char raw[];
    F9Smem& s = *reinterpret_cast<F9Smem*>(raw);

    const int bh = blockIdx.y;
    const int qt0 = blockIdx.x;
    const int tid = threadIdx.x;
    const int wid = tid >> 5;
    const int lid = tid & 31;
    const int g = lid >> 2;
    const int t = lid & 3;
    const int wm = wid * 16;
    const int r0 = wm + g, r1 = wm + g + 8;

    const uint32_t qaddr = smem_u32(s.qs);
    const uint32_t kaddr = smem_u32(s.kt);
    const uint32_t vaddr = smem_u32(s.vs);
    const uint32_t rhaddr = smem_u32(s.rh);
    const uint32_t rwaddr = smem_u32(s.rw);

    // ---- prologue group: Q + rh + rw; khkw table ----
#pragma unroll
    for (int it = 0; it < 4; it++) {
        int idx = it * 256 + tid;
        int r = idx >> 3, cc = idx & 7;
        int n = qt0 * 128 + r;
        const __half* src = g_q + (n < NN ? (size_t)(bh * NN + n) * HD + cc * 8 : 0);
        cpa16(qaddr + (uint32_t)(r * 144 + cc * 16), src, n < NN ? 16u : 0u);
    }
#pragma unroll
    for (int it = 0; it < 7; it++) {
        int idx = it * 256 + tid;
        int r = idx / 14, cc = idx % 14;
        int n = qt0 * 128 + r;
        const float* src = g_relh + (n < NN ? (size_t)(bh * NN + n) * HH + cc * 4 : 0);
        cpa16(rhaddr + (uint32_t)(r * HH + cc * 4) * 4, src, n < NN ? 16u : 0u);
    }
#pragma unroll
    for (int it = 0; it < 4; it++) {
        int idx = it * 256 + tid;
        if (idx < 128 * 7) {
            int r = idx / 7, cc = idx % 7;
            int n = qt0 * 128 + r;
            const float* src = g_relw + (n < NN ? (size_t)(bh * NN + n) * WW + cc * 4 : 0);
            cpa16(rwaddr + (uint32_t)(r * WW + cc * 4) * 4, src, n < NN ? 16u : 0u);
        }
    }
    CPA_COMMIT();
#pragma unroll
    for (int it = 0; it < 7; it++) {
        int kn = it * 256 + tid;
        if (kn < NKEY) {
            int kh = (kn < NN) ? kn / WW : 0xFF;
            int kw = (kn < NN) ? kn - (kn / WW) * WW : 0;
            s.khkw[kn] = (uint16_t)((kh << 8) | kw);
        }
    }

    // combined K+V issue for one tile into buffer j&1
    auto issueKV = [&](int j) {
        const int kb = j * 64;
        const uint32_t ka = kaddr + (uint32_t)((j & 1) * 64 * 144);
        const uint32_t va = vaddr + (uint32_t)((j & 1) * 64 * 144);
#pragma unroll
        for (int it = 0; it < 2; it++) {
            int idx = it * 256 + tid;
            int r = idx >> 3, cc = idx & 7;
            int kn = kb + r;
            bool ok = kn < NN;
            const __half* src = g_k + (ok ? (size_t)(bh * NN + kn) * HD + cc * 8 : 0);
            cpa16(ka + (uint32_t)(r * 144 + cc * 16), src, ok ? 16u : 0u);
        }
#pragma unroll
        for (int it = 0; it < 2; it++) {
            int idx = it * 256 + tid;
            int r = idx >> 3, cc = idx & 7;
            bool ok = (kb + cc * 8 + 8) <= NN;
            const __half* src = g_vt + (ok ? (size_t)(bh * HD + r) * NN + kb + cc * 8 : 0);
            cpa16(va + (uint32_t)(r * 144 + cc * 16), src, ok ? 16u : 0u);
        }
        CPA_COMMIT();
    };

    issueKV(0);
    issueKV(1);

    float acc[8][4];
#pragma unroll
    for (int ni = 0; ni < 8; ni++)
#pragma unroll
        for (int e = 0; e < 4; e++) acc[ni][e] = 0.f;
    float accL[4] = {0.f, 0.f, 0.f, 0.f};   // ones-column: row sums
    float rowm0 = -1e30f, rowm1 = -1e30f;

    const uint32_t* kk32 = (const uint32_t*)s.khkw;
    const uint32_t ONES2 = 0x3C003C00u;      // half2(1.0, 1.0)

    for (int kt2 = 0; kt2 < 25; kt2++) {
        const int kbase = kt2 * 64;
        const int p = kt2 & 1;

        if (kt2 < 24) CPA_WAIT1(); else CPA_WAIT0();
        __syncthreads();   // (1) K/V (+ prologue tables on iter 0) visible

        const char* ktp = (const char*)s.kt[p];
        const char* vsp = (const char*)s.vs[p];

        // ---- QK^T mma ----
        float c[8][4];
#pragma unroll
        for (int ni = 0; ni < 8; ni++)
#pragma unroll
            for (int e = 0; e < 4; e++) c[ni][e] = 0.f;
#pragma unroll
        for (int kc = 0; kc < 4; kc++) {
            const int qo = kc * 32 + t * 8;
            uint2 v0 = *(const uint2*)((const char*)s.qs + r0 * 144 + qo);
            uint2 v1 = *(const uint2*)((const char*)s.qs + r1 * 144 + qo);
            uint32_t a[4] = {v0.x, v1.x, v0.y, v1.y};
#pragma unroll
            for (int ni = 0; ni < 8; ni++) {
                uint2 u = *(const uint2*)(ktp + (ni * 8 + g) * 144 + qo);
                uint32_t b[2] = {u.x, u.y};
                mma_f16(c[ni], a, b);
            }
        }
        // ---- bias + mask (packed table: 1 LDS.32 per ni) ----
#pragma unroll
        for (int ni = 0; ni < 8; ni++) {
            int key0 = kbase + ni * 8 + 2 * t;      // even
            uint32_t w = kk32[key0 >> 1];
            int kh0 = (w >> 8) & 0xFF, kw0 = w & 0xFF;
            int kh1 = w >> 24,         kw1 = (w >> 16) & 0xFF;
            if (kh0 != 0xFF) {
                c[ni][0] += s.rh[r0][kh0] + s.rw[r0][kw0];
                c[ni][2] += s.rh[r1][kh0] + s.rw[r1][kw0];
            } else { c[ni][0] = -1e30f; c[ni][2] = -1e30f; }
            if (kh1 != 0xFF) {
                c[ni][1] += s.rh[r0][kh1] + s.rw[r0][kw1];
                c[ni][3] += s.rh[r1][kh1] + s.rw[r1][kw1];
            } else { c[ni][1] = -1e30f; c[ni][3] = -1e30f; }
        }

        // ---- in-warp max (log2 units) ----
        float tm0 = -1e30f, tm1 = -1e30f;
#pragma unroll
        for (int ni = 0; ni < 8; ni++) {
            tm0 = fmaxf(tm0, fmaxf(c[ni][0], c[ni][1]));
            tm1 = fmaxf(tm1, fmaxf(c[ni][2], c[ni][3]));
        }
        tm0 = fmaxf(tm0, __shfl_xor_sync(0xffffffffu, tm0, 1));
        tm0 = fmaxf(tm0, __shfl_xor_sync(0xffffffffu, tm0, 2));
        tm1 = fmaxf(tm1, __shfl_xor_sync(0xffffffffu, tm1, 1));
        tm1 = fmaxf(tm1, __shfl_xor_sync(0xffffffffu, tm1, 2));

        float mn0 = fmaxf(rowm0, tm0), mn1 = fmaxf(rowm1, tm1);
        float fac0 = fexp2(rowm0 - mn0), fac1 = fexp2(rowm1 - mn1);
        rowm0 = mn0; rowm1 = mn1;

        // ---- P = exp2(c - mn) directly as fp16x2 PV A-fragments ----
        uint32_t pf[8][2];
#pragma unroll
        for (int ni = 0; ni < 8; ni++) {
            pf[ni][0] = h2exp2(packh2(c[ni][0] - mn0, c[ni][1] - mn0));
            pf[ni][1] = h2exp2(packh2(c[ni][2] - mn1, c[ni][3] - mn1));
        }

        // ---- rescale running accumulators (incl. ones column) ----
#pragma unroll
        for (int ni = 0; ni < 8; ni++) {
            acc[ni][0] *= fac0; acc[ni][1] *= fac0;
            acc[ni][2] *= fac1; acc[ni][3] *= fac1;
        }
        accL[0] *= fac0; accL[1] *= fac0;
        accL[2] *= fac1; accL[3] *= fac1;

        // ---- P @ V (+ ones column for row sums) ----
#pragma unroll
        for (int kc = 0; kc < 4; kc++) {
            uint32_t a[4] = {pf[2 * kc][0], pf[2 * kc][1],
                             pf[2 * kc + 1][0], pf[2 * kc + 1][1]};
            const int vo = kc * 32 + t * 8;
#pragma unroll
            for (int ni = 0; ni < 8; ni++) {
                uint2 u = *(const uint2*)(vsp + (ni * 8 + g) * 144 + vo);
                uint32_t b[2] = {u.x, u.y};
                mma_f16(acc[ni], a, b);
            }
            uint32_t bo[2] = {ONES2, ONES2};
            mma_f16(accL, a, bo);
        }

        __syncthreads();   // (2) all readers of buffer p done
        if (kt2 + 2 < 25) issueKV(kt2 + 2);
    }

    // ---- normalize + store g_ao (fp16, k-permuted) ----
    const int b = bh >> 4;
    const int head = bh & 15;
    const int n0g = qt0 * 128 + r0;
    const int n1g = qt0 * 128 + r1;
    float li0 = 1.f / accL[0];
    float li1 = 1.f / accL[2];
#pragma unroll
    for (int ni = 0; ni < 8; ni++) {
        int col = head * HD + ni * 8 + 2 * t;
        int colp = (col & ~15) + posj((col & 15) >> 1) * 2;
        if (n0g < NN)
            *(__half2*)&g_ao[(size_t)(b * NN + n0g) * CD + colp] =
                __floats2half2_rn(acc[ni][0] * li0, acc[ni][1] * li0);
        if (n1g < NN)
            *(__half2*)&g_ao[(size_t)(b * NN + n1g) * CD + colp] =
                __floats2half2_rn(acc[ni][2] * li1, acc[ni][3] * li1);
    }
}

// ---------------- launch -----------------------------------------------------
extern "C" void kernel_launch(void* const* d_in, const int* in_sizes, int n_in,
                              void* d_out, int out_size) {
    const float* hidden = (const float*)d_in[0];
    const float* qkv_w  = (const float*)d_in[1];
    const float* qkv_b  = (const float*)d_in[2];
    const float* proj_w = (const float*)d_in[3];
    const float* proj_b = (const float*)d_in[4];
    const float* rph    = (const float*)d_in[5];
    const float* rpw    = (const float*)d_in[6];
    float* out = (float*)d_out;

    cudaFuncSetAttribute(flash9_kernel, cudaFuncAttributeMaxDynamicSharedMemorySize,
                         (int)sizeof(F9Smem));
    cudaFuncSetAttribute(mm_cp<0>, cudaFuncAttributeMaxDynamicSharedMemorySize, MM_SMEM);
    cudaFuncSetAttribute(mm_cp<1>, cudaFuncAttributeMaxDynamicSharedMemorySize, MM_SMEM);

    const int ptot = PREP_N1 + PREP_N2 + PREP_N3;
    prep_all<<<(ptot + 255) / 256, 256>>>(hidden, qkv_w, proj_w);

    // QKV: [6272,3072] = hidden . qkv_w^T
    mm_cp<0><<<dim3(3 * CD / 128, (BN + 255) / 256), 256, MM_SMEM>>>(qkv_b, nullptr);

    relpos_kernel<<<dim3(HH, BHN), 256>>>(rph, rpw);

    flash9_kernel<<<dim3((NN + 127) / 128, BHN), 256, sizeof(F9Smem)>>>();

    // proj: [6272,1024] = g_ao . proj_w^T
    mm_cp<1><<<dim3(CD / 128, (BN + 255) / 256), 256, MM_SMEM>>>(proj_b, out);
}

// round 13
// speedup vs baseline: 6.2003x; 1.1172x over previous
#include <cuda_runtime.h>
#include <cuda_fp16.h>
#include <cstdint>

#define NH   16
#define HD   64
#define CD   1024
#define BB   4
#define HH   56
#define WW   28
#define NN   1568          // HH*WW
#define BHN  64            // BB*NH
#define BN   6272          // BB*NN
#define QSCALE 0.125f      // 64^-0.5
#define QS2   0.1803368801f // QSCALE * log2(e)

// ---------------- scratch (device globals; no allocations allowed) ----------
__device__ __half g_q[BHN * NN * HD];    // fp16, d-permuted, pre-scaled by QS2
__device__ __half g_k[BHN * NN * HD];    // fp16, d-permuted
__device__ __half g_vt[BHN * HD * NN];   // fp16, transposed [bh][d][n], n-permuted
__device__ float  g_relh[BHN * NN * HH]; // log2e units
__device__ float  g_relw[BHN * NN * WW]; // log2e units
__device__ __half g_ao[BN * CD];         // fp16, k-permuted, [B,N,heads,d]
__device__ __half g_hp[BN * CD];         // hidden prepped
__device__ __half g_wp[3 * CD * CD];     // qkv_w prepped
__device__ __half g_pwp[CD * CD];        // proj_w prepped

// ---------------- helpers ----------------------------------------------------
__device__ __forceinline__ uint32_t packh2(float a, float b) {
    __half2 h = __floats2half2_rn(a, b);
    return *reinterpret_cast<uint32_t*>(&h);
}

__device__ __forceinline__ uint32_t h2exp2(uint32_t x) {
    uint32_t r;
    asm("ex2.approx.f16x2 %0, %1;" : "=r"(r) : "r"(x));
    return r;
}
__device__ __forceinline__ float fexp2(float x) {
    float r;
    asm("ex2.approx.ftz.f32 %0, %1;" : "=f"(r) : "f"(x));
    return r;
}

__device__ __forceinline__ void mma_f16(float* c, const uint32_t* a, const uint32_t* b) {
    asm volatile(
        "mma.sync.aligned.m16n8k16.row.col.f32.f16.f16.f32 "
        "{%0,%1,%2,%3}, {%4,%5,%6,%7}, {%8,%9}, {%0,%1,%2,%3};"
        : "+f"(c[0]), "+f"(c[1]), "+f"(c[2]), "+f"(c[3])
        : "r"(a[0]), "r"(a[1]), "r"(a[2]), "r"(a[3]), "r"(b[0]), "r"(b[1]));
}

__device__ __forceinline__ uint32_t smem_u32(const void* p) {
    uint32_t a;
    asm("{ .reg .u64 t; cvta.to.shared.u64 t, %1; cvt.u32.u64 %0, t; }"
        : "=r"(a) : "l"(p));
    return a;
}

__device__ __forceinline__ void cpa16(uint32_t dst, const void* src, uint32_t srcsize) {
    asm volatile("cp.async.cg.shared.global [%0], [%1], 16, %2;"
                 :: "r"(dst), "l"(src), "r"(srcsize) : "memory");
}
#define CPA_COMMIT() asm volatile("cp.async.commit_group;" ::: "memory")
#define CPA_WAIT0()  asm volatile("cp.async.wait_group 0;" ::: "memory")
#define CPA_WAIT1()  asm volatile("cp.async.wait_group 1;" ::: "memory")

// permuted position of half2-unit j within a 16-half group
__device__ __forceinline__ int posj(int j) { return (j < 4) ? 2 * j : 2 * j - 7; }
// permuted half-index of key n within its 16-group
__device__ __forceinline__ int permn(int n) {
    int u = (n >> 1) & 7;
    return (n & ~15) | (posj(u) << 1) | (n & 1);
}

// ---------------- prep: f32 -> fp16, half2-unit interleave per 16 ------------
#define PREP_N1 (BN * CD / 16)
#define PREP_N2 (3 * CD * CD / 16)
#define PREP_N3 (CD * CD / 16)

__global__ void __launch_bounds__(256) prep_all(const float* __restrict__ hidden,
                                                const float* __restrict__ w1,
                                                const float* __restrict__ w2) {
    int i = blockIdx.x * 256 + threadIdx.x;
    const float* src;
    __half* dst;
    if (i < PREP_N1) { src = hidden + (size_t)i * 16; dst = g_hp + (size_t)i * 16; }
    else if (i < PREP_N1 + PREP_N2) {
        int j = i - PREP_N1; src = w1 + (size_t)j * 16; dst = g_wp + (size_t)j * 16;
    } else if (i < PREP_N1 + PREP_N2 + PREP_N3) {
        int j = i - PREP_N1 - PREP_N2; src = w2 + (size_t)j * 16; dst = g_pwp + (size_t)j * 16;
    } else return;
    const float4* s = (const float4*)src;
    float4 A = s[0], B = s[1], C = s[2], D = s[3];
    uint4* d = (uint4*)dst;
    d[0] = make_uint4(packh2(A.x, A.y), packh2(C.x, C.y),
                      packh2(A.z, A.w), packh2(C.z, C.w));
    d[1] = make_uint4(packh2(B.x, B.y), packh2(D.x, D.y),
                      packh2(B.z, B.w), packh2(D.z, D.w));
}

// ================== cp.async 3-stage FP16 GEMM, 256x128 tile, BK=64 ==========
#define ATSZB (256 * 128)      // A tile bytes
#define BTSZB (128 * 128)
#define STGB  (ATSZB + BTSZB)  // 49152
#define MM_SMEM (3 * STGB)

template <int MODE>
__global__ void __launch_bounds__(256, 1) mm_cp(const float* __restrict__ bias,
                                                float* __restrict__ Cout) {
    extern __shared__ char smemc[];
    uint32_t sb = smem_u32(smemc);
    const __half* A  = (MODE == 0) ? g_hp : g_ao;
    const __half* Bm = (MODE == 0) ? g_wp : g_pwp;

    const int tid = threadIdx.x;
    const int wid = tid >> 5;
    const int lid = tid & 31;
    const int g = lid >> 2;
    const int t = lid & 3;
    const int m0 = blockIdx.y * 256;
    const int n0 = blockIdx.x * 128;
    const int wm = (wid & 3) * 64;
    const int wn = (wid >> 2) * 64;

    float acc[4][8][4];
#pragma unroll
    for (int mi = 0; mi < 4; mi++)
#pragma unroll
        for (int ni = 0; ni < 8; ni++)
#pragma unroll
            for (int e = 0; e < 4; e++) acc[mi][ni][e] = 0.f;

    const int lr = tid >> 3;
    const int lq = tid & 7;
    const uint32_t ldst = (uint32_t)(lr * 128 + ((lq ^ (lr & 7)) << 4));

    auto issue = [&](int kt) {
        const int st = kt % 3;
        const int k0 = kt * 64;
        uint32_t ab = sb + (uint32_t)st * STGB;
        uint32_t bb = ab + ATSZB;
#pragma unroll
        for (int it = 0; it < 8; it++) {
            int r = lr + it * 32;
            int gr = m0 + r;
            bool ok = gr < BN;
            cpa16(ab + ldst + (uint32_t)(it * 32 * 128),
                  A + (ok ? (size_t)gr * CD + k0 + lq * 8 : 0), ok ? 16u : 0u);
        }
#pragma unroll
        for (int it = 0; it < 4; it++) {
            int r = lr + it * 32;
            cpa16(bb + ldst + (uint32_t)(it * 32 * 128),
                  Bm + (size_t)(n0 + r) * CD + k0 + lq * 8, 16);
        }
        CPA_COMMIT();
    };

    issue(0); issue(1);
    for (int kt = 0; kt < 16; kt++) {
        if (kt < 15) CPA_WAIT1(); else CPA_WAIT0();
        __syncthreads();
        if (kt + 2 < 16) issue(kt + 2);

        const char* As = smemc + (size_t)(kt % 3) * STGB;
        const char* Bs = As + ATSZB;

#pragma unroll
        for (int kc = 0; kc < 4; kc++) {
            const int coff = (((kc * 2 + (t >> 1)) ^ g) << 4) + ((t & 1) << 3);
            uint32_t a[4][4];
            uint32_t b[8][2];
#pragma unroll
            for (int mi = 0; mi < 4; mi++) {
                uint2 v0 = *(const uint2*)(As + (wm + mi * 16 + g) * 128 + coff);
                uint2 v1 = *(const uint2*)(As + (wm + mi * 16 + g + 8) * 128 + coff);
                a[mi][0] = v0.x; a[mi][1] = v1.x; a[mi][2] = v0.y; a[mi][3] = v1.y;
            }
#pragma unroll
            for (int ni = 0; ni < 8; ni++) {
                uint2 u = *(const uint2*)(Bs + (wn + ni * 8 + g) * 128 + coff);
                b[ni][0] = u.x; b[ni][1] = u.y;
            }
#pragma unroll
            for (int mi = 0; mi < 4; mi++)
#pragma unroll
                for (int ni = 0; ni < 8; ni++) mma_f16(acc[mi][ni], a[mi], b[ni]);
        }
    }

#pragma unroll
    for (int mi = 0; mi < 4; mi++) {
        int mr0 = m0 + wm + mi * 16 + g;
        int mr1 = mr0 + 8;
        bool ok0 = mr0 < BN, ok1 = mr1 < BN;
#pragma unroll
        for (int ni = 0; ni < 8; ni++) {
            int jj = n0 + wn + ni * 8 + 2 * t;
            float b0 = bias[jj], b1 = bias[jj + 1];
            float v00 = acc[mi][ni][0] + b0, v01 = acc[mi][ni][1] + b1;
            float v10 = acc[mi][ni][2] + b0, v11 = acc[mi][ni][3] + b1;
            if (MODE == 0) {
                int tsel = jj >> 10;
                int rr = jj & 1023;
                int head = rr >> 6;
                int d = rr & 63;
                int dperm = (d & ~15) + posj((d & 15) >> 1) * 2;
                if (ok0) {
                    int b_ = mr0 / NN, n_ = mr0 - b_ * NN;
                    int bh = b_ * NH + head;
                    if (tsel == 0) {
                        *(__half2*)&g_q[((size_t)bh * NN + n_) * HD + dperm] =
                            __floats2half2_rn(v00 * QS2, v01 * QS2);
                    } else if (tsel == 1) {
                        *(__half2*)&g_k[((size_t)bh * NN + n_) * HD + dperm] =
                            __floats2half2_rn(v00, v01);
                    } else {
                        int np = permn(n_);
                        g_vt[((size_t)bh * HD + d) * NN + np]     = __float2half_rn(v00);
                        g_vt[((size_t)bh * HD + d + 1) * NN + np] = __float2half_rn(v01);
                    }
                }
                if (ok1) {
                    int b_ = mr1 / NN, n_ = mr1 - b_ * NN;
                    int bh = b_ * NH + head;
                    if (tsel == 0) {
                        *(__half2*)&g_q[((size_t)bh * NN + n_) * HD + dperm] =
                            __floats2half2_rn(v10 * QS2, v11 * QS2);
                    } else if (tsel == 1) {
                        *(__half2*)&g_k[((size_t)bh * NN + n_) * HD + dperm] =
                            __floats2half2_rn(v10, v11);
                    } else {
                        int np = permn(n_);
                        g_vt[((size_t)bh * HD + d) * NN + np]     = __float2half_rn(v10);
                        g_vt[((size_t)bh * HD + d + 1) * NN + np] = __float2half_rn(v11);
                    }
                }
            } else {
                if (ok0) { float2 o = {v00, v01}; *(float2*)&Cout[(size_t)mr0 * CD + jj] = o; }
                if (ok1) { float2 o = {v10, v11}; *(float2*)&Cout[(size_t)mr1 * CD + jj] = o; }
            }
        }
    }
}

// ---------------- rel-pos bias via FP16 mma -----------------------------------
__global__ void __launch_bounds__(256) relpos_kernel(const float* __restrict__ rph,
                                                     const float* __restrict__ rpw) {
    __shared__ __align__(16) __half qp[32 * 72];
    __shared__ __align__(16) __half Bp[112 * 72];
    __shared__ float outw[32 * 60];

    const int h = blockIdx.x;
    const int bh = blockIdx.y;
    const int tid = threadIdx.x;
    const int wid = tid >> 5;
    const int lid = tid & 31;
    const int g = lid >> 2;
    const int t = lid & 3;

    {
        int r = tid >> 3, cc = tid & 7;
        uint4 v = make_uint4(0, 0, 0, 0);
        if (r < WW)
            v = *(const uint4*)&g_q[((size_t)bh * NN + h * WW + r) * HD + cc * 8];
        *(uint4*)&qp[r * 72 + cc * 8] = v;
    }
#pragma unroll
    for (int it = 0; it < 2; it++) {
        int idx = it * 256 + tid;
        if (idx < 448) {
            int r = idx >> 2, grp = idx & 3;
            float4 A = {0,0,0,0}, B = {0,0,0,0}, C = {0,0,0,0}, D = {0,0,0,0};
            const float* sp = nullptr;
            if (r < 56)       sp = rph + (size_t)(h + 55 - r) * HD + grp * 16;
            else if (r < 111) sp = rpw + (size_t)(r - 56) * HD + grp * 16;
            if (sp) { A = ((const float4*)sp)[0]; B = ((const float4*)sp)[1];
                      C = ((const float4*)sp)[2]; D = ((const float4*)sp)[3]; }
            *(uint4*)&Bp[r * 72 + grp * 16] =
                make_uint4(packh2(A.x, A.y), packh2(C.x, C.y),
                           packh2(A.z, A.w), packh2(C.z, C.w));
            *(uint4*)&Bp[r * 72 + grp * 16 + 8] =
                make_uint4(packh2(B.x, B.y), packh2(D.x, D.y),
                           packh2(B.z, B.w), packh2(D.z, D.w));
        }
    }
    __syncthreads();

    for (int ti = wid; ti < 14; ti += 8) {
        float c[2][4];
#pragma unroll
        for (int mi = 0; mi < 2; mi++)
#pragma unroll
            for (int e = 0; e < 4; e++) c[mi][e] = 0.f;
#pragma unroll
        for (int kc = 0; kc < 4; kc++) {
            int qo = kc * 16 + t * 4;
            uint2 v0 = *(const uint2*)&qp[g * 72 + qo];
            uint2 v1 = *(const uint2*)&qp[(g + 8) * 72 + qo];
            uint2 v2 = *(const uint2*)&qp[(16 + g) * 72 + qo];
            uint2 v3 = *(const uint2*)&qp[(24 + g) * 72 + qo];
            uint32_t a0[4] = {v0.x, v1.x, v0.y, v1.y};
            uint32_t a1[4] = {v2.x, v3.x, v2.y, v3.y};
            uint2 u = *(const uint2*)&Bp[(ti * 8 + g) * 72 + qo];
            uint32_t b[2] = {u.x, u.y};
            mma_f16(c[0], a0, b);
            mma_f16(c[1], a1, b);
        }
        if (ti < 7) {
            int kh0 = ti * 8 + 2 * t, kh1 = kh0 + 1;
            size_t nb = (size_t)(bh * NN) + h * WW;
            g_relh[(nb + g) * HH + kh0]      = c[0][0] * 8.f;
            g_relh[(nb + g) * HH + kh1]      = c[0][1] * 8.f;
            g_relh[(nb + g + 8) * HH + kh0]  = c[0][2] * 8.f;
            g_relh[(nb + g + 8) * HH + kh1]  = c[0][3] * 8.f;
            g_relh[(nb + 16 + g) * HH + kh0] = c[1][0] * 8.f;
            g_relh[(nb + 16 + g) * HH + kh1] = c[1][1] * 8.f;
            if (g < 4) {
                g_relh[(nb + 24 + g) * HH + kh0] = c[1][2] * 8.f;
                g_relh[(nb + 24 + g) * HH + kh1] = c[1][3] * 8.f;
            }
        } else {
            int cb = (ti - 7) * 8 + 2 * t;
            outw[g * 60 + cb] = c[0][0];        outw[g * 60 + cb + 1] = c[0][1];
            outw[(g + 8) * 60 + cb] = c[0][2];  outw[(g + 8) * 60 + cb + 1] = c[0][3];
            outw[(16 + g) * 60 + cb] = c[1][0]; outw[(16 + g) * 60 + cb + 1] = c[1][1];
            outw[(24 + g) * 60 + cb] = c[1][2]; outw[(24 + g) * 60 + cb + 1] = c[1][3];
        }
    }
    __syncthreads();

    for (int idx = tid; idx < WW * WW; idx += 256) {
        int w = idx / WW, kw = idx - w * WW;
        g_relw[((size_t)(bh * NN) + h * WW + w) * WW + kw] =
            outw[w * 60 + (w - kw + 27)] * 8.f;
    }
}

// ------- flash v10: 4 warps, m=32/warp (half K/V fragment traffic) -----------
#define FPH 72   // halves pitch (144B rows)
#define NKEY 1600

struct F10Smem {
    __align__(16) __half qs[128 * FPH];
    __align__(16) __half kt[2][64 * FPH];
    __align__(16) __half vs[2][64 * FPH];   // transposed: row=d, col=keys (perm)
    float rh[128][HH];
    float rw[128][WW];
    __align__(4) uint16_t khkw[NKEY];       // (kh<<8)|kw ; kh=0xFF invalid
};

__global__ void __launch_bounds__(128, 2) flash10_kernel() {
    extern __shared__ char raw[];
    F10Smem& s = *reinterpret_cast<F10Smem*>(raw);

    const int bh = blockIdx.y;
    const int qt0 = blockIdx.x;
    const int tid = threadIdx.x;
    const int wid = tid >> 5;      // 0..3
    const int lid = tid & 31;
    const int g = lid >> 2;
    const int t = lid & 3;
    const int wm = wid * 32;       // 32 q-rows per warp
    // row indices for the two m16 tiles
    const int rA0 = wm + g,      rA1 = wm + g + 8;
    const int rB0 = wm + g + 16, rB1 = wm + g + 24;

    const uint32_t qaddr = smem_u32(s.qs);
    const uint32_t kaddr = smem_u32(s.kt);
    const uint32_t vaddr = smem_u32(s.vs);
    const uint32_t rhaddr = smem_u32(s.rh);
    const uint32_t rwaddr = smem_u32(s.rw);

    // ---- prologue group: Q + rh + rw; khkw table ----
#pragma unroll
    for (int it = 0; it < 8; it++) {
        int idx = it * 128 + tid;
        int r = idx >> 3, cc = idx & 7;
        int n = qt0 * 128 + r;
        const __half* src = g_q + (n < NN ? (size_t)(bh * NN + n) * HD + cc * 8 : 0);
        cpa16(qaddr + (uint32_t)(r * 144 + cc * 16), src, n < NN ? 16u : 0u);
    }
#pragma unroll
    for (int it = 0; it < 14; it++) {
        int idx = it * 128 + tid;
        int r = idx / 14, cc = idx % 14;
        int n = qt0 * 128 + r;
        const float* src = g_relh + (n < NN ? (size_t)(bh * NN + n) * HH + cc * 4 : 0);
        cpa16(rhaddr + (uint32_t)(r * HH + cc * 4) * 4, src, n < NN ? 16u : 0u);
    }
#pragma unroll
    for (int it = 0; it < 7; it++) {
        int idx = it * 128 + tid;
        int r = idx / 7, cc = idx % 7;
        int n = qt0 * 128 + r;
        const float* src = g_relw + (n < NN ? (size_t)(bh * NN + n) * WW + cc * 4 : 0);
        cpa16(rwaddr + (uint32_t)(r * WW + cc * 4) * 4, src, n < NN ? 16u : 0u);
    }
    CPA_COMMIT();
#pragma unroll
    for (int it = 0; it < 13; it++) {
        int kn = it * 128 + tid;
        if (kn < NKEY) {
            int kh = (kn < NN) ? kn / WW : 0xFF;
            int kw = (kn < NN) ? kn - (kn / WW) * WW : 0;
            s.khkw[kn] = (uint16_t)((kh << 8) | kw);
        }
    }

    // combined K+V issue for one tile into buffer j&1
    auto issueKV = [&](int j) {
        const int kb = j * 64;
        const uint32_t ka = kaddr + (uint32_t)((j & 1) * 64 * 144);
        const uint32_t va = vaddr + (uint32_t)((j & 1) * 64 * 144);
#pragma unroll
        for (int it = 0; it < 4; it++) {
            int idx = it * 128 + tid;
            int r = idx >> 3, cc = idx & 7;
            int kn = kb + r;
            bool ok = kn < NN;
            const __half* src = g_k + (ok ? (size_t)(bh * NN + kn) * HD + cc * 8 : 0);
            cpa16(ka + (uint32_t)(r * 144 + cc * 16), src, ok ? 16u : 0u);
        }
#pragma unroll
        for (int it = 0; it < 4; it++) {
            int idx = it * 128 + tid;
            int r = idx >> 3, cc = idx & 7;
            bool ok = (kb + cc * 8 + 8) <= NN;
            const __half* src = g_vt + (ok ? (size_t)(bh * HD + r) * NN + kb + cc * 8 : 0);
            cpa16(va + (uint32_t)(r * 144 + cc * 16), src, ok ? 16u : 0u);
        }
        CPA_COMMIT();
    };

    issueKV(0);
    issueKV(1);

    float acc[2][8][4];
#pragma unroll
    for (int m = 0; m < 2; m++)
#pragma unroll
        for (int ni = 0; ni < 8; ni++)
#pragma unroll
            for (int e = 0; e < 4; e++) acc[m][ni][e] = 0.f;
    float accL[2][4] = {{0.f, 0.f, 0.f, 0.f}, {0.f, 0.f, 0.f, 0.f}};
    float rowm[4] = {-1e30f, -1e30f, -1e30f, -1e30f};

    const uint32_t* kk32 = (const uint32_t*)s.khkw;
    const uint32_t ONES2 = 0x3C003C00u;

    for (int kt2 = 0; kt2 < 25; kt2++) {
        const int kbase = kt2 * 64;
        const int p = kt2 & 1;

        if (kt2 < 24) CPA_WAIT1(); else CPA_WAIT0();
        __syncthreads();   // (1) K/V (+ prologue on iter 0) visible

        const char* ktp = (const char*)s.kt[p];
        const char* vsp = (const char*)s.vs[p];

        // ---- QK^T mma: two m16 tiles per warp ----
        float c[2][8][4];
#pragma unroll
        for (int m = 0; m < 2; m++)
#pragma unroll
            for (int ni = 0; ni < 8; ni++)
#pragma unroll
                for (int e = 0; e < 4; e++) c[m][ni][e] = 0.f;
#pragma unroll
        for (int kc = 0; kc < 4; kc++) {
            const int qo = kc * 32 + t * 8;
            uint2 v0 = *(const uint2*)((const char*)s.qs + rA0 * 144 + qo);
            uint2 v1 = *(const uint2*)((const char*)s.qs + rA1 * 144 + qo);
            uint2 v2 = *(const uint2*)((const char*)s.qs + rB0 * 144 + qo);
            uint2 v3 = *(const uint2*)((const char*)s.qs + rB1 * 144 + qo);
            uint32_t a0[4] = {v0.x, v1.x, v0.y, v1.y};
            uint32_t a1[4] = {v2.x, v3.x, v2.y, v3.y};
#pragma unroll
            for (int ni = 0; ni < 8; ni++) {
                uint2 u = *(const uint2*)(ktp + (ni * 8 + g) * 144 + qo);
                uint32_t b[2] = {u.x, u.y};
                mma_f16(c[0][ni], a0, b);
                mma_f16(c[1][ni], a1, b);
            }
        }
        // ---- bias + mask ----
#pragma unroll
        for (int ni = 0; ni < 8; ni++) {
            int key0 = kbase + ni * 8 + 2 * t;
            uint32_t w = kk32[key0 >> 1];
            int kh0 = (w >> 8) & 0xFF, kw0 = w & 0xFF;
            int kh1 = w >> 24,         kw1 = (w >> 16) & 0xFF;
            if (kh0 != 0xFF) {
                c[0][ni][0] += s.rh[rA0][kh0] + s.rw[rA0][kw0];
                c[0][ni][2] += s.rh[rA1][kh0] + s.rw[rA1][kw0];
                c[1][ni][0] += s.rh[rB0][kh0] + s.rw[rB0][kw0];
                c[1][ni][2] += s.rh[rB1][kh0] + s.rw[rB1][kw0];
            } else {
                c[0][ni][0] = -1e30f; c[0][ni][2] = -1e30f;
                c[1][ni][0] = -1e30f; c[1][ni][2] = -1e30f;
            }
            if (kh1 != 0xFF) {
                c[0][ni][1] += s.rh[rA0][kh1] + s.rw[rA0][kw1];
                c[0][ni][3] += s.rh[rA1][kh1] + s.rw[rA1][kw1];
                c[1][ni][1] += s.rh[rB0][kh1] + s.rw[rB0][kw1];
                c[1][ni][3] += s.rh[rB1][kh1] + s.rw[rB1][kw1];
            } else {
                c[0][ni][1] = -1e30f; c[0][ni][3] = -1e30f;
                c[1][ni][1] = -1e30f; c[1][ni][3] = -1e30f;
            }
        }

        // ---- in-warp max (log2 units); rows: 0->rA0, 1->rA1, 2->rB0, 3->rB1 --
        float tm[4] = {-1e30f, -1e30f, -1e30f, -1e30f};
#pragma unroll
        for (int ni = 0; ni < 8; ni++) {
            tm[0] = fmaxf(tm[0], fmaxf(c[0][ni][0], c[0][ni][1]));
            tm[1] = fmaxf(tm[1], fmaxf(c[0][ni][2], c[0][ni][3]));
            tm[2] = fmaxf(tm[2], fmaxf(c[1][ni][0], c[1][ni][1]));
            tm[3] = fmaxf(tm[3], fmaxf(c[1][ni][2], c[1][ni][3]));
        }
#pragma unroll
        for (int j = 0; j < 4; j++) {
            tm[j] = fmaxf(tm[j], __shfl_xor_sync(0xffffffffu, tm[j], 1));
            tm[j] = fmaxf(tm[j], __shfl_xor_sync(0xffffffffu, tm[j], 2));
        }
        float mn[4], fac[4];
#pragma unroll
        for (int j = 0; j < 4; j++) {
            mn[j] = fmaxf(rowm[j], tm[j]);
            fac[j] = fexp2(rowm[j] - mn[j]);
            rowm[j] = mn[j];
        }

        // ---- P = exp2(c - mn) as fp16x2 PV A-fragments ----
        uint32_t pf[2][8][2];
#pragma unroll
        for (int ni = 0; ni < 8; ni++) {
            pf[0][ni][0] = h2exp2(packh2(c[0][ni][0] - mn[0], c[0][ni][1] - mn[0]));
            pf[0][ni][1] = h2exp2(packh2(c[0][ni][2] - mn[1], c[0][ni][3] - mn[1]));
            pf[1][ni][0] = h2exp2(packh2(c[1][ni][0] - mn[2], c[1][ni][1] - mn[2]));
            pf[1][ni][1] = h2exp2(packh2(c[1][ni][2] - mn[3], c[1][ni][3] - mn[3]));
        }

        // ---- rescale accumulators ----
#pragma unroll
        for (int ni = 0; ni < 8; ni++) {
            acc[0][ni][0] *= fac[0]; acc[0][ni][1] *= fac[0];
            acc[0][ni][2] *= fac[1]; acc[0][ni][3] *= fac[1];
            acc[1][ni][0] *= fac[2]; acc[1][ni][1] *= fac[2];
            acc[1][ni][2] *= fac[3]; acc[1][ni][3] *= fac[3];
        }
        accL[0][0] *= fac[0]; accL[0][1] *= fac[0];
        accL[0][2] *= fac[1]; accL[0][3] *= fac[1];
        accL[1][0] *= fac[2]; accL[1][1] *= fac[2];
        accL[1][2] *= fac[3]; accL[1][3] *= fac[3];

        // ---- P @ V (+ ones column) ----
#pragma unroll
        for (int kc = 0; kc < 4; kc++) {
            uint32_t a0[4] = {pf[0][2 * kc][0], pf[0][2 * kc][1],
                              pf[0][2 * kc + 1][0], pf[0][2 * kc + 1][1]};
            uint32_t a1[4] = {pf[1][2 * kc][0], pf[1][2 * kc][1],
                              pf[1][2 * kc + 1][0], pf[1][2 * kc + 1][1]};
            const int vo = kc * 32 + t * 8;
#pragma unroll
            for (int ni = 0; ni < 8; ni++) {
                uint2 u = *(const uint2*)(vsp + (ni * 8 + g) * 144 + vo);
                uint32_t b[2] = {u.x, u.y};
                mma_f16(acc[0][ni], a0, b);
                mma_f16(acc[1][ni], a1, b);
            }
            uint32_t bo[2] = {ONES2, ONES2};
            mma_f16(accL[0], a0, bo);
            mma_f16(accL[1], a1, bo);
        }

        __syncthreads();   // (2) all readers of buffer p done
        if (kt2 + 2 < 25) issueKV(kt2 + 2);
    }

    // ---- normalize + store g_ao (fp16, k-permuted) ----
    const int b = bh >> 4;
    const int head = bh & 15;
    const int nrow[4] = {qt0 * 128 + rA0, qt0 * 128 + rA1,
                         qt0 * 128 + rB0, qt0 * 128 + rB1};
    const float li[4] = {1.f / accL[0][0], 1.f / accL[0][2],
                         1.f / accL[1][0], 1.f / accL[1][2]};
#pragma unroll
    for (int ni = 0; ni < 8; ni++) {
        int col = head * HD + ni * 8 + 2 * t;
        int colp = (col & ~15) + posj((col & 15) >> 1) * 2;
#pragma unroll
        for (int j = 0; j < 4; j++) {
            if (nrow[j] < NN) {
                int m = j >> 1, eo = (j & 1) * 2;
                *(__half2*)&g_ao[(size_t)(b * NN + nrow[j]) * CD + colp] =
                    __floats2half2_rn(acc[m][ni][eo] * li[j], acc[m][ni][eo + 1] * li[j]);
            }
        }
    }
}

// ---------------- launch -----------------------------------------------------
extern "C" void kernel_launch(void* const* d_in, const int* in_sizes, int n_in,
                              void* d_out, int out_size) {
    const float* hidden = (const float*)d_in[0];
    const float* qkv_w  = (const float*)d_in[1];
    const float* qkv_b  = (const float*)d_in[2];
    const float* proj_w = (const float*)d_in[3];
    const float* proj_b = (const float*)d_in[4];
    const float* rph    = (const float*)d_in[5];
    const float* rpw    = (const float*)d_in[6];
    float* out = (float*)d_out;

    cudaFuncSetAttribute(flash10_kernel, cudaFuncAttributeMaxDynamicSharedMemorySize,
                         (int)sizeof(F10Smem));
    cudaFuncSetAttribute(mm_cp<0>, cudaFuncAttributeMaxDynamicSharedMemorySize, MM_SMEM);
    cudaFuncSetAttribute(mm_cp<1>, cudaFuncAttributeMaxDynamicSharedMemorySize, MM_SMEM);

    const int ptot = PREP_N1 + PREP_N2 + PREP_N3;
    prep_all<<<(ptot + 255) / 256, 256>>>(hidden, qkv_w, proj_w);

    // QKV: [6272,3072] = hidden . qkv_w^T
    mm_cp<0><<<dim3(3 * CD / 128, (BN + 255) / 256), 256, MM_SMEM>>>(qkv_b, nullptr);

    relpos_kernel<<<dim3(HH, BHN), 256>>>(rph, rpw);

    flash10_kernel<<<dim3((NN + 127) / 128, BHN), 128, sizeof(F10Smem)>>>();

    // proj: [6272,1024] = g_ao . proj_w^T
    mm_cp<1><<<dim3(CD / 128, (BN + 255) / 256), 256, MM_SMEM>>>(proj_b, out);
}

// round 14
// speedup vs baseline: 7.0307x; 1.1339x over previous
#include <cuda_runtime.h>
#include <cuda_fp16.h>
#include <cstdint>

#define NH   16
#define HD   64
#define CD   1024
#define BB   4
#define HH   56
#define WW   28
#define NN   1568          // HH*WW
#define BHN  64            // BB*NH
#define BN   6272          // BB*NN
#define QSCALE 0.125f      // 64^-0.5
#define QS2   0.1803368801f // QSCALE * log2(e)

// ---------------- scratch (device globals; no allocations allowed) ----------
__device__ __half g_q[BHN * NN * HD];     // fp16, d-permuted, pre-scaled by QS2
__device__ __half g_k[BHN * NN * HD];     // fp16, d-permuted
__device__ __half g_vt[BHN * HD * NN];    // fp16, transposed [bh][d][n], n-permuted
__device__ __half g_relh16[BHN * NN * HH];   // log2e units, fp16
__device__ __half g_relw16[BHN * NN * 32];   // log2e units, fp16, rows padded to 32
__device__ __half g_ao[BN * CD];          // fp16, k-permuted, [B,N,heads,d]
__device__ __half g_hp[BN * CD];
__device__ __half g_wp[3 * CD * CD];
__device__ __half g_pwp[CD * CD];

// ---------------- helpers ----------------------------------------------------
__device__ __forceinline__ uint32_t packh2(float a, float b) {
    __half2 h = __floats2half2_rn(a, b);
    return *reinterpret_cast<uint32_t*>(&h);
}
__device__ __forceinline__ uint32_t h2exp2(uint32_t x) {
    uint32_t r;
    asm("ex2.approx.f16x2 %0, %1;" : "=r"(r) : "r"(x));
    return r;
}
__device__ __forceinline__ float fexp2(float x) {
    float r;
    asm("ex2.approx.ftz.f32 %0, %1;" : "=f"(r) : "f"(x));
    return r;
}
__device__ __forceinline__ uint32_t h2add(uint32_t a, uint32_t b) {
    __half2 r = __hadd2(*reinterpret_cast<__half2*>(&a), *reinterpret_cast<__half2*>(&b));
    return *reinterpret_cast<uint32_t*>(&r);
}
__device__ __forceinline__ uint32_t hdup(__half h) {
    __half2 r = __half2half2(h);
    return *reinterpret_cast<uint32_t*>(&r);
}

__device__ __forceinline__ void mma_f16(float* c, const uint32_t* a, const uint32_t* b) {
    asm volatile(
        "mma.sync.aligned.m16n8k16.row.col.f32.f16.f16.f32 "
        "{%0,%1,%2,%3}, {%4,%5,%6,%7}, {%8,%9}, {%0,%1,%2,%3};"
        : "+f"(c[0]), "+f"(c[1]), "+f"(c[2]), "+f"(c[3])
        : "r"(a[0]), "r"(a[1]), "r"(a[2]), "r"(a[3]), "r"(b[0]), "r"(b[1]));
}

__device__ __forceinline__ uint32_t smem_u32(const void* p) {
    uint32_t a;
    asm("{ .reg .u64 t; cvta.to.shared.u64 t, %1; cvt.u32.u64 %0, t; }"
        : "=r"(a) : "l"(p));
    return a;
}

__device__ __forceinline__ void cpa16(uint32_t dst, const void* src, uint32_t srcsize) {
    asm volatile("cp.async.cg.shared.global [%0], [%1], 16, %2;"
                 :: "r"(dst), "l"(src), "r"(srcsize) : "memory");
}
#define CPA_COMMIT() asm volatile("cp.async.commit_group;" ::: "memory")
#define CPA_WAIT0()  asm volatile("cp.async.wait_group 0;" ::: "memory")
#define CPA_WAIT1()  asm volatile("cp.async.wait_group 1;" ::: "memory")
#define CPA_WAIT2()  asm volatile("cp.async.wait_group 2;" ::: "memory")

__device__ __forceinline__ int posj(int j) { return (j < 4) ? 2 * j : 2 * j - 7; }
__device__ __forceinline__ int permn(int n) {
    int u = (n >> 1) & 7;
    return (n & ~15) | (posj(u) << 1) | (n & 1);
}

// ---------------- prep: f32 -> fp16, half2-unit interleave per 16 ------------
#define PREP_N1 (BN * CD / 16)
#define PREP_N2 (3 * CD * CD / 16)
#define PREP_N3 (CD * CD / 16)

__global__ void __launch_bounds__(256) prep_all(const float* __restrict__ hidden,
                                                const float* __restrict__ w1,
                                                const float* __restrict__ w2) {
    int i = blockIdx.x * 256 + threadIdx.x;
    const float* src;
    __half* dst;
    if (i < PREP_N1) { src = hidden + (size_t)i * 16; dst = g_hp + (size_t)i * 16; }
    else if (i < PREP_N1 + PREP_N2) {
        int j = i - PREP_N1; src = w1 + (size_t)j * 16; dst = g_wp + (size_t)j * 16;
    } else if (i < PREP_N1 + PREP_N2 + PREP_N3) {
        int j = i - PREP_N1 - PREP_N2; src = w2 + (size_t)j * 16; dst = g_pwp + (size_t)j * 16;
    } else return;
    const float4* s = (const float4*)src;
    float4 A = s[0], B = s[1], C = s[2], D = s[3];
    uint4* d = (uint4*)dst;
    d[0] = make_uint4(packh2(A.x, A.y), packh2(C.x, C.y),
                      packh2(A.z, A.w), packh2(C.z, C.w));
    d[1] = make_uint4(packh2(B.x, B.y), packh2(D.x, D.y),
                      packh2(B.z, B.w), packh2(D.z, D.w));
}

// ================== cp.async 3-stage FP16 GEMM, 256x128 tile, BK=64 ==========
#define ATSZB (256 * 128)
#define BTSZB (128 * 128)
#define STGB  (ATSZB + BTSZB)
#define MM_SMEM (3 * STGB)

template <int MODE>
__global__ void __launch_bounds__(256, 1) mm_cp(const float* __restrict__ bias,
                                                float* __restrict__ Cout) {
    extern __shared__ char smemc[];
    uint32_t sb = smem_u32(smemc);
    const __half* A  = (MODE == 0) ? g_hp : g_ao;
    const __half* Bm = (MODE == 0) ? g_wp : g_pwp;

    const int tid = threadIdx.x;
    const int wid = tid >> 5;
    const int lid = tid & 31;
    const int g = lid >> 2;
    const int t = lid & 3;
    const int m0 = blockIdx.y * 256;
    const int n0 = blockIdx.x * 128;
    const int wm = (wid & 3) * 64;
    const int wn = (wid >> 2) * 64;

    float acc[4][8][4];
#pragma unroll
    for (int mi = 0; mi < 4; mi++)
#pragma unroll
        for (int ni = 0; ni < 8; ni++)
#pragma unroll
            for (int e = 0; e < 4; e++) acc[mi][ni][e] = 0.f;

    const int lr = tid >> 3;
    const int lq = tid & 7;
    const uint32_t ldst = (uint32_t)(lr * 128 + ((lq ^ (lr & 7)) << 4));

    auto issue = [&](int kt) {
        const int st = kt % 3;
        const int k0 = kt * 64;
        uint32_t ab = sb + (uint32_t)st * STGB;
        uint32_t bb = ab + ATSZB;
#pragma unroll
        for (int it = 0; it < 8; it++) {
            int r = lr + it * 32;
            int gr = m0 + r;
            bool ok = gr < BN;
            cpa16(ab + ldst + (uint32_t)(it * 32 * 128),
                  A + (ok ? (size_t)gr * CD + k0 + lq * 8 : 0), ok ? 16u : 0u);
        }
#pragma unroll
        for (int it = 0; it < 4; it++) {
            int r = lr + it * 32;
            cpa16(bb + ldst + (uint32_t)(it * 32 * 128),
                  Bm + (size_t)(n0 + r) * CD + k0 + lq * 8, 16);
        }
        CPA_COMMIT();
    };

    issue(0); issue(1);
    for (int kt = 0; kt < 16; kt++) {
        if (kt < 15) CPA_WAIT1(); else CPA_WAIT0();
        __syncthreads();
        if (kt + 2 < 16) issue(kt + 2);

        const char* As = smemc + (size_t)(kt % 3) * STGB;
        const char* Bs = As + ATSZB;

#pragma unroll
        for (int kc = 0; kc < 4; kc++) {
            const int coff = (((kc * 2 + (t >> 1)) ^ g) << 4) + ((t & 1) << 3);
            uint32_t a[4][4];
            uint32_t b[8][2];
#pragma unroll
            for (int mi = 0; mi < 4; mi++) {
                uint2 v0 = *(const uint2*)(As + (wm + mi * 16 + g) * 128 + coff);
                uint2 v1 = *(const uint2*)(As + (wm + mi * 16 + g + 8) * 128 + coff);
                a[mi][0] = v0.x; a[mi][1] = v1.x; a[mi][2] = v0.y; a[mi][3] = v1.y;
            }
#pragma unroll
            for (int ni = 0; ni < 8; ni++) {
                uint2 u = *(const uint2*)(Bs + (wn + ni * 8 + g) * 128 + coff);
                b[ni][0] = u.x; b[ni][1] = u.y;
            }
#pragma unroll
            for (int mi = 0; mi < 4; mi++)
#pragma unroll
                for (int ni = 0; ni < 8; ni++) mma_f16(acc[mi][ni], a[mi], b[ni]);
        }
    }

#pragma unroll
    for (int mi = 0; mi < 4; mi++) {
        int mr0 = m0 + wm + mi * 16 + g;
        int mr1 = mr0 + 8;
        bool ok0 = mr0 < BN, ok1 = mr1 < BN;
#pragma unroll
        for (int ni = 0; ni < 8; ni++) {
            int jj = n0 + wn + ni * 8 + 2 * t;
            float b0 = bias[jj], b1 = bias[jj + 1];
            float v00 = acc[mi][ni][0] + b0, v01 = acc[mi][ni][1] + b1;
            float v10 = acc[mi][ni][2] + b0, v11 = acc[mi][ni][3] + b1;
            if (MODE == 0) {
                int tsel = jj >> 10;
                int rr = jj & 1023;
                int head = rr >> 6;
                int d = rr & 63;
                int dperm = (d & ~15) + posj((d & 15) >> 1) * 2;
                if (ok0) {
                    int b_ = mr0 / NN, n_ = mr0 - b_ * NN;
                    int bh = b_ * NH + head;
                    if (tsel == 0) {
                        *(__half2*)&g_q[((size_t)bh * NN + n_) * HD + dperm] =
                            __floats2half2_rn(v00 * QS2, v01 * QS2);
                    } else if (tsel == 1) {
                        *(__half2*)&g_k[((size_t)bh * NN + n_) * HD + dperm] =
                            __floats2half2_rn(v00, v01);
                    } else {
                        int np = permn(n_);
                        g_vt[((size_t)bh * HD + d) * NN + np]     = __float2half_rn(v00);
                        g_vt[((size_t)bh * HD + d + 1) * NN + np] = __float2half_rn(v01);
                    }
                }
                if (ok1) {
                    int b_ = mr1 / NN, n_ = mr1 - b_ * NN;
                    int bh = b_ * NH + head;
                    if (tsel == 0) {
                        *(__half2*)&g_q[((size_t)bh * NN + n_) * HD + dperm] =
                            __floats2half2_rn(v10 * QS2, v11 * QS2);
                    } else if (tsel == 1) {
                        *(__half2*)&g_k[((size_t)bh * NN + n_) * HD + dperm] =
                            __floats2half2_rn(v10, v11);
                    } else {
                        int np = permn(n_);
                        g_vt[((size_t)bh * HD + d) * NN + np]     = __float2half_rn(v10);
                        g_vt[((size_t)bh * HD + d + 1) * NN + np] = __float2half_rn(v11);
                    }
                }
            } else {
                if (ok0) { float2 o = {v00, v01}; *(float2*)&Cout[(size_t)mr0 * CD + jj] = o; }
                if (ok1) { float2 o = {v10, v11}; *(float2*)&Cout[(size_t)mr1 * CD + jj] = o; }
            }
        }
    }
}

// ---------------- rel-pos bias via FP16 mma (fp16 outputs) --------------------
__global__ void __launch_bounds__(256) relpos_kernel(const float* __restrict__ rph,
                                                     const float* __restrict__ rpw) {
    __shared__ __align__(16) __half qp[32 * 72];
    __shared__ __align__(16) __half Bp[112 * 72];
    __shared__ float outw[32 * 60];

    const int h = blockIdx.x;
    const int bh = blockIdx.y;
    const int tid = threadIdx.x;
    const int wid = tid >> 5;
    const int lid = tid & 31;
    const int g = lid >> 2;
    const int t = lid & 3;

    {
        int r = tid >> 3, cc = tid & 7;
        uint4 v = make_uint4(0, 0, 0, 0);
        if (r < WW)
            v = *(const uint4*)&g_q[((size_t)bh * NN + h * WW + r) * HD + cc * 8];
        *(uint4*)&qp[r * 72 + cc * 8] = v;
    }
#pragma unroll
    for (int it = 0; it < 2; it++) {
        int idx = it * 256 + tid;
        if (idx < 448) {
            int r = idx >> 2, grp = idx & 3;
            float4 A = {0,0,0,0}, B = {0,0,0,0}, C = {0,0,0,0}, D = {0,0,0,0};
            const float* sp = nullptr;
            if (r < 56)       sp = rph + (size_t)(h + 55 - r) * HD + grp * 16;
            else if (r < 111) sp = rpw + (size_t)(r - 56) * HD + grp * 16;
            if (sp) { A = ((const float4*)sp)[0]; B = ((const float4*)sp)[1];
                      C = ((const float4*)sp)[2]; D = ((const float4*)sp)[3]; }
            *(uint4*)&Bp[r * 72 + grp * 16] =
                make_uint4(packh2(A.x, A.y), packh2(C.x, C.y),
                           packh2(A.z, A.w), packh2(C.z, C.w));
            *(uint4*)&Bp[r * 72 + grp * 16 + 8] =
                make_uint4(packh2(B.x, B.y), packh2(D.x, D.y),
                           packh2(B.z, B.w), packh2(D.z, D.w));
        }
    }
    __syncthreads();

    for (int ti = wid; ti < 14; ti += 8) {
        float c[2][4];
#pragma unroll
        for (int mi = 0; mi < 2; mi++)
#pragma unroll
            for (int e = 0; e < 4; e++) c[mi][e] = 0.f;
#pragma unroll
        for (int kc = 0; kc < 4; kc++) {
            int qo = kc * 16 + t * 4;
            uint2 v0 = *(const uint2*)&qp[g * 72 + qo];
            uint2 v1 = *(const uint2*)&qp[(g + 8) * 72 + qo];
            uint2 v2 = *(const uint2*)&qp[(16 + g) * 72 + qo];
            uint2 v3 = *(const uint2*)&qp[(24 + g) * 72 + qo];
            uint32_t a0[4] = {v0.x, v1.x, v0.y, v1.y};
            uint32_t a1[4] = {v2.x, v3.x, v2.y, v3.y};
            uint2 u = *(const uint2*)&Bp[(ti * 8 + g) * 72 + qo];
            uint32_t b[2] = {u.x, u.y};
            mma_f16(c[0], a0, b);
            mma_f16(c[1], a1, b);
        }
        if (ti < 7) {
            int kh0 = ti * 8 + 2 * t, kh1 = kh0 + 1;
            size_t nb = (size_t)(bh * NN) + h * WW;
            g_relh16[(nb + g) * HH + kh0]      = __float2half_rn(c[0][0] * 8.f);
            g_relh16[(nb + g) * HH + kh1]      = __float2half_rn(c[0][1] * 8.f);
            g_relh16[(nb + g + 8) * HH + kh0]  = __float2half_rn(c[0][2] * 8.f);
            g_relh16[(nb + g + 8) * HH + kh1]  = __float2half_rn(c[0][3] * 8.f);
            g_relh16[(nb + 16 + g) * HH + kh0] = __float2half_rn(c[1][0] * 8.f);
            g_relh16[(nb + 16 + g) * HH + kh1] = __float2half_rn(c[1][1] * 8.f);
            if (g < 4) {
                g_relh16[(nb + 24 + g) * HH + kh0] = __float2half_rn(c[1][2] * 8.f);
                g_relh16[(nb + 24 + g) * HH + kh1] = __float2half_rn(c[1][3] * 8.f);
            }
        } else {
            int cb = (ti - 7) * 8 + 2 * t;
            outw[g * 60 + cb] = c[0][0];        outw[g * 60 + cb + 1] = c[0][1];
            outw[(g + 8) * 60 + cb] = c[0][2];  outw[(g + 8) * 60 + cb + 1] = c[0][3];
            outw[(16 + g) * 60 + cb] = c[1][0]; outw[(16 + g) * 60 + cb + 1] = c[1][1];
            outw[(24 + g) * 60 + cb] = c[1][2]; outw[(24 + g) * 60 + cb + 1] = c[1][3];
        }
    }
    __syncthreads();

    for (int idx = tid; idx < WW * WW; idx += 256) {
        int w = idx / WW, kw = idx - w * WW;
        g_relw16[((size_t)(bh * NN) + h * WW + w) * 32 + kw] =
            __float2half_rn(outw[w * 60 + (w - kw + 27)] * 8.f);
    }
}

// ------- flash v11: fp16 bias tables, bias folded into packed exp ------------
#define FPH 72    // halves pitch (144B rows) for q/k/v
#define RWP 40    // rw16 smem pitch in halves (80B rows, conflict-free)

struct F11Smem {
    __align__(16) __half qs[128 * FPH];
    __align__(16) __half kt[2][64 * FPH];
    __align__(16) __half vs[2][64 * FPH];
    __align__(16) __half rh16[128 * HH];   // 56 halves/row (112B, 16B-mult)
    __align__(16) __half rw16[128 * RWP];  // first 28 valid, loaded into [0,32)
};

__global__ void __launch_bounds__(128, 2) flash11_kernel() {
    extern __shared__ char raw[];
    F11Smem& s = *reinterpret_cast<F11Smem*>(raw);

    const int bh = blockIdx.y;
    const int qt0 = blockIdx.x;
    const int tid = threadIdx.x;
    const int wid = tid >> 5;
    const int lid = tid & 31;
    const int g = lid >> 2;
    const int t = lid & 3;
    const int wm = wid * 32;
    const int rows[4] = {wm + g, wm + g + 8, wm + g + 16, wm + g + 24};

    const uint32_t qaddr = smem_u32(s.qs);
    const uint32_t kaddr = smem_u32(s.kt);
    const uint32_t vaddr = smem_u32(s.vs);
    const uint32_t rhaddr = smem_u32(s.rh16);
    const uint32_t rwaddr = smem_u32(s.rw16);

    // ---- prologue group: Q + rh16 + rw16 ----
#pragma unroll
    for (int it = 0; it < 8; it++) {
        int idx = it * 128 + tid;
        int r = idx >> 3, cc = idx & 7;
        int n = qt0 * 128 + r;
        const __half* src = g_q + (n < NN ? (size_t)(bh * NN + n) * HD + cc * 8 : 0);
        cpa16(qaddr + (uint32_t)(r * 144 + cc * 16), src, n < NN ? 16u : 0u);
    }
#pragma unroll
    for (int it = 0; it < 7; it++) {
        int idx = it * 128 + tid;
        int r = idx / 7, cc = idx % 7;          // 128 rows x 7 chunks (112B)
        int n = qt0 * 128 + r;
        const __half* src = g_relh16 + (n < NN ? (size_t)(bh * NN + n) * HH + cc * 8 : 0);
        cpa16(rhaddr + (uint32_t)(r * 112 + cc * 16), src, n < NN ? 16u : 0u);
    }
#pragma unroll
    for (int it = 0; it < 4; it++) {
        int idx = it * 128 + tid;
        int r = idx >> 2, cc = idx & 3;         // 128 rows x 4 chunks (64B of 80B row)
        int n = qt0 * 128 + r;
        const __half* src = g_relw16 + (n < NN ? (size_t)(bh * NN + n) * 32 + cc * 8 : 0);
        cpa16(rwaddr + (uint32_t)(r * 80 + cc * 16), src, n < NN ? 16u : 0u);
    }
    CPA_COMMIT();

    auto issueKV = [&](int j) {
        const int kb = j * 64;
        const uint32_t ka = kaddr + (uint32_t)((j & 1) * 64 * 144);
        const uint32_t va = vaddr + (uint32_t)((j & 1) * 64 * 144);
#pragma unroll
        for (int it = 0; it < 4; it++) {
            int idx = it * 128 + tid;
            int r = idx >> 3, cc = idx & 7;
            int kn = kb + r;
            bool ok = kn < NN;
            const __half* src = g_k + (ok ? (size_t)(bh * NN + kn) * HD + cc * 8 : 0);
            cpa16(ka + (uint32_t)(r * 144 + cc * 16), src, ok ? 16u : 0u);
        }
#pragma unroll
        for (int it = 0; it < 4; it++) {
            int idx = it * 128 + tid;
            int r = idx >> 3, cc = idx & 7;
            bool ok = (kb + cc * 8 + 8) <= NN;
            const __half* src = g_vt + (ok ? (size_t)(bh * HD + r) * NN + kb + cc * 8 : 0);
            cpa16(va + (uint32_t)(r * 144 + cc * 16), src, ok ? 16u : 0u);
        }
        CPA_COMMIT();
    };

    issueKV(0);
    issueKV(1);

    // ---- wait for prologue only; compute per-row bias upper bounds ----
    CPA_WAIT2();
    __syncthreads();
    float bmax[4];
#pragma unroll
    for (int j = 0; j < 4; j++) {
        int r = rows[j];
        float mh = -1e30f, mw = -1e30f;
        for (int kh = 0; kh < HH; kh++)
            mh = fmaxf(mh, __half2float(s.rh16[r * HH + kh]));
        for (int kw = 0; kw < WW; kw++)
            mw = fmaxf(mw, __half2float(s.rw16[r * RWP + kw]));
        bmax[j] = mh + mw;
    }

    float acc[2][8][4];
#pragma unroll
    for (int m = 0; m < 2; m++)
#pragma unroll
        for (int ni = 0; ni < 8; ni++)
#pragma unroll
            for (int e = 0; e < 4; e++) acc[m][ni][e] = 0.f;
    float accL[2][4] = {{0.f, 0.f, 0.f, 0.f}, {0.f, 0.f, 0.f, 0.f}};
    float rowm[4] = {-1e30f, -1e30f, -1e30f, -1e30f};

    const uint32_t ONES2 = 0x3C003C00u;

    for (int kt2 = 0; kt2 < 25; kt2++) {
        const int kbase = kt2 * 64;
        const int p = kt2 & 1;

        if (kt2 < 24) CPA_WAIT1(); else CPA_WAIT0();
        __syncthreads();   // (1) K/V visible

        const char* ktp = (const char*)s.kt[p];
        const char* vsp = (const char*)s.vs[p];

        // ---- QK^T mma: two m16 tiles per warp ----
        float c[2][8][4];
#pragma unroll
        for (int m = 0; m < 2; m++)
#pragma unroll
            for (int ni = 0; ni < 8; ni++)
#pragma unroll
                for (int e = 0; e < 4; e++) c[m][ni][e] = 0.f;
#pragma unroll
        for (int kc = 0; kc < 4; kc++) {
            const int qo = kc * 32 + t * 8;
            uint2 v0 = *(const uint2*)((const char*)s.qs + rows[0] * 144 + qo);
            uint2 v1 = *(const uint2*)((const char*)s.qs + rows[1] * 144 + qo);
            uint2 v2 = *(const uint2*)((const char*)s.qs + rows[2] * 144 + qo);
            uint2 v3 = *(const uint2*)((const char*)s.qs + rows[3] * 144 + qo);
            uint32_t a0[4] = {v0.x, v1.x, v0.y, v1.y};
            uint32_t a1[4] = {v2.x, v3.x, v2.y, v3.y};
#pragma unroll
            for (int ni = 0; ni < 8; ni++) {
                uint2 u = *(const uint2*)(ktp + (ni * 8 + g) * 144 + qo);
                uint32_t b[2] = {u.x, u.y};
                mma_f16(c[0][ni], a0, b);
                mma_f16(c[1][ni], a1, b);
            }
        }

        // ---- in-warp max of pure qk; rows j: 0->rA0,1->rA1,2->rB0,3->rB1 ----
        float tm[4] = {-1e30f, -1e30f, -1e30f, -1e30f};
#pragma unroll
        for (int ni = 0; ni < 8; ni++) {
            tm[0] = fmaxf(tm[0], fmaxf(c[0][ni][0], c[0][ni][1]));
            tm[1] = fmaxf(tm[1], fmaxf(c[0][ni][2], c[0][ni][3]));
            tm[2] = fmaxf(tm[2], fmaxf(c[1][ni][0], c[1][ni][1]));
            tm[3] = fmaxf(tm[3], fmaxf(c[1][ni][2], c[1][ni][3]));
        }
        float mn[4], fac[4];
#pragma unroll
        for (int j = 0; j < 4; j++) {
            float v = tm[j];
            v = fmaxf(v, __shfl_xor_sync(0xffffffffu, v, 1));
            v = fmaxf(v, __shfl_xor_sync(0xffffffffu, v, 2));
            mn[j] = fmaxf(rowm[j], v + bmax[j]);
            fac[j] = fexp2(rowm[j] - mn[j]);
            rowm[j] = mn[j];
        }

        // ---- P = exp2(c + bias - mn), bias added in fp16 ----
        uint32_t pf[2][8][2];
#pragma unroll
        for (int ni = 0; ni < 8; ni++) {
            int kn0 = kbase + ni * 8 + 2 * t;            // always even; kw0 <= 26
            int kh = ((kn0 >> 2) * 9363) >> 16;          // kn0/28 exact
            int kw = kn0 - kh * 28;
#pragma unroll
            for (int m = 0; m < 2; m++) {
                int r0 = rows[2 * m], r1 = rows[2 * m + 1];
                float mn0 = mn[2 * m], mn1 = mn[2 * m + 1];
                uint32_t rw0 = *(const uint32_t*)&s.rw16[r0 * RWP + kw];
                uint32_t rw1 = *(const uint32_t*)&s.rw16[r1 * RWP + kw];
                uint32_t b0 = h2add(hdup(s.rh16[r0 * HH + kh]), rw0);
                uint32_t b1 = h2add(hdup(s.rh16[r1 * HH + kh]), rw1);
                pf[m][ni][0] = h2exp2(h2add(packh2(c[m][ni][0] - mn0, c[m][ni][1] - mn0), b0));
                pf[m][ni][1] = h2exp2(h2add(packh2(c[m][ni][2] - mn1, c[m][ni][3] - mn1), b1));
            }
            if (kbase + ni * 8 >= NN) {                  // last-tile whole-ni mask
                pf[0][ni][0] = 0; pf[0][ni][1] = 0;
                pf[1][ni][0] = 0; pf[1][ni][1] = 0;
            }
        }

        // ---- rescale accumulators ----
#pragma unroll
        for (int ni = 0; ni < 8; ni++) {
            acc[0][ni][0] *= fac[0]; acc[0][ni][1] *= fac[0];
            acc[0][ni][2] *= fac[1]; acc[0][ni][3] *= fac[1];
            acc[1][ni][0] *= fac[2]; acc[1][ni][1] *= fac[2];
            acc[1][ni][2] *= fac[3]; acc[1][ni][3] *= fac[3];
        }
        accL[0][0] *= fac[0]; accL[0][1] *= fac[0];
        accL[0][2] *= fac[1]; accL[0][3] *= fac[1];
        accL[1][0] *= fac[2]; accL[1][1] *= fac[2];
        accL[1][2] *= fac[3]; accL[1][3] *= fac[3];

        // ---- P @ V (+ ones column for row sums) ----
#pragma unroll
        for (int kc = 0; kc < 4; kc++) {
            uint32_t a0[4] = {pf[0][2 * kc][0], pf[0][2 * kc][1],
                              pf[0][2 * kc + 1][0], pf[0][2 * kc + 1][1]};
            uint32_t a1[4] = {pf[1][2 * kc][0], pf[1][2 * kc][1],
                              pf[1][2 * kc + 1][0], pf[1][2 * kc + 1][1]};
            const int vo = kc * 32 + t * 8;
#pragma unroll
            for (int ni = 0; ni < 8; ni++) {
                uint2 u = *(const uint2*)(vsp + (ni * 8 + g) * 144 + vo);
                uint32_t b[2] = {u.x, u.y};
                mma_f16(acc[0][ni], a0, b);
                mma_f16(acc[1][ni], a1, b);
            }
            uint32_t bo[2] = {ONES2, ONES2};
            mma_f16(accL[0], a0, bo);
            mma_f16(accL[1], a1, bo);
        }

        __syncthreads();   // (2) all readers of buffer p done
        if (kt2 + 2 < 25) issueKV(kt2 + 2);
    }

    // ---- normalize + store g_ao (fp16, k-permuted) ----
    const int b = bh >> 4;
    const int head = bh & 15;
    const int nrow[4] = {qt0 * 128 + rows[0], qt0 * 128 + rows[1],
                         qt0 * 128 + rows[2], qt0 * 128 + rows[3]};
    const float li[4] = {1.f / accL[0][0], 1.f / accL[0][2],
                         1.f / accL[1][0], 1.f / accL[1][2]};
#pragma unroll
    for (int ni = 0; ni < 8; ni++) {
        int col = head * HD + ni * 8 + 2 * t;
        int colp = (col & ~15) + posj((col & 15) >> 1) * 2;
#pragma unroll
        for (int j = 0; j < 4; j++) {
            if (nrow[j] < NN) {
                int m = j >> 1, eo = (j & 1) * 2;
                *(__half2*)&g_ao[(size_t)(b * NN + nrow[j]) * CD + colp] =
                    __floats2half2_rn(acc[m][ni][eo] * li[j], acc[m][ni][eo + 1] * li[j]);
            }
        }
    }
}

// ---------------- launch -----------------------------------------------------
extern "C" void kernel_launch(void* const* d_in, const int* in_sizes, int n_in,
                              void* d_out, int out_size) {
    const float* hidden = (const float*)d_in[0];
    const float* qkv_w  = (const float*)d_in[1];
    const float* qkv_b  = (const float*)d_in[2];
    const float* proj_w = (const float*)d_in[3];
    const float* proj_b = (const float*)d_in[4];
    const float* rph    = (const float*)d_in[5];
    const float* rpw    = (const float*)d_in[6];
    float* out = (float*)d_out;

    cudaFuncSetAttribute(flash11_kernel, cudaFuncAttributeMaxDynamicSharedMemorySize,
                         (int)sizeof(F11Smem));
    cudaFuncSetAttribute(mm_cp<0>, cudaFuncAttributeMaxDynamicSharedMemorySize, MM_SMEM);
    cudaFuncSetAttribute(mm_cp<1>, cudaFuncAttributeMaxDynamicSharedMemorySize, MM_SMEM);

    const int ptot = PREP_N1 + PREP_N2 + PREP_N3;
    prep_all<<<(ptot + 255) / 256, 256>>>(hidden, qkv_w, proj_w);

    // QKV: [6272,3072] = hidden . qkv_w^T
    mm_cp<0><<<dim3(3 * CD / 128, (BN + 255) / 256), 256, MM_SMEM>>>(qkv_b, nullptr);

    relpos_kernel<<<dim3(HH, BHN), 256>>>(rph, rpw);

    flash11_kernel<<<dim3((NN + 127) / 128, BHN), 128, sizeof(F11Smem)>>>();

    // proj: [6272,1024] = g_ao . proj_w^T
    mm_cp<1><<<dim3(CD / 128, (BN + 255) / 256), 256, MM_SMEM>>>(proj_b, out);
}

// round 15
// speedup vs baseline: 7.5136x; 1.0687x over previous
#include <cuda_runtime.h>
#include <cuda_fp16.h>
#include <cstdint>

#define NH   16
#define HD   64
#define CD   1024
#define BB   4
#define HH   56
#define WW   28
#define NN   1568          // HH*WW
#define BHN  64            // BB*NH
#define BN   6272          // BB*NN
#define QSCALE 0.125f      // 64^-0.5
#define QS2   0.1803368801f // QSCALE * log2(e)

// ---------------- scratch (device globals; no allocations allowed) ----------
__device__ __half g_q[BHN * NN * HD];     // fp16, NATURAL d order, pre-scaled by QS2
__device__ __half g_k[BHN * NN * HD];     // fp16, NATURAL
__device__ __half g_vt[BHN * HD * NN];    // fp16, transposed [bh][d][n], NATURAL n
__device__ __half g_relh16[BHN * NN * HH];   // log2e units, fp16
__device__ __half g_relw16[BHN * NN * 32];   // log2e units, fp16, rows padded to 32
__device__ __half g_ao[BN * CD];          // fp16, k-permuted, [B,N,heads,d]
__device__ __half g_hp[BN * CD];          // prepped (tf-perm) for mm
__device__ __half g_wp[3 * CD * CD];
__device__ __half g_pwp[CD * CD];

// ---------------- helpers ----------------------------------------------------
__device__ __forceinline__ uint32_t packh2(float a, float b) {
    __half2 h = __floats2half2_rn(a, b);
    return *reinterpret_cast<uint32_t*>(&h);
}
__device__ __forceinline__ uint32_t h2exp2(uint32_t x) {
    uint32_t r;
    asm("ex2.approx.f16x2 %0, %1;" : "=r"(r) : "r"(x));
    return r;
}
__device__ __forceinline__ float fexp2(float x) {
    float r;
    asm("ex2.approx.ftz.f32 %0, %1;" : "=f"(r) : "f"(x));
    return r;
}
__device__ __forceinline__ uint32_t h2add(uint32_t a, uint32_t b) {
    __half2 r = __hadd2(*reinterpret_cast<__half2*>(&a), *reinterpret_cast<__half2*>(&b));
    return *reinterpret_cast<uint32_t*>(&r);
}
__device__ __forceinline__ uint32_t hdup(__half h) {
    __half2 r = __half2half2(h);
    return *reinterpret_cast<uint32_t*>(&r);
}

__device__ __forceinline__ void mma_f16(float* c, const uint32_t* a, const uint32_t* b) {
    asm volatile(
        "mma.sync.aligned.m16n8k16.row.col.f32.f16.f16.f32 "
        "{%0,%1,%2,%3}, {%4,%5,%6,%7}, {%8,%9}, {%0,%1,%2,%3};"
        : "+f"(c[0]), "+f"(c[1]), "+f"(c[2]), "+f"(c[3])
        : "r"(a[0]), "r"(a[1]), "r"(a[2]), "r"(a[3]), "r"(b[0]), "r"(b[1]));
}

__device__ __forceinline__ void ldsm4(uint32_t* r, uint32_t addr) {
    asm volatile("ldmatrix.sync.aligned.m8n8.x4.shared.b16 {%0,%1,%2,%3}, [%4];"
        : "=r"(r[0]), "=r"(r[1]), "=r"(r[2]), "=r"(r[3]) : "r"(addr));
}

__device__ __forceinline__ uint32_t smem_u32(const void* p) {
    uint32_t a;
    asm("{ .reg .u64 t; cvta.to.shared.u64 t, %1; cvt.u32.u64 %0, t; }"
        : "=r"(a) : "l"(p));
    return a;
}

__device__ __forceinline__ void cpa16(uint32_t dst, const void* src, uint32_t srcsize) {
    asm volatile("cp.async.cg.shared.global [%0], [%1], 16, %2;"
                 :: "r"(dst), "l"(src), "r"(srcsize) : "memory");
}
#define CPA_COMMIT() asm volatile("cp.async.commit_group;" ::: "memory")
#define CPA_WAIT0()  asm volatile("cp.async.wait_group 0;" ::: "memory")
#define CPA_WAIT1()  asm volatile("cp.async.wait_group 1;" ::: "memory")
#define CPA_WAIT2()  asm volatile("cp.async.wait_group 2;" ::: "memory")

__device__ __forceinline__ int posj(int j) { return (j < 4) ? 2 * j : 2 * j - 7; }

// ---------------- prep: f32 -> fp16, half2-unit interleave per 16 ------------
#define PREP_N1 (BN * CD / 16)
#define PREP_N2 (3 * CD * CD / 16)
#define PREP_N3 (CD * CD / 16)

__global__ void __launch_bounds__(256) prep_all(const float* __restrict__ hidden,
                                                const float* __restrict__ w1,
                                                const float* __restrict__ w2) {
    int i = blockIdx.x * 256 + threadIdx.x;
    const float* src;
    __half* dst;
    if (i < PREP_N1) { src = hidden + (size_t)i * 16; dst = g_hp + (size_t)i * 16; }
    else if (i < PREP_N1 + PREP_N2) {
        int j = i - PREP_N1; src = w1 + (size_t)j * 16; dst = g_wp + (size_t)j * 16;
    } else if (i < PREP_N1 + PREP_N2 + PREP_N3) {
        int j = i - PREP_N1 - PREP_N2; src = w2 + (size_t)j * 16; dst = g_pwp + (size_t)j * 16;
    } else return;
    const float4* s = (const float4*)src;
    float4 A = s[0], B = s[1], C = s[2], D = s[3];
    uint4* d = (uint4*)dst;
    d[0] = make_uint4(packh2(A.x, A.y), packh2(C.x, C.y),
                      packh2(A.z, A.w), packh2(C.z, C.w));
    d[1] = make_uint4(packh2(B.x, B.y), packh2(D.x, D.y),
                      packh2(B.z, B.w), packh2(D.z, D.w));
}

// ================== cp.async 3-stage FP16 GEMM, 256x128 tile, BK=64 ==========
#define ATSZB (256 * 128)
#define BTSZB (128 * 128)
#define STGB  (ATSZB + BTSZB)
#define MM_SMEM (3 * STGB)

template <int MODE>
__global__ void __launch_bounds__(256, 1) mm_cp(const float* __restrict__ bias,
                                                float* __restrict__ Cout) {
    extern __shared__ char smemc[];
    uint32_t sb = smem_u32(smemc);
    const __half* A  = (MODE == 0) ? g_hp : g_ao;
    const __half* Bm = (MODE == 0) ? g_wp : g_pwp;

    const int tid = threadIdx.x;
    const int wid = tid >> 5;
    const int lid = tid & 31;
    const int g = lid >> 2;
    const int t = lid & 3;
    const int m0 = blockIdx.y * 256;
    const int n0 = blockIdx.x * 128;
    const int wm = (wid & 3) * 64;
    const int wn = (wid >> 2) * 64;

    float acc[4][8][4];
#pragma unroll
    for (int mi = 0; mi < 4; mi++)
#pragma unroll
        for (int ni = 0; ni < 8; ni++)
#pragma unroll
            for (int e = 0; e < 4; e++) acc[mi][ni][e] = 0.f;

    const int lr = tid >> 3;
    const int lq = tid & 7;
    const uint32_t ldst = (uint32_t)(lr * 128 + ((lq ^ (lr & 7)) << 4));

    auto issue = [&](int kt) {
        const int st = kt % 3;
        const int k0 = kt * 64;
        uint32_t ab = sb + (uint32_t)st * STGB;
        uint32_t bb = ab + ATSZB;
#pragma unroll
        for (int it = 0; it < 8; it++) {
            int r = lr + it * 32;
            int gr = m0 + r;
            bool ok = gr < BN;
            cpa16(ab + ldst + (uint32_t)(it * 32 * 128),
                  A + (ok ? (size_t)gr * CD + k0 + lq * 8 : 0), ok ? 16u : 0u);
        }
#pragma unroll
        for (int it = 0; it < 4; it++) {
            int r = lr + it * 32;
            cpa16(bb + ldst + (uint32_t)(it * 32 * 128),
                  Bm + (size_t)(n0 + r) * CD + k0 + lq * 8, 16);
        }
        CPA_COMMIT();
    };

    issue(0); issue(1);
    for (int kt = 0; kt < 16; kt++) {
        if (kt < 15) CPA_WAIT1(); else CPA_WAIT0();
        __syncthreads();
        if (kt + 2 < 16) issue(kt + 2);

        const char* As = smemc + (size_t)(kt % 3) * STGB;
        const char* Bs = As + ATSZB;

#pragma unroll
        for (int kc = 0; kc < 4; kc++) {
            const int coff = (((kc * 2 + (t >> 1)) ^ g) << 4) + ((t & 1) << 3);
            uint32_t a[4][4];
            uint32_t b[8][2];
#pragma unroll
            for (int mi = 0; mi < 4; mi++) {
                uint2 v0 = *(const uint2*)(As + (wm + mi * 16 + g) * 128 + coff);
                uint2 v1 = *(const uint2*)(As + (wm + mi * 16 + g + 8) * 128 + coff);
                a[mi][0] = v0.x; a[mi][1] = v1.x; a[mi][2] = v0.y; a[mi][3] = v1.y;
            }
#pragma unroll
            for (int ni = 0; ni < 8; ni++) {
                uint2 u = *(const uint2*)(Bs + (wn + ni * 8 + g) * 128 + coff);
                b[ni][0] = u.x; b[ni][1] = u.y;
            }
#pragma unroll
            for (int mi = 0; mi < 4; mi++)
#pragma unroll
                for (int ni = 0; ni < 8; ni++) mma_f16(acc[mi][ni], a[mi], b[ni]);
        }
    }

#pragma unroll
    for (int mi = 0; mi < 4; mi++) {
        int mr0 = m0 + wm + mi * 16 + g;
        int mr1 = mr0 + 8;
        bool ok0 = mr0 < BN, ok1 = mr1 < BN;
#pragma unroll
        for (int ni = 0; ni < 8; ni++) {
            int jj = n0 + wn + ni * 8 + 2 * t;
            float b0 = bias[jj], b1 = bias[jj + 1];
            float v00 = acc[mi][ni][0] + b0, v01 = acc[mi][ni][1] + b1;
            float v10 = acc[mi][ni][2] + b0, v11 = acc[mi][ni][3] + b1;
            if (MODE == 0) {
                int tsel = jj >> 10;
                int rr = jj & 1023;
                int head = rr >> 6;
                int d = rr & 63;
                if (ok0) {
                    int b_ = mr0 / NN, n_ = mr0 - b_ * NN;
                    int bh = b_ * NH + head;
                    if (tsel == 0) {
                        *(__half2*)&g_q[((size_t)bh * NN + n_) * HD + d] =
                            __floats2half2_rn(v00 * QS2, v01 * QS2);
                    } else if (tsel == 1) {
                        *(__half2*)&g_k[((size_t)bh * NN + n_) * HD + d] =
                            __floats2half2_rn(v00, v01);
                    } else {
                        g_vt[((size_t)bh * HD + d) * NN + n_]     = __float2half_rn(v00);
                        g_vt[((size_t)bh * HD + d + 1) * NN + n_] = __float2half_rn(v01);
                    }
                }
                if (ok1) {
                    int b_ = mr1 / NN, n_ = mr1 - b_ * NN;
                    int bh = b_ * NH + head;
                    if (tsel == 0) {
                        *(__half2*)&g_q[((size_t)bh * NN + n_) * HD + d] =
                            __floats2half2_rn(v10 * QS2, v11 * QS2);
                    } else if (tsel == 1) {
                        *(__half2*)&g_k[((size_t)bh * NN + n_) * HD + d] =
                            __floats2half2_rn(v10, v11);
                    } else {
                        g_vt[((size_t)bh * HD + d) * NN + n_]     = __float2half_rn(v10);
                        g_vt[((size_t)bh * HD + d + 1) * NN + n_] = __float2half_rn(v11);
                    }
                }
            } else {
                if (ok0) { float2 o = {v00, v01}; *(float2*)&Cout[(size_t)mr0 * CD + jj] = o; }
                if (ok1) { float2 o = {v10, v11}; *(float2*)&Cout[(size_t)mr1 * CD + jj] = o; }
            }
        }
    }
}

// ---------------- rel-pos bias via FP16 mma (fp16 outputs) --------------------
// g_q is now NATURAL: permute it during qp staging (Bp stays permuted).
__global__ void __launch_bounds__(256) relpos_kernel(const float* __restrict__ rph,
                                                     const float* __restrict__ rpw) {
    __shared__ __align__(16) __half qp[32 * 72];
    __shared__ __align__(16) __half Bp[112 * 72];
    __shared__ float outw[32 * 60];

    const int h = blockIdx.x;
    const int bh = blockIdx.y;
    const int tid = threadIdx.x;
    const int wid = tid >> 5;
    const int lid = tid & 31;
    const int g = lid >> 2;
    const int t = lid & 3;

    if (tid < 128) {
        int r = tid >> 2, grp = tid & 3;
        uint4 A4 = make_uint4(0, 0, 0, 0), B4 = A4;
        if (r < WW) {
            const uint4* sp = (const uint4*)&g_q[((size_t)bh * NN + h * WW + r) * HD + grp * 16];
            A4 = sp[0]; B4 = sp[1];
        }
        uint4 o0 = make_uint4(A4.x, B4.x, A4.y, B4.y);
        uint4 o1 = make_uint4(A4.z, B4.z, A4.w, B4.w);
        *(uint4*)&qp[r * 72 + grp * 16] = o0;
        *(uint4*)&qp[r * 72 + grp * 16 + 8] = o1;
    }
#pragma unroll
    for (int it = 0; it < 2; it++) {
        int idx = it * 256 + tid;
        if (idx < 448) {
            int r = idx >> 2, grp = idx & 3;
            float4 A = {0,0,0,0}, B = {0,0,0,0}, C = {0,0,0,0}, D = {0,0,0,0};
            const float* sp = nullptr;
            if (r < 56)       sp = rph + (size_t)(h + 55 - r) * HD + grp * 16;
            else if (r < 111) sp = rpw + (size_t)(r - 56) * HD + grp * 16;
            if (sp) { A = ((const float4*)sp)[0]; B = ((const float4*)sp)[1];
                      C = ((const float4*)sp)[2]; D = ((const float4*)sp)[3]; }
            *(uint4*)&Bp[r * 72 + grp * 16] =
                make_uint4(packh2(A.x, A.y), packh2(C.x, C.y),
                           packh2(A.z, A.w), packh2(C.z, C.w));
            *(uint4*)&Bp[r * 72 + grp * 16 + 8] =
                make_uint4(packh2(B.x, B.y), packh2(D.x, D.y),
                           packh2(B.z, B.w), packh2(D.z, D.w));
        }
    }
    __syncthreads();

    for (int ti = wid; ti < 14; ti += 8) {
        float c[2][4];
#pragma unroll
        for (int mi = 0; mi < 2; mi++)
#pragma unroll
            for (int e = 0; e < 4; e++) c[mi][e] = 0.f;
#pragma unroll
        for (int kc = 0; kc < 4; kc++) {
            int qo = kc * 16 + t * 4;
            uint2 v0 = *(const uint2*)&qp[g * 72 + qo];
            uint2 v1 = *(const uint2*)&qp[(g + 8) * 72 + qo];
            uint2 v2 = *(const uint2*)&qp[(16 + g) * 72 + qo];
            uint2 v3 = *(const uint2*)&qp[(24 + g) * 72 + qo];
            uint32_t a0[4] = {v0.x, v1.x, v0.y, v1.y};
            uint32_t a1[4] = {v2.x, v3.x, v2.y, v3.y};
            uint2 u = *(const uint2*)&Bp[(ti * 8 + g) * 72 + qo];
            uint32_t b[2] = {u.x, u.y};
            mma_f16(c[0], a0, b);
            mma_f16(c[1], a1, b);
        }
        if (ti < 7) {
            int kh0 = ti * 8 + 2 * t, kh1 = kh0 + 1;
            size_t nb = (size_t)(bh * NN) + h * WW;
            g_relh16[(nb + g) * HH + kh0]      = __float2half_rn(c[0][0] * 8.f);
            g_relh16[(nb + g) * HH + kh1]      = __float2half_rn(c[0][1] * 8.f);
            g_relh16[(nb + g + 8) * HH + kh0]  = __float2half_rn(c[0][2] * 8.f);
            g_relh16[(nb + g + 8) * HH + kh1]  = __float2half_rn(c[0][3] * 8.f);
            g_relh16[(nb + 16 + g) * HH + kh0] = __float2half_rn(c[1][0] * 8.f);
            g_relh16[(nb + 16 + g) * HH + kh1] = __float2half_rn(c[1][1] * 8.f);
            if (g < 4) {
                g_relh16[(nb + 24 + g) * HH + kh0] = __float2half_rn(c[1][2] * 8.f);
                g_relh16[(nb + 24 + g) * HH + kh1] = __float2half_rn(c[1][3] * 8.f);
            }
        } else {
            int cb = (ti - 7) * 8 + 2 * t;
            outw[g * 60 + cb] = c[0][0];        outw[g * 60 + cb + 1] = c[0][1];
            outw[(g + 8) * 60 + cb] = c[0][2];  outw[(g + 8) * 60 + cb + 1] = c[0][3];
            outw[(16 + g) * 60 + cb] = c[1][0]; outw[(16 + g) * 60 + cb + 1] = c[1][1];
            outw[(24 + g) * 60 + cb] = c[1][2]; outw[(24 + g) * 60 + cb + 1] = c[1][3];
        }
    }
    __syncthreads();

    for (int idx = tid; idx < WW * WW; idx += 256) {
        int w = idx / WW, kw = idx - w * WW;
        g_relw16[((size_t)(bh * NN) + h * WW + w) * 32 + kw] =
            __float2half_rn(outw[w * 60 + (w - kw + 27)] * 8.f);
    }
}

// ------- flash v12: natural layout + ldmatrix frags + hoisted Q --------------
#define FPH 72    // halves pitch (144B rows)
#define RWP 40

struct F12Smem {
    __align__(16) __half qs[128 * FPH];
    __align__(16) __half kt[2][64 * FPH];
    __align__(16) __half vs[2][64 * FPH];
    __align__(16) __half rh16[128 * HH];
    __align__(16) __half rw16[128 * RWP];
};

__global__ void __launch_bounds__(128, 2) flash12_kernel() {
    extern __shared__ char raw[];
    F12Smem& s = *reinterpret_cast<F12Smem*>(raw);

    const int bh = blockIdx.y;
    const int qt0 = blockIdx.x;
    const int tid = threadIdx.x;
    const int wid = tid >> 5;
    const int lid = tid & 31;
    const int g = lid >> 2;
    const int t = lid & 3;
    const int wm = wid * 32;
    const int rows[4] = {wm + g, wm + g + 8, wm + g + 16, wm + g + 24};

    const uint32_t qaddr = smem_u32(s.qs);
    const uint32_t kaddr = smem_u32(s.kt);
    const uint32_t vaddr = smem_u32(s.vs);
    const uint32_t rhaddr = smem_u32(s.rh16);
    const uint32_t rwaddr = smem_u32(s.rw16);

    // per-lane ldmatrix base offsets (bytes)
    // B-operand (K/V): m0 rows l cols0 | m1 rows l cols+8 | m2 rows l+8 cols0 | m3 rows l+8 cols+8
    const uint32_t bB = (uint32_t)((lid & 7) * 144 + ((lid >> 4) & 1) * 8 * 144 +
                                   ((lid >> 3) & 1) * 16);
    // A-operand (Q): m0 rows l cols0 | m1 rows l+8 cols0 | m2 rows l cols+8 | m3 rows l+8 cols+8
    const uint32_t bA = (uint32_t)(((lid & 7) + ((lid >> 3) & 1) * 8) * 144 +
                                   ((lid >> 4) & 1) * 16);

    // ---- prologue group: Q + rh16 + rw16 ----
#pragma unroll
    for (int it = 0; it < 8; it++) {
        int idx = it * 128 + tid;
        int r = idx >> 3, cc = idx & 7;
        int n = qt0 * 128 + r;
        const __half* src = g_q + (n < NN ? (size_t)(bh * NN + n) * HD + cc * 8 : 0);
        cpa16(qaddr + (uint32_t)(r * 144 + cc * 16), src, n < NN ? 16u : 0u);
    }
#pragma unroll
    for (int it = 0; it < 7; it++) {
        int idx = it * 128 + tid;
        int r = idx / 7, cc = idx % 7;
        int n = qt0 * 128 + r;
        const __half* src = g_relh16 + (n < NN ? (size_t)(bh * NN + n) * HH + cc * 8 : 0);
        cpa16(rhaddr + (uint32_t)(r * 112 + cc * 16), src, n < NN ? 16u : 0u);
    }
#pragma unroll
    for (int it = 0; it < 4; it++) {
        int idx = it * 128 + tid;
        int r = idx >> 2, cc = idx & 3;
        int n = qt0 * 128 + r;
        const __half* src = g_relw16 + (n < NN ? (size_t)(bh * NN + n) * 32 + cc * 8 : 0);
        cpa16(rwaddr + (uint32_t)(r * 80 + cc * 16), src, n < NN ? 16u : 0u);
    }
    CPA_COMMIT();

    auto issueKV = [&](int j) {
        const int kb = j * 64;
        const uint32_t ka = kaddr + (uint32_t)((j & 1) * 64 * 144);
        const uint32_t va = vaddr + (uint32_t)((j & 1) * 64 * 144);
#pragma unroll
        for (int it = 0; it < 4; it++) {
            int idx = it * 128 + tid;
            int r = idx >> 3, cc = idx & 7;
            int kn = kb + r;
            bool ok = kn < NN;
            const __half* src = g_k + (ok ? (size_t)(bh * NN + kn) * HD + cc * 8 : 0);
            cpa16(ka + (uint32_t)(r * 144 + cc * 16), src, ok ? 16u : 0u);
        }
#pragma unroll
        for (int it = 0; it < 4; it++) {
            int idx = it * 128 + tid;
            int r = idx >> 3, cc = idx & 7;
            bool ok = (kb + cc * 8 + 8) <= NN;
            const __half* src = g_vt + (ok ? (size_t)(bh * HD + r) * NN + kb + cc * 8 : 0);
            cpa16(va + (uint32_t)(r * 144 + cc * 16), src, ok ? 16u : 0u);
        }
        CPA_COMMIT();
    };

    issueKV(0);
    issueKV(1);

    // ---- wait for prologue; bias bounds + hoisted Q fragments ----
    CPA_WAIT2();
    __syncthreads();
    float bmax[4];
#pragma unroll
    for (int j = 0; j < 4; j++) {
        int r = rows[j];
        float mh = -1e30f, mw = -1e30f;
        for (int kh = 0; kh < HH; kh++)
            mh = fmaxf(mh, __half2float(s.rh16[r * HH + kh]));
        for (int kw = 0; kw < WW; kw++)
            mw = fmaxf(mw, __half2float(s.rw16[r * RWP + kw]));
        bmax[j] = mh + mw;
    }
    uint32_t qf[4][2][4];
#pragma unroll
    for (int kc = 0; kc < 4; kc++)
#pragma unroll
        for (int m = 0; m < 2; m++)
            ldsm4(qf[kc][m], qaddr + (uint32_t)((wm + m * 16) * 144 + kc * 32) + bA);

    float acc[2][8][4];
#pragma unroll
    for (int m = 0; m < 2; m++)
#pragma unroll
        for (int ni = 0; ni < 8; ni++)
#pragma unroll
            for (int e = 0; e < 4; e++) acc[m][ni][e] = 0.f;
    float accL[2][4] = {{0.f, 0.f, 0.f, 0.f}, {0.f, 0.f, 0.f, 0.f}};
    float rowm[4] = {-1e30f, -1e30f, -1e30f, -1e30f};

    const uint32_t ONES2 = 0x3C003C00u;

    for (int kt2 = 0; kt2 < 25; kt2++) {
        const int kbase = kt2 * 64;
        const int p = kt2 & 1;

        if (kt2 < 24) CPA_WAIT1(); else CPA_WAIT0();
        __syncthreads();   // (1) K/V visible

        const uint32_t kbuf = kaddr + (uint32_t)(p * 64 * 144) + bB;
        const uint32_t vbuf = vaddr + (uint32_t)(p * 64 * 144) + bB;

        // ---- QK^T mma (K b-frags via ldmatrix.x4, 2 ni per call) ----
        float c[2][8][4];
#pragma unroll
        for (int m = 0; m < 2; m++)
#pragma unroll
            for (int ni = 0; ni < 8; ni++)
#pragma unroll
                for (int e = 0; e < 4; e++) c[m][ni][e] = 0.f;
#pragma unroll
        for (int kc = 0; kc < 4; kc++) {
#pragma unroll
            for (int j = 0; j < 4; j++) {
                uint32_t kb4[4];
                ldsm4(kb4, kbuf + (uint32_t)(j * 16 * 144 + kc * 32));
                mma_f16(c[0][2 * j],     qf[kc][0], kb4);
                mma_f16(c[0][2 * j + 1], qf[kc][0], kb4 + 2);
                mma_f16(c[1][2 * j],     qf[kc][1], kb4);
                mma_f16(c[1][2 * j + 1], qf[kc][1], kb4 + 2);
            }
        }

        // ---- in-warp max of pure qk ----
        float tm[4] = {-1e30f, -1e30f, -1e30f, -1e30f};
#pragma unroll
        for (int ni = 0; ni < 8; ni++) {
            tm[0] = fmaxf(tm[0], fmaxf(c[0][ni][0], c[0][ni][1]));
            tm[1] = fmaxf(tm[1], fmaxf(c[0][ni][2], c[0][ni][3]));
            tm[2] = fmaxf(tm[2], fmaxf(c[1][ni][0], c[1][ni][1]));
            tm[3] = fmaxf(tm[3], fmaxf(c[1][ni][2], c[1][ni][3]));
        }
        float mn[4], fac[4];
#pragma unroll
        for (int j = 0; j < 4; j++) {
            float v = tm[j];
            v = fmaxf(v, __shfl_xor_sync(0xffffffffu, v, 1));
            v = fmaxf(v, __shfl_xor_sync(0xffffffffu, v, 2));
            mn[j] = fmaxf(rowm[j], v + bmax[j]);
            fac[j] = fexp2(rowm[j] - mn[j]);
            rowm[j] = mn[j];
        }

        // ---- P = exp2(c + bias - mn), bias added in fp16 ----
        uint32_t pf[2][8][2];
#pragma unroll
        for (int ni = 0; ni < 8; ni++) {
            int kn0 = kbase + ni * 8 + 2 * t;            // even; kw0 <= 26
            int kh = ((kn0 >> 2) * 9363) >> 16;          // kn0/28 exact
            int kw = kn0 - kh * 28;
#pragma unroll
            for (int m = 0; m < 2; m++) {
                int r0 = rows[2 * m], r1 = rows[2 * m + 1];
                float mn0 = mn[2 * m], mn1 = mn[2 * m + 1];
                uint32_t rw0 = *(const uint32_t*)&s.rw16[r0 * RWP + kw];
                uint32_t rw1 = *(const uint32_t*)&s.rw16[r1 * RWP + kw];
                uint32_t b0 = h2add(hdup(s.rh16[r0 * HH + kh]), rw0);
                uint32_t b1 = h2add(hdup(s.rh16[r1 * HH + kh]), rw1);
                pf[m][ni][0] = h2exp2(h2add(packh2(c[m][ni][0] - mn0, c[m][ni][1] - mn0), b0));
                pf[m][ni][1] = h2exp2(h2add(packh2(c[m][ni][2] - mn1, c[m][ni][3] - mn1), b1));
            }
            if (kbase + ni * 8 >= NN) {
                pf[0][ni][0] = 0; pf[0][ni][1] = 0;
                pf[1][ni][0] = 0; pf[1][ni][1] = 0;
            }
        }

        // ---- rescale accumulators (skip when max unchanged; warp-uniform) ----
        if (!(fac[0] == 1.f && fac[1] == 1.f && fac[2] == 1.f && fac[3] == 1.f)) {
#pragma unroll
            for (int ni = 0; ni < 8; ni++) {
                acc[0][ni][0] *= fac[0]; acc[0][ni][1] *= fac[0];
                acc[0][ni][2] *= fac[1]; acc[0][ni][3] *= fac[1];
                acc[1][ni][0] *= fac[2]; acc[1][ni][1] *= fac[2];
                acc[1][ni][2] *= fac[3]; acc[1][ni][3] *= fac[3];
            }
            accL[0][0] *= fac[0]; accL[0][1] *= fac[0];
            accL[0][2] *= fac[1]; accL[0][3] *= fac[1];
            accL[1][0] *= fac[2]; accL[1][1] *= fac[2];
            accL[1][2] *= fac[3]; accL[1][3] *= fac[3];
        }

        // ---- P @ V (V b-frags via ldmatrix) + ones column ----
#pragma unroll
        for (int kc = 0; kc < 4; kc++) {
            uint32_t a0[4] = {pf[0][2 * kc][0], pf[0][2 * kc][1],
                              pf[0][2 * kc + 1][0], pf[0][2 * kc + 1][1]};
            uint32_t a1[4] = {pf[1][2 * kc][0], pf[1][2 * kc][1],
                              pf[1][2 * kc + 1][0], pf[1][2 * kc + 1][1]};
#pragma unroll
            for (int j = 0; j < 4; j++) {
                uint32_t vb4[4];
                ldsm4(vb4, vbuf + (uint32_t)(j * 16 * 144 + kc * 32));
                mma_f16(acc[0][2 * j],     a0, vb4);
                mma_f16(acc[0][2 * j + 1], a0, vb4 + 2);
                mma_f16(acc[1][2 * j],     a1, vb4);
                mma_f16(acc[1][2 * j + 1], a1, vb4 + 2);
            }
            uint32_t bo[2] = {ONES2, ONES2};
            mma_f16(accL[0], a0, bo);
            mma_f16(accL[1], a1, bo);
        }

        __syncthreads();   // (2) all readers of buffer p done
        if (kt2 + 2 < 25) issueKV(kt2 + 2);
    }

    // ---- normalize + store g_ao (fp16, k-permuted for mm<1>) ----
    const int b = bh >> 4;
    const int head = bh & 15;
    const int nrow[4] = {qt0 * 128 + rows[0], qt0 * 128 + rows[1],
                         qt0 * 128 + rows[2], qt0 * 128 + rows[3]};
    const float li[4] = {1.f / accL[0][0], 1.f / accL[0][2],
                         1.f / accL[1][0], 1.f / accL[1][2]};
#pragma unroll
    for (int ni = 0; ni < 8; ni++) {
        int col = head * HD + ni * 8 + 2 * t;
        int colp = (col & ~15) + posj((col & 15) >> 1) * 2;
#pragma unroll
        for (int j = 0; j < 4; j++) {
            if (nrow[j] < NN) {
                int m = j >> 1, eo = (j & 1) * 2;
                *(__half2*)&g_ao[(size_t)(b * NN + nrow[j]) * CD + colp] =
                    __floats2half2_rn(acc[m][ni][eo] * li[j], acc[m][ni][eo + 1] * li[j]);
            }
        }
    }
}

// ---------------- launch -----------------------------------------------------
extern "C" void kernel_launch(void* const* d_in, const int* in_sizes, int n_in,
                              void* d_out, int out_size) {
    const float* hidden = (const float*)d_in[0];
    const float* qkv_w  = (const float*)d_in[1];
    const float* qkv_b  = (const float*)d_in[2];
    const float* proj_w = (const float*)d_in[3];
    const float* proj_b = (const float*)d_in[4];
    const float* rph    = (const float*)d_in[5];
    const float* rpw    = (const float*)d_in[6];
    float* out = (float*)d_out;

    cudaFuncSetAttribute(flash12_kernel, cudaFuncAttributeMaxDynamicSharedMemorySize,
                         (int)sizeof(F12Smem));
    cudaFuncSetAttribute(mm_cp<0>, cudaFuncAttributeMaxDynamicSharedMemorySize, MM_SMEM);
    cudaFuncSetAttribute(mm_cp<1>, cudaFuncAttributeMaxDynamicSharedMemorySize, MM_SMEM);

    const int ptot = PREP_N1 + PREP_N2 + PREP_N3;
    prep_all<<<(ptot + 255) / 256, 256>>>(hidden, qkv_w, proj_w);

    // QKV: [6272,3072] = hidden . qkv_w^T
    mm_cp<0><<<dim3(3 * CD / 128, (BN + 255) / 256), 256, MM_SMEM>>>(qkv_b, nullptr);

    relpos_kernel<<<dim3(HH, BHN), 256>>>(rph, rpw);

    flash12_kernel<<<dim3((NN + 127) / 128, BHN), 128, sizeof(F12Smem)>>>();

    // proj: [6272,1024] = g_ao . proj_w^T
    mm_cp<1><<<dim3(CD / 128, (BN + 255) / 256), 256, MM_SMEM>>>(proj_b, out);
}

// round 16
// speedup vs baseline: 7.6086x; 1.0126x over previous
#include <cuda_runtime.h>
#include <cuda_fp16.h>
#include <cstdint>

#define NH   16
#define HD   64
#define CD   1024
#define BB   4
#define HH   56
#define WW   28
#define NN   1568          // HH*WW
#define BHN  64            // BB*NH
#define BN   6272          // BB*NN
#define QSCALE 0.125f      // 64^-0.5
#define QS2   0.1803368801f // QSCALE * log2(e)

// ---------------- scratch (device globals; no allocations allowed) ----------
__device__ __half g_q[BHN * NN * HD];     // fp16, NATURAL d order, pre-scaled by QS2
__device__ __half g_k[BHN * NN * HD];     // fp16, NATURAL
__device__ __half g_vt[BHN * HD * NN];    // fp16, transposed [bh][d][n], NATURAL n
__device__ __half g_relh16[BHN * NN * HH];   // log2e units, fp16
__device__ __half g_relw16[BHN * NN * 32];   // log2e units, fp16, rows padded to 32
__device__ __half g_ao[BN * CD];          // fp16, k-permuted, [B,N,heads,d]
__device__ __half g_hp[BN * CD];          // prepped (tf-perm) for mm
__device__ __half g_wp[3 * CD * CD];
__device__ __half g_pwp[CD * CD];

// ---------------- helpers ----------------------------------------------------
__device__ __forceinline__ uint32_t packh2(float a, float b) {
    __half2 h = __floats2half2_rn(a, b);
    return *reinterpret_cast<uint32_t*>(&h);
}
__device__ __forceinline__ uint32_t h2exp2(uint32_t x) {
    uint32_t r;
    asm("ex2.approx.f16x2 %0, %1;" : "=r"(r) : "r"(x));
    return r;
}
__device__ __forceinline__ float fexp2(float x) {
    float r;
    asm("ex2.approx.ftz.f32 %0, %1;" : "=f"(r) : "f"(x));
    return r;
}
__device__ __forceinline__ uint32_t h2add(uint32_t a, uint32_t b) {
    __half2 r = __hadd2(*reinterpret_cast<__half2*>(&a), *reinterpret_cast<__half2*>(&b));
    return *reinterpret_cast<uint32_t*>(&r);
}
__device__ __forceinline__ uint32_t hdup(__half h) {
    __half2 r = __half2half2(h);
    return *reinterpret_cast<uint32_t*>(&r);
}

__device__ __forceinline__ void mma_f16(float* c, const uint32_t* a, const uint32_t* b) {
    asm volatile(
        "mma.sync.aligned.m16n8k16.row.col.f32.f16.f16.f32 "
        "{%0,%1,%2,%3}, {%4,%5,%6,%7}, {%8,%9}, {%0,%1,%2,%3};"
        : "+f"(c[0]), "+f"(c[1]), "+f"(c[2]), "+f"(c[3])
        : "r"(a[0]), "r"(a[1]), "r"(a[2]), "r"(a[3]), "r"(b[0]), "r"(b[1]));
}

__device__ __forceinline__ void ldsm4(uint32_t* r, uint32_t addr) {
    asm volatile("ldmatrix.sync.aligned.m8n8.x4.shared.b16 {%0,%1,%2,%3}, [%4];"
        : "=r"(r[0]), "=r"(r[1]), "=r"(r[2]), "=r"(r[3]) : "r"(addr));
}

__device__ __forceinline__ uint32_t smem_u32(const void* p) {
    uint32_t a;
    asm("{ .reg .u64 t; cvta.to.shared.u64 t, %1; cvt.u32.u64 %0, t; }"
        : "=r"(a) : "l"(p));
    return a;
}

__device__ __forceinline__ void cpa16(uint32_t dst, const void* src, uint32_t srcsize) {
    asm volatile("cp.async.cg.shared.global [%0], [%1], 16, %2;"
                 :: "r"(dst), "l"(src), "r"(srcsize) : "memory");
}
#define CPA_COMMIT() asm volatile("cp.async.commit_group;" ::: "memory")
#define CPA_WAIT0()  asm volatile("cp.async.wait_group 0;" ::: "memory")
#define CPA_WAIT1()  asm volatile("cp.async.wait_group 1;" ::: "memory")
#define CPA_WAIT2()  asm volatile("cp.async.wait_group 2;" ::: "memory")

__device__ __forceinline__ int posj(int j) { return (j < 4) ? 2 * j : 2 * j - 7; }

// ---------------- prep: f32 -> fp16, half2-unit interleave per 16 ------------
#define PREP_N1 (BN * CD / 16)
#define PREP_N2 (3 * CD * CD / 16)
#define PREP_N3 (CD * CD / 16)

__global__ void __launch_bounds__(256) prep_all(const float* __restrict__ hidden,
                                                const float* __restrict__ w1,
                                                const float* __restrict__ w2) {
    int i = blockIdx.x * 256 + threadIdx.x;
    const float* src;
    __half* dst;
    if (i < PREP_N1) { src = hidden + (size_t)i * 16; dst = g_hp + (size_t)i * 16; }
    else if (i < PREP_N1 + PREP_N2) {
        int j = i - PREP_N1; src = w1 + (size_t)j * 16; dst = g_wp + (size_t)j * 16;
    } else if (i < PREP_N1 + PREP_N2 + PREP_N3) {
        int j = i - PREP_N1 - PREP_N2; src = w2 + (size_t)j * 16; dst = g_pwp + (size_t)j * 16;
    } else return;
    const float4* s = (const float4*)src;
    float4 A = s[0], B = s[1], C = s[2], D = s[3];
    uint4* d = (uint4*)dst;
    d[0] = make_uint4(packh2(A.x, A.y), packh2(C.x, C.y),
                      packh2(A.z, A.w), packh2(C.z, C.w));
    d[1] = make_uint4(packh2(B.x, B.y), packh2(D.x, D.y),
                      packh2(B.z, B.w), packh2(D.z, D.w));
}

// ================== cp.async 3-stage FP16 GEMM, 256x128 tile, BK=64 ==========
#define ATSZB (256 * 128)
#define BTSZB (128 * 128)
#define STGB  (ATSZB + BTSZB)
#define MM_SMEM (3 * STGB)

template <int MODE>
__global__ void __launch_bounds__(256, 1) mm_cp(const float* __restrict__ bias,
                                                float* __restrict__ Cout) {
    extern __shared__ char smemc[];
    uint32_t sb = smem_u32(smemc);
    const __half* A  = (MODE == 0) ? g_hp : g_ao;
    const __half* Bm = (MODE == 0) ? g_wp : g_pwp;

    const int tid = threadIdx.x;
    const int wid = tid >> 5;
    const int lid = tid & 31;
    const int g = lid >> 2;
    const int t = lid & 3;
    const int m0 = blockIdx.y * 256;
    const int n0 = blockIdx.x * 128;
    const int wm = (wid & 3) * 64;
    const int wn = (wid >> 2) * 64;

    float acc[4][8][4];
#pragma unroll
    for (int mi = 0; mi < 4; mi++)
#pragma unroll
        for (int ni = 0; ni < 8; ni++)
#pragma unroll
            for (int e = 0; e < 4; e++) acc[mi][ni][e] = 0.f;

    const int lr = tid >> 3;
    const int lq = tid & 7;
    const uint32_t ldst = (uint32_t)(lr * 128 + ((lq ^ (lr & 7)) << 4));

    auto issue = [&](int kt) {
        const int st = kt % 3;
        const int k0 = kt * 64;
        uint32_t ab = sb + (uint32_t)st * STGB;
        uint32_t bb = ab + ATSZB;
#pragma unroll
        for (int it = 0; it < 8; it++) {
            int r = lr + it * 32;
            int gr = m0 + r;
            bool ok = gr < BN;
            cpa16(ab + ldst + (uint32_t)(it * 32 * 128),
                  A + (ok ? (size_t)gr * CD + k0 + lq * 8 : 0), ok ? 16u : 0u);
        }
#pragma unroll
        for (int it = 0; it < 4; it++) {
            int r = lr + it * 32;
            cpa16(bb + ldst + (uint32_t)(it * 32 * 128),
                  Bm + (size_t)(n0 + r) * CD + k0 + lq * 8, 16);
        }
        CPA_COMMIT();
    };

    issue(0); issue(1);
    for (int kt = 0; kt < 16; kt++) {
        if (kt < 15) CPA_WAIT1(); else CPA_WAIT0();
        __syncthreads();
        if (kt + 2 < 16) issue(kt + 2);

        const char* As = smemc + (size_t)(kt % 3) * STGB;
        const char* Bs = As + ATSZB;

#pragma unroll
        for (int kc = 0; kc < 4; kc++) {
            const int coff = (((kc * 2 + (t >> 1)) ^ g) << 4) + ((t & 1) << 3);
            uint32_t a[4][4];
            uint32_t b[8][2];
#pragma unroll
            for (int mi = 0; mi < 4; mi++) {
                uint2 v0 = *(const uint2*)(As + (wm + mi * 16 + g) * 128 + coff);
                uint2 v1 = *(const uint2*)(As + (wm + mi * 16 + g + 8) * 128 + coff);
                a[mi][0] = v0.x; a[mi][1] = v1.x; a[mi][2] = v0.y; a[mi][3] = v1.y;
            }
#pragma unroll
            for (int ni = 0; ni < 8; ni++) {
                uint2 u = *(const uint2*)(Bs + (wn + ni * 8 + g) * 128 + coff);
                b[ni][0] = u.x; b[ni][1] = u.y;
            }
#pragma unroll
            for (int mi = 0; mi < 4; mi++)
#pragma unroll
                for (int ni = 0; ni < 8; ni++) mma_f16(acc[mi][ni], a[mi], b[ni]);
        }
    }

#pragma unroll
    for (int mi = 0; mi < 4; mi++) {
        int mr0 = m0 + wm + mi * 16 + g;
        int mr1 = mr0 + 8;
        bool ok0 = mr0 < BN, ok1 = mr1 < BN;
#pragma unroll
        for (int ni = 0; ni < 8; ni++) {
            int jj = n0 + wn + ni * 8 + 2 * t;
            float b0 = bias[jj], b1 = bias[jj + 1];
            float v00 = acc[mi][ni][0] + b0, v01 = acc[mi][ni][1] + b1;
            float v10 = acc[mi][ni][2] + b0, v11 = acc[mi][ni][3] + b1;
            if (MODE == 0) {
                int tsel = jj >> 10;
                int rr = jj & 1023;
                int head = rr >> 6;
                int d = rr & 63;
                if (ok0) {
                    int b_ = mr0 / NN, n_ = mr0 - b_ * NN;
                    int bh = b_ * NH + head;
                    if (tsel == 0) {
                        *(__half2*)&g_q[((size_t)bh * NN + n_) * HD + d] =
                            __floats2half2_rn(v00 * QS2, v01 * QS2);
                    } else if (tsel == 1) {
                        *(__half2*)&g_k[((size_t)bh * NN + n_) * HD + d] =
                            __floats2half2_rn(v00, v01);
                    } else {
                        g_vt[((size_t)bh * HD + d) * NN + n_]     = __float2half_rn(v00);
                        g_vt[((size_t)bh * HD + d + 1) * NN + n_] = __float2half_rn(v01);
                    }
                }
                if (ok1) {
                    int b_ = mr1 / NN, n_ = mr1 - b_ * NN;
                    int bh = b_ * NH + head;
                    if (tsel == 0) {
                        *(__half2*)&g_q[((size_t)bh * NN + n_) * HD + d] =
                            __floats2half2_rn(v10 * QS2, v11 * QS2);
                    } else if (tsel == 1) {
                        *(__half2*)&g_k[((size_t)bh * NN + n_) * HD + d] =
                            __floats2half2_rn(v10, v11);
                    } else {
                        g_vt[((size_t)bh * HD + d) * NN + n_]     = __float2half_rn(v10);
                        g_vt[((size_t)bh * HD + d + 1) * NN + n_] = __float2half_rn(v11);
                    }
                }
            } else {
                if (ok0) { float2 o = {v00, v01}; *(float2*)&Cout[(size_t)mr0 * CD + jj] = o; }
                if (ok1) { float2 o = {v10, v11}; *(float2*)&Cout[(size_t)mr1 * CD + jj] = o; }
            }
        }
    }
}

// ---------------- rel-pos bias via FP16 mma (fp16 outputs) --------------------
__global__ void __launch_bounds__(256) relpos_kernel(const float* __restrict__ rph,
                                                     const float* __restrict__ rpw) {
    __shared__ __align__(16) __half qp[32 * 72];
    __shared__ __align__(16) __half Bp[112 * 72];
    __shared__ float outw[32 * 60];

    const int h = blockIdx.x;
    const int bh = blockIdx.y;
    const int tid = threadIdx.x;
    const int wid = tid >> 5;
    const int lid = tid & 31;
    const int g = lid >> 2;
    const int t = lid & 3;

    if (tid < 128) {
        int r = tid >> 2, grp = tid & 3;
        uint4 A4 = make_uint4(0, 0, 0, 0), B4 = A4;
        if (r < WW) {
            const uint4* sp = (const uint4*)&g_q[((size_t)bh * NN + h * WW + r) * HD + grp * 16];
            A4 = sp[0]; B4 = sp[1];
        }
        uint4 o0 = make_uint4(A4.x, B4.x, A4.y, B4.y);
        uint4 o1 = make_uint4(A4.z, B4.z, A4.w, B4.w);
        *(uint4*)&qp[r * 72 + grp * 16] = o0;
        *(uint4*)&qp[r * 72 + grp * 16 + 8] = o1;
    }
#pragma unroll
    for (int it = 0; it < 2; it++) {
        int idx = it * 256 + tid;
        if (idx < 448) {
            int r = idx >> 2, grp = idx & 3;
            float4 A = {0,0,0,0}, B = {0,0,0,0}, C = {0,0,0,0}, D = {0,0,0,0};
            const float* sp = nullptr;
            if (r < 56)       sp = rph + (size_t)(h + 55 - r) * HD + grp * 16;
            else if (r < 111) sp = rpw + (size_t)(r - 56) * HD + grp * 16;
            if (sp) { A = ((const float4*)sp)[0]; B = ((const float4*)sp)[1];
                      C = ((const float4*)sp)[2]; D = ((const float4*)sp)[3]; }
            *(uint4*)&Bp[r * 72 + grp * 16] =
                make_uint4(packh2(A.x, A.y), packh2(C.x, C.y),
                           packh2(A.z, A.w), packh2(C.z, C.w));
            *(uint4*)&Bp[r * 72 + grp * 16 + 8] =
                make_uint4(packh2(B.x, B.y), packh2(D.x, D.y),
                           packh2(B.z, B.w), packh2(D.z, D.w));
        }
    }
    __syncthreads();

    for (int ti = wid; ti < 14; ti += 8) {
        float c[2][4];
#pragma unroll
        for (int mi = 0; mi < 2; mi++)
#pragma unroll
            for (int e = 0; e < 4; e++) c[mi][e] = 0.f;
#pragma unroll
        for (int kc = 0; kc < 4; kc++) {
            int qo = kc * 16 + t * 4;
            uint2 v0 = *(const uint2*)&qp[g * 72 + qo];
            uint2 v1 = *(const uint2*)&qp[(g + 8) * 72 + qo];
            uint2 v2 = *(const uint2*)&qp[(16 + g) * 72 + qo];
            uint2 v3 = *(const uint2*)&qp[(24 + g) * 72 + qo];
            uint32_t a0[4] = {v0.x, v1.x, v0.y, v1.y};
            uint32_t a1[4] = {v2.x, v3.x, v2.y, v3.y};
            uint2 u = *(const uint2*)&Bp[(ti * 8 + g) * 72 + qo];
            uint32_t b[2] = {u.x, u.y};
            mma_f16(c[0], a0, b);
            mma_f16(c[1], a1, b);
        }
        if (ti < 7) {
            int kh0 = ti * 8 + 2 * t, kh1 = kh0 + 1;
            size_t nb = (size_t)(bh * NN) + h * WW;
            g_relh16[(nb + g) * HH + kh0]      = __float2half_rn(c[0][0] * 8.f);
            g_relh16[(nb + g) * HH + kh1]      = __float2half_rn(c[0][1] * 8.f);
            g_relh16[(nb + g + 8) * HH + kh0]  = __float2half_rn(c[0][2] * 8.f);
            g_relh16[(nb + g + 8) * HH + kh1]  = __float2half_rn(c[0][3] * 8.f);
            g_relh16[(nb + 16 + g) * HH + kh0] = __float2half_rn(c[1][0] * 8.f);
            g_relh16[(nb + 16 + g) * HH + kh1] = __float2half_rn(c[1][1] * 8.f);
            if (g < 4) {
                g_relh16[(nb + 24 + g) * HH + kh0] = __float2half_rn(c[1][2] * 8.f);
                g_relh16[(nb + 24 + g) * HH + kh1] = __float2half_rn(c[1][3] * 8.f);
            }
        } else {
            int cb = (ti - 7) * 8 + 2 * t;
            outw[g * 60 + cb] = c[0][0];        outw[g * 60 + cb + 1] = c[0][1];
            outw[(g + 8) * 60 + cb] = c[0][2];  outw[(g + 8) * 60 + cb + 1] = c[0][3];
            outw[(16 + g) * 60 + cb] = c[1][0]; outw[(16 + g) * 60 + cb + 1] = c[1][1];
            outw[(24 + g) * 60 + cb] = c[1][2]; outw[(24 + g) * 60 + cb + 1] = c[1][3];
        }
    }
    __syncthreads();

    for (int idx = tid; idx < WW * WW; idx += 256) {
        int w = idx / WW, kw = idx - w * WW;
        g_relw16[((size_t)(bh * NN) + h * WW + w) * 32 + kw] =
            __float2half_rn(outw[w * 60 + (w - kw + 27)] * 8.f);
    }
}

// ------- flash v13: 3-buffer KV (1 barrier/tile), early issue, mn-folded bias
#define FPH 72    // halves pitch (144B rows)
#define RWP 40

struct F13Smem {
    __align__(16) __half qs[128 * FPH];
    __align__(16) __half kt[3][64 * FPH];
    __align__(16) __half vs[3][64 * FPH];
    __align__(16) __half rh16[128 * HH];
    __align__(16) __half rw16[128 * RWP];
};

__global__ void __launch_bounds__(128, 2) flash13_kernel() {
    extern __shared__ char raw[];
    F13Smem& s = *reinterpret_cast<F13Smem*>(raw);

    const int bh = blockIdx.y;
    const int qt0 = blockIdx.x;
    const int tid = threadIdx.x;
    const int wid = tid >> 5;
    const int lid = tid & 31;
    const int g = lid >> 2;
    const int t = lid & 3;
    const int wm = wid * 32;
    const int rows[4] = {wm + g, wm + g + 8, wm + g + 16, wm + g + 24};

    const uint32_t qaddr = smem_u32(s.qs);
    const uint32_t kaddr = smem_u32(s.kt);
    const uint32_t vaddr = smem_u32(s.vs);
    const uint32_t rhaddr = smem_u32(s.rh16);
    const uint32_t rwaddr = smem_u32(s.rw16);

    // per-lane ldmatrix base offsets (bytes)
    const uint32_t bB = (uint32_t)((lid & 7) * 144 + ((lid >> 4) & 1) * 8 * 144 +
                                   ((lid >> 3) & 1) * 16);
    const uint32_t bA = (uint32_t)(((lid & 7) + ((lid >> 3) & 1) * 8) * 144 +
                                   ((lid >> 4) & 1) * 16);

    // ---- prologue group: Q + rh16 + rw16 ----
#pragma unroll
    for (int it = 0; it < 8; it++) {
        int idx = it * 128 + tid;
        int r = idx >> 3, cc = idx & 7;
        int n = qt0 * 128 + r;
        const __half* src = g_q + (n < NN ? (size_t)(bh * NN + n) * HD + cc * 8 : 0);
        cpa16(qaddr + (uint32_t)(r * 144 + cc * 16), src, n < NN ? 16u : 0u);
    }
#pragma unroll
    for (int it = 0; it < 7; it++) {
        int idx = it * 128 + tid;
        int r = idx / 7, cc = idx % 7;
        int n = qt0 * 128 + r;
        const __half* src = g_relh16 + (n < NN ? (size_t)(bh * NN + n) * HH + cc * 8 : 0);
        cpa16(rhaddr + (uint32_t)(r * 112 + cc * 16), src, n < NN ? 16u : 0u);
    }
#pragma unroll
    for (int it = 0; it < 4; it++) {
        int idx = it * 128 + tid;
        int r = idx >> 2, cc = idx & 3;
        int n = qt0 * 128 + r;
        const __half* src = g_relw16 + (n < NN ? (size_t)(bh * NN + n) * 32 + cc * 8 : 0);
        cpa16(rwaddr + (uint32_t)(r * 80 + cc * 16), src, n < NN ? 16u : 0u);
    }
    CPA_COMMIT();

    auto issueKV = [&](int j) {
        const int kb = j * 64;
        const int st = j % 3;
        const uint32_t ka = kaddr + (uint32_t)(st * 64 * 144);
        const uint32_t va = vaddr + (uint32_t)(st * 64 * 144);
#pragma unroll
        for (int it = 0; it < 4; it++) {
            int idx = it * 128 + tid;
            int r = idx >> 3, cc = idx & 7;
            int kn = kb + r;
            bool ok = kn < NN;
            const __half* src = g_k + (ok ? (size_t)(bh * NN + kn) * HD + cc * 8 : 0);
            cpa16(ka + (uint32_t)(r * 144 + cc * 16), src, ok ? 16u : 0u);
        }
#pragma unroll
        for (int it = 0; it < 4; it++) {
            int idx = it * 128 + tid;
            int r = idx >> 3, cc = idx & 7;
            bool ok = (kb + cc * 8 + 8) <= NN;
            const __half* src = g_vt + (ok ? (size_t)(bh * HD + r) * NN + kb + cc * 8 : 0);
            cpa16(va + (uint32_t)(r * 144 + cc * 16), src, ok ? 16u : 0u);
        }
        CPA_COMMIT();
    };

    issueKV(0);
    issueKV(1);

    // ---- wait for prologue; bias bounds + hoisted Q fragments ----
    CPA_WAIT2();
    __syncthreads();
    float bmax[4];
#pragma unroll
    for (int j = 0; j < 4; j++) {
        int r = rows[j];
        float mh = -1e30f, mw = -1e30f;
        for (int kh = 0; kh < HH; kh++)
            mh = fmaxf(mh, __half2float(s.rh16[r * HH + kh]));
        for (int kw = 0; kw < WW; kw++)
            mw = fmaxf(mw, __half2float(s.rw16[r * RWP + kw]));
        bmax[j] = mh + mw;
    }
    uint32_t qf[4][2][4];
#pragma unroll
    for (int kc = 0; kc < 4; kc++)
#pragma unroll
        for (int m = 0; m < 2; m++)
            ldsm4(qf[kc][m], qaddr + (uint32_t)((wm + m * 16) * 144 + kc * 32) + bA);

    float acc[2][8][4];
#pragma unroll
    for (int m = 0; m < 2; m++)
#pragma unroll
        for (int ni = 0; ni < 8; ni++)
#pragma unroll
            for (int e = 0; e < 4; e++) acc[m][ni][e] = 0.f;
    float accL[2][4] = {{0.f, 0.f, 0.f, 0.f}, {0.f, 0.f, 0.f, 0.f}};
    float rowm[4] = {-1e30f, -1e30f, -1e30f, -1e30f};

    const uint32_t ONES2 = 0x3C003C00u;

    for (int kt2 = 0; kt2 < 25; kt2++) {
        const int kbase = kt2 * 64;
        const int p = kt2 % 3;

        if (kt2 < 24) CPA_WAIT1(); else CPA_WAIT0();
        __syncthreads();   // (single barrier) K/V for kt2 visible; prior readers done
        if (kt2 + 2 < 25) issueKV(kt2 + 2);   // writes buf (kt2+2)%3 == (kt2-1)%3, free

        const uint32_t kbuf = kaddr + (uint32_t)(p * 64 * 144) + bB;
        const uint32_t vbuf = vaddr + (uint32_t)(p * 64 * 144) + bB;

        // ---- QK^T mma (K b-frags via ldmatrix.x4) ----
        float c[2][8][4];
#pragma unroll
        for (int m = 0; m < 2; m++)
#pragma unroll
            for (int ni = 0; ni < 8; ni++)
#pragma unroll
                for (int e = 0; e < 4; e++) c[m][ni][e] = 0.f;
#pragma unroll
        for (int kc = 0; kc < 4; kc++) {
#pragma unroll
            for (int j = 0; j < 4; j++) {
                uint32_t kb4[4];
                ldsm4(kb4, kbuf + (uint32_t)(j * 16 * 144 + kc * 32));
                mma_f16(c[0][2 * j],     qf[kc][0], kb4);
                mma_f16(c[0][2 * j + 1], qf[kc][0], kb4 + 2);
                mma_f16(c[1][2 * j],     qf[kc][1], kb4);
                mma_f16(c[1][2 * j + 1], qf[kc][1], kb4 + 2);
            }
        }

        // ---- in-warp max of pure qk ----
        float tm[4] = {-1e30f, -1e30f, -1e30f, -1e30f};
#pragma unroll
        for (int ni = 0; ni < 8; ni++) {
            tm[0] = fmaxf(tm[0], fmaxf(c[0][ni][0], c[0][ni][1]));
            tm[1] = fmaxf(tm[1], fmaxf(c[0][ni][2], c[0][ni][3]));
            tm[2] = fmaxf(tm[2], fmaxf(c[1][ni][0], c[1][ni][1]));
            tm[3] = fmaxf(tm[3], fmaxf(c[1][ni][2], c[1][ni][3]));
        }
        float mn[4], fac[4];
        __half nm[4];
#pragma unroll
        for (int j = 0; j < 4; j++) {
            float v = tm[j];
            v = fmaxf(v, __shfl_xor_sync(0xffffffffu, v, 1));
            v = fmaxf(v, __shfl_xor_sync(0xffffffffu, v, 2));
            mn[j] = fmaxf(rowm[j], v + bmax[j]);
            fac[j] = fexp2(rowm[j] - mn[j]);
            rowm[j] = mn[j];
            nm[j] = __float2half_rn(-mn[j]);
        }

        // ---- P = exp2(c + (bias - mn)), all adds in fp16 ----
        uint32_t pf[2][8][2];
#pragma unroll
        for (int ni = 0; ni < 8; ni++) {
            int kn0 = kbase + ni * 8 + 2 * t;            // even; kw0 <= 26
            int kh = ((kn0 >> 2) * 9363) >> 16;          // kn0/28 exact
            int kw = kn0 - kh * 28;
#pragma unroll
            for (int m = 0; m < 2; m++) {
                int r0 = rows[2 * m], r1 = rows[2 * m + 1];
                uint32_t rw0 = *(const uint32_t*)&s.rw16[r0 * RWP + kw];
                uint32_t rw1 = *(const uint32_t*)&s.rw16[r1 * RWP + kw];
                __half h0 = __hadd(s.rh16[r0 * HH + kh], nm[2 * m]);
                __half h1 = __hadd(s.rh16[r1 * HH + kh], nm[2 * m + 1]);
                uint32_t b0 = h2add(hdup(h0), rw0);
                uint32_t b1 = h2add(hdup(h1), rw1);
                pf[m][ni][0] = h2exp2(h2add(packh2(c[m][ni][0], c[m][ni][1]), b0));
                pf[m][ni][1] = h2exp2(h2add(packh2(c[m][ni][2], c[m][ni][3]), b1));
            }
            if (kbase + ni * 8 >= NN) {
                pf[0][ni][0] = 0; pf[0][ni][1] = 0;
                pf[1][ni][0] = 0; pf[1][ni][1] = 0;
            }
        }

        // ---- rescale accumulators (skip when max unchanged; warp-uniform) ----
        if (!(fac[0] == 1.f && fac[1] == 1.f && fac[2] == 1.f && fac[3] == 1.f)) {
#pragma unroll
            for (int ni = 0; ni < 8; ni++) {
                acc[0][ni][0] *= fac[0]; acc[0][ni][1] *= fac[0];
                acc[0][ni][2] *= fac[1]; acc[0][ni][3] *= fac[1];
                acc[1][ni][0] *= fac[2]; acc[1][ni][1] *= fac[2];
                acc[1][ni][2] *= fac[3]; acc[1][ni][3] *= fac[3];
            }
            accL[0][0] *= fac[0]; accL[0][1] *= fac[0];
            accL[0][2] *= fac[1]; accL[0][3] *= fac[1];
            accL[1][0] *= fac[2]; accL[1][1] *= fac[2];
            accL[1][2] *= fac[3]; accL[1][3] *= fac[3];
        }

        // ---- P @ V (V b-frags via ldmatrix) + ones column ----
#pragma unroll
        for (int kc = 0; kc < 4; kc++) {
            uint32_t a0[4] = {pf[0][2 * kc][0], pf[0][2 * kc][1],
                              pf[0][2 * kc + 1][0], pf[0][2 * kc + 1][1]};
            uint32_t a1[4] = {pf[1][2 * kc][0], pf[1][2 * kc][1],
                              pf[1][2 * kc + 1][0], pf[1][2 * kc + 1][1]};
#pragma unroll
            for (int j = 0; j < 4; j++) {
                uint32_t vb4[4];
                ldsm4(vb4, vbuf + (uint32_t)(j * 16 * 144 + kc * 32));
                mma_f16(acc[0][2 * j],     a0, vb4);
                mma_f16(acc[0][2 * j + 1], a0, vb4 + 2);
                mma_f16(acc[1][2 * j],     a1, vb4);
                mma_f16(acc[1][2 * j + 1], a1, vb4 + 2);
            }
            uint32_t bo[2] = {ONES2, ONES2};
            mma_f16(accL[0], a0, bo);
            mma_f16(accL[1], a1, bo);
        }
    }

    // ---- normalize + store g_ao (fp16, k-permuted for mm<1>) ----
    const int b = bh >> 4;
    const int head = bh & 15;
    const int nrow[4] = {qt0 * 128 + rows[0], qt0 * 128 + rows[1],
                         qt0 * 128 + rows[2], qt0 * 128 + rows[3]};
    const float li[4] = {1.f / accL[0][0], 1.f / accL[0][2],
                         1.f / accL[1][0], 1.f / accL[1][2]};
#pragma unroll
    for (int ni = 0; ni < 8; ni++) {
        int col = head * HD + ni * 8 + 2 * t;
        int colp = (col & ~15) + posj((col & 15) >> 1) * 2;
#pragma unroll
        for (int j = 0; j < 4; j++) {
            if (nrow[j] < NN) {
                int m = j >> 1, eo = (j & 1) * 2;
                *(__half2*)&g_ao[(size_t)(b * NN + nrow[j]) * CD + colp] =
                    __floats2half2_rn(acc[m][ni][eo] * li[j], acc[m][ni][eo + 1] * li[j]);
            }
        }
    }
}

// ---------------- launch -----------------------------------------------------
extern "C" void kernel_launch(void* const* d_in, const int* in_sizes, int n_in,
                              void* d_out, int out_size) {
    const float* hidden = (const float*)d_in[0];
    const float* qkv_w  = (const float*)d_in[1];
    const float* qkv_b  = (const float*)d_in[2];
    const float* proj_w = (const float*)d_in[3];
    const float* proj_b = (const float*)d_in[4];
    const float* rph    = (const float*)d_in[5];
    const float* rpw    = (const float*)d_in[6];
    float* out = (float*)d_out;

    cudaFuncSetAttribute(flash13_kernel, cudaFuncAttributeMaxDynamicSharedMemorySize,
                         (int)sizeof(F13Smem));
    cudaFuncSetAttribute(mm_cp<0>, cudaFuncAttributeMaxDynamicSharedMemorySize, MM_SMEM);
    cudaFuncSetAttribute(mm_cp<1>, cudaFuncAttributeMaxDynamicSharedMemorySize, MM_SMEM);

    const int ptot = PREP_N1 + PREP_N2 + PREP_N3;
    prep_all<<<(ptot + 255) / 256, 256>>>(hidden, qkv_w, proj_w);

    // QKV: [6272,3072] = hidden . qkv_w^T
    mm_cp<0><<<dim3(3 * CD / 128, (BN + 255) / 256), 256, MM_SMEM>>>(qkv_b, nullptr);

    relpos_kernel<<<dim3(HH, BHN), 256>>>(rph, rpw);

    flash13_kernel<<<dim3((NN + 127) / 128, BHN), 128, sizeof(F13Smem)>>>();

    // proj: [6272,1024] = g_ao . proj_w^T
    mm_cp<1><<<dim3(CD / 128, (BN + 255) / 256), 256, MM_SMEM>>>(proj_b, out);
}

// round 17
// speedup vs baseline: 7.6878x; 1.0104x over previous
#include <cuda_runtime.h>
#include <cuda_fp16.h>
#include <cstdint>

#define NH   16
#define HD   64
#define CD   1024
#define BB   4
#define HH   56
#define WW   28
#define NN   1568          // HH*WW
#define BHN  64            // BB*NH
#define BN   6272          // BB*NN
#define QSCALE 0.125f      // 64^-0.5
#define QS2   0.1803368801f // QSCALE * log2(e)

// ---------------- scratch (device globals; no allocations allowed) ----------
__device__ __half g_q[BHN * NN * HD];     // fp16, NATURAL d order, pre-scaled by QS2
__device__ __half g_k[BHN * NN * HD];     // fp16, NATURAL
__device__ __half g_vt[BHN * HD * NN];    // fp16, transposed [bh][d][n], NATURAL n
__device__ __half g_relh16[BHN * NN * HH];   // log2e units, fp16
__device__ __half g_relw16[BHN * NN * 32];   // log2e units, fp16, rows padded to 32
__device__ __half g_ao[BN * CD];          // fp16, k-permuted, [B,N,heads,d]
__device__ __half g_hp[BN * CD];          // prepped fp16 (interleaved) for mm
__device__ __half g_wp[3 * CD * CD];
__device__ __half g_pwp[CD * CD];

// ---------------- helpers ----------------------------------------------------
__device__ __forceinline__ uint32_t packh2(float a, float b) {
    __half2 h = __floats2half2_rn(a, b);
    return *reinterpret_cast<uint32_t*>(&h);
}
__device__ __forceinline__ uint32_t h2exp2(uint32_t x) {
    uint32_t r;
    asm("ex2.approx.f16x2 %0, %1;" : "=r"(r) : "r"(x));
    return r;
}
__device__ __forceinline__ float fexp2(float x) {
    float r;
    asm("ex2.approx.ftz.f32 %0, %1;" : "=f"(r) : "f"(x));
    return r;
}
__device__ __forceinline__ uint32_t h2add(uint32_t a, uint32_t b) {
    __half2 r = __hadd2(*reinterpret_cast<__half2*>(&a), *reinterpret_cast<__half2*>(&b));
    return *reinterpret_cast<uint32_t*>(&r);
}
__device__ __forceinline__ uint32_t hdup(__half h) {
    __half2 r = __half2half2(h);
    return *reinterpret_cast<uint32_t*>(&r);
}

__device__ __forceinline__ void mma_f16(float* c, const uint32_t* a, const uint32_t* b) {
    asm volatile(
        "mma.sync.aligned.m16n8k16.row.col.f32.f16.f16.f32 "
        "{%0,%1,%2,%3}, {%4,%5,%6,%7}, {%8,%9}, {%0,%1,%2,%3};"
        : "+f"(c[0]), "+f"(c[1]), "+f"(c[2]), "+f"(c[3])
        : "r"(a[0]), "r"(a[1]), "r"(a[2]), "r"(a[3]), "r"(b[0]), "r"(b[1]));
}

__device__ __forceinline__ void ldsm4(uint32_t* r, uint32_t addr) {
    asm volatile("ldmatrix.sync.aligned.m8n8.x4.shared.b16 {%0,%1,%2,%3}, [%4];"
        : "=r"(r[0]), "=r"(r[1]), "=r"(r[2]), "=r"(r[3]) : "r"(addr));
}

__device__ __forceinline__ uint32_t smem_u32(const void* p) {
    uint32_t a;
    asm("{ .reg .u64 t; cvta.to.shared.u64 t, %1; cvt.u32.u64 %0, t; }"
        : "=r"(a) : "l"(p));
    return a;
}

__device__ __forceinline__ void cpa16(uint32_t dst, const void* src, uint32_t srcsize) {
    asm volatile("cp.async.cg.shared.global [%0], [%1], 16, %2;"
                 :: "r"(dst), "l"(src), "r"(srcsize) : "memory");
}
#define CPA_COMMIT() asm volatile("cp.async.commit_group;" ::: "memory")
#define CPA_WAIT0()  asm volatile("cp.async.wait_group 0;" ::: "memory")
#define CPA_WAIT1()  asm volatile("cp.async.wait_group 1;" ::: "memory")
#define CPA_WAIT2()  asm volatile("cp.async.wait_group 2;" ::: "memory")

__device__ __forceinline__ int posj(int j) { return (j < 4) ? 2 * j : 2 * j - 7; }

// ---------------- prep: f32 -> fp16, half2-unit interleave per 16 ------------
#define PREP_N1 (BN * CD / 16)
#define PREP_N2 (3 * CD * CD / 16)
#define PREP_N3 (CD * CD / 16)

__global__ void __launch_bounds__(256) prep_all(const float* __restrict__ hidden,
                                                const float* __restrict__ w1,
                                                const float* __restrict__ w2) {
    int i = blockIdx.x * 256 + threadIdx.x;
    const float* src;
    __half* dst;
    if (i < PREP_N1) { src = hidden + (size_t)i * 16; dst = g_hp + (size_t)i * 16; }
    else if (i < PREP_N1 + PREP_N2) {
        int j = i - PREP_N1; src = w1 + (size_t)j * 16; dst = g_wp + (size_t)j * 16;
    } else if (i < PREP_N1 + PREP_N2 + PREP_N3) {
        int j = i - PREP_N1 - PREP_N2; src = w2 + (size_t)j * 16; dst = g_pwp + (size_t)j * 16;
    } else return;
    const float4* s = (const float4*)src;
    float4 A = s[0], B = s[1], C = s[2], D = s[3];
    uint4* d = (uint4*)dst;
    d[0] = make_uint4(packh2(A.x, A.y), packh2(C.x, C.y),
                      packh2(A.z, A.w), packh2(C.z, C.w));
    d[1] = make_uint4(packh2(B.x, B.y), packh2(D.x, D.y),
                      packh2(B.z, B.w), packh2(D.z, D.w));
}

// ====== cp.async 3-stage FP16 GEMM, 256x128 tile, BK=64, ldmatrix frags ======
// smem tiles: 144B-pitch rows (64 halves data + 8 pad), no swizzle.
#define MMP   144                    // bytes per row
#define ATSZB (256 * MMP)
#define BTSZB (128 * MMP)
#define STGB  (ATSZB + BTSZB)
#define MM_SMEM (3 * STGB)

template <int MODE>
__global__ void __launch_bounds__(256, 1) mm_cp(const float* __restrict__ bias,
                                                float* __restrict__ Cout) {
    extern __shared__ char smemc[];
    uint32_t sb = smem_u32(smemc);
    const __half* A  = (MODE == 0) ? g_hp : g_ao;
    const __half* Bm = (MODE == 0) ? g_wp : g_pwp;

    const int tid = threadIdx.x;
    const int wid = tid >> 5;
    const int lid = tid & 31;
    const int g = lid >> 2;
    const int t = lid & 3;
    const int m0 = blockIdx.y * 256;
    const int n0 = blockIdx.x * 128;
    const int wm = (wid & 3) * 64;
    const int wn = (wid >> 2) * 64;

    // ldmatrix per-lane offsets (bytes), same mapping validated in flash
    const uint32_t bA = (uint32_t)(((lid & 7) + ((lid >> 3) & 1) * 8) * MMP +
                                   ((lid >> 4) & 1) * 16);
    const uint32_t bB = (uint32_t)((lid & 7) * MMP + ((lid >> 4) & 1) * 8 * MMP +
                                   ((lid >> 3) & 1) * 16);

    float acc[4][8][4];
#pragma unroll
    for (int mi = 0; mi < 4; mi++)
#pragma unroll
        for (int ni = 0; ni < 8; ni++)
#pragma unroll
            for (int e = 0; e < 4; e++) acc[mi][ni][e] = 0.f;

    const int lr = tid >> 3;     // 0..31
    const int lq = tid & 7;      // chunk

    auto issue = [&](int kt) {
        const int st = kt % 3;
        const int k0 = kt * 64;
        uint32_t ab = sb + (uint32_t)st * STGB;
        uint32_t bb = ab + ATSZB;
#pragma unroll
        for (int it = 0; it < 8; it++) {
            int r = lr + it * 32;
            int gr = m0 + r;
            bool ok = gr < BN;
            cpa16(ab + (uint32_t)(r * MMP + lq * 16),
                  A + (ok ? (size_t)gr * CD + k0 + lq * 8 : 0), ok ? 16u : 0u);
        }
#pragma unroll
        for (int it = 0; it < 4; it++) {
            int r = lr + it * 32;
            cpa16(bb + (uint32_t)(r * MMP + lq * 16),
                  Bm + (size_t)(n0 + r) * CD + k0 + lq * 8, 16);
        }
        CPA_COMMIT();
    };

    issue(0); issue(1);
    for (int kt = 0; kt < 16; kt++) {
        if (kt < 15) CPA_WAIT1(); else CPA_WAIT0();
        __syncthreads();
        if (kt + 2 < 16) issue(kt + 2);

        const uint32_t ab = sb + (uint32_t)(kt % 3) * STGB;
        const uint32_t bb = ab + ATSZB;
        const uint32_t aw = ab + (uint32_t)(wm * MMP) + bA;
        const uint32_t bw = bb + (uint32_t)(wn * MMP) + bB;

#pragma unroll
        for (int kc = 0; kc < 4; kc++) {
            uint32_t af[4][4];
#pragma unroll
            for (int mi = 0; mi < 4; mi++)
                ldsm4(af[mi], aw + (uint32_t)(mi * 16 * MMP + kc * 32));
#pragma unroll
            for (int j = 0; j < 4; j++) {
                uint32_t bf[4];
                ldsm4(bf, bw + (uint32_t)(j * 16 * MMP + kc * 32));
#pragma unroll
                for (int mi = 0; mi < 4; mi++) {
                    mma_f16(acc[mi][2 * j],     af[mi], bf);
                    mma_f16(acc[mi][2 * j + 1], af[mi], bf + 2);
                }
            }
        }
    }

#pragma unroll
    for (int mi = 0; mi < 4; mi++) {
        int mr0 = m0 + wm + mi * 16 + g;
        int mr1 = mr0 + 8;
        bool ok0 = mr0 < BN, ok1 = mr1 < BN;
#pragma unroll
        for (int ni = 0; ni < 8; ni++) {
            int jj = n0 + wn + ni * 8 + 2 * t;
            float b0 = bias[jj], b1 = bias[jj + 1];
            float v00 = acc[mi][ni][0] + b0, v01 = acc[mi][ni][1] + b1;
            float v10 = acc[mi][ni][2] + b0, v11 = acc[mi][ni][3] + b1;
            if (MODE == 0) {
                int tsel = jj >> 10;
                int rr = jj & 1023;
                int head = rr >> 6;
                int d = rr & 63;
                if (ok0) {
                    int b_ = mr0 / NN, n_ = mr0 - b_ * NN;
                    int bh = b_ * NH + head;
                    if (tsel == 0) {
                        *(__half2*)&g_q[((size_t)bh * NN + n_) * HD + d] =
                            __floats2half2_rn(v00 * QS2, v01 * QS2);
                    } else if (tsel == 1) {
                        *(__half2*)&g_k[((size_t)bh * NN + n_) * HD + d] =
                            __floats2half2_rn(v00, v01);
                    } else {
                        g_vt[((size_t)bh * HD + d) * NN + n_]     = __float2half_rn(v00);
                        g_vt[((size_t)bh * HD + d + 1) * NN + n_] = __float2half_rn(v01);
                    }
                }
                if (ok1) {
                    int b_ = mr1 / NN, n_ = mr1 - b_ * NN;
                    int bh = b_ * NH + head;
                    if (tsel == 0) {
                        *(__half2*)&g_q[((size_t)bh * NN + n_) * HD + d] =
                            __floats2half2_rn(v10 * QS2, v11 * QS2);
                    } else if (tsel == 1) {
                        *(__half2*)&g_k[((size_t)bh * NN + n_) * HD + d] =
                            __floats2half2_rn(v10, v11);
                    } else {
                        g_vt[((size_t)bh * HD + d) * NN + n_]     = __float2half_rn(v10);
                        g_vt[((size_t)bh * HD + d + 1) * NN + n_] = __float2half_rn(v11);
                    }
                }
            } else {
                if (ok0) { float2 o = {v00, v01}; *(float2*)&Cout[(size_t)mr0 * CD + jj] = o; }
                if (ok1) { float2 o = {v10, v11}; *(float2*)&Cout[(size_t)mr1 * CD + jj] = o; }
            }
        }
    }
}

// ---------------- rel-pos bias via FP16 mma (fp16 outputs) --------------------
__global__ void __launch_bounds__(256) relpos_kernel(const float* __restrict__ rph,
                                                     const float* __restrict__ rpw) {
    __shared__ __align__(16) __half qp[32 * 72];
    __shared__ __align__(16) __half Bp[112 * 72];
    __shared__ float outw[32 * 60];

    const int h = blockIdx.x;
    const int bh = blockIdx.y;
    const int tid = threadIdx.x;
    const int wid = tid >> 5;
    const int lid = tid & 31;
    const int g = lid >> 2;
    const int t = lid & 3;

    if (tid < 128) {
        int r = tid >> 2, grp = tid & 3;
        uint4 A4 = make_uint4(0, 0, 0, 0), B4 = A4;
        if (r < WW) {
            const uint4* sp = (const uint4*)&g_q[((size_t)bh * NN + h * WW + r) * HD + grp * 16];
            A4 = sp[0]; B4 = sp[1];
        }
        uint4 o0 = make_uint4(A4.x, B4.x, A4.y, B4.y);
        uint4 o1 = make_uint4(A4.z, B4.z, A4.w, B4.w);
        *(uint4*)&qp[r * 72 + grp * 16] = o0;
        *(uint4*)&qp[r * 72 + grp * 16 + 8] = o1;
    }
#pragma unroll
    for (int it = 0; it < 2; it++) {
        int idx = it * 256 + tid;
        if (idx < 448) {
            int r = idx >> 2, grp = idx & 3;
            float4 A = {0,0,0,0}, B = {0,0,0,0}, C = {0,0,0,0}, D = {0,0,0,0};
            const float* sp = nullptr;
            if (r < 56)       sp = rph + (size_t)(h + 55 - r) * HD + grp * 16;
            else if (r < 111) sp = rpw + (size_t)(r - 56) * HD + grp * 16;
            if (sp) { A = ((const float4*)sp)[0]; B = ((const float4*)sp)[1];
                      C = ((const float4*)sp)[2]; D = ((const float4*)sp)[3]; }
            *(uint4*)&Bp[r * 72 + grp * 16] =
                make_uint4(packh2(A.x, A.y), packh2(C.x, C.y),
                           packh2(A.z, A.w), packh2(C.z, C.w));
            *(uint4*)&Bp[r * 72 + grp * 16 + 8] =
                make_uint4(packh2(B.x, B.y), packh2(D.x, D.y),
                           packh2(B.z, B.w), packh2(D.z, D.w));
        }
    }
    __syncthreads();

    for (int ti = wid; ti < 14; ti += 8) {
        float c[2][4];
#pragma unroll
        for (int mi = 0; mi < 2; mi++)
#pragma unroll
            for (int e = 0; e < 4; e++) c[mi][e] = 0.f;
#pragma unroll
        for (int kc = 0; kc < 4; kc++) {
            int qo = kc * 16 + t * 4;
            uint2 v0 = *(const uint2*)&qp[g * 72 + qo];
            uint2 v1 = *(const uint2*)&qp[(g + 8) * 72 + qo];
            uint2 v2 = *(const uint2*)&qp[(16 + g) * 72 + qo];
            uint2 v3 = *(const uint2*)&qp[(24 + g) * 72 + qo];
            uint32_t a0[4] = {v0.x, v1.x, v0.y, v1.y};
            uint32_t a1[4] = {v2.x, v3.x, v2.y, v3.y};
            uint2 u = *(const uint2*)&Bp[(ti * 8 + g) * 72 + qo];
            uint32_t b[2] = {u.x, u.y};
            mma_f16(c[0], a0, b);
            mma_f16(c[1], a1, b);
        }
        if (ti < 7) {
            int kh0 = ti * 8 + 2 * t, kh1 = kh0 + 1;
            size_t nb = (size_t)(bh * NN) + h * WW;
            g_relh16[(nb + g) * HH + kh0]      = __float2half_rn(c[0][0] * 8.f);
            g_relh16[(nb + g) * HH + kh1]      = __float2half_rn(c[0][1] * 8.f);
            g_relh16[(nb + g + 8) * HH + kh0]  = __float2half_rn(c[0][2] * 8.f);
            g_relh16[(nb + g + 8) * HH + kh1]  = __float2half_rn(c[0][3] * 8.f);
            g_relh16[(nb + 16 + g) * HH + kh0] = __float2half_rn(c[1][0] * 8.f);
            g_relh16[(nb + 16 + g) * HH + kh1] = __float2half_rn(c[1][1] * 8.f);
            if (g < 4) {
                g_relh16[(nb + 24 + g) * HH + kh0] = __float2half_rn(c[1][2] * 8.f);
                g_relh16[(nb + 24 + g) * HH + kh1] = __float2half_rn(c[1][3] * 8.f);
            }
        } else {
            int cb = (ti - 7) * 8 + 2 * t;
            outw[g * 60 + cb] = c[0][0];        outw[g * 60 + cb + 1] = c[0][1];
            outw[(g + 8) * 60 + cb] = c[0][2];  outw[(g + 8) * 60 + cb + 1] = c[0][3];
            outw[(16 + g) * 60 + cb] = c[1][0]; outw[(16 + g) * 60 + cb + 1] = c[1][1];
            outw[(24 + g) * 60 + cb] = c[1][2]; outw[(24 + g) * 60 + cb + 1] = c[1][3];
        }
    }
    __syncthreads();

    for (int idx = tid; idx < WW * WW; idx += 256) {
        int w = idx / WW, kw = idx - w * WW;
        g_relw16[((size_t)(bh * NN) + h * WW + w) * 32 + kw] =
            __float2half_rn(outw[w * 60 + (w - kw + 27)] * 8.f);
    }
}

// ------- flash v13: 3-buffer KV (1 barrier/tile), early issue, mn-folded bias
#define FPH 72    // halves pitch (144B rows)
#define RWP 40

struct F13Smem {
    __align__(16) __half qs[128 * FPH];
    __align__(16) __half kt[3][64 * FPH];
    __align__(16) __half vs[3][64 * FPH];
    __align__(16) __half rh16[128 * HH];
    __align__(16) __half rw16[128 * RWP];
};

__global__ void __launch_bounds__(128, 2) flash13_kernel() {
    extern __shared__ char raw[];
    F13Smem& s = *reinterpret_cast<F13Smem*>(raw);

    const int bh = blockIdx.y;
    const int qt0 = blockIdx.x;
    const int tid = threadIdx.x;
    const int wid = tid >> 5;
    const int lid = tid & 31;
    const int g = lid >> 2;
    const int t = lid & 3;
    const int wm = wid * 32;
    const int rows[4] = {wm + g, wm + g + 8, wm + g + 16, wm + g + 24};

    const uint32_t qaddr = smem_u32(s.qs);
    const uint32_t kaddr = smem_u32(s.kt);
    const uint32_t vaddr = smem_u32(s.vs);
    const uint32_t rhaddr = smem_u32(s.rh16);
    const uint32_t rwaddr = smem_u32(s.rw16);

    const uint32_t bB = (uint32_t)((lid & 7) * 144 + ((lid >> 4) & 1) * 8 * 144 +
                                   ((lid >> 3) & 1) * 16);
    const uint32_t bA = (uint32_t)(((lid & 7) + ((lid >> 3) & 1) * 8) * 144 +
                                   ((lid >> 4) & 1) * 16);

    // ---- prologue group: Q + rh16 + rw16 ----
#pragma unroll
    for (int it = 0; it < 8; it++) {
        int idx = it * 128 + tid;
        int r = idx >> 3, cc = idx & 7;
        int n = qt0 * 128 + r;
        const __half* src = g_q + (n < NN ? (size_t)(bh * NN + n) * HD + cc * 8 : 0);
        cpa16(qaddr + (uint32_t)(r * 144 + cc * 16), src, n < NN ? 16u : 0u);
    }
#pragma unroll
    for (int it = 0; it < 7; it++) {
        int idx = it * 128 + tid;
        int r = idx / 7, cc = idx % 7;
        int n = qt0 * 128 + r;
        const __half* src = g_relh16 + (n < NN ? (size_t)(bh * NN + n) * HH + cc * 8 : 0);
        cpa16(rhaddr + (uint32_t)(r * 112 + cc * 16), src, n < NN ? 16u : 0u);
    }
#pragma unroll
    for (int it = 0; it < 4; it++) {
        int idx = it * 128 + tid;
        int r = idx >> 2, cc = idx & 3;
        int n = qt0 * 128 + r;
        const __half* src = g_relw16 + (n < NN ? (size_t)(bh * NN + n) * 32 + cc * 8 : 0);
        cpa16(rwaddr + (uint32_t)(r * 80 + cc * 16), src, n < NN ? 16u : 0u);
    }
    CPA_COMMIT();

    auto issueKV = [&](int j) {
        const int kb = j * 64;
        const int st = j % 3;
        const uint32_t ka = kaddr + (uint32_t)(st * 64 * 144);
        const uint32_t va = vaddr + (uint32_t)(st * 64 * 144);
#pragma unroll
        for (int it = 0; it < 4; it++) {
            int idx = it * 128 + tid;
            int r = idx >> 3, cc = idx & 7;
            int kn = kb + r;
            bool ok = kn < NN;
            const __half* src = g_k + (ok ? (size_t)(bh * NN + kn) * HD + cc * 8 : 0);
            cpa16(ka + (uint32_t)(r * 144 + cc * 16), src, ok ? 16u : 0u);
        }
#pragma unroll
        for (int it = 0; it < 4; it++) {
            int idx = it * 128 + tid;
            int r = idx >> 3, cc = idx & 7;
            bool ok = (kb + cc * 8 + 8) <= NN;
            const __half* src = g_vt + (ok ? (size_t)(bh * HD + r) * NN + kb + cc * 8 : 0);
            cpa16(va + (uint32_t)(r * 144 + cc * 16), src, ok ? 16u : 0u);
        }
        CPA_COMMIT();
    };

    issueKV(0);
    issueKV(1);

    CPA_WAIT2();
    __syncthreads();
    float bmax[4];
#pragma unroll
    for (int j = 0; j < 4; j++) {
        int r = rows[j];
        float mh = -1e30f, mw = -1e30f;
        for (int kh = 0; kh < HH; kh++)
            mh = fmaxf(mh, __half2float(s.rh16[r * HH + kh]));
        for (int kw = 0; kw < WW; kw++)
            mw = fmaxf(mw, __half2float(s.rw16[r * RWP + kw]));
        bmax[j] = mh + mw;
    }
    uint32_t qf[4][2][4];
#pragma unroll
    for (int kc = 0; kc < 4; kc++)
#pragma unroll
        for (int m = 0; m < 2; m++)
            ldsm4(qf[kc][m], qaddr + (uint32_t)((wm + m * 16) * 144 + kc * 32) + bA);

    float acc[2][8][4];
#pragma unroll
    for (int m = 0; m < 2; m++)
#pragma unroll
        for (int ni = 0; ni < 8; ni++)
#pragma unroll
            for (int e = 0; e < 4; e++) acc[m][ni][e] = 0.f;
    float accL[2][4] = {{0.f, 0.f, 0.f, 0.f}, {0.f, 0.f, 0.f, 0.f}};
    float rowm[4] = {-1e30f, -1e30f, -1e30f, -1e30f};

    const uint32_t ONES2 = 0x3C003C00u;

    for (int kt2 = 0; kt2 < 25; kt2++) {
        const int kbase = kt2 * 64;
        const int p = kt2 % 3;

        if (kt2 < 24) CPA_WAIT1(); else CPA_WAIT0();
        __syncthreads();
        if (kt2 + 2 < 25) issueKV(kt2 + 2);

        const uint32_t kbuf = kaddr + (uint32_t)(p * 64 * 144) + bB;
        const uint32_t vbuf = vaddr + (uint32_t)(p * 64 * 144) + bB;

        float c[2][8][4];
#pragma unroll
        for (int m = 0; m < 2; m++)
#pragma unroll
            for (int ni = 0; ni < 8; ni++)
#pragma unroll
                for (int e = 0; e < 4; e++) c[m][ni][e] = 0.f;
#pragma unroll
        for (int kc = 0; kc < 4; kc++) {
#pragma unroll
            for (int j = 0; j < 4; j++) {
                uint32_t kb4[4];
                ldsm4(kb4, kbuf + (uint32_t)(j * 16 * 144 + kc * 32));
                mma_f16(c[0][2 * j],     qf[kc][0], kb4);
                mma_f16(c[0][2 * j + 1], qf[kc][0], kb4 + 2);
                mma_f16(c[1][2 * j],     qf[kc][1], kb4);
                mma_f16(c[1][2 * j + 1], qf[kc][1], kb4 + 2);
            }
        }

        float tm[4] = {-1e30f, -1e30f, -1e30f, -1e30f};
#pragma unroll
        for (int ni = 0; ni < 8; ni++) {
            tm[0] = fmaxf(tm[0], fmaxf(c[0][ni][0], c[0][ni][1]));
            tm[1] = fmaxf(tm[1], fmaxf(c[0][ni][2], c[0][ni][3]));
            tm[2] = fmaxf(tm[2], fmaxf(c[1][ni][0], c[1][ni][1]));
            tm[3] = fmaxf(tm[3], fmaxf(c[1][ni][2], c[1][ni][3]));
        }
        float mn[4], fac[4];
        __half nm[4];
#pragma unroll
        for (int j = 0; j < 4; j++) {
            float v = tm[j];
            v = fmaxf(v, __shfl_xor_sync(0xffffffffu, v, 1));
            v = fmaxf(v, __shfl_xor_sync(0xffffffffu, v, 2));
            mn[j] = fmaxf(rowm[j], v + bmax[j]);
            fac[j] = fexp2(rowm[j] - mn[j]);
            rowm[j] = mn[j];
            nm[j] = __float2half_rn(-mn[j]);
        }

        uint32_t pf[2][8][2];
#pragma unroll
        for (int ni = 0; ni < 8; ni++) {
            int kn0 = kbase + ni * 8 + 2 * t;
            int kh = ((kn0 >> 2) * 9363) >> 16;
            int kw = kn0 - kh * 28;
#pragma unroll
            for (int m = 0; m < 2; m++) {
                int r0 = rows[2 * m], r1 = rows[2 * m + 1];
                uint32_t rw0 = *(const uint32_t*)&s.rw16[r0 * RWP + kw];
                uint32_t rw1 = *(const uint32_t*)&s.rw16[r1 * RWP + kw];
                __half h0 = __hadd(s.rh16[r0 * HH + kh], nm[2 * m]);
                __half h1 = __hadd(s.rh16[r1 * HH + kh], nm[2 * m + 1]);
                uint32_t b0 = h2add(hdup(h0), rw0);
                uint32_t b1 = h2add(hdup(h1), rw1);
                pf[m][ni][0] = h2exp2(h2add(packh2(c[m][ni][0], c[m][ni][1]), b0));
                pf[m][ni][1] = h2exp2(h2add(packh2(c[m][ni][2], c[m][ni][3]), b1));
            }
            if (kbase + ni * 8 >= NN) {
                pf[0][ni][0] = 0; pf[0][ni][1] = 0;
                pf[1][ni][0] = 0; pf[1][ni][1] = 0;
            }
        }

        if (!(fac[0] == 1.f && fac[1] == 1.f && fac[2] == 1.f && fac[3] == 1.f)) {
#pragma unroll
            for (int ni = 0; ni < 8; ni++) {
                acc[0][ni][0] *= fac[0]; acc[0][ni][1] *= fac[0];
                acc[0][ni][2] *= fac[1]; acc[0][ni][3] *= fac[1];
                acc[1][ni][0] *= fac[2]; acc[1][ni][1] *= fac[2];
                acc[1][ni][2] *= fac[3]; acc[1][ni][3] *= fac[3];
            }
            accL[0][0] *= fac[0]; accL[0][1] *= fac[0];
            accL[0][2] *= fac[1]; accL[0][3] *= fac[1];
            accL[1][0] *= fac[2]; accL[1][1] *= fac[2];
            accL[1][2] *= fac[3]; accL[1][3] *= fac[3];
        }

#pragma unroll
        for (int kc = 0; kc < 4; kc++) {
            uint32_t a0[4] = {pf[0][2 * kc][0], pf[0][2 * kc][1],
                              pf[0][2 * kc + 1][0], pf[0][2 * kc + 1][1]};
            uint32_t a1[4] = {pf[1][2 * kc][0], pf[1][2 * kc][1],
                              pf[1][2 * kc + 1][0], pf[1][2 * kc + 1][1]};
#pragma unroll
            for (int j = 0; j < 4; j++) {
                uint32_t vb4[4];
                ldsm4(vb4, vbuf + (uint32_t)(j * 16 * 144 + kc * 32));
                mma_f16(acc[0][2 * j],     a0, vb4);
                mma_f16(acc[0][2 * j + 1], a0, vb4 + 2);
                mma_f16(acc[1][2 * j],     a1, vb4);
                mma_f16(acc[1][2 * j + 1], a1, vb4 + 2);
            }
            uint32_t bo[2] = {ONES2, ONES2};
            mma_f16(accL[0], a0, bo);
            mma_f16(accL[1], a1, bo);
        }
    }

    // ---- normalize + store g_ao (fp16, k-permuted for mm<1>) ----
    const int b = bh >> 4;
    const int head = bh & 15;
    const int nrow[4] = {qt0 * 128 + rows[0], qt0 * 128 + rows[1],
                         qt0 * 128 + rows[2], qt0 * 128 + rows[3]};
    const float li[4] = {1.f / accL[0][0], 1.f / accL[0][2],
                         1.f / accL[1][0], 1.f / accL[1][2]};
#pragma unroll
    for (int ni = 0; ni < 8; ni++) {
        int col = head * HD + ni * 8 + 2 * t;
        int colp = (col & ~15) + posj((col & 15) >> 1) * 2;
#pragma unroll
        for (int j = 0; j < 4; j++) {
            if (nrow[j] < NN) {
                int m = j >> 1, eo = (j & 1) * 2;
                *(__half2*)&g_ao[(size_t)(b * NN + nrow[j]) * CD + colp] =
                    __floats2half2_rn(acc[m][ni][eo] * li[j], acc[m][ni][eo + 1] * li[j]);
            }
        }
    }
}

// ---------------- launch -----------------------------------------------------
extern "C" void kernel_launch(void* const* d_in, const int* in_sizes, int n_in,
                              void* d_out, int out_size) {
    const float* hidden = (const float*)d_in[0];
    const float* qkv_w  = (const float*)d_in[1];
    const float* qkv_b  = (const float*)d_in[2];
    const float* proj_w = (const float*)d_in[3];
    const float* proj_b = (const float*)d_in[4];
    const float* rph    = (const float*)d_in[5];
    const float* rpw    = (const float*)d_in[6];
    float* out = (float*)d_out;

    cudaFuncSetAttribute(flash13_kernel, cudaFuncAttributeMaxDynamicSharedMemorySize,
                         (int)sizeof(F13Smem));
    cudaFuncSetAttribute(mm_cp<0>, cudaFuncAttributeMaxDynamicSharedMemorySize, MM_SMEM);
    cudaFuncSetAttribute(mm_cp<1>, cudaFuncAttributeMaxDynamicSharedMemorySize, MM_SMEM);

    const int ptot = PREP_N1 + PREP_N2 + PREP_N3;
    prep_all<<<(ptot + 255) / 256, 256>>>(hidden, qkv_w, proj_w);

    // QKV: [6272,3072] = hidden . qkv_w^T
    mm_cp<0><<<dim3(3 * CD / 128, (BN + 255) / 256), 256, MM_SMEM>>>(qkv_b, nullptr);

    relpos_kernel<<<dim3(HH, BHN), 256>>>(rph, rpw);

    flash13_kernel<<<dim3((NN + 127) / 128, BHN), 128, sizeof(F13Smem)>>>();

    // proj: [6272,1024] = g_ao . proj_w^T
    mm_cp<1><<<dim3(CD / 128, (BN + 255) / 256), 256, MM_SMEM>>>(proj_b, out);
}